// round 1
// baseline (speedup 1.0000x reference)
#include <cuda_runtime.h>
#include <math.h>

#define EE 4
#define NTOK 2048
#define DD 512
#define HH 8
#define DHH 64
#define FFD 2048
#define LL 4
#define MMEM 4096

// ---------------- static scratch (allocation-free rule) ----------------
__device__ float g_xln[EE * NTOK * DD];               // LN(tokens)
__device__ float g_x[EE * NTOK * DD];                 // working x / outs
__device__ float g_qkv[NTOK * 3 * DD];
__device__ float g_sa[NTOK * DD];
__device__ float g_y[NTOK * DD];
__device__ float g_ff1buf[NTOK * FFD];
__device__ float g_scores[(size_t)HH * NTOK * NTOK];  // 33.55M floats; also [L][N][M] and [N][3N]
__device__ float g_retr[LL * NTOK * DD];
__device__ float g_retrp[NTOK * LL * DD];
__device__ float g_upd[LL * MMEM * DD];
__device__ float g_pooled[EE * DD];
__device__ float g_gatew[EE];

// ---------------- generic strided SGEMM with fused epilogues ----------------
// C[m,n] = epilogue( alpha * sum_k a(m,k) * b(n,k) )
//   a(m,k) = A[m*Am + k*Ak],  b(n,k) = B[n'*Bn + k'*Bk]
// remap_n / remap_k: add NTOK to that logical index when >= thresh (expert-context gather)
// batch via blockIdx.z with strides Az/Bz/Cz.
// ep: 0 store, 1 clip+-10, 2 +bias, 3 relu(+bias), 4 +bias+res, 5 C+=clip+-1, 6 +res
__global__ void __launch_bounds__(256) sgemm_kernel(
    const float* __restrict__ A, const float* __restrict__ B, float* __restrict__ C,
    int Kdim, int Am, int Ak, int Bn, int Bk, int ldc,
    float alpha, int ep,
    const float* __restrict__ bias, const float* __restrict__ Rres,
    int remap_n, int remap_k, int thresh,
    long Az, long Bz, long Cz)
{
    A += (long)blockIdx.z * Az;
    B += (long)blockIdx.z * Bz;
    C += (long)blockIdx.z * Cz;

    __shared__ float As[16][64];
    __shared__ float Bs[16][64];

    const int tid = threadIdx.x;
    const int tx = tid & 15, ty = tid >> 4;
    const int row0 = blockIdx.y * 64;
    const int col0 = blockIdx.x * 64;

    float acc[4][4] = {};

    for (int k0 = 0; k0 < Kdim; k0 += 16) {
        #pragma unroll
        for (int r = 0; r < 4; r++) {
            int idx = tid + r * 256;
            int m, kk;
            if (Ak == 1) { m = idx >> 4; kk = idx & 15; }
            else         { m = idx & 63; kk = idx >> 6; }
            As[kk][m] = A[(long)(row0 + m) * Am + (long)(k0 + kk) * Ak];
        }
        #pragma unroll
        for (int r = 0; r < 4; r++) {
            int idx = tid + r * 256;
            int n, kk;
            if (Bk == 1) { n = idx >> 4; kk = idx & 15; }
            else         { n = idx & 63; kk = idx >> 6; }
            int ng = col0 + n;
            int kg = k0 + kk;
            if (remap_n && ng >= thresh) ng += NTOK;
            if (remap_k && kg >= thresh) kg += NTOK;
            Bs[kk][n] = B[(long)ng * Bn + (long)kg * Bk];
        }
        __syncthreads();
        #pragma unroll
        for (int kk = 0; kk < 16; kk++) {
            float a[4], b[4];
            #pragma unroll
            for (int i = 0; i < 4; i++) a[i] = As[kk][ty * 4 + i];
            #pragma unroll
            for (int j = 0; j < 4; j++) b[j] = Bs[kk][tx * 4 + j];
            #pragma unroll
            for (int i = 0; i < 4; i++)
                #pragma unroll
                for (int j = 0; j < 4; j++)
                    acc[i][j] += a[i] * b[j];
        }
        __syncthreads();
    }

    #pragma unroll
    for (int i = 0; i < 4; i++) {
        int mg = row0 + ty * 4 + i;
        #pragma unroll
        for (int j = 0; j < 4; j++) {
            int ng = col0 + tx * 4 + j;
            float v = acc[i][j] * alpha;
            long ci = (long)mg * ldc + ng;
            switch (ep) {
            case 0: C[ci] = v; break;
            case 1: C[ci] = fminf(fmaxf(v, -10.f), 10.f); break;
            case 2: C[ci] = v + bias[ng]; break;
            case 3: C[ci] = fmaxf(v + bias[ng], 0.f); break;
            case 4: C[ci] = v + bias[ng] + Rres[ci]; break;
            case 5: C[ci] += fminf(fmaxf(v, -1.f), 1.f); break;
            case 6: C[ci] = v + Rres[ci]; break;
            }
        }
    }
}

// ---------------- LayerNorm over D=512 (optional affine) ----------------
__global__ void ln_kernel(const float* __restrict__ in, float* __restrict__ out,
                          const float* __restrict__ w, const float* __restrict__ b)
{
    const long row = blockIdx.x;
    const float* p = in + row * DD;
    float* q = out + row * DD;
    const int t = threadIdx.x; // 128 threads
    __shared__ float sh[4];

    float v[4];
    float s = 0.f;
    #pragma unroll
    for (int i = 0; i < 4; i++) { v[i] = p[t + i * 128]; s += v[i]; }
    #pragma unroll
    for (int o = 16; o; o >>= 1) s += __shfl_down_sync(0xffffffffu, s, o);
    if ((t & 31) == 0) sh[t >> 5] = s;
    __syncthreads();
    float mu = (sh[0] + sh[1] + sh[2] + sh[3]) * (1.f / DD);
    __syncthreads();

    float sq = 0.f;
    #pragma unroll
    for (int i = 0; i < 4; i++) { float d = v[i] - mu; sq += d * d; }
    #pragma unroll
    for (int o = 16; o; o >>= 1) sq += __shfl_down_sync(0xffffffffu, sq, o);
    if ((t & 31) == 0) sh[t >> 5] = sq;
    __syncthreads();
    float var = (sh[0] + sh[1] + sh[2] + sh[3]) * (1.f / DD);
    float rstd = rsqrtf(var + 1e-5f);

    #pragma unroll
    for (int i = 0; i < 4; i++) {
        int d = t + i * 128;
        float o = (v[i] - mu) * rstd;
        if (w) o = o * w[d] + b[d];
        q[d] = o;
    }
}

// ---------------- row softmax (one block per row) ----------------
__global__ void softmax_kernel(float* __restrict__ S, int cols)
{
    float* row = S + (long)blockIdx.x * cols;
    const int t = threadIdx.x; // 256 threads
    __shared__ float sh[8];

    float m = -1e30f;
    for (int i = t; i < cols; i += 256) m = fmaxf(m, row[i]);
    #pragma unroll
    for (int o = 16; o; o >>= 1) m = fmaxf(m, __shfl_down_sync(0xffffffffu, m, o));
    if ((t & 31) == 0) sh[t >> 5] = m;
    __syncthreads();
    if (t == 0) {
        float mm = sh[0];
        #pragma unroll
        for (int w = 1; w < 8; w++) mm = fmaxf(mm, sh[w]);
        sh[0] = mm;
    }
    __syncthreads();
    m = sh[0];
    __syncthreads();

    float s = 0.f;
    for (int i = t; i < cols; i += 256) { float e = expf(row[i] - m); row[i] = e; s += e; }
    #pragma unroll
    for (int o = 16; o; o >>= 1) s += __shfl_down_sync(0xffffffffu, s, o);
    if ((t & 31) == 0) sh[t >> 5] = s;
    __syncthreads();
    if (t == 0) {
        float ss = 0.f;
        #pragma unroll
        for (int w = 0; w < 8; w++) ss += sh[w];
        sh[0] = ss;
    }
    __syncthreads();
    float inv = 1.f / sh[0];
    for (int i = t; i < cols; i += 256) row[i] *= inv;
}

// ---------------- small utility kernels ----------------
__global__ void zero_kernel(float* p, long n)
{
    long i = (long)blockIdx.x * blockDim.x + threadIdx.x;
    if (i < n) p[i] = 0.f;
}

__global__ void repack_kernel(const float* __restrict__ retr, float* __restrict__ retrp)
{
    long idx = (long)blockIdx.x * blockDim.x + threadIdx.x; // NTOK*LL*DD
    if (idx >= (long)NTOK * LL * DD) return;
    int n = (int)(idx / (LL * DD));
    int r = (int)(idx % (LL * DD));
    int l = r / DD, d = r % DD;
    retrp[idx] = retr[((long)l * NTOK + n) * DD + d];
}

__global__ void pool_kernel(const float* __restrict__ x, float* __restrict__ pooled)
{
    int idx = blockIdx.x * blockDim.x + threadIdx.x; // EE*DD
    if (idx >= EE * DD) return;
    int e = idx / DD, d = idx % DD;
    const float* p = x + (long)e * NTOK * DD + d;
    float s = 0.f;
    for (int n = 0; n < NTOK; n++) s += p[(long)n * DD];
    pooled[idx] = s * (1.f / NTOK);
}

__global__ void gate_kernel(const float* __restrict__ pooled, const float* __restrict__ gate,
                            float* __restrict__ out_gw, float* __restrict__ gdev)
{
    const int t = threadIdx.x; // 128
    const int wid = t >> 5, lane = t & 31;
    __shared__ float logits[4];
    float s = 0.f;
    for (int d = lane; d < DD; d += 32) s += pooled[wid * DD + d] * gate[d];
    #pragma unroll
    for (int o = 16; o; o >>= 1) s += __shfl_down_sync(0xffffffffu, s, o);
    if (lane == 0) logits[wid] = fminf(fmaxf(s, -10.f), 10.f);
    __syncthreads();
    if (t == 0) {
        float mx = fmaxf(fmaxf(logits[0], logits[1]), fmaxf(logits[2], logits[3]));
        float e0 = expf(logits[0] - mx), e1 = expf(logits[1] - mx);
        float e2 = expf(logits[2] - mx), e3 = expf(logits[3] - mx);
        float inv = 1.f / (e0 + e1 + e2 + e3);
        out_gw[0] = gdev[0] = e0 * inv;
        out_gw[1] = gdev[1] = e1 * inv;
        out_gw[2] = gdev[2] = e2 * inv;
        out_gw[3] = gdev[3] = e3 * inv;
    }
}

__global__ void fused_kernel(const float* __restrict__ x, const float* __restrict__ gw,
                             float* __restrict__ out)
{
    long i = (long)blockIdx.x * blockDim.x + threadIdx.x;
    if (i >= (long)NTOK * DD) return;
    float s = 0.f;
    #pragma unroll
    for (int e = 0; e < EE; e++) s += gw[e] * x[(long)e * NTOK * DD + i];
    out[i] = s;
}

__global__ void newmem_kernel(const float* __restrict__ mem, const float* __restrict__ upd,
                              float* __restrict__ out)
{
    long i = (long)blockIdx.x * blockDim.x + threadIdx.x;
    if (i >= (long)LL * MMEM * DD) return;
    float u = 0.1f * upd[i];
    u = fminf(fmaxf(u, -0.1f), 0.1f);
    out[i] = 0.9f * mem[i] + u;
}

// ---------------- host-side GEMM launcher ----------------
static void gemm(const float* A, const float* B, float* C,
                 int Mdim, int Nc, int Kdim,
                 int Am, int Ak, int Bn, int Bk, int ldc,
                 float alpha, int ep, const float* bias, const float* R,
                 int remap_n, int remap_k, int thresh,
                 int batch, long Az, long Bz, long Cz)
{
    dim3 g(Nc / 64, Mdim / 64, batch);
    sgemm_kernel<<<g, 256>>>(A, B, C, Kdim, Am, Ak, Bn, Bk, ldc, alpha, ep,
                             bias, R, remap_n, remap_k, thresh, Az, Bz, Cz);
}

extern "C" void kernel_launch(void* const* d_in, const int* in_sizes, int n_in,
                              void* d_out, int out_size)
{
    const float* tokens   = (const float*)d_in[0];
    const float* memories = (const float*)d_in[1];
    const float* ipw      = (const float*)d_in[2];
    const float* ipb      = (const float*)d_in[3];
    const float* opw      = (const float*)d_in[4];
    const float* opb      = (const float*)d_in[5];
    const float* w1       = (const float*)d_in[6];
    const float* b1       = (const float*)d_in[7];
    const float* w2       = (const float*)d_in[8];
    const float* b2       = (const float*)d_in[9];
    const float* n1w      = (const float*)d_in[10];
    const float* n1b      = (const float*)d_in[11];
    const float* n2w      = (const float*)d_in[12];
    const float* n2b      = (const float*)d_in[13];
    const float* aggw     = (const float*)d_in[14];
    const float* aggb     = (const float*)d_in[15];
    const float* gate     = (const float*)d_in[16];
    float* out = (float*)d_out;

    float *xln, *x, *qkv, *sa, *y, *ff1p, *sc, *retr, *retrp, *upd, *pooled, *gatew;
    cudaGetSymbolAddress((void**)&xln,    g_xln);
    cudaGetSymbolAddress((void**)&x,      g_x);
    cudaGetSymbolAddress((void**)&qkv,    g_qkv);
    cudaGetSymbolAddress((void**)&sa,     g_sa);
    cudaGetSymbolAddress((void**)&y,      g_y);
    cudaGetSymbolAddress((void**)&ff1p,   g_ff1buf);
    cudaGetSymbolAddress((void**)&sc,     g_scores);
    cudaGetSymbolAddress((void**)&retr,   g_retr);
    cudaGetSymbolAddress((void**)&retrp,  g_retrp);
    cudaGetSymbolAddress((void**)&upd,    g_upd);
    cudaGetSymbolAddress((void**)&pooled, g_pooled);
    cudaGetSymbolAddress((void**)&gatew,  g_gatew);

    const float isd = 1.0f / sqrtf((float)DD);

    // LN of all tokens (x and contexts share this)
    ln_kernel<<<EE * NTOK, 128>>>(tokens, xln, nullptr, nullptr);
    // zero update accumulator (re-zeroed on every replay: determinism)
    {
        long n = (long)LL * MMEM * DD;
        zero_kernel<<<(unsigned)((n + 255) / 256), 256>>>(upd, n);
    }

    for (int e = 0; e < EE; e++) {
        const long eoff = (long)e * NTOK * DD;
        const int thr = e * NTOK;

        // ---- cross-expert attention ----
        // S = clip(xln_e @ ctx^T / sqrt(D))   [N, 3N], ctx = xln rows with remap
        gemm(xln + eoff, xln, sc, NTOK, 3 * NTOK, DD,
             DD, 1, DD, 1, 3 * NTOK, isd, 1, nullptr, nullptr,
             1, 0, thr, 1, 0, 0, 0);
        softmax_kernel<<<NTOK, 256>>>(sc, 3 * NTOK);
        // x = xln_e + P @ ctx
        gemm(sc, xln, x + eoff, NTOK, DD, 3 * NTOK,
             3 * NTOK, 1, 1, DD, DD, 1.f, 6, nullptr, xln + eoff,
             0, 1, thr, 1, 0, 0, 0);

        // ---- transformer encoder layer ----
        gemm(x + eoff, ipw + (long)e * 3 * DD * DD, qkv, NTOK, 3 * DD, DD,
             DD, 1, DD, 1, 3 * DD, 1.f, 2, ipb + (long)e * 3 * DD, nullptr,
             0, 0, 0, 1, 0, 0, 0);
        // per-head scores, batched over heads (blockIdx.z)
        gemm(qkv, qkv + DD, sc, NTOK, NTOK, DHH,
             3 * DD, 1, 3 * DD, 1, NTOK, 0.125f, 0, nullptr, nullptr,
             0, 0, 0, HH, DHH, DHH, (long)NTOK * NTOK);
        softmax_kernel<<<HH * NTOK, 256>>>(sc, NTOK);
        // sa = P @ V (batched over heads)
        gemm(sc, qkv + 2 * DD, sa, NTOK, DHH, NTOK,
             NTOK, 1, 1, 3 * DD, DD, 1.f, 0, nullptr, nullptr,
             0, 0, 0, HH, (long)NTOK * NTOK, DHH, DHH);
        // out_proj + residual, then LN*w+b (norm1)
        gemm(sa, opw + (long)e * DD * DD, y, NTOK, DD, DD,
             DD, 1, DD, 1, DD, 1.f, 4, opb + (long)e * DD, x + eoff,
             0, 0, 0, 1, 0, 0, 0);
        ln_kernel<<<NTOK, 128>>>(y, x + eoff, n1w + (long)e * DD, n1b + (long)e * DD);
        // FFN
        gemm(x + eoff, w1 + (long)e * FFD * DD, ff1p, NTOK, FFD, DD,
             DD, 1, DD, 1, FFD, 1.f, 3, b1 + (long)e * FFD, nullptr,
             0, 0, 0, 1, 0, 0, 0);
        gemm(ff1p, w2 + (long)e * DD * FFD, y, NTOK, DD, FFD,
             FFD, 1, FFD, 1, DD, 1.f, 4, b2 + (long)e * DD, x + eoff,
             0, 0, 0, 1, 0, 0, 0);
        ln_kernel<<<NTOK, 128>>>(y, x + eoff, n2w + (long)e * DD, n2b + (long)e * DD);

        // ---- hierarchical memory (batched over L layers) ----
        // scores = clip(x @ mem_l^T / sqrt(D))  [L][N][M]
        gemm(x + eoff, memories, sc, NTOK, MMEM, DD,
             DD, 1, DD, 1, MMEM, isd, 1, nullptr, nullptr,
             0, 0, 0, LL, 0, (long)MMEM * DD, (long)NTOK * MMEM);
        softmax_kernel<<<LL * NTOK, 256>>>(sc, MMEM);
        // retr_l = A @ mem_l   [L][N][D]
        gemm(sc, memories, retr, NTOK, DD, MMEM,
             MMEM, 1, 1, DD, DD, 1.f, 0, nullptr, nullptr,
             0, 0, 0, LL, (long)NTOK * MMEM, (long)MMEM * DD, (long)NTOK * DD);
        // upd_sum_l += clip(A^T @ x, -1, 1)   [L][M][D]
        gemm(sc, x + eoff, upd, MMEM, DD, NTOK,
             1, MMEM, 1, DD, DD, 1.f, 5, nullptr, nullptr,
             0, 0, 0, LL, (long)NTOK * MMEM, 0, (long)MMEM * DD);
        // multi = retr(N, L*D) @ agg_w^T + agg_b ; out = x + multi
        {
            long n = (long)NTOK * LL * DD;
            repack_kernel<<<(unsigned)((n + 255) / 256), 256>>>(retr, retrp);
        }
        gemm(retrp, aggw, x + eoff, NTOK, DD, LL * DD,
             LL * DD, 1, LL * DD, 1, DD, 1.f, 4, aggb, x + eoff,
             0, 0, 0, 1, 0, 0, 0);
    }

    // ---- gating + fusion + memory EMA ----
    pool_kernel<<<(EE * DD + 255) / 256, 256>>>(x, pooled);
    gate_kernel<<<1, 128>>>(pooled, gate, out + (long)NTOK * DD, gatew);
    {
        long n = (long)NTOK * DD;
        fused_kernel<<<(unsigned)((n + 255) / 256), 256>>>(x, gatew, out);
    }
    {
        long n = (long)LL * MMEM * DD;
        newmem_kernel<<<(unsigned)((n + 255) / 256), 256>>>(memories, upd,
                                                            out + (long)NTOK * DD + EE);
    }
}

// round 2
// speedup vs baseline: 1.2278x; 1.2278x over previous
#include <cuda_runtime.h>
#include <math.h>

#define EE 4
#define NTOK 2048
#define DD 512
#define HH 8
#define DHH 64
#define FFD 2048
#define LL 4
#define MMEM 4096

// ---------------- static scratch (allocation-free rule) ----------------
__device__ float g_xln[EE * NTOK * DD];               // LN(tokens)
__device__ float g_x[EE * NTOK * DD];                 // working x / outs
__device__ float g_qkv[NTOK * 3 * DD];
__device__ float g_sa[NTOK * DD];
__device__ float g_y[NTOK * DD];
__device__ float g_ff1buf[NTOK * FFD];
__device__ float g_scores[(size_t)HH * NTOK * NTOK];  // reused as [N,3N] and [L][N][M]
__device__ float g_retr[LL * NTOK * DD];
__device__ float g_retrp[NTOK * LL * DD];
__device__ float g_upd[LL * MMEM * DD];
__device__ float g_pooled[EE * DD];
__device__ float g_gatew[EE];

// ---------------- 128x128x8 double-buffered SGEMM ----------------
// C[m,n] = epilogue( alpha * sum_k a(m,k) * b(n,k) )
//   a(m,k) = A[m*Am + k*Ak]  (requires Ak==1  OR  Am==1)
//   b(n,k) = B[n*Bn + k*Bk]  (requires Bk==1  OR  Bn==1)
// remapB: the non-contiguous ("row") index of B gets +NTOK when >= thresh.
// ep: 0 store, 1 clip+-10, 2 +bias, 3 relu(+bias), 4 +bias+res, 5 C+=clip+-1,
//     6 +res, 7 store clip+-1
template<int BN, int TN>
__global__ void __launch_bounds__(256, 2) sgemm_t(
    const float* __restrict__ A, const float* __restrict__ B, float* __restrict__ C,
    int Kdim, int Am, int Ak, int Bn, int Bk, int ldc,
    float alpha, int ep,
    const float* __restrict__ bias, const float* __restrict__ Rres,
    int remapB, int thresh,
    long Az, long Bz, long Cz)
{
    constexpr int BM = 128, BK = 8, TM = 8;

    A += (long)blockIdx.z * Az;
    B += (long)blockIdx.z * Bz;
    C += (long)blockIdx.z * Cz;

    __shared__ float As[2][BK][BM];
    __shared__ float Bs[2][BK][BN];

    const int tid = threadIdx.x;
    const int tx = tid & 15;          // 16 col groups
    const int ty = tid >> 4;          // 16 row groups
    const int row0 = blockIdx.y * BM;
    const int col0 = blockIdx.x * BN;

    const bool aK = (Ak == 1);
    const bool bK = (Bk == 1);
    const bool bAct = (BN == 128) || (tid < 128);

    float acc[TM][TN] = {};

    auto loadA = [&](int k0) -> float4 {
        if (aK) {
            int m = tid >> 1, k4 = (tid & 1) * 4;
            return *(const float4*)(A + (long)(row0 + m) * Am + (k0 + k4));
        } else {
            int kk = tid >> 5, mg = (tid & 31) * 4;
            return *(const float4*)(A + (row0 + mg) + (long)(k0 + kk) * Ak);
        }
    };
    auto storeA = [&](int buf, float4 v) {
        if (aK) {
            int m = tid >> 1, k4 = (tid & 1) * 4;
            As[buf][k4 + 0][m] = v.x;
            As[buf][k4 + 1][m] = v.y;
            As[buf][k4 + 2][m] = v.z;
            As[buf][k4 + 3][m] = v.w;
        } else {
            int kk = tid >> 5, mg = (tid & 31) * 4;
            *(float4*)&As[buf][kk][mg] = v;
        }
    };
    auto loadB = [&](int k0) -> float4 {
        if (!bAct) return make_float4(0.f, 0.f, 0.f, 0.f);
        if (bK) {
            int n = tid >> 1, k4 = (tid & 1) * 4;
            int ng = col0 + n;
            if (remapB && ng >= thresh) ng += NTOK;
            return *(const float4*)(B + (long)ng * Bn + (k0 + k4));
        } else {
            constexpr int NG = BN / 4;
            int kk = tid / NG, ng4 = (tid % NG) * 4;
            int kg = k0 + kk;
            if (remapB && kg >= thresh) kg += NTOK;
            return *(const float4*)(B + (col0 + ng4) + (long)kg * Bk);
        }
    };
    auto storeB = [&](int buf, float4 v) {
        if (!bAct) return;
        if (bK) {
            int n = tid >> 1, k4 = (tid & 1) * 4;
            Bs[buf][k4 + 0][n] = v.x;
            Bs[buf][k4 + 1][n] = v.y;
            Bs[buf][k4 + 2][n] = v.z;
            Bs[buf][k4 + 3][n] = v.w;
        } else {
            constexpr int NG = BN / 4;
            int kk = tid / NG, ng4 = (tid % NG) * 4;
            *(float4*)&Bs[buf][kk][ng4] = v;
        }
    };
    auto compute = [&](int buf) {
        #pragma unroll
        for (int kk = 0; kk < BK; kk++) {
            float a[TM], b[TN];
            *(float4*)&a[0] = *(const float4*)&As[buf][kk][ty * TM];
            *(float4*)&a[4] = *(const float4*)&As[buf][kk][ty * TM + 4];
            *(float4*)&b[0] = *(const float4*)&Bs[buf][kk][tx * TN];
            if (TN == 8)
                *(float4*)&b[4] = *(const float4*)&Bs[buf][kk][tx * TN + 4];
            #pragma unroll
            for (int i = 0; i < TM; i++)
                #pragma unroll
                for (int j = 0; j < TN; j++)
                    acc[i][j] += a[i] * b[j];
        }
    };

    const int nk = Kdim / BK;
    float4 ra = loadA(0), rb = loadB(0);
    storeA(0, ra); storeB(0, rb);
    __syncthreads();

    for (int t = 0; t < nk; t++) {
        int buf = t & 1;
        if (t + 1 < nk) { ra = loadA((t + 1) * BK); rb = loadB((t + 1) * BK); }
        compute(buf);
        if (t + 1 < nk) {
            storeA(buf ^ 1, ra); storeB(buf ^ 1, rb);
            __syncthreads();
        }
    }

    #pragma unroll
    for (int i = 0; i < TM; i++) {
        int mg = row0 + ty * TM + i;
        #pragma unroll
        for (int j = 0; j < TN; j++) {
            int ng = col0 + tx * TN + j;
            float v = acc[i][j] * alpha;
            long ci = (long)mg * ldc + ng;
            switch (ep) {
            case 0: C[ci] = v; break;
            case 1: C[ci] = fminf(fmaxf(v, -10.f), 10.f); break;
            case 2: C[ci] = v + bias[ng]; break;
            case 3: C[ci] = fmaxf(v + bias[ng], 0.f); break;
            case 4: C[ci] = v + bias[ng] + Rres[ci]; break;
            case 5: C[ci] += fminf(fmaxf(v, -1.f), 1.f); break;
            case 6: C[ci] = v + Rres[ci]; break;
            case 7: C[ci] = fminf(fmaxf(v, -1.f), 1.f); break;
            }
        }
    }
}

// ---------------- LayerNorm over D=512 (optional affine) ----------------
__global__ void ln_kernel(const float* __restrict__ in, float* __restrict__ out,
                          const float* __restrict__ w, const float* __restrict__ b)
{
    const long row = blockIdx.x;
    const float* p = in + row * DD;
    float* q = out + row * DD;
    const int t = threadIdx.x; // 128 threads
    __shared__ float sh[4];

    float v[4];
    float s = 0.f;
    #pragma unroll
    for (int i = 0; i < 4; i++) { v[i] = p[t + i * 128]; s += v[i]; }
    #pragma unroll
    for (int o = 16; o; o >>= 1) s += __shfl_down_sync(0xffffffffu, s, o);
    if ((t & 31) == 0) sh[t >> 5] = s;
    __syncthreads();
    float mu = (sh[0] + sh[1] + sh[2] + sh[3]) * (1.f / DD);
    __syncthreads();

    float sq = 0.f;
    #pragma unroll
    for (int i = 0; i < 4; i++) { float d = v[i] - mu; sq += d * d; }
    #pragma unroll
    for (int o = 16; o; o >>= 1) sq += __shfl_down_sync(0xffffffffu, sq, o);
    if ((t & 31) == 0) sh[t >> 5] = sq;
    __syncthreads();
    float var = (sh[0] + sh[1] + sh[2] + sh[3]) * (1.f / DD);
    float rstd = rsqrtf(var + 1e-5f);

    #pragma unroll
    for (int i = 0; i < 4; i++) {
        int d = t + i * 128;
        float o = (v[i] - mu) * rstd;
        if (w) o = o * w[d] + b[d];
        q[d] = o;
    }
}

// ---------------- row softmax (one block per row) ----------------
__global__ void softmax_kernel(float* __restrict__ S, int cols)
{
    float* row = S + (long)blockIdx.x * cols;
    const int t = threadIdx.x; // 256 threads
    __shared__ float sh[8];

    float m = -1e30f;
    for (int i = t; i < cols; i += 256) m = fmaxf(m, row[i]);
    #pragma unroll
    for (int o = 16; o; o >>= 1) m = fmaxf(m, __shfl_down_sync(0xffffffffu, m, o));
    if ((t & 31) == 0) sh[t >> 5] = m;
    __syncthreads();
    if (t == 0) {
        float mm = sh[0];
        #pragma unroll
        for (int w = 1; w < 8; w++) mm = fmaxf(mm, sh[w]);
        sh[0] = mm;
    }
    __syncthreads();
    m = sh[0];
    __syncthreads();

    float s = 0.f;
    for (int i = t; i < cols; i += 256) { float e = expf(row[i] - m); row[i] = e; s += e; }
    #pragma unroll
    for (int o = 16; o; o >>= 1) s += __shfl_down_sync(0xffffffffu, s, o);
    if ((t & 31) == 0) sh[t >> 5] = s;
    __syncthreads();
    if (t == 0) {
        float ss = 0.f;
        #pragma unroll
        for (int w = 0; w < 8; w++) ss += sh[w];
        sh[0] = ss;
    }
    __syncthreads();
    float inv = 1.f / sh[0];
    for (int i = t; i < cols; i += 256) row[i] *= inv;
}

// ---------------- small utility kernels ----------------
__global__ void repack_kernel(const float* __restrict__ retr, float* __restrict__ retrp)
{
    long idx = (long)blockIdx.x * blockDim.x + threadIdx.x; // NTOK*LL*DD
    if (idx >= (long)NTOK * LL * DD) return;
    int n = (int)(idx / (LL * DD));
    int r = (int)(idx % (LL * DD));
    int l = r / DD, d = r % DD;
    retrp[idx] = retr[((long)l * NTOK + n) * DD + d];
}

__global__ void pool_kernel(const float* __restrict__ x, float* __restrict__ pooled)
{
    int idx = blockIdx.x * blockDim.x + threadIdx.x; // EE*DD
    if (idx >= EE * DD) return;
    int e = idx / DD, d = idx % DD;
    const float* p = x + (long)e * NTOK * DD + d;
    float s = 0.f;
    for (int n = 0; n < NTOK; n++) s += p[(long)n * DD];
    pooled[idx] = s * (1.f / NTOK);
}

__global__ void gate_kernel(const float* __restrict__ pooled, const float* __restrict__ gate,
                            float* __restrict__ out_gw, float* __restrict__ gdev)
{
    const int t = threadIdx.x; // 128
    const int wid = t >> 5, lane = t & 31;
    __shared__ float logits[4];
    float s = 0.f;
    for (int d = lane; d < DD; d += 32) s += pooled[wid * DD + d] * gate[d];
    #pragma unroll
    for (int o = 16; o; o >>= 1) s += __shfl_down_sync(0xffffffffu, s, o);
    if (lane == 0) logits[wid] = fminf(fmaxf(s, -10.f), 10.f);
    __syncthreads();
    if (t == 0) {
        float mx = fmaxf(fmaxf(logits[0], logits[1]), fmaxf(logits[2], logits[3]));
        float e0 = expf(logits[0] - mx), e1 = expf(logits[1] - mx);
        float e2 = expf(logits[2] - mx), e3 = expf(logits[3] - mx);
        float inv = 1.f / (e0 + e1 + e2 + e3);
        out_gw[0] = gdev[0] = e0 * inv;
        out_gw[1] = gdev[1] = e1 * inv;
        out_gw[2] = gdev[2] = e2 * inv;
        out_gw[3] = gdev[3] = e3 * inv;
    }
}

__global__ void fused_kernel(const float* __restrict__ x, const float* __restrict__ gw,
                             float* __restrict__ out)
{
    long i = (long)blockIdx.x * blockDim.x + threadIdx.x;
    if (i >= (long)NTOK * DD) return;
    float s = 0.f;
    #pragma unroll
    for (int e = 0; e < EE; e++) s += gw[e] * x[(long)e * NTOK * DD + i];
    out[i] = s;
}

__global__ void newmem_kernel(const float* __restrict__ mem, const float* __restrict__ upd,
                              float* __restrict__ out)
{
    long i = (long)blockIdx.x * blockDim.x + threadIdx.x;
    if (i >= (long)LL * MMEM * DD) return;
    float u = 0.1f * upd[i];
    u = fminf(fmaxf(u, -0.1f), 0.1f);
    out[i] = 0.9f * mem[i] + u;
}

// ---------------- host-side GEMM launcher ----------------
static void gemm(const float* A, const float* B, float* C,
                 int Mdim, int Nc, int Kdim,
                 int Am, int Ak, int Bn, int Bk, int ldc,
                 float alpha, int ep, const float* bias, const float* R,
                 int remapB, int thresh,
                 int batch, long Az, long Bz, long Cz)
{
    if (Nc % 128 == 0) {
        dim3 g(Nc / 128, Mdim / 128, batch);
        sgemm_t<128, 8><<<g, 256>>>(A, B, C, Kdim, Am, Ak, Bn, Bk, ldc, alpha, ep,
                                    bias, R, remapB, thresh, Az, Bz, Cz);
    } else {
        dim3 g(Nc / 64, Mdim / 128, batch);
        sgemm_t<64, 4><<<g, 256>>>(A, B, C, Kdim, Am, Ak, Bn, Bk, ldc, alpha, ep,
                                   bias, R, remapB, thresh, Az, Bz, Cz);
    }
}

extern "C" void kernel_launch(void* const* d_in, const int* in_sizes, int n_in,
                              void* d_out, int out_size)
{
    const float* tokens   = (const float*)d_in[0];
    const float* memories = (const float*)d_in[1];
    const float* ipw      = (const float*)d_in[2];
    const float* ipb      = (const float*)d_in[3];
    const float* opw      = (const float*)d_in[4];
    const float* opb      = (const float*)d_in[5];
    const float* w1       = (const float*)d_in[6];
    const float* b1       = (const float*)d_in[7];
    const float* w2       = (const float*)d_in[8];
    const float* b2       = (const float*)d_in[9];
    const float* n1w      = (const float*)d_in[10];
    const float* n1b      = (const float*)d_in[11];
    const float* n2w      = (const float*)d_in[12];
    const float* n2b      = (const float*)d_in[13];
    const float* aggw     = (const float*)d_in[14];
    const float* aggb     = (const float*)d_in[15];
    const float* gate     = (const float*)d_in[16];
    float* out = (float*)d_out;

    float *xln, *x, *qkv, *sa, *y, *ff1p, *sc, *retr, *retrp, *upd, *pooled, *gatew;
    cudaGetSymbolAddress((void**)&xln,    g_xln);
    cudaGetSymbolAddress((void**)&x,      g_x);
    cudaGetSymbolAddress((void**)&qkv,    g_qkv);
    cudaGetSymbolAddress((void**)&sa,     g_sa);
    cudaGetSymbolAddress((void**)&y,      g_y);
    cudaGetSymbolAddress((void**)&ff1p,   g_ff1buf);
    cudaGetSymbolAddress((void**)&sc,     g_scores);
    cudaGetSymbolAddress((void**)&retr,   g_retr);
    cudaGetSymbolAddress((void**)&retrp,  g_retrp);
    cudaGetSymbolAddress((void**)&upd,    g_upd);
    cudaGetSymbolAddress((void**)&pooled, g_pooled);
    cudaGetSymbolAddress((void**)&gatew,  g_gatew);

    const float isd = 1.0f / sqrtf((float)DD);

    // LN of all tokens (x and contexts share this)
    ln_kernel<<<EE * NTOK, 128>>>(tokens, xln, nullptr, nullptr);

    for (int e = 0; e < EE; e++) {
        const long eoff = (long)e * NTOK * DD;
        const int thr = e * NTOK;

        // ---- cross-expert attention ----
        // S = clip(xln_e @ ctx^T / sqrt(D))   [N, 3N], ctx = xln rows with remap
        gemm(xln + eoff, xln, sc, NTOK, 3 * NTOK, DD,
             DD, 1, DD, 1, 3 * NTOK, isd, 1, nullptr, nullptr,
             1, thr, 1, 0, 0, 0);
        softmax_kernel<<<NTOK, 256>>>(sc, 3 * NTOK);
        // x = xln_e + P @ ctx
        gemm(sc, xln, x + eoff, NTOK, DD, 3 * NTOK,
             3 * NTOK, 1, 1, DD, DD, 1.f, 6, nullptr, xln + eoff,
             1, thr, 1, 0, 0, 0);

        // ---- transformer encoder layer ----
        gemm(x + eoff, ipw + (long)e * 3 * DD * DD, qkv, NTOK, 3 * DD, DD,
             DD, 1, DD, 1, 3 * DD, 1.f, 2, ipb + (long)e * 3 * DD, nullptr,
             0, 0, 1, 0, 0, 0);
        // per-head scores, batched over heads (blockIdx.z)
        gemm(qkv, qkv + DD, sc, NTOK, NTOK, DHH,
             3 * DD, 1, 3 * DD, 1, NTOK, 0.125f, 0, nullptr, nullptr,
             0, 0, HH, DHH, DHH, (long)NTOK * NTOK);
        softmax_kernel<<<HH * NTOK, 256>>>(sc, NTOK);
        // sa = P @ V (batched over heads)
        gemm(sc, qkv + 2 * DD, sa, NTOK, DHH, NTOK,
             NTOK, 1, 1, 3 * DD, DD, 1.f, 0, nullptr, nullptr,
             0, 0, HH, (long)NTOK * NTOK, DHH, DHH);
        // out_proj + residual, then LN*w+b (norm1)
        gemm(sa, opw + (long)e * DD * DD, y, NTOK, DD, DD,
             DD, 1, DD, 1, DD, 1.f, 4, opb + (long)e * DD, x + eoff,
             0, 0, 1, 0, 0, 0);
        ln_kernel<<<NTOK, 128>>>(y, x + eoff, n1w + (long)e * DD, n1b + (long)e * DD);
        // FFN
        gemm(x + eoff, w1 + (long)e * FFD * DD, ff1p, NTOK, FFD, DD,
             DD, 1, DD, 1, FFD, 1.f, 3, b1 + (long)e * FFD, nullptr,
             0, 0, 1, 0, 0, 0);
        gemm(ff1p, w2 + (long)e * DD * FFD, y, NTOK, DD, FFD,
             FFD, 1, FFD, 1, DD, 1.f, 4, b2 + (long)e * DD, x + eoff,
             0, 0, 1, 0, 0, 0);
        ln_kernel<<<NTOK, 128>>>(y, x + eoff, n2w + (long)e * DD, n2b + (long)e * DD);

        // ---- hierarchical memory (batched over L layers) ----
        // scores = clip(x @ mem_l^T / sqrt(D))  [L][N][M]
        gemm(x + eoff, memories, sc, NTOK, MMEM, DD,
             DD, 1, DD, 1, MMEM, isd, 1, nullptr, nullptr,
             0, 0, LL, 0, (long)MMEM * DD, (long)NTOK * MMEM);
        softmax_kernel<<<LL * NTOK, 256>>>(sc, MMEM);
        // retr_l = A @ mem_l   [L][N][D]
        gemm(sc, memories, retr, NTOK, DD, MMEM,
             MMEM, 1, 1, DD, DD, 1.f, 0, nullptr, nullptr,
             0, 0, LL, (long)NTOK * MMEM, (long)MMEM * DD, (long)NTOK * DD);
        // upd_l (+)= clip(A^T @ x, -1, 1)   [L][M][D]; e==0 stores, others accumulate
        gemm(sc, x + eoff, upd, MMEM, DD, NTOK,
             1, MMEM, 1, DD, DD, 1.f, (e == 0) ? 7 : 5, nullptr, nullptr,
             0, 0, LL, (long)NTOK * MMEM, 0, (long)MMEM * DD);
        // multi = retr(N, L*D) @ agg_w^T + agg_b ; out = x + multi
        {
            long n = (long)NTOK * LL * DD;
            repack_kernel<<<(unsigned)((n + 255) / 256), 256>>>(retr, retrp);
        }
        gemm(retrp, aggw, x + eoff, NTOK, DD, LL * DD,
             LL * DD, 1, LL * DD, 1, DD, 1.f, 4, aggb, x + eoff,
             0, 0, 1, 0, 0, 0);
    }

    // ---- gating + fusion + memory EMA ----
    pool_kernel<<<(EE * DD + 255) / 256, 256>>>(x, pooled);
    gate_kernel<<<1, 128>>>(pooled, gate, out + (long)NTOK * DD, gatew);
    {
        long n = (long)NTOK * DD;
        fused_kernel<<<(unsigned)((n + 255) / 256), 256>>>(x, gatew, out);
    }
    {
        long n = (long)LL * MMEM * DD;
        newmem_kernel<<<(unsigned)((n + 255) / 256), 256>>>(memories, upd,
                                                            out + (long)NTOK * DD + EE);
    }
}

// round 4
// speedup vs baseline: 2.4308x; 1.9799x over previous
#include <cuda_runtime.h>
#include <cuda_bf16.h>
#include <math.h>
#include <stdint.h>

#define EE 4
#define NTOK 2048
#define DD 512
#define HH 8
#define DHH 64
#define FFD 2048
#define LL 4
#define MMEM 4096

typedef __nv_bfloat16 bf16;

// ---------------- static scratch (allocation-free rule) ----------------
__device__ float g_xln[EE * NTOK * DD];
__device__ float g_x[EE * NTOK * DD];
__device__ float g_y[NTOK * DD];
__device__ float g_scores[(size_t)HH * NTOK * NTOK];
__device__ float g_retr[LL * NTOK * DD];
__device__ float g_upd[LL * MMEM * DD];
__device__ float g_pooled[EE * DD];
__device__ float g_gatew[EE];

__device__ bf16 g_xlnh[EE * NTOK * DD], g_xlnl[EE * NTOK * DD];
__device__ bf16 g_xh[NTOK * DD], g_xl[NTOK * DD];
__device__ bf16 g_qkvh[NTOK * 3 * DD], g_qkvl[NTOK * 3 * DD];
__device__ bf16 g_sah[NTOK * DD], g_sal[NTOK * DD];
__device__ bf16 g_ff1h[NTOK * FFD], g_ff1l[NTOK * FFD];
__device__ bf16 g_sch[(size_t)HH * NTOK * NTOK], g_scl[(size_t)HH * NTOK * NTOK];
__device__ bf16 g_retrph[NTOK * LL * DD];
__device__ bf16 g_memh[LL * MMEM * DD];
__device__ bf16 g_ipwh[EE * 3 * DD * DD], g_ipwl[EE * 3 * DD * DD];
__device__ bf16 g_opwh[EE * DD * DD], g_opwl[EE * DD * DD];
__device__ bf16 g_w1h[EE * FFD * DD], g_w1l[EE * FFD * DD];
__device__ bf16 g_w2h[EE * DD * FFD], g_w2l[EE * DD * FFD];
__device__ bf16 g_aggwh[DD * LL * DD];

__device__ __forceinline__ void split_bf16(float v, bf16& h, bf16& l) {
    h = __float2bfloat16(v);
    l = __float2bfloat16(v - __bfloat162float(h));
}

#define MMA16816(d, a0, a1, a2, a3, b0, b1) \
    asm volatile("mma.sync.aligned.m16n8k16.row.col.f32.bf16.bf16.f32 " \
                 "{%0,%1,%2,%3}, {%4,%5,%6,%7}, {%8,%9}, {%0,%1,%2,%3};" \
                 : "+f"((d)[0]), "+f"((d)[1]), "+f"((d)[2]), "+f"((d)[3]) \
                 : "r"(a0), "r"(a1), "r"(a2), "r"(a3), "r"(b0), "r"(b1))

// ---------------- HMMA bf16 GEMM (128 x BN x 32 tiles, double-buffered) ----------------
// C[m,n] = ep( alpha * sum_k a(m,k) b(n,k) )
// a(m,k) = A[m*Arow + k] (tA=0) or A[k*Arow + m] (tA=1); same for B with n.
// remapB: gmem row index of B (n if tB=0, k if tB=1) gets +NTOK when >= thresh.
// NS=3: D = Ah Bh + Ah Bl + Al Bh ; NS=1: D = Ah Bh
// ep: 0 none, 1 clip±10, 2 +bias, 3 relu+bias, 4 +bias+res, 5 C+=clip±1, 6 +res, 7 clip±1
template<int BN, int NS>
__global__ void __launch_bounds__(256) hgemm(
    const bf16* __restrict__ Ahg, const bf16* __restrict__ Alg,
    const bf16* __restrict__ Bhg, const bf16* __restrict__ Blg,
    float* __restrict__ C, bf16* __restrict__ Ch, bf16* __restrict__ Cl,
    int Kdim, int Arow, int tA, int Brow, int tB, int ldc,
    float alpha, int ep,
    const float* __restrict__ bias, const float* __restrict__ Rres,
    int remapB, int thresh,
    long Az, long Bz, long Cz)
{
    constexpr int ATILE = 128 * 40;
    constexpr int BTILE = BN * 40;
    constexpr int NT = BN / 32;        // n8-tiles per warp
    constexpr int BIT = (BN * 4) / 256;

    Ahg += (long)blockIdx.z * Az; Bhg += (long)blockIdx.z * Bz;
    if (NS == 3) { Alg += (long)blockIdx.z * Az; Blg += (long)blockIdx.z * Bz; }
    if (C)  C  += (long)blockIdx.z * Cz;
    if (Ch) { Ch += (long)blockIdx.z * Cz; Cl += (long)blockIdx.z * Cz; }
    if (Rres) Rres += (long)blockIdx.z * Cz;

    extern __shared__ bf16 dsm[];
    bf16* sAh = dsm;
    bf16* sBh = sAh + 2 * ATILE;
    bf16* sAl = sBh + 2 * BTILE;
    bf16* sBl = sAl + 2 * ATILE;

    const int tid = threadIdx.x;
    const int lane = tid & 31;
    const int wid = tid >> 5;
    const int wm = (wid >> 2) * 64;
    const int wn = (wid & 3) * (BN / 4);
    const int row0 = blockIdx.y * 128;
    const int col0 = blockIdx.x * BN;

    float acc[4][NT][4];
    #pragma unroll
    for (int i = 0; i < 4; i++)
        #pragma unroll
        for (int j = 0; j < NT; j++)
            #pragma unroll
            for (int r = 0; r < 4; r++) acc[i][j][r] = 0.f;

    uint4 pah[2], pal[2], pbh[BIT], pbl[BIT];

    auto loadA = [&](int k0) {
        #pragma unroll
        for (int r = 0; r < 2; r++) {
            int idx = tid + r * 256;
            long go;
            if (!tA) { int row = idx >> 2, seg = idx & 3;
                go = (long)(row0 + row) * Arow + k0 + seg * 8; }
            else { int k = idx >> 4, m8 = (idx & 15) * 8;
                go = (long)(k0 + k) * Arow + row0 + m8; }
            pah[r] = *(const uint4*)(Ahg + go);
            if (NS == 3) pal[r] = *(const uint4*)(Alg + go);
        }
    };
    auto storeA = [&](int buf) {
        bf16* dh = sAh + buf * ATILE;
        bf16* dl = sAl + buf * ATILE;
        #pragma unroll
        for (int r = 0; r < 2; r++) {
            int idx = tid + r * 256;
            if (!tA) {
                int row = idx >> 2, seg = idx & 3;
                *(uint4*)(dh + row * 40 + seg * 8) = pah[r];
                if (NS == 3) *(uint4*)(dl + row * 40 + seg * 8) = pal[r];
            } else {
                int k = idx >> 4, m8 = (idx & 15) * 8;
                const bf16* ph = (const bf16*)&pah[r];
                const bf16* pl = (const bf16*)&pal[r];
                #pragma unroll
                for (int i = 0; i < 8; i++) {
                    dh[(m8 + i) * 40 + k] = ph[i];
                    if (NS == 3) dl[(m8 + i) * 40 + k] = pl[i];
                }
            }
        }
    };
    auto loadB = [&](int k0) {
        #pragma unroll
        for (int r = 0; r < BIT; r++) {
            int idx = tid + r * 256;
            long go;
            if (!tB) { int row = idx >> 2, seg = idx & 3;
                int ng = col0 + row;
                if (remapB && ng >= thresh) ng += NTOK;
                go = (long)ng * Brow + k0 + seg * 8; }
            else { int k = idx / (BN / 8), n8 = (idx % (BN / 8)) * 8;
                int kg = k0 + k;
                if (remapB && kg >= thresh) kg += NTOK;
                go = (long)kg * Brow + col0 + n8; }
            pbh[r] = *(const uint4*)(Bhg + go);
            if (NS == 3) pbl[r] = *(const uint4*)(Blg + go);
        }
    };
    auto storeB = [&](int buf) {
        bf16* dh = sBh + buf * BTILE;
        bf16* dl = sBl + buf * BTILE;
        #pragma unroll
        for (int r = 0; r < BIT; r++) {
            int idx = tid + r * 256;
            if (!tB) {
                int row = idx >> 2, seg = idx & 3;
                *(uint4*)(dh + row * 40 + seg * 8) = pbh[r];
                if (NS == 3) *(uint4*)(dl + row * 40 + seg * 8) = pbl[r];
            } else {
                int k = idx / (BN / 8), n8 = (idx % (BN / 8)) * 8;
                const bf16* ph = (const bf16*)&pbh[r];
                const bf16* pl = (const bf16*)&pbl[r];
                #pragma unroll
                for (int i = 0; i < 8; i++) {
                    dh[(n8 + i) * 40 + k] = ph[i];
                    if (NS == 3) dl[(n8 + i) * 40 + k] = pl[i];
                }
            }
        }
    };
    auto compute = [&](int buf) {
        const bf16* ah = sAh + buf * ATILE;
        const bf16* al = sAl + buf * ATILE;
        const bf16* bh = sBh + buf * BTILE;
        const bf16* bl = sBl + buf * BTILE;
        #pragma unroll
        for (int s = 0; s < 2; s++) {
            const int kb = s * 16 + (lane & 3) * 2;
            uint32_t fbh[NT][2], fbl[NT][2];
            #pragma unroll
            for (int nt = 0; nt < NT; nt++) {
                int n = wn + nt * 8 + (lane >> 2);
                fbh[nt][0] = *(const uint32_t*)(bh + n * 40 + kb);
                fbh[nt][1] = *(const uint32_t*)(bh + n * 40 + kb + 8);
                if (NS == 3) {
                    fbl[nt][0] = *(const uint32_t*)(bl + n * 40 + kb);
                    fbl[nt][1] = *(const uint32_t*)(bl + n * 40 + kb + 8);
                }
            }
            #pragma unroll
            for (int mt = 0; mt < 4; mt++) {
                int m = wm + mt * 16 + (lane >> 2);
                uint32_t a0 = *(const uint32_t*)(ah + m * 40 + kb);
                uint32_t a1 = *(const uint32_t*)(ah + (m + 8) * 40 + kb);
                uint32_t a2 = *(const uint32_t*)(ah + m * 40 + kb + 8);
                uint32_t a3 = *(const uint32_t*)(ah + (m + 8) * 40 + kb + 8);
                #pragma unroll
                for (int nt = 0; nt < NT; nt++)
                    MMA16816(acc[mt][nt], a0, a1, a2, a3, fbh[nt][0], fbh[nt][1]);
                if (NS == 3) {
                    #pragma unroll
                    for (int nt = 0; nt < NT; nt++)
                        MMA16816(acc[mt][nt], a0, a1, a2, a3, fbl[nt][0], fbl[nt][1]);
                    uint32_t l0 = *(const uint32_t*)(al + m * 40 + kb);
                    uint32_t l1 = *(const uint32_t*)(al + (m + 8) * 40 + kb);
                    uint32_t l2 = *(const uint32_t*)(al + m * 40 + kb + 8);
                    uint32_t l3 = *(const uint32_t*)(al + (m + 8) * 40 + kb + 8);
                    #pragma unroll
                    for (int nt = 0; nt < NT; nt++)
                        MMA16816(acc[mt][nt], l0, l1, l2, l3, fbh[nt][0], fbh[nt][1]);
                }
            }
        }
    };

    const int nk = Kdim / 32;
    loadA(0); loadB(0);
    storeA(0); storeB(0);
    __syncthreads();

    for (int t = 0; t < nk; t++) {
        int buf = t & 1;
        if (t + 1 < nk) { loadA((t + 1) * 32); loadB((t + 1) * 32); }
        compute(buf);
        if (t + 1 < nk) {
            storeA(buf ^ 1); storeB(buf ^ 1);
            __syncthreads();
        }
    }

    // epilogue
    #pragma unroll
    for (int mt = 0; mt < 4; mt++) {
        #pragma unroll
        for (int nt = 0; nt < NT; nt++) {
            #pragma unroll
            for (int rg = 0; rg < 4; rg++) {
                int mg = row0 + wm + mt * 16 + (lane >> 2) + ((rg >= 2) ? 8 : 0);
                int ng = col0 + wn + nt * 8 + (lane & 3) * 2 + (rg & 1);
                long ci = (long)mg * ldc + ng;
                float v = acc[mt][nt][rg] * alpha;
                switch (ep) {
                case 1: v = fminf(fmaxf(v, -10.f), 10.f); break;
                case 2: v += bias[ng]; break;
                case 3: v = fmaxf(v + bias[ng], 0.f); break;
                case 4: v += bias[ng] + Rres[ci]; break;
                case 5: v = C[ci] + fminf(fmaxf(v, -1.f), 1.f); break;
                case 6: v += Rres[ci]; break;
                case 7: v = fminf(fmaxf(v, -1.f), 1.f); break;
                }
                if (C) C[ci] = v;
                if (Ch) { bf16 h, l; split_bf16(v, h, l); Ch[ci] = h; Cl[ci] = l; }
            }
        }
    }
}

// ---------------- elementwise kernels ----------------
__global__ void convert_kernel(const float* __restrict__ src, bf16* __restrict__ h,
                               bf16* __restrict__ l, long n)
{
    long i = (long)blockIdx.x * blockDim.x + threadIdx.x;
    if (i >= n) return;
    bf16 hh, ll;
    split_bf16(src[i], hh, ll);
    h[i] = hh;
    if (l) l[i] = ll;
}

__global__ void ln_kernel(const float* __restrict__ in, float* __restrict__ out,
                          const float* __restrict__ w, const float* __restrict__ b,
                          bf16* __restrict__ oh, bf16* __restrict__ ol)
{
    const long row = blockIdx.x;
    const float* p = in + row * DD;
    const int t = threadIdx.x; // 128
    __shared__ float sh[4];

    float v[4];
    float s = 0.f;
    #pragma unroll
    for (int i = 0; i < 4; i++) { v[i] = p[t + i * 128]; s += v[i]; }
    #pragma unroll
    for (int o = 16; o; o >>= 1) s += __shfl_down_sync(0xffffffffu, s, o);
    if ((t & 31) == 0) sh[t >> 5] = s;
    __syncthreads();
    float mu = (sh[0] + sh[1] + sh[2] + sh[3]) * (1.f / DD);
    __syncthreads();
    float sq = 0.f;
    #pragma unroll
    for (int i = 0; i < 4; i++) { float d = v[i] - mu; sq += d * d; }
    #pragma unroll
    for (int o = 16; o; o >>= 1) sq += __shfl_down_sync(0xffffffffu, sq, o);
    if ((t & 31) == 0) sh[t >> 5] = sq;
    __syncthreads();
    float rstd = rsqrtf((sh[0] + sh[1] + sh[2] + sh[3]) * (1.f / DD) + 1e-5f);

    #pragma unroll
    for (int i = 0; i < 4; i++) {
        int d = t + i * 128;
        float o = (v[i] - mu) * rstd;
        if (w) o = o * w[d] + b[d];
        long gi = row * DD + d;
        if (out) out[gi] = o;
        bf16 hh, ll; split_bf16(o, hh, ll);
        oh[gi] = hh; ol[gi] = ll;
    }
}

__global__ void softmax_kernel(float* __restrict__ S, bf16* __restrict__ Oh,
                               bf16* __restrict__ Ol, int cols)
{
    float* row = S + (long)blockIdx.x * cols;
    bf16* oh = Oh + (long)blockIdx.x * cols;
    bf16* ol = Ol ? Ol + (long)blockIdx.x * cols : nullptr;
    const int t = threadIdx.x; // 256
    __shared__ float sh[8];

    float m = -1e30f;
    for (int i = t; i < cols; i += 256) m = fmaxf(m, row[i]);
    #pragma unroll
    for (int o = 16; o; o >>= 1) m = fmaxf(m, __shfl_down_sync(0xffffffffu, m, o));
    if ((t & 31) == 0) sh[t >> 5] = m;
    __syncthreads();
    if (t == 0) {
        float mm = sh[0];
        #pragma unroll
        for (int w = 1; w < 8; w++) mm = fmaxf(mm, sh[w]);
        sh[0] = mm;
    }
    __syncthreads();
    m = sh[0];
    __syncthreads();

    float s = 0.f;
    for (int i = t; i < cols; i += 256) { float e = expf(row[i] - m); row[i] = e; s += e; }
    #pragma unroll
    for (int o = 16; o; o >>= 1) s += __shfl_down_sync(0xffffffffu, s, o);
    if ((t & 31) == 0) sh[t >> 5] = s;
    __syncthreads();
    if (t == 0) {
        float ss = 0.f;
        #pragma unroll
        for (int w = 0; w < 8; w++) ss += sh[w];
        sh[0] = ss;
    }
    __syncthreads();
    float inv = 1.f / sh[0];
    for (int i = t; i < cols; i += 256) {
        float v = row[i] * inv;
        bf16 hh, ll; split_bf16(v, hh, ll);
        oh[i] = hh;
        if (ol) ol[i] = ll;
    }
}

__global__ void repack_kernel(const float* __restrict__ retr, bf16* __restrict__ oh)
{
    long idx = (long)blockIdx.x * blockDim.x + threadIdx.x;
    if (idx >= (long)NTOK * LL * DD) return;
    int n = (int)(idx / (LL * DD));
    int r = (int)(idx % (LL * DD));
    int l = r / DD, d = r % DD;
    oh[idx] = __float2bfloat16(retr[((long)l * NTOK + n) * DD + d]);
}

__global__ void pool_kernel(const float* __restrict__ x, float* __restrict__ pooled)
{
    int idx = blockIdx.x * blockDim.x + threadIdx.x;
    if (idx >= EE * DD) return;
    int e = idx / DD, d = idx % DD;
    const float* p = x + (long)e * NTOK * DD + d;
    float s = 0.f;
    for (int n = 0; n < NTOK; n++) s += p[(long)n * DD];
    pooled[idx] = s * (1.f / NTOK);
}

__global__ void gate_kernel(const float* __restrict__ pooled, const float* __restrict__ gate,
                            float* __restrict__ out_gw, float* __restrict__ gdev)
{
    const int t = threadIdx.x;
    const int wid = t >> 5, lane = t & 31;
    __shared__ float logits[4];
    float s = 0.f;
    for (int d = lane; d < DD; d += 32) s += pooled[wid * DD + d] * gate[d];
    #pragma unroll
    for (int o = 16; o; o >>= 1) s += __shfl_down_sync(0xffffffffu, s, o);
    if (lane == 0) logits[wid] = fminf(fmaxf(s, -10.f), 10.f);
    __syncthreads();
    if (t == 0) {
        float mx = fmaxf(fmaxf(logits[0], logits[1]), fmaxf(logits[2], logits[3]));
        float e0 = expf(logits[0] - mx), e1 = expf(logits[1] - mx);
        float e2 = expf(logits[2] - mx), e3 = expf(logits[3] - mx);
        float inv = 1.f / (e0 + e1 + e2 + e3);
        out_gw[0] = gdev[0] = e0 * inv;
        out_gw[1] = gdev[1] = e1 * inv;
        out_gw[2] = gdev[2] = e2 * inv;
        out_gw[3] = gdev[3] = e3 * inv;
    }
}

__global__ void fused_kernel(const float* __restrict__ x, const float* __restrict__ gw,
                             float* __restrict__ out)
{
    long i = (long)blockIdx.x * blockDim.x + threadIdx.x;
    if (i >= (long)NTOK * DD) return;
    float s = 0.f;
    #pragma unroll
    for (int e = 0; e < EE; e++) s += gw[e] * x[(long)e * NTOK * DD + i];
    out[i] = s;
}

__global__ void newmem_kernel(const float* __restrict__ mem, const float* __restrict__ upd,
                              float* __restrict__ out)
{
    long i = (long)blockIdx.x * blockDim.x + threadIdx.x;
    if (i >= (long)LL * MMEM * DD) return;
    float u = 0.1f * upd[i];
    u = fminf(fmaxf(u, -0.1f), 0.1f);
    out[i] = 0.9f * mem[i] + u;
}

// ---------------- host-side launcher ----------------
static void hg(const bf16* Ah, const bf16* Al, const bf16* Bh, const bf16* Bl,
               float* C, bf16* Ch, bf16* Cl,
               int Mdim, int Nc, int Kdim, int Arow, int tA, int Brow, int tB,
               int ldc, float alpha, int ep, const float* bias, const float* R,
               int remapB, int thresh, int batch, long Az, long Bz, long Cz, int NS)
{
    if (Nc % 128 == 0) {
        dim3 g(Nc / 128, Mdim / 128, batch);
        if (NS == 3)
            hgemm<128, 3><<<g, 256, 81920>>>(Ah, Al, Bh, Bl, C, Ch, Cl, Kdim, Arow, tA,
                                             Brow, tB, ldc, alpha, ep, bias, R,
                                             remapB, thresh, Az, Bz, Cz);
        else
            hgemm<128, 1><<<g, 256, 40960>>>(Ah, Al, Bh, Bl, C, Ch, Cl, Kdim, Arow, tA,
                                             Brow, tB, ldc, alpha, ep, bias, R,
                                             remapB, thresh, Az, Bz, Cz);
    } else {
        dim3 g(Nc / 64, Mdim / 128, batch);
        hgemm<64, 3><<<g, 256, 61440>>>(Ah, Al, Bh, Bl, C, Ch, Cl, Kdim, Arow, tA,
                                        Brow, tB, ldc, alpha, ep, bias, R,
                                        remapB, thresh, Az, Bz, Cz);
    }
}

static void conv(const float* s, bf16* h, bf16* l, long n)
{
    convert_kernel<<<(unsigned)((n + 255) / 256), 256>>>(s, h, l, n);
}

extern "C" void kernel_launch(void* const* d_in, const int* in_sizes, int n_in,
                              void* d_out, int out_size)
{
    const float* tokens   = (const float*)d_in[0];
    const float* memories = (const float*)d_in[1];
    const float* ipw      = (const float*)d_in[2];
    const float* ipb      = (const float*)d_in[3];
    const float* opw      = (const float*)d_in[4];
    const float* opb      = (const float*)d_in[5];
    const float* w1       = (const float*)d_in[6];
    const float* b1       = (const float*)d_in[7];
    const float* w2       = (const float*)d_in[8];
    const float* b2       = (const float*)d_in[9];
    const float* n1w      = (const float*)d_in[10];
    const float* n1b      = (const float*)d_in[11];
    const float* n2w      = (const float*)d_in[12];
    const float* n2b      = (const float*)d_in[13];
    const float* aggw     = (const float*)d_in[14];
    const float* aggb     = (const float*)d_in[15];
    const float* gate     = (const float*)d_in[16];
    float* out = (float*)d_out;

    static bool inited = false;
    if (!inited) {
        cudaFuncSetAttribute(hgemm<128, 3>, cudaFuncAttributeMaxDynamicSharedMemorySize, 81920);
        cudaFuncSetAttribute(hgemm<128, 1>, cudaFuncAttributeMaxDynamicSharedMemorySize, 40960);
        cudaFuncSetAttribute(hgemm<64, 3>,  cudaFuncAttributeMaxDynamicSharedMemorySize, 61440);
        inited = true;
    }

    float *xln, *x, *y, *sc, *retr, *upd, *pooled, *gatew;
    cudaGetSymbolAddress((void**)&xln, g_xln);
    cudaGetSymbolAddress((void**)&x, g_x);
    cudaGetSymbolAddress((void**)&y, g_y);
    cudaGetSymbolAddress((void**)&sc, g_scores);
    cudaGetSymbolAddress((void**)&retr, g_retr);
    cudaGetSymbolAddress((void**)&upd, g_upd);
    cudaGetSymbolAddress((void**)&pooled, g_pooled);
    cudaGetSymbolAddress((void**)&gatew, g_gatew);

    bf16 *xlnh, *xlnl, *xh, *xl, *qkvh, *qkvl, *sah, *sal, *ff1h, *ff1l;
    bf16 *sch, *scl, *retrph, *memh;
    bf16 *ipwh, *ipwl, *opwh, *opwl, *w1h, *w1l, *w2h, *w2l, *aggwh;
    cudaGetSymbolAddress((void**)&xlnh, g_xlnh);   cudaGetSymbolAddress((void**)&xlnl, g_xlnl);
    cudaGetSymbolAddress((void**)&xh, g_xh);       cudaGetSymbolAddress((void**)&xl, g_xl);
    cudaGetSymbolAddress((void**)&qkvh, g_qkvh);   cudaGetSymbolAddress((void**)&qkvl, g_qkvl);
    cudaGetSymbolAddress((void**)&sah, g_sah);     cudaGetSymbolAddress((void**)&sal, g_sal);
    cudaGetSymbolAddress((void**)&ff1h, g_ff1h);   cudaGetSymbolAddress((void**)&ff1l, g_ff1l);
    cudaGetSymbolAddress((void**)&sch, g_sch);     cudaGetSymbolAddress((void**)&scl, g_scl);
    cudaGetSymbolAddress((void**)&retrph, g_retrph);
    cudaGetSymbolAddress((void**)&memh, g_memh);
    cudaGetSymbolAddress((void**)&ipwh, g_ipwh);   cudaGetSymbolAddress((void**)&ipwl, g_ipwl);
    cudaGetSymbolAddress((void**)&opwh, g_opwh);   cudaGetSymbolAddress((void**)&opwl, g_opwl);
    cudaGetSymbolAddress((void**)&w1h, g_w1h);     cudaGetSymbolAddress((void**)&w1l, g_w1l);
    cudaGetSymbolAddress((void**)&w2h, g_w2h);     cudaGetSymbolAddress((void**)&w2l, g_w2l);
    cudaGetSymbolAddress((void**)&aggwh, g_aggwh);

    const float isd = 1.0f / sqrtf((float)DD);

    conv(ipw, ipwh, ipwl, (long)EE * 3 * DD * DD);
    conv(opw, opwh, opwl, (long)EE * DD * DD);
    conv(w1, w1h, w1l, (long)EE * FFD * DD);
    conv(w2, w2h, w2l, (long)EE * DD * FFD);
    conv(aggw, aggwh, nullptr, (long)DD * LL * DD);
    conv(memories, memh, nullptr, (long)LL * MMEM * DD);

    ln_kernel<<<EE * NTOK, 128>>>(tokens, xln, nullptr, nullptr, xlnh, xlnl);

    for (int e = 0; e < EE; e++) {
        const long eoff = (long)e * NTOK * DD;
        const int thr = e * NTOK;

        // cross-expert scores: S = clip(xln_e @ ctx^T / sqrt(D))  [N, 3N]
        hg(xlnh + eoff, xlnl + eoff, xlnh, xlnl, sc, nullptr, nullptr,
           NTOK, 3 * NTOK, DD, DD, 0, DD, 0, 3 * NTOK, isd, 1, nullptr, nullptr,
           1, thr, 1, 0, 0, 0, 3);
        softmax_kernel<<<NTOK, 256>>>(sc, sch, scl, 3 * NTOK);
        // x = xln_e + P @ ctx   (B transposed, remap on k)
        hg(sch, scl, xlnh, xlnl, x + eoff, xh, xl,
           NTOK, DD, 3 * NTOK, 3 * NTOK, 0, DD, 1, DD, 1.f, 6, nullptr, xln + eoff,
           1, thr, 1, 0, 0, 0, 3);

        // qkv = x @ ipw^T + ipb
        hg(xh, xl, ipwh + (long)e * 3 * DD * DD, ipwl + (long)e * 3 * DD * DD,
           nullptr, qkvh, qkvl,
           NTOK, 3 * DD, DD, DD, 0, DD, 0, 3 * DD, 1.f, 2, ipb + (long)e * 3 * DD,
           nullptr, 0, 0, 1, 0, 0, 0, 3);
        // head scores (batch H)
        hg(qkvh, qkvl, qkvh + DD, qkvl + DD, sc, nullptr, nullptr,
           NTOK, NTOK, DHH, 3 * DD, 0, 3 * DD, 0, NTOK, 0.125f, 0, nullptr, nullptr,
           0, 0, HH, DHH, DHH, (long)NTOK * NTOK, 3);
        softmax_kernel<<<HH * NTOK, 256>>>(sc, sch, scl, NTOK);
        // sa = P @ V (B transposed; batch H)
        hg(sch, scl, qkvh + 2 * DD, qkvl + 2 * DD, nullptr, sah, sal,
           NTOK, DHH, NTOK, NTOK, 0, 3 * DD, 1, DD, 1.f, 0, nullptr, nullptr,
           0, 0, HH, (long)NTOK * NTOK, DHH, DHH, 3);
        // out_proj + bias + residual
        hg(sah, sal, opwh + (long)e * DD * DD, opwl + (long)e * DD * DD,
           y, nullptr, nullptr,
           NTOK, DD, DD, DD, 0, DD, 0, DD, 1.f, 4, opb + (long)e * DD, x + eoff,
           0, 0, 1, 0, 0, 0, 3);
        ln_kernel<<<NTOK, 128>>>(y, x + eoff, n1w + (long)e * DD, n1b + (long)e * DD, xh, xl);
        // FFN
        hg(xh, xl, w1h + (long)e * FFD * DD, w1l + (long)e * FFD * DD,
           nullptr, ff1h, ff1l,
           NTOK, FFD, DD, DD, 0, DD, 0, FFD, 1.f, 3, b1 + (long)e * FFD, nullptr,
           0, 0, 1, 0, 0, 0, 3);
        hg(ff1h, ff1l, w2h + (long)e * DD * FFD, w2l + (long)e * DD * FFD,
           y, nullptr, nullptr,
           NTOK, DD, FFD, FFD, 0, FFD, 0, DD, 1.f, 4, b2 + (long)e * DD, x + eoff,
           0, 0, 1, 0, 0, 0, 3);
        ln_kernel<<<NTOK, 128>>>(y, x + eoff, n2w + (long)e * DD, n2b + (long)e * DD, xh, xl);

        // ---- hierarchical memory: bf16 single (error damped by gamma/agg scale) ----
        // memory scores (batch L)
        hg(xh, xh, memh, memh, sc, nullptr, nullptr,
           NTOK, MMEM, DD, DD, 0, DD, 0, MMEM, isd, 1, nullptr, nullptr,
           0, 0, LL, 0, (long)MMEM * DD, (long)NTOK * MMEM, 1);
        softmax_kernel<<<LL * NTOK, 256>>>(sc, sch, nullptr, MMEM);
        // retr = A @ mem (B transposed; batch L)
        hg(sch, sch, memh, memh, retr, nullptr, nullptr,
           NTOK, DD, MMEM, MMEM, 0, DD, 1, DD, 1.f, 0, nullptr, nullptr,
           0, 0, LL, (long)NTOK * MMEM, (long)MMEM * DD, (long)NTOK * DD, 1);
        // upd (+)= clip(A^T @ x)  (both transposed; batch L)
        hg(sch, sch, xh, xh, upd, nullptr, nullptr,
           MMEM, DD, NTOK, MMEM, 1, DD, 1, DD, 1.f, (e == 0) ? 7 : 5, nullptr, nullptr,
           0, 0, LL, (long)NTOK * MMEM, 0, (long)MMEM * DD, 1);
        {
            long n = (long)NTOK * LL * DD;
            repack_kernel<<<(unsigned)((n + 255) / 256), 256>>>(retr, retrph);
        }
        // x = x + retrp @ agg_w^T + agg_b
        hg(retrph, retrph, aggwh, aggwh, x + eoff, nullptr, nullptr,
           NTOK, DD, LL * DD, LL * DD, 0, LL * DD, 0, DD, 1.f, 4, aggb, x + eoff,
           0, 0, 1, 0, 0, 0, 1);
    }

    pool_kernel<<<(EE * DD + 255) / 256, 256>>>(x, pooled);
    gate_kernel<<<1, 128>>>(pooled, gate, out + (long)NTOK * DD, gatew);
    {
        long n = (long)NTOK * DD;
        fused_kernel<<<(unsigned)((n + 255) / 256), 256>>>(x, gatew, out);
    }
    {
        long n = (long)LL * MMEM * DD;
        newmem_kernel<<<(unsigned)((n + 255) / 256), 256>>>(memories, upd,
                                                            out + (long)NTOK * DD + EE);
    }
}

// round 5
// speedup vs baseline: 4.3504x; 1.7897x over previous
#include <cuda_runtime.h>
#include <cuda_bf16.h>
#include <math.h>
#include <stdint.h>

#define EE 4
#define NTOK 2048
#define DD 512
#define HH 8
#define DHH 64
#define FFD 2048
#define LL 4
#define MMEM 4096

typedef __nv_bfloat16 bf16;

// ---------------- static scratch ----------------
__device__ float g_xln[EE * NTOK * DD];
__device__ float g_x[EE * NTOK * DD];
__device__ float g_y[NTOK * DD];
__device__ float g_scores[(size_t)HH * NTOK * NTOK];
__device__ float g_retr[LL * NTOK * DD];
__device__ float g_upd[LL * MMEM * DD];
__device__ float g_pooled[EE * DD];
__device__ float g_gatew[EE];

__device__ bf16 g_xlnh[EE * NTOK * DD], g_xlnl[EE * NTOK * DD];
__device__ bf16 g_xlnTh[DD * EE * NTOK], g_xlnTl[DD * EE * NTOK];
__device__ bf16 g_xh[NTOK * DD], g_xl[NTOK * DD];
__device__ bf16 g_xTh[DD * NTOK];
__device__ bf16 g_qkvh[NTOK * 3 * DD], g_qkvl[NTOK * 3 * DD];
__device__ bf16 g_vTh[DD * NTOK], g_vTl[DD * NTOK];
__device__ bf16 g_sah[NTOK * DD], g_sal[NTOK * DD];
__device__ bf16 g_ff1h[NTOK * FFD], g_ff1l[NTOK * FFD];
__device__ bf16 g_sch[(size_t)HH * NTOK * NTOK], g_scl[(size_t)HH * NTOK * NTOK];
__device__ bf16 g_schT[(size_t)LL * MMEM * NTOK];
__device__ bf16 g_retrph[NTOK * LL * DD];
__device__ bf16 g_memh[LL * MMEM * DD];
__device__ bf16 g_memTh[LL * DD * MMEM];
__device__ bf16 g_ipwh[EE * 3 * DD * DD], g_ipwl[EE * 3 * DD * DD];
__device__ bf16 g_opwh[EE * DD * DD], g_opwl[EE * DD * DD];
__device__ bf16 g_w1h[EE * FFD * DD], g_w1l[EE * FFD * DD];
__device__ bf16 g_w2h[EE * DD * FFD], g_w2l[EE * DD * FFD];
__device__ bf16 g_aggwh[DD * LL * DD];

__device__ __forceinline__ void split_bf16(float v, bf16& h, bf16& l) {
    h = __float2bfloat16(v);
    l = __float2bfloat16(v - __bfloat162float(h));
}
__device__ __forceinline__ uint32_t smem_u32(const void* p) {
    uint32_t a;
    asm("{ .reg .u64 t; cvta.to.shared.u64 t, %1; cvt.u32.u64 %0, t; }" : "=r"(a) : "l"(p));
    return a;
}

#define MMA16816(d, a0, a1, a2, a3, b0, b1) \
    asm volatile("mma.sync.aligned.m16n8k16.row.col.f32.bf16.bf16.f32 " \
                 "{%0,%1,%2,%3}, {%4,%5,%6,%7}, {%8,%9}, {%0,%1,%2,%3};" \
                 : "+f"((d)[0]), "+f"((d)[1]), "+f"((d)[2]), "+f"((d)[3]) \
                 : "r"(a0), "r"(a1), "r"(a2), "r"(a3), "r"(b0), "r"(b1))

#define LDSM4(r0, r1, r2, r3, addr) \
    asm volatile("ldmatrix.sync.aligned.m8n8.x4.shared.b16 {%0,%1,%2,%3}, [%4];" \
                 : "=r"(r0), "=r"(r1), "=r"(r2), "=r"(r3) : "r"(addr))

#define CP16(dst, src) \
    asm volatile("cp.async.cg.shared.global [%0], [%1], 16;" :: "r"(dst), "l"(src))
#define CPCOMMIT() asm volatile("cp.async.commit_group;")
#define CPWAIT(n)  asm volatile("cp.async.wait_group %0;" :: "n"(n))

// ---------------- HMMA bf16 GEMM: cp.async + ldmatrix pipeline ----------------
// C[m,n] = ep( alpha * sum_k A[m*Arow+k] * B[n*Brow+k] )   (both operands k-contiguous)
// nRemap: B row n += NTOK when >= thresh.  kRemap: B col k += NTOK when k-tile >= thresh.
// NS=3: D = AhBh + AhBl + AlBh ; NS=1: D = AhBh
// ep: 0 none,1 clip±10,2 +bias,3 relu+bias,4 +bias+res,5 C+=clip±1,6 +res,7 clip±1
template<int BN, int NS, int STAGES>
__global__ void __launch_bounds__(256, 2) hgemm(
    const bf16* __restrict__ Ahg, const bf16* __restrict__ Alg,
    const bf16* __restrict__ Bhg, const bf16* __restrict__ Blg,
    float* __restrict__ C, bf16* __restrict__ Ch, bf16* __restrict__ Cl,
    int Kdim, int Arow, int Brow, int ldc,
    float alpha, int ep,
    const float* __restrict__ bias, const float* __restrict__ Rres,
    int nRemap, int kRemap, int thresh,
    long Az, long Bz, long Cz)
{
    constexpr int AST = 128 * 80;           // bytes per A stage per matrix
    constexpr int BST = BN * 80;
    constexpr int NT = BN / 32;
    constexpr int BIT = BN / 64;

    Ahg += (long)blockIdx.z * Az; Bhg += (long)blockIdx.z * Bz;
    if (NS == 3) { Alg += (long)blockIdx.z * Az; Blg += (long)blockIdx.z * Bz; }
    if (C)  C  += (long)blockIdx.z * Cz;
    if (Ch) { Ch += (long)blockIdx.z * Cz; Cl += (long)blockIdx.z * Cz; }
    if (Rres) Rres += (long)blockIdx.z * Cz;

    extern __shared__ char sm[];
    const uint32_t smBase = smem_u32(sm);
    const uint32_t offAh = 0;
    const uint32_t offAl = STAGES * AST;
    const uint32_t offBh = (NS == 3 ? 2u : 1u) * STAGES * AST;
    const uint32_t offBl = offBh + STAGES * BST;

    const int tid = threadIdx.x;
    const int lane = tid & 31;
    const int wid = tid >> 5;
    const int wm = (wid >> 2) * 64;
    const int wn = (wid & 3) * (BN / 4);
    const int row0 = blockIdx.y * 128;
    const int col0 = blockIdx.x * BN;

    const int g = lane >> 3;
    const uint32_t laneOff = ((g & 1) * 8 + (lane & 7)) * 80 + (g >> 1) * 16;

    float acc[4][NT][4];
    #pragma unroll
    for (int i = 0; i < 4; i++)
        #pragma unroll
        for (int j = 0; j < NT; j++)
            #pragma unroll
            for (int r = 0; r < 4; r++) acc[i][j][r] = 0.f;

    auto fill = [&](int s, int t) {
        int k0 = t * 32;
        long kb = k0 + ((kRemap && k0 >= thresh) ? NTOK : 0);
        #pragma unroll
        for (int r = 0; r < 2; r++) {
            int idx = tid + r * 256;
            int row = idx >> 2, c = idx & 3;
            long go = (long)(row0 + row) * Arow + k0 + c * 8;
            uint32_t dst = smBase + offAh + s * AST + row * 80 + c * 16;
            CP16(dst, Ahg + go);
            if (NS == 3) CP16(dst + (offAl - offAh), Alg + go);
        }
        #pragma unroll
        for (int r = 0; r < BIT; r++) {
            int idx = tid + r * 256;
            int row = idx >> 2, c = idx & 3;
            int ng = col0 + row;
            if (nRemap && ng >= thresh) ng += NTOK;
            long go = (long)ng * Brow + kb + c * 8;
            uint32_t dst = smBase + offBh + s * BST + row * 80 + c * 16;
            CP16(dst, Bhg + go);
            if (NS == 3) CP16(dst + (offBl - offBh), Blg + go);
        }
    };

    auto compute = [&](int buf) {
        const uint32_t aH = smBase + offAh + buf * AST + laneOff;
        const uint32_t aL = smBase + offAl + buf * AST + laneOff;
        const uint32_t bH = smBase + offBh + buf * BST + laneOff;
        const uint32_t bL = smBase + offBl + buf * BST + laneOff;
        #pragma unroll
        for (int s = 0; s < 2; s++) {
            uint32_t bh[NT][2], bl[NT][2];
            #pragma unroll
            for (int p = 0; p < NT / 2; p++) {
                uint32_t addr = bH + (wn + p * 16) * 80 + s * 32;
                LDSM4(bh[2*p][0], bh[2*p+1][0], bh[2*p][1], bh[2*p+1][1], addr);
                if (NS == 3) {
                    uint32_t addr2 = bL + (wn + p * 16) * 80 + s * 32;
                    LDSM4(bl[2*p][0], bl[2*p+1][0], bl[2*p][1], bl[2*p+1][1], addr2);
                }
            }
            #pragma unroll
            for (int mt = 0; mt < 4; mt++) {
                uint32_t a0, a1, a2, a3;
                LDSM4(a0, a1, a2, a3, aH + (wm + mt * 16) * 80 + s * 32);
                #pragma unroll
                for (int nt = 0; nt < NT; nt++)
                    MMA16816(acc[mt][nt], a0, a1, a2, a3, bh[nt][0], bh[nt][1]);
                if (NS == 3) {
                    uint32_t l0, l1, l2, l3;
                    LDSM4(l0, l1, l2, l3, aL + (wm + mt * 16) * 80 + s * 32);
                    #pragma unroll
                    for (int nt = 0; nt < NT; nt++)
                        MMA16816(acc[mt][nt], a0, a1, a2, a3, bl[nt][0], bl[nt][1]);
                    #pragma unroll
                    for (int nt = 0; nt < NT; nt++)
                        MMA16816(acc[mt][nt], l0, l1, l2, l3, bh[nt][0], bh[nt][1]);
                }
            }
        }
    };

    const int nk = Kdim / 32;
    #pragma unroll
    for (int s = 0; s < STAGES - 1; s++) {
        if (s < nk) fill(s, s);
        CPCOMMIT();
    }
    for (int t = 0; t < nk; t++) {
        CPWAIT(STAGES - 2);
        __syncthreads();
        int tn = t + STAGES - 1;
        if (tn < nk) fill(tn % STAGES, tn);
        CPCOMMIT();
        compute(t % STAGES);
    }

    // epilogue
    #pragma unroll
    for (int mt = 0; mt < 4; mt++) {
        #pragma unroll
        for (int nt = 0; nt < NT; nt++) {
            #pragma unroll
            for (int rg = 0; rg < 4; rg++) {
                int mg = row0 + wm + mt * 16 + (lane >> 2) + ((rg >= 2) ? 8 : 0);
                int ng = col0 + wn + nt * 8 + (lane & 3) * 2 + (rg & 1);
                long ci = (long)mg * ldc + ng;
                float v = acc[mt][nt][rg] * alpha;
                switch (ep) {
                case 1: v = fminf(fmaxf(v, -10.f), 10.f); break;
                case 2: v += bias[ng]; break;
                case 3: v = fmaxf(v + bias[ng], 0.f); break;
                case 4: v += bias[ng] + Rres[ci]; break;
                case 5: v = C[ci] + fminf(fmaxf(v, -1.f), 1.f); break;
                case 6: v += Rres[ci]; break;
                case 7: v = fminf(fmaxf(v, -1.f), 1.f); break;
                }
                if (C) C[ci] = v;
                if (Ch) { bf16 h, l; split_bf16(v, h, l); Ch[ci] = h; Cl[ci] = l; }
            }
        }
    }
}

// ---------------- transpose (bf16) ----------------
__global__ void transpose_bf16(const bf16* __restrict__ in, bf16* __restrict__ out,
                               int ldin, int ldout, long inz, long outz)
{
    __shared__ bf16 t[32][33];
    in += (long)blockIdx.z * inz;
    out += (long)blockIdx.z * outz;
    int r0 = blockIdx.y * 32, c0 = blockIdx.x * 32;
    int tx = threadIdx.x & 31, ty = threadIdx.x >> 5;  // 256 thr
    #pragma unroll
    for (int i = 0; i < 32; i += 8)
        t[ty + i][tx] = in[(long)(r0 + ty + i) * ldin + c0 + tx];
    __syncthreads();
    #pragma unroll
    for (int i = 0; i < 32; i += 8)
        out[(long)(c0 + ty + i) * ldout + r0 + tx] = t[tx][ty + i];
}

// ---------------- elementwise kernels ----------------
__global__ void convert_kernel(const float* __restrict__ src, bf16* __restrict__ h,
                               bf16* __restrict__ l, long n)
{
    long i = (long)blockIdx.x * blockDim.x + threadIdx.x;
    if (i >= n) return;
    bf16 hh, ll;
    split_bf16(src[i], hh, ll);
    h[i] = hh;
    if (l) l[i] = ll;
}

__global__ void ln_kernel(const float* __restrict__ in, float* __restrict__ out,
                          const float* __restrict__ w, const float* __restrict__ b,
                          bf16* __restrict__ oh, bf16* __restrict__ ol)
{
    const long row = blockIdx.x;
    const float* p = in + row * DD;
    const int t = threadIdx.x; // 128
    __shared__ float sh[4];

    float v[4];
    float s = 0.f;
    #pragma unroll
    for (int i = 0; i < 4; i++) { v[i] = p[t + i * 128]; s += v[i]; }
    #pragma unroll
    for (int o = 16; o; o >>= 1) s += __shfl_down_sync(0xffffffffu, s, o);
    if ((t & 31) == 0) sh[t >> 5] = s;
    __syncthreads();
    float mu = (sh[0] + sh[1] + sh[2] + sh[3]) * (1.f / DD);
    __syncthreads();
    float sq = 0.f;
    #pragma unroll
    for (int i = 0; i < 4; i++) { float d = v[i] - mu; sq += d * d; }
    #pragma unroll
    for (int o = 16; o; o >>= 1) sq += __shfl_down_sync(0xffffffffu, sq, o);
    if ((t & 31) == 0) sh[t >> 5] = sq;
    __syncthreads();
    float rstd = rsqrtf((sh[0] + sh[1] + sh[2] + sh[3]) * (1.f / DD) + 1e-5f);

    #pragma unroll
    for (int i = 0; i < 4; i++) {
        int d = t + i * 128;
        float o = (v[i] - mu) * rstd;
        if (w) o = o * w[d] + b[d];
        long gi = row * DD + d;
        if (out) out[gi] = o;
        bf16 hh, ll; split_bf16(o, hh, ll);
        oh[gi] = hh; ol[gi] = ll;
    }
}

__global__ void softmax_kernel(float* __restrict__ S, bf16* __restrict__ Oh,
                               bf16* __restrict__ Ol, int cols)
{
    float* row = S + (long)blockIdx.x * cols;
    bf16* oh = Oh + (long)blockIdx.x * cols;
    bf16* ol = Ol ? Ol + (long)blockIdx.x * cols : nullptr;
    const int t = threadIdx.x; // 256
    __shared__ float sh[8];

    float m = -1e30f;
    for (int i = t; i < cols; i += 256) m = fmaxf(m, row[i]);
    #pragma unroll
    for (int o = 16; o; o >>= 1) m = fmaxf(m, __shfl_down_sync(0xffffffffu, m, o));
    if ((t & 31) == 0) sh[t >> 5] = m;
    __syncthreads();
    if (t == 0) {
        float mm = sh[0];
        #pragma unroll
        for (int w = 1; w < 8; w++) mm = fmaxf(mm, sh[w]);
        sh[0] = mm;
    }
    __syncthreads();
    m = sh[0];
    __syncthreads();

    float s = 0.f;
    for (int i = t; i < cols; i += 256) { float e = expf(row[i] - m); row[i] = e; s += e; }
    #pragma unroll
    for (int o = 16; o; o >>= 1) s += __shfl_down_sync(0xffffffffu, s, o);
    if ((t & 31) == 0) sh[t >> 5] = s;
    __syncthreads();
    if (t == 0) {
        float ss = 0.f;
        #pragma unroll
        for (int w = 0; w < 8; w++) ss += sh[w];
        sh[0] = ss;
    }
    __syncthreads();
    float inv = 1.f / sh[0];
    for (int i = t; i < cols; i += 256) {
        float v = row[i] * inv;
        bf16 hh, ll; split_bf16(v, hh, ll);
        oh[i] = hh;
        if (ol) ol[i] = ll;
    }
}

__global__ void repack_kernel(const float* __restrict__ retr, bf16* __restrict__ oh)
{
    long idx = (long)blockIdx.x * blockDim.x + threadIdx.x;
    if (idx >= (long)NTOK * LL * DD) return;
    int n = (int)(idx / (LL * DD));
    int r = (int)(idx % (LL * DD));
    int l = r / DD, d = r % DD;
    oh[idx] = __float2bfloat16(retr[((long)l * NTOK + n) * DD + d]);
}

__global__ void pool_kernel(const float* __restrict__ x, float* __restrict__ pooled)
{
    int idx = blockIdx.x * blockDim.x + threadIdx.x;
    if (idx >= EE * DD) return;
    int e = idx / DD, d = idx % DD;
    const float* p = x + (long)e * NTOK * DD + d;
    float s = 0.f;
    for (int n = 0; n < NTOK; n++) s += p[(long)n * DD];
    pooled[idx] = s * (1.f / NTOK);
}

__global__ void gate_kernel(const float* __restrict__ pooled, const float* __restrict__ gate,
                            float* __restrict__ out_gw, float* __restrict__ gdev)
{
    const int t = threadIdx.x;
    const int wid = t >> 5, lane = t & 31;
    __shared__ float logits[4];
    float s = 0.f;
    for (int d = lane; d < DD; d += 32) s += pooled[wid * DD + d] * gate[d];
    #pragma unroll
    for (int o = 16; o; o >>= 1) s += __shfl_down_sync(0xffffffffu, s, o);
    if (lane == 0) logits[wid] = fminf(fmaxf(s, -10.f), 10.f);
    __syncthreads();
    if (t == 0) {
        float mx = fmaxf(fmaxf(logits[0], logits[1]), fmaxf(logits[2], logits[3]));
        float e0 = expf(logits[0] - mx), e1 = expf(logits[1] - mx);
        float e2 = expf(logits[2] - mx), e3 = expf(logits[3] - mx);
        float inv = 1.f / (e0 + e1 + e2 + e3);
        out_gw[0] = gdev[0] = e0 * inv;
        out_gw[1] = gdev[1] = e1 * inv;
        out_gw[2] = gdev[2] = e2 * inv;
        out_gw[3] = gdev[3] = e3 * inv;
    }
}

__global__ void fused_kernel(const float* __restrict__ x, const float* __restrict__ gw,
                             float* __restrict__ out)
{
    long i = (long)blockIdx.x * blockDim.x + threadIdx.x;
    if (i >= (long)NTOK * DD) return;
    float s = 0.f;
    #pragma unroll
    for (int e = 0; e < EE; e++) s += gw[e] * x[(long)e * NTOK * DD + i];
    out[i] = s;
}

__global__ void newmem_kernel(const float* __restrict__ mem, const float* __restrict__ upd,
                              float* __restrict__ out)
{
    long i = (long)blockIdx.x * blockDim.x + threadIdx.x;
    if (i >= (long)LL * MMEM * DD) return;
    float u = 0.1f * upd[i];
    u = fminf(fmaxf(u, -0.1f), 0.1f);
    out[i] = 0.9f * mem[i] + u;
}

// ---------------- host-side launcher ----------------
static void hg(const bf16* Ah, const bf16* Al, const bf16* Bh, const bf16* Bl,
               float* C, bf16* Ch, bf16* Cl,
               int Mdim, int Nc, int Kdim, int Arow, int Brow,
               int ldc, float alpha, int ep, const float* bias, const float* R,
               int nRemap, int kRemap, int thresh, int batch,
               long Az, long Bz, long Cz, int NS)
{
    if (NS == 3) {
        if (Nc % 128 == 0) {
            dim3 g(Nc / 128, Mdim / 128, batch);
            hgemm<128, 3, 2><<<g, 256, 81920>>>(Ah, Al, Bh, Bl, C, Ch, Cl, Kdim, Arow,
                                                Brow, ldc, alpha, ep, bias, R,
                                                nRemap, kRemap, thresh, Az, Bz, Cz);
        } else {
            dim3 g(Nc / 64, Mdim / 128, batch);
            hgemm<64, 3, 2><<<g, 256, 61440>>>(Ah, Al, Bh, Bl, C, Ch, Cl, Kdim, Arow,
                                               Brow, ldc, alpha, ep, bias, R,
                                               nRemap, kRemap, thresh, Az, Bz, Cz);
        }
    } else {
        dim3 g(Nc / 128, Mdim / 128, batch);
        hgemm<128, 1, 3><<<g, 256, 61440>>>(Ah, Ah, Bh, Bh, C, Ch, Cl, Kdim, Arow,
                                            Brow, ldc, alpha, ep, bias, R,
                                            nRemap, kRemap, thresh, Az, Bz, Cz);
    }
}

static void tr(const bf16* in, bf16* out, int R, int C, int ldin, int ldout,
               int batch, long inz, long outz)
{
    dim3 g(C / 32, R / 32, batch);
    transpose_bf16<<<g, 256>>>(in, out, ldin, ldout, inz, outz);
}

static void conv(const float* s, bf16* h, bf16* l, long n)
{
    convert_kernel<<<(unsigned)((n + 255) / 256), 256>>>(s, h, l, n);
}

extern "C" void kernel_launch(void* const* d_in, const int* in_sizes, int n_in,
                              void* d_out, int out_size)
{
    const float* tokens   = (const float*)d_in[0];
    const float* memories = (const float*)d_in[1];
    const float* ipw      = (const float*)d_in[2];
    const float* ipb      = (const float*)d_in[3];
    const float* opw      = (const float*)d_in[4];
    const float* opb      = (const float*)d_in[5];
    const float* w1       = (const float*)d_in[6];
    const float* b1       = (const float*)d_in[7];
    const float* w2       = (const float*)d_in[8];
    const float* b2       = (const float*)d_in[9];
    const float* n1w      = (const float*)d_in[10];
    const float* n1b      = (const float*)d_in[11];
    const float* n2w      = (const float*)d_in[12];
    const float* n2b      = (const float*)d_in[13];
    const float* aggw     = (const float*)d_in[14];
    const float* aggb     = (const float*)d_in[15];
    const float* gate     = (const float*)d_in[16];
    float* out = (float*)d_out;

    static bool inited = false;
    if (!inited) {
        cudaFuncSetAttribute((const void*)hgemm<128, 3, 2>, cudaFuncAttributeMaxDynamicSharedMemorySize, 81920);
        cudaFuncSetAttribute((const void*)hgemm<64, 3, 2>,  cudaFuncAttributeMaxDynamicSharedMemorySize, 61440);
        cudaFuncSetAttribute((const void*)hgemm<128, 1, 3>, cudaFuncAttributeMaxDynamicSharedMemorySize, 61440);
        inited = true;
    }

    float *xln, *x, *y, *sc, *retr, *upd, *pooled, *gatew;
    cudaGetSymbolAddress((void**)&xln, g_xln);
    cudaGetSymbolAddress((void**)&x, g_x);
    cudaGetSymbolAddress((void**)&y, g_y);
    cudaGetSymbolAddress((void**)&sc, g_scores);
    cudaGetSymbolAddress((void**)&retr, g_retr);
    cudaGetSymbolAddress((void**)&upd, g_upd);
    cudaGetSymbolAddress((void**)&pooled, g_pooled);
    cudaGetSymbolAddress((void**)&gatew, g_gatew);

    bf16 *xlnh, *xlnl, *xlnTh, *xlnTl, *xh, *xl, *xTh, *qkvh, *qkvl, *vTh, *vTl;
    bf16 *sah, *sal, *ff1h, *ff1l, *sch, *scl, *schT, *retrph, *memh, *memTh;
    bf16 *ipwh, *ipwl, *opwh, *opwl, *w1h, *w1l, *w2h, *w2l, *aggwh;
    cudaGetSymbolAddress((void**)&xlnh, g_xlnh);   cudaGetSymbolAddress((void**)&xlnl, g_xlnl);
    cudaGetSymbolAddress((void**)&xlnTh, g_xlnTh); cudaGetSymbolAddress((void**)&xlnTl, g_xlnTl);
    cudaGetSymbolAddress((void**)&xh, g_xh);       cudaGetSymbolAddress((void**)&xl, g_xl);
    cudaGetSymbolAddress((void**)&xTh, g_xTh);
    cudaGetSymbolAddress((void**)&qkvh, g_qkvh);   cudaGetSymbolAddress((void**)&qkvl, g_qkvl);
    cudaGetSymbolAddress((void**)&vTh, g_vTh);     cudaGetSymbolAddress((void**)&vTl, g_vTl);
    cudaGetSymbolAddress((void**)&sah, g_sah);     cudaGetSymbolAddress((void**)&sal, g_sal);
    cudaGetSymbolAddress((void**)&ff1h, g_ff1h);   cudaGetSymbolAddress((void**)&ff1l, g_ff1l);
    cudaGetSymbolAddress((void**)&sch, g_sch);     cudaGetSymbolAddress((void**)&scl, g_scl);
    cudaGetSymbolAddress((void**)&schT, g_schT);
    cudaGetSymbolAddress((void**)&retrph, g_retrph);
    cudaGetSymbolAddress((void**)&memh, g_memh);   cudaGetSymbolAddress((void**)&memTh, g_memTh);
    cudaGetSymbolAddress((void**)&ipwh, g_ipwh);   cudaGetSymbolAddress((void**)&ipwl, g_ipwl);
    cudaGetSymbolAddress((void**)&opwh, g_opwh);   cudaGetSymbolAddress((void**)&opwl, g_opwl);
    cudaGetSymbolAddress((void**)&w1h, g_w1h);     cudaGetSymbolAddress((void**)&w1l, g_w1l);
    cudaGetSymbolAddress((void**)&w2h, g_w2h);     cudaGetSymbolAddress((void**)&w2l, g_w2l);
    cudaGetSymbolAddress((void**)&aggwh, g_aggwh);

    const float isd = 1.0f / sqrtf((float)DD);

    conv(ipw, ipwh, ipwl, (long)EE * 3 * DD * DD);
    conv(opw, opwh, opwl, (long)EE * DD * DD);
    conv(w1, w1h, w1l, (long)EE * FFD * DD);
    conv(w2, w2h, w2l, (long)EE * DD * FFD);
    conv(aggw, aggwh, nullptr, (long)DD * LL * DD);
    conv(memories, memh, nullptr, (long)LL * MMEM * DD);
    // memT[l][d][m] once
    tr(memh, memTh, MMEM, DD, DD, MMEM, LL, (long)MMEM * DD, (long)DD * MMEM);

    ln_kernel<<<EE * NTOK, 128>>>(tokens, xln, nullptr, nullptr, xlnh, xlnl);
    // xlnT [D][4N]
    tr(xlnh, xlnTh, EE * NTOK, DD, DD, EE * NTOK, 1, 0, 0);
    tr(xlnl, xlnTl, EE * NTOK, DD, DD, EE * NTOK, 1, 0, 0);

    for (int e = 0; e < EE; e++) {
        const long eoff = (long)e * NTOK * DD;
        const int thr = e * NTOK;

        // cross scores: S = clip(xln_e @ ctx^T / sqrt(D))  [N, 3N]  (remap on n)
        hg(xlnh + eoff, xlnl + eoff, xlnh, xlnl, sc, nullptr, nullptr,
           NTOK, 3 * NTOK, DD, DD, DD, 3 * NTOK, isd, 1, nullptr, nullptr,
           1, 0, thr, 1, 0, 0, 0, 3);
        softmax_kernel<<<NTOK, 256>>>(sc, sch, scl, 3 * NTOK);
        // x = xln_e + P @ ctx   (B = xlnT, remap on k)
        hg(sch, scl, xlnTh, xlnTl, x + eoff, xh, xl,
           NTOK, DD, 3 * NTOK, 3 * NTOK, EE * NTOK, DD, 1.f, 6, nullptr, xln + eoff,
           0, 1, thr, 1, 0, 0, 0, 3);

        // qkv = x @ ipw^T + ipb
        hg(xh, xl, ipwh + (long)e * 3 * DD * DD, ipwl + (long)e * 3 * DD * DD,
           nullptr, qkvh, qkvl,
           NTOK, 3 * DD, DD, DD, DD, 3 * DD, 1.f, 2, ipb + (long)e * 3 * DD,
           nullptr, 0, 0, 0, 1, 0, 0, 0, 3);
        // vT [512][2048] from qkv V block
        tr(qkvh + 2 * DD, vTh, NTOK, DD, 3 * DD, NTOK, 1, 0, 0);
        tr(qkvl + 2 * DD, vTl, NTOK, DD, 3 * DD, NTOK, 1, 0, 0);
        // head scores (batch H)
        hg(qkvh, qkvl, qkvh + DD, qkvl + DD, sc, nullptr, nullptr,
           NTOK, NTOK, DHH, 3 * DD, 3 * DD, NTOK, 0.125f, 0, nullptr, nullptr,
           0, 0, 0, HH, DHH, DHH, (long)NTOK * NTOK, 3);
        softmax_kernel<<<HH * NTOK, 256>>>(sc, sch, scl, NTOK);
        // sa = P @ V  (B = vT; batch H)
        hg(sch, scl, vTh, vTl, nullptr, sah, sal,
           NTOK, DHH, NTOK, NTOK, NTOK, DD, 1.f, 0, nullptr, nullptr,
           0, 0, 0, HH, (long)NTOK * NTOK, (long)DHH * NTOK, DHH, 3);
        // out_proj + bias + residual
        hg(sah, sal, opwh + (long)e * DD * DD, opwl + (long)e * DD * DD,
           y, nullptr, nullptr,
           NTOK, DD, DD, DD, DD, DD, 1.f, 4, opb + (long)e * DD, x + eoff,
           0, 0, 0, 1, 0, 0, 0, 3);
        ln_kernel<<<NTOK, 128>>>(y, x + eoff, n1w + (long)e * DD, n1b + (long)e * DD, xh, xl);
        // FFN
        hg(xh, xl, w1h + (long)e * FFD * DD, w1l + (long)e * FFD * DD,
           nullptr, ff1h, ff1l,
           NTOK, FFD, DD, DD, DD, FFD, 1.f, 3, b1 + (long)e * FFD, nullptr,
           0, 0, 0, 1, 0, 0, 0, 3);
        hg(ff1h, ff1l, w2h + (long)e * DD * FFD, w2l + (long)e * DD * FFD,
           y, nullptr, nullptr,
           NTOK, DD, FFD, FFD, FFD, DD, 1.f, 4, b2 + (long)e * DD, x + eoff,
           0, 0, 0, 1, 0, 0, 0, 3);
        ln_kernel<<<NTOK, 128>>>(y, x + eoff, n2w + (long)e * DD, n2b + (long)e * DD, xh, xl);
        // xT for upd
        tr(xh, xTh, NTOK, DD, DD, NTOK, 1, 0, 0);

        // memory scores (batch L)
        hg(xh, xh, memh, memh, sc, nullptr, nullptr,
           NTOK, MMEM, DD, DD, DD, MMEM, isd, 1, nullptr, nullptr,
           0, 0, 0, LL, 0, (long)MMEM * DD, (long)NTOK * MMEM, 1);
        softmax_kernel<<<LL * NTOK, 256>>>(sc, sch, nullptr, MMEM);
        // schT [L][M][N]
        tr(sch, schT, NTOK, MMEM, MMEM, NTOK, LL, (long)NTOK * MMEM, (long)NTOK * MMEM);
        // retr = A @ mem  (B = memT; batch L)
        hg(sch, sch, memTh, memTh, retr, nullptr, nullptr,
           NTOK, DD, MMEM, MMEM, MMEM, DD, 1.f, 0, nullptr, nullptr,
           0, 0, 0, LL, (long)NTOK * MMEM, (long)DD * MMEM, (long)NTOK * DD, 1);
        // upd (+)= clip(A^T @ x)  (A = schT, B = xT; batch L)
        hg(schT, schT, xTh, xTh, upd, nullptr, nullptr,
           MMEM, DD, NTOK, NTOK, NTOK, DD, 1.f, (e == 0) ? 7 : 5, nullptr, nullptr,
           0, 0, 0, LL, (long)MMEM * NTOK, 0, (long)MMEM * DD, 1);
        {
            long n = (long)NTOK * LL * DD;
            repack_kernel<<<(unsigned)((n + 255) / 256), 256>>>(retr, retrph);
        }
        // x = x + retrp @ agg_w^T + agg_b
        hg(retrph, retrph, aggwh, aggwh, x + eoff, nullptr, nullptr,
           NTOK, DD, LL * DD, LL * DD, LL * DD, DD, 1.f, 4, aggb, x + eoff,
           0, 0, 0, 1, 0, 0, 0, 1);
    }

    pool_kernel<<<(EE * DD + 255) / 256, 256>>>(x, pooled);
    gate_kernel<<<1, 128>>>(pooled, gate, out + (long)NTOK * DD, gatew);
    {
        long n = (long)NTOK * DD;
        fused_kernel<<<(unsigned)((n + 255) / 256), 256>>>(x, gatew, out);
    }
    {
        long n = (long)LL * MMEM * DD;
        newmem_kernel<<<(unsigned)((n + 255) / 256), 256>>>(memories, upd,
                                                            out + (long)NTOK * DD + EE);
    }
}

// round 6
// speedup vs baseline: 4.3799x; 1.0068x over previous
#include <cuda_runtime.h>
#include <cuda_bf16.h>
#include <math.h>
#include <stdint.h>

#define EE 4
#define NTOK 2048
#define DD 512
#define HH 8
#define DHH 64
#define FFD 2048
#define LL 4
#define MMEM 4096

typedef __nv_bfloat16 bf16;

// ---------------- static scratch ----------------
__device__ float g_xln[EE * NTOK * DD];
__device__ float g_x[EE * NTOK * DD];
__device__ float g_y[NTOK * DD];
__device__ float g_scores[(size_t)HH * NTOK * NTOK];
__device__ float g_upd[LL * MMEM * DD];
__device__ float g_pooled[EE * DD];
__device__ float g_gatew[EE];

__device__ bf16 g_xlnh[EE * NTOK * DD], g_xlnl[EE * NTOK * DD];
__device__ bf16 g_xlnTh[DD * EE * NTOK], g_xlnTl[DD * EE * NTOK];
__device__ bf16 g_xh[NTOK * DD], g_xl[NTOK * DD];
__device__ bf16 g_xTh[DD * NTOK];
__device__ bf16 g_qkvh[NTOK * 3 * DD], g_qkvl[NTOK * 3 * DD];
__device__ bf16 g_vTh[DD * NTOK], g_vTl[DD * NTOK];
__device__ bf16 g_sah[NTOK * DD], g_sal[NTOK * DD];
__device__ bf16 g_ff1h[NTOK * FFD], g_ff1l[NTOK * FFD];
__device__ bf16 g_sch[(size_t)HH * NTOK * NTOK], g_scl[(size_t)HH * NTOK * NTOK];
__device__ bf16 g_schT[(size_t)LL * MMEM * NTOK];
__device__ bf16 g_retrph[NTOK * LL * DD];
__device__ bf16 g_memh[LL * MMEM * DD];
__device__ bf16 g_memTh[LL * DD * MMEM];
__device__ bf16 g_ipwh[EE * 3 * DD * DD], g_ipwl[EE * 3 * DD * DD];
__device__ bf16 g_opwh[EE * DD * DD], g_opwl[EE * DD * DD];
__device__ bf16 g_w1h[EE * FFD * DD], g_w1l[EE * FFD * DD];
__device__ bf16 g_w2h[EE * DD * FFD], g_w2l[EE * DD * FFD];
__device__ bf16 g_aggwh[DD * LL * DD];

__device__ __forceinline__ void split_bf16(float v, bf16& h, bf16& l) {
    h = __float2bfloat16(v);
    l = __float2bfloat16(v - __bfloat162float(h));
}
__device__ __forceinline__ uint32_t smem_u32(const void* p) {
    uint32_t a;
    asm("{ .reg .u64 t; cvta.to.shared.u64 t, %1; cvt.u32.u64 %0, t; }" : "=r"(a) : "l"(p));
    return a;
}

#define MMA16816(d, a0, a1, a2, a3, b0, b1) \
    asm volatile("mma.sync.aligned.m16n8k16.row.col.f32.bf16.bf16.f32 " \
                 "{%0,%1,%2,%3}, {%4,%5,%6,%7}, {%8,%9}, {%0,%1,%2,%3};" \
                 : "+f"((d)[0]), "+f"((d)[1]), "+f"((d)[2]), "+f"((d)[3]) \
                 : "r"(a0), "r"(a1), "r"(a2), "r"(a3), "r"(b0), "r"(b1))

#define LDSM4(r0, r1, r2, r3, addr) \
    asm volatile("ldmatrix.sync.aligned.m8n8.x4.shared.b16 {%0,%1,%2,%3}, [%4];" \
                 : "=r"(r0), "=r"(r1), "=r"(r2), "=r"(r3) : "r"(addr))

#define CP16(dst, src) \
    asm volatile("cp.async.cg.shared.global [%0], [%1], 16;" :: "r"(dst), "l"(src))
#define CPCOMMIT() asm volatile("cp.async.commit_group;")
#define CPWAIT(n)  asm volatile("cp.async.wait_group %0;" :: "n"(n))

// ---------------- HMMA bf16 GEMM: cp.async + ldmatrix pipeline ----------------
// C[m,n] = ep( alpha * sum_k A[m*Arow+k] * B[n*Brow+k] )
// nRemap: B row n += NTOK when >= thresh.  kRemap: B col k += NTOK when k-tile >= thresh.
// NS=3: D = AhBh + AhBl + AlBh ; NS=1: D = AhBh
// ep: 0 none,1 clip±10,2 +bias,3 relu+bias,4 +bias+res,5 C+=clip±1,6 +res,7 clip±1
template<int BN, int NS, int STAGES>
__global__ void __launch_bounds__(256, 2) hgemm(
    const bf16* __restrict__ Ahg, const bf16* __restrict__ Alg,
    const bf16* __restrict__ Bhg, const bf16* __restrict__ Blg,
    float* __restrict__ C, bf16* __restrict__ Ch, bf16* __restrict__ Cl,
    int Kdim, int Arow, int Brow, int ldc,
    float alpha, int ep,
    const float* __restrict__ bias, const float* __restrict__ Rres,
    int nRemap, int kRemap, int thresh,
    long Az, long Bz, long Cz)
{
    constexpr int AST = 128 * 80;
    constexpr int BST = BN * 80;
    constexpr int NT = BN / 32;
    constexpr int BIT = BN / 64;

    Ahg += (long)blockIdx.z * Az; Bhg += (long)blockIdx.z * Bz;
    if (NS == 3) { Alg += (long)blockIdx.z * Az; Blg += (long)blockIdx.z * Bz; }
    if (C)  C  += (long)blockIdx.z * Cz;
    if (Ch) Ch += (long)blockIdx.z * Cz;
    if (Cl) Cl += (long)blockIdx.z * Cz;
    if (Rres) Rres += (long)blockIdx.z * Cz;

    extern __shared__ char sm[];
    const uint32_t smBase = smem_u32(sm);
    const uint32_t offAh = 0;
    const uint32_t offAl = STAGES * AST;
    const uint32_t offBh = (NS == 3 ? 2u : 1u) * STAGES * AST;
    const uint32_t offBl = offBh + STAGES * BST;

    const int tid = threadIdx.x;
    const int lane = tid & 31;
    const int wid = tid >> 5;
    const int wm = (wid >> 2) * 64;
    const int wn = (wid & 3) * (BN / 4);
    const int row0 = blockIdx.y * 128;
    const int col0 = blockIdx.x * BN;

    const int g = lane >> 3;
    const uint32_t laneOff = ((g & 1) * 8 + (lane & 7)) * 80 + (g >> 1) * 16;

    float acc[4][NT][4];
    #pragma unroll
    for (int i = 0; i < 4; i++)
        #pragma unroll
        for (int j = 0; j < NT; j++)
            #pragma unroll
            for (int r = 0; r < 4; r++) acc[i][j][r] = 0.f;

    auto fill = [&](int s, int t) {
        int k0 = t * 32;
        long kb = k0 + ((kRemap && k0 >= thresh) ? NTOK : 0);
        #pragma unroll
        for (int r = 0; r < 2; r++) {
            int idx = tid + r * 256;
            int row = idx >> 2, c = idx & 3;
            long go = (long)(row0 + row) * Arow + k0 + c * 8;
            uint32_t dst = smBase + offAh + s * AST + row * 80 + c * 16;
            CP16(dst, Ahg + go);
            if (NS == 3) CP16(dst + (offAl - offAh), Alg + go);
        }
        #pragma unroll
        for (int r = 0; r < BIT; r++) {
            int idx = tid + r * 256;
            int row = idx >> 2, c = idx & 3;
            int ng = col0 + row;
            if (nRemap && ng >= thresh) ng += NTOK;
            long go = (long)ng * Brow + kb + c * 8;
            uint32_t dst = smBase + offBh + s * BST + row * 80 + c * 16;
            CP16(dst, Bhg + go);
            if (NS == 3) CP16(dst + (offBl - offBh), Blg + go);
        }
    };

    auto compute = [&](int buf) {
        const uint32_t aH = smBase + offAh + buf * AST + laneOff;
        const uint32_t aL = smBase + offAl + buf * AST + laneOff;
        const uint32_t bH = smBase + offBh + buf * BST + laneOff;
        const uint32_t bL = smBase + offBl + buf * BST + laneOff;
        #pragma unroll
        for (int s = 0; s < 2; s++) {
            uint32_t bh[NT][2], bl[NT][2];
            #pragma unroll
            for (int p = 0; p < NT / 2; p++) {
                uint32_t addr = bH + (wn + p * 16) * 80 + s * 32;
                LDSM4(bh[2*p][0], bh[2*p+1][0], bh[2*p][1], bh[2*p+1][1], addr);
                if (NS == 3) {
                    uint32_t addr2 = bL + (wn + p * 16) * 80 + s * 32;
                    LDSM4(bl[2*p][0], bl[2*p+1][0], bl[2*p][1], bl[2*p+1][1], addr2);
                }
            }
            #pragma unroll
            for (int mt = 0; mt < 4; mt++) {
                uint32_t a0, a1, a2, a3;
                LDSM4(a0, a1, a2, a3, aH + (wm + mt * 16) * 80 + s * 32);
                #pragma unroll
                for (int nt = 0; nt < NT; nt++)
                    MMA16816(acc[mt][nt], a0, a1, a2, a3, bh[nt][0], bh[nt][1]);
                if (NS == 3) {
                    uint32_t l0, l1, l2, l3;
                    LDSM4(l0, l1, l2, l3, aL + (wm + mt * 16) * 80 + s * 32);
                    #pragma unroll
                    for (int nt = 0; nt < NT; nt++)
                        MMA16816(acc[mt][nt], a0, a1, a2, a3, bl[nt][0], bl[nt][1]);
                    #pragma unroll
                    for (int nt = 0; nt < NT; nt++)
                        MMA16816(acc[mt][nt], l0, l1, l2, l3, bh[nt][0], bh[nt][1]);
                }
            }
        }
    };

    const int nk = Kdim / 32;
    #pragma unroll
    for (int s = 0; s < STAGES - 1; s++) {
        if (s < nk) fill(s, s);
        CPCOMMIT();
    }
    for (int t = 0; t < nk; t++) {
        CPWAIT(STAGES - 2);
        __syncthreads();
        int tn = t + STAGES - 1;
        if (tn < nk) fill(tn % STAGES, tn);
        CPCOMMIT();
        compute(t % STAGES);
    }

    // epilogue
    #pragma unroll
    for (int mt = 0; mt < 4; mt++) {
        #pragma unroll
        for (int nt = 0; nt < NT; nt++) {
            #pragma unroll
            for (int rg = 0; rg < 4; rg++) {
                int mg = row0 + wm + mt * 16 + (lane >> 2) + ((rg >= 2) ? 8 : 0);
                int ng = col0 + wn + nt * 8 + (lane & 3) * 2 + (rg & 1);
                long ci = (long)mg * ldc + ng;
                float v = acc[mt][nt][rg] * alpha;
                switch (ep) {
                case 1: v = fminf(fmaxf(v, -10.f), 10.f); break;
                case 2: v += bias[ng]; break;
                case 3: v = fmaxf(v + bias[ng], 0.f); break;
                case 4: v += bias[ng] + Rres[ci]; break;
                case 5: v = C[ci] + fminf(fmaxf(v, -1.f), 1.f); break;
                case 6: v += Rres[ci]; break;
                case 7: v = fminf(fmaxf(v, -1.f), 1.f); break;
                }
                if (C) C[ci] = v;
                if (Ch) {
                    bf16 h, l; split_bf16(v, h, l);
                    Ch[ci] = h;
                    if (Cl) Cl[ci] = l;
                }
            }
        }
    }
}

// ---------------- transpose (bf16) ----------------
__global__ void transpose_bf16(const bf16* __restrict__ in, bf16* __restrict__ out,
                               int ldin, int ldout, long inz, long outz)
{
    __shared__ bf16 t[32][33];
    in += (long)blockIdx.z * inz;
    out += (long)blockIdx.z * outz;
    int r0 = blockIdx.y * 32, c0 = blockIdx.x * 32;
    int tx = threadIdx.x & 31, ty = threadIdx.x >> 5;
    #pragma unroll
    for (int i = 0; i < 32; i += 8)
        t[ty + i][tx] = in[(long)(r0 + ty + i) * ldin + c0 + tx];
    __syncthreads();
    #pragma unroll
    for (int i = 0; i < 32; i += 8)
        out[(long)(c0 + ty + i) * ldout + r0 + tx] = t[tx][ty + i];
}

// ---------------- elementwise kernels ----------------
__global__ void convert_kernel(const float* __restrict__ src, bf16* __restrict__ h,
                               bf16* __restrict__ l, long n4)
{
    long i = (long)blockIdx.x * blockDim.x + threadIdx.x;
    if (i >= n4) return;
    float4 v = ((const float4*)src)[i];
    bf16 hx, lx, hy, ly, hz, lz, hw, lw;
    split_bf16(v.x, hx, lx); split_bf16(v.y, hy, ly);
    split_bf16(v.z, hz, lz); split_bf16(v.w, hw, lw);
    __nv_bfloat162* h2 = (__nv_bfloat162*)h;
    h2[i * 2]     = __nv_bfloat162(hx, hy);
    h2[i * 2 + 1] = __nv_bfloat162(hz, hw);
    if (l) {
        __nv_bfloat162* l2 = (__nv_bfloat162*)l;
        l2[i * 2]     = __nv_bfloat162(lx, ly);
        l2[i * 2 + 1] = __nv_bfloat162(lz, lw);
    }
}

__global__ void ln_kernel(const float* __restrict__ in, float* __restrict__ out,
                          const float* __restrict__ w, const float* __restrict__ b,
                          bf16* __restrict__ oh, bf16* __restrict__ ol)
{
    const long row = blockIdx.x;
    const float* p = in + row * DD;
    const int t = threadIdx.x; // 128
    __shared__ float sh[4];

    float v[4];
    float s = 0.f;
    #pragma unroll
    for (int i = 0; i < 4; i++) { v[i] = p[t + i * 128]; s += v[i]; }
    #pragma unroll
    for (int o = 16; o; o >>= 1) s += __shfl_down_sync(0xffffffffu, s, o);
    if ((t & 31) == 0) sh[t >> 5] = s;
    __syncthreads();
    float mu = (sh[0] + sh[1] + sh[2] + sh[3]) * (1.f / DD);
    __syncthreads();
    float sq = 0.f;
    #pragma unroll
    for (int i = 0; i < 4; i++) { float d = v[i] - mu; sq += d * d; }
    #pragma unroll
    for (int o = 16; o; o >>= 1) sq += __shfl_down_sync(0xffffffffu, sq, o);
    if ((t & 31) == 0) sh[t >> 5] = sq;
    __syncthreads();
    float rstd = rsqrtf((sh[0] + sh[1] + sh[2] + sh[3]) * (1.f / DD) + 1e-5f);

    #pragma unroll
    for (int i = 0; i < 4; i++) {
        int d = t + i * 128;
        float o = (v[i] - mu) * rstd;
        if (w) o = o * w[d] + b[d];
        long gi = row * DD + d;
        if (out) out[gi] = o;
        bf16 hh, ll; split_bf16(o, hh, ll);
        oh[gi] = hh; ol[gi] = ll;
    }
}

// online softmax: single read pass (running max+sum), single write pass (bf16 h/l only)
__global__ void softmax_kernel(const float* __restrict__ S, bf16* __restrict__ Oh,
                               bf16* __restrict__ Ol, int cols)
{
    const float4* row = (const float4*)(S + (long)blockIdx.x * cols);
    __nv_bfloat162* oh = (__nv_bfloat162*)(Oh + (long)blockIdx.x * cols);
    __nv_bfloat162* ol = Ol ? (__nv_bfloat162*)(Ol + (long)blockIdx.x * cols) : nullptr;
    const int t = threadIdx.x; // 256
    const int n4 = cols >> 2;
    __shared__ float shm[8], shs[8];

    float m = -1e30f, s = 0.f;
    for (int i = t; i < n4; i += 256) {
        float4 v = row[i];
        float mx = fmaxf(fmaxf(v.x, v.y), fmaxf(v.z, v.w));
        if (mx > m) { s *= expf(m - mx); m = mx; }
        s += expf(v.x - m) + expf(v.y - m) + expf(v.z - m) + expf(v.w - m);
    }
    #pragma unroll
    for (int o = 16; o; o >>= 1) {
        float mo = __shfl_xor_sync(0xffffffffu, m, o);
        float so = __shfl_xor_sync(0xffffffffu, s, o);
        float mn = fmaxf(m, mo);
        s = s * expf(m - mn) + so * expf(mo - mn);
        m = mn;
    }
    if ((t & 31) == 0) { shm[t >> 5] = m; shs[t >> 5] = s; }
    __syncthreads();
    if (t == 0) {
        float M = shm[0], Sm = shs[0];
        #pragma unroll
        for (int w = 1; w < 8; w++) {
            float mn = fmaxf(M, shm[w]);
            Sm = Sm * expf(M - mn) + shs[w] * expf(shm[w] - mn);
            M = mn;
        }
        shm[0] = M; shs[0] = 1.f / Sm;
    }
    __syncthreads();
    const float M = shm[0], inv = shs[0];

    for (int i = t; i < n4; i += 256) {
        float4 v = row[i];
        float p0 = expf(v.x - M) * inv, p1 = expf(v.y - M) * inv;
        float p2 = expf(v.z - M) * inv, p3 = expf(v.w - M) * inv;
        bf16 h0, l0, h1, l1, h2, l2, h3, l3;
        split_bf16(p0, h0, l0); split_bf16(p1, h1, l1);
        split_bf16(p2, h2, l2); split_bf16(p3, h3, l3);
        oh[i * 2]     = __nv_bfloat162(h0, h1);
        oh[i * 2 + 1] = __nv_bfloat162(h2, h3);
        if (ol) {
            ol[i * 2]     = __nv_bfloat162(l0, l1);
            ol[i * 2 + 1] = __nv_bfloat162(l2, l3);
        }
    }
}

__global__ void pool_kernel(const float* __restrict__ x, float* __restrict__ pooled)
{
    int idx = blockIdx.x * blockDim.x + threadIdx.x;
    if (idx >= EE * DD) return;
    int e = idx / DD, d = idx % DD;
    const float* p = x + (long)e * NTOK * DD + d;
    float s = 0.f;
    for (int n = 0; n < NTOK; n++) s += p[(long)n * DD];
    pooled[idx] = s * (1.f / NTOK);
}

__global__ void gate_kernel(const float* __restrict__ pooled, const float* __restrict__ gate,
                            float* __restrict__ out_gw, float* __restrict__ gdev)
{
    const int t = threadIdx.x;
    const int wid = t >> 5, lane = t & 31;
    __shared__ float logits[4];
    float s = 0.f;
    for (int d = lane; d < DD; d += 32) s += pooled[wid * DD + d] * gate[d];
    #pragma unroll
    for (int o = 16; o; o >>= 1) s += __shfl_down_sync(0xffffffffu, s, o);
    if (lane == 0) logits[wid] = fminf(fmaxf(s, -10.f), 10.f);
    __syncthreads();
    if (t == 0) {
        float mx = fmaxf(fmaxf(logits[0], logits[1]), fmaxf(logits[2], logits[3]));
        float e0 = expf(logits[0] - mx), e1 = expf(logits[1] - mx);
        float e2 = expf(logits[2] - mx), e3 = expf(logits[3] - mx);
        float inv = 1.f / (e0 + e1 + e2 + e3);
        out_gw[0] = gdev[0] = e0 * inv;
        out_gw[1] = gdev[1] = e1 * inv;
        out_gw[2] = gdev[2] = e2 * inv;
        out_gw[3] = gdev[3] = e3 * inv;
    }
}

__global__ void fused_kernel(const float* __restrict__ x, const float* __restrict__ gw,
                             float* __restrict__ out)
{
    long i = (long)blockIdx.x * blockDim.x + threadIdx.x;
    if (i >= (long)NTOK * DD) return;
    float s = 0.f;
    #pragma unroll
    for (int e = 0; e < EE; e++) s += gw[e] * x[(long)e * NTOK * DD + i];
    out[i] = s;
}

__global__ void newmem_kernel(const float* __restrict__ mem, const float* __restrict__ upd,
                              float* __restrict__ out)
{
    long i = (long)blockIdx.x * blockDim.x + threadIdx.x;
    if (i >= (long)LL * MMEM * DD) return;
    float u = 0.1f * upd[i];
    u = fminf(fmaxf(u, -0.1f), 0.1f);
    out[i] = 0.9f * mem[i] + u;
}

// ---------------- host-side launcher ----------------
static void hg(const bf16* Ah, const bf16* Al, const bf16* Bh, const bf16* Bl,
               float* C, bf16* Ch, bf16* Cl,
               int Mdim, int Nc, int Kdim, int Arow, int Brow,
               int ldc, float alpha, int ep, const float* bias, const float* R,
               int nRemap, int kRemap, int thresh, int batch,
               long Az, long Bz, long Cz, int NS)
{
    if (NS == 3) {
        if (Nc % 128 == 0) {
            dim3 g(Nc / 128, Mdim / 128, batch);
            hgemm<128, 3, 2><<<g, 256, 81920>>>(Ah, Al, Bh, Bl, C, Ch, Cl, Kdim, Arow,
                                                Brow, ldc, alpha, ep, bias, R,
                                                nRemap, kRemap, thresh, Az, Bz, Cz);
        } else {
            dim3 g(Nc / 64, Mdim / 128, batch);
            hgemm<64, 3, 2><<<g, 256, 61440>>>(Ah, Al, Bh, Bl, C, Ch, Cl, Kdim, Arow,
                                               Brow, ldc, alpha, ep, bias, R,
                                               nRemap, kRemap, thresh, Az, Bz, Cz);
        }
    } else {
        dim3 g(Nc / 128, Mdim / 128, batch);
        hgemm<128, 1, 4><<<g, 256, 81920>>>(Ah, Ah, Bh, Bh, C, Ch, Cl, Kdim, Arow,
                                            Brow, ldc, alpha, ep, bias, R,
                                            nRemap, kRemap, thresh, Az, Bz, Cz);
    }
}

static void tr(const bf16* in, bf16* out, int R, int C, int ldin, int ldout,
               int batch, long inz, long outz)
{
    dim3 g(C / 32, R / 32, batch);
    transpose_bf16<<<g, 256>>>(in, out, ldin, ldout, inz, outz);
}

static void conv(const float* s, bf16* h, bf16* l, long n)
{
    long n4 = n / 4;
    convert_kernel<<<(unsigned)((n4 + 255) / 256), 256>>>(s, h, l, n4);
}

extern "C" void kernel_launch(void* const* d_in, const int* in_sizes, int n_in,
                              void* d_out, int out_size)
{
    const float* tokens   = (const float*)d_in[0];
    const float* memories = (const float*)d_in[1];
    const float* ipw      = (const float*)d_in[2];
    const float* ipb      = (const float*)d_in[3];
    const float* opw      = (const float*)d_in[4];
    const float* opb      = (const float*)d_in[5];
    const float* w1       = (const float*)d_in[6];
    const float* b1       = (const float*)d_in[7];
    const float* w2       = (const float*)d_in[8];
    const float* b2       = (const float*)d_in[9];
    const float* n1w      = (const float*)d_in[10];
    const float* n1b      = (const float*)d_in[11];
    const float* n2w      = (const float*)d_in[12];
    const float* n2b      = (const float*)d_in[13];
    const float* aggw     = (const float*)d_in[14];
    const float* aggb     = (const float*)d_in[15];
    const float* gate     = (const float*)d_in[16];
    float* out = (float*)d_out;

    static bool inited = false;
    if (!inited) {
        cudaFuncSetAttribute((const void*)hgemm<128, 3, 2>, cudaFuncAttributeMaxDynamicSharedMemorySize, 81920);
        cudaFuncSetAttribute((const void*)hgemm<64, 3, 2>,  cudaFuncAttributeMaxDynamicSharedMemorySize, 61440);
        cudaFuncSetAttribute((const void*)hgemm<128, 1, 4>, cudaFuncAttributeMaxDynamicSharedMemorySize, 81920);
        inited = true;
    }

    float *xln, *x, *y, *sc, *upd, *pooled, *gatew;
    cudaGetSymbolAddress((void**)&xln, g_xln);
    cudaGetSymbolAddress((void**)&x, g_x);
    cudaGetSymbolAddress((void**)&y, g_y);
    cudaGetSymbolAddress((void**)&sc, g_scores);
    cudaGetSymbolAddress((void**)&upd, g_upd);
    cudaGetSymbolAddress((void**)&pooled, g_pooled);
    cudaGetSymbolAddress((void**)&gatew, g_gatew);

    bf16 *xlnh, *xlnl, *xlnTh, *xlnTl, *xh, *xl, *xTh, *qkvh, *qkvl, *vTh, *vTl;
    bf16 *sah, *sal, *ff1h, *ff1l, *sch, *scl, *schT, *retrph, *memh, *memTh;
    bf16 *ipwh, *ipwl, *opwh, *opwl, *w1h, *w1l, *w2h, *w2l, *aggwh;
    cudaGetSymbolAddress((void**)&xlnh, g_xlnh);   cudaGetSymbolAddress((void**)&xlnl, g_xlnl);
    cudaGetSymbolAddress((void**)&xlnTh, g_xlnTh); cudaGetSymbolAddress((void**)&xlnTl, g_xlnTl);
    cudaGetSymbolAddress((void**)&xh, g_xh);       cudaGetSymbolAddress((void**)&xl, g_xl);
    cudaGetSymbolAddress((void**)&xTh, g_xTh);
    cudaGetSymbolAddress((void**)&qkvh, g_qkvh);   cudaGetSymbolAddress((void**)&qkvl, g_qkvl);
    cudaGetSymbolAddress((void**)&vTh, g_vTh);     cudaGetSymbolAddress((void**)&vTl, g_vTl);
    cudaGetSymbolAddress((void**)&sah, g_sah);     cudaGetSymbolAddress((void**)&sal, g_sal);
    cudaGetSymbolAddress((void**)&ff1h, g_ff1h);   cudaGetSymbolAddress((void**)&ff1l, g_ff1l);
    cudaGetSymbolAddress((void**)&sch, g_sch);     cudaGetSymbolAddress((void**)&scl, g_scl);
    cudaGetSymbolAddress((void**)&schT, g_schT);
    cudaGetSymbolAddress((void**)&retrph, g_retrph);
    cudaGetSymbolAddress((void**)&memh, g_memh);   cudaGetSymbolAddress((void**)&memTh, g_memTh);
    cudaGetSymbolAddress((void**)&ipwh, g_ipwh);   cudaGetSymbolAddress((void**)&ipwl, g_ipwl);
    cudaGetSymbolAddress((void**)&opwh, g_opwh);   cudaGetSymbolAddress((void**)&opwl, g_opwl);
    cudaGetSymbolAddress((void**)&w1h, g_w1h);     cudaGetSymbolAddress((void**)&w1l, g_w1l);
    cudaGetSymbolAddress((void**)&w2h, g_w2h);     cudaGetSymbolAddress((void**)&w2l, g_w2l);
    cudaGetSymbolAddress((void**)&aggwh, g_aggwh);

    const float isd = 1.0f / sqrtf((float)DD);

    conv(ipw, ipwh, ipwl, (long)EE * 3 * DD * DD);
    conv(opw, opwh, opwl, (long)EE * DD * DD);
    conv(w1, w1h, w1l, (long)EE * FFD * DD);
    conv(w2, w2h, w2l, (long)EE * DD * FFD);
    conv(aggw, aggwh, nullptr, (long)DD * LL * DD);
    conv(memories, memh, nullptr, (long)LL * MMEM * DD);
    tr(memh, memTh, MMEM, DD, DD, MMEM, LL, (long)MMEM * DD, (long)DD * MMEM);

    ln_kernel<<<EE * NTOK, 128>>>(tokens, xln, nullptr, nullptr, xlnh, xlnl);
    tr(xlnh, xlnTh, EE * NTOK, DD, DD, EE * NTOK, 1, 0, 0);
    tr(xlnl, xlnTl, EE * NTOK, DD, DD, EE * NTOK, 1, 0, 0);

    for (int e = 0; e < EE; e++) {
        const long eoff = (long)e * NTOK * DD;
        const int thr = e * NTOK;

        // cross scores: S = clip(xln_e @ ctx^T / sqrt(D))  [N, 3N]  (remap on n)
        hg(xlnh + eoff, xlnl + eoff, xlnh, xlnl, sc, nullptr, nullptr,
           NTOK, 3 * NTOK, DD, DD, DD, 3 * NTOK, isd, 1, nullptr, nullptr,
           1, 0, thr, 1, 0, 0, 0, 3);
        softmax_kernel<<<NTOK, 256>>>(sc, sch, scl, 3 * NTOK);
        // x = xln_e + P @ ctx   (B = xlnT, remap on k)
        hg(sch, scl, xlnTh, xlnTl, x + eoff, xh, xl,
           NTOK, DD, 3 * NTOK, 3 * NTOK, EE * NTOK, DD, 1.f, 6, nullptr, xln + eoff,
           0, 1, thr, 1, 0, 0, 0, 3);

        // qkv = x @ ipw^T + ipb
        hg(xh, xl, ipwh + (long)e * 3 * DD * DD, ipwl + (long)e * 3 * DD * DD,
           nullptr, qkvh, qkvl,
           NTOK, 3 * DD, DD, DD, DD, 3 * DD, 1.f, 2, ipb + (long)e * 3 * DD,
           nullptr, 0, 0, 0, 1, 0, 0, 0, 3);
        tr(qkvh + 2 * DD, vTh, NTOK, DD, 3 * DD, NTOK, 1, 0, 0);
        tr(qkvl + 2 * DD, vTl, NTOK, DD, 3 * DD, NTOK, 1, 0, 0);
        // head scores (batch H)
        hg(qkvh, qkvl, qkvh + DD, qkvl + DD, sc, nullptr, nullptr,
           NTOK, NTOK, DHH, 3 * DD, 3 * DD, NTOK, 0.125f, 0, nullptr, nullptr,
           0, 0, 0, HH, DHH, DHH, (long)NTOK * NTOK, 3);
        softmax_kernel<<<HH * NTOK, 256>>>(sc, sch, scl, NTOK);
        // sa = P @ V  (B = vT; batch H)
        hg(sch, scl, vTh, vTl, nullptr, sah, sal,
           NTOK, DHH, NTOK, NTOK, NTOK, DD, 1.f, 0, nullptr, nullptr,
           0, 0, 0, HH, (long)NTOK * NTOK, (long)DHH * NTOK, DHH, 3);
        // out_proj + bias + residual
        hg(sah, sal, opwh + (long)e * DD * DD, opwl + (long)e * DD * DD,
           y, nullptr, nullptr,
           NTOK, DD, DD, DD, DD, DD, 1.f, 4, opb + (long)e * DD, x + eoff,
           0, 0, 0, 1, 0, 0, 0, 3);
        ln_kernel<<<NTOK, 128>>>(y, x + eoff, n1w + (long)e * DD, n1b + (long)e * DD, xh, xl);
        // FFN
        hg(xh, xl, w1h + (long)e * FFD * DD, w1l + (long)e * FFD * DD,
           nullptr, ff1h, ff1l,
           NTOK, FFD, DD, DD, DD, FFD, 1.f, 3, b1 + (long)e * FFD, nullptr,
           0, 0, 0, 1, 0, 0, 0, 3);
        hg(ff1h, ff1l, w2h + (long)e * DD * FFD, w2l + (long)e * DD * FFD,
           y, nullptr, nullptr,
           NTOK, DD, FFD, FFD, FFD, DD, 1.f, 4, b2 + (long)e * DD, x + eoff,
           0, 0, 0, 1, 0, 0, 0, 3);
        ln_kernel<<<NTOK, 128>>>(y, x + eoff, n2w + (long)e * DD, n2b + (long)e * DD, xh, xl);
        tr(xh, xTh, NTOK, DD, DD, NTOK, 1, 0, 0);

        // memory scores (batch L)
        hg(xh, xh, memh, memh, sc, nullptr, nullptr,
           NTOK, MMEM, DD, DD, DD, MMEM, isd, 1, nullptr, nullptr,
           0, 0, 0, LL, 0, (long)MMEM * DD, (long)NTOK * MMEM, 1);
        softmax_kernel<<<LL * NTOK, 256>>>(sc, sch, nullptr, MMEM);
        // schT [L][M][N]
        tr(sch, schT, NTOK, MMEM, MMEM, NTOK, LL, (long)NTOK * MMEM, (long)NTOK * MMEM);
        // retr = A @ mem, written DIRECTLY as bf16 into retrph [N][L*D] (permuted epilogue)
        hg(sch, sch, memTh, memTh, nullptr, retrph, nullptr,
           NTOK, DD, MMEM, MMEM, MMEM, LL * DD, 1.f, 0, nullptr, nullptr,
           0, 0, 0, LL, (long)NTOK * MMEM, (long)DD * MMEM, DD, 1);
        // upd (+)= clip(A^T @ x)  (A = schT, B = xT; batch L)
        hg(schT, schT, xTh, xTh, upd, nullptr, nullptr,
           MMEM, DD, NTOK, NTOK, NTOK, DD, 1.f, (e == 0) ? 7 : 5, nullptr, nullptr,
           0, 0, 0, LL, (long)MMEM * NTOK, 0, (long)MMEM * DD, 1);
        // x = x + retrp @ agg_w^T + agg_b
        hg(retrph, retrph, aggwh, aggwh, x + eoff, nullptr, nullptr,
           NTOK, DD, LL * DD, LL * DD, LL * DD, DD, 1.f, 4, aggb, x + eoff,
           0, 0, 0, 1, 0, 0, 0, 1);
    }

    pool_kernel<<<(EE * DD + 255) / 256, 256>>>(x, pooled);
    gate_kernel<<<1, 128>>>(pooled, gate, out + (long)NTOK * DD, gatew);
    {
        long n = (long)NTOK * DD;
        fused_kernel<<<(unsigned)((n + 255) / 256), 256>>>(x, gatew, out);
    }
    {
        long n = (long)LL * MMEM * DD;
        newmem_kernel<<<(unsigned)((n + 255) / 256), 256>>>(memories, upd,
                                                            out + (long)NTOK * DD + EE);
    }
}

// round 7
// speedup vs baseline: 5.2748x; 1.2043x over previous
#include <cuda_runtime.h>
#include <cuda_bf16.h>
#include <math.h>
#include <stdint.h>

#define EE 4
#define NTOK 2048
#define DD 512
#define HH 8
#define DHH 64
#define FFD 2048
#define LL 4
#define MMEM 4096

typedef __nv_bfloat16 bf16;

// ---------------- static scratch ----------------
__device__ float g_xln[EE * NTOK * DD];
__device__ float g_x[EE * NTOK * DD];
__device__ float g_y[NTOK * DD];
__device__ float g_scores[(size_t)HH * NTOK * NTOK];
__device__ float g_upd[LL * MMEM * DD];
__device__ float g_pooled[EE * DD];
__device__ float g_gatew[EE];

__device__ bf16 g_xlnh[EE * NTOK * DD], g_xlnl[EE * NTOK * DD];
__device__ bf16 g_xlnTh[DD * EE * NTOK], g_xlnTl[DD * EE * NTOK];
__device__ bf16 g_xh[NTOK * DD];
__device__ bf16 g_xTh[DD * NTOK];
__device__ bf16 g_qkvh[NTOK * 3 * DD], g_qkvl[NTOK * 3 * DD];
__device__ bf16 g_vTh[DD * NTOK], g_vTl[DD * NTOK];
__device__ bf16 g_sah[NTOK * DD];
__device__ bf16 g_ff1h[NTOK * FFD];
__device__ bf16 g_sch[(size_t)HH * NTOK * NTOK];
__device__ bf16 g_schT[(size_t)LL * MMEM * NTOK];
__device__ bf16 g_retrph[NTOK * LL * DD];
__device__ bf16 g_memh[LL * MMEM * DD];
__device__ bf16 g_memTh[LL * DD * MMEM];
__device__ bf16 g_ipwh[EE * 3 * DD * DD], g_ipwl[EE * 3 * DD * DD];
__device__ bf16 g_opwh[EE * DD * DD], g_opwl[EE * DD * DD];
__device__ bf16 g_w1h[EE * FFD * DD], g_w1l[EE * FFD * DD];
__device__ bf16 g_w2h[EE * DD * FFD], g_w2l[EE * DD * FFD];
__device__ bf16 g_aggwh[DD * LL * DD];

__device__ __forceinline__ void split_bf16(float v, bf16& h, bf16& l) {
    h = __float2bfloat16(v);
    l = __float2bfloat16(v - __bfloat162float(h));
}
__device__ __forceinline__ uint32_t smem_u32(const void* p) {
    uint32_t a;
    asm("{ .reg .u64 t; cvta.to.shared.u64 t, %1; cvt.u32.u64 %0, t; }" : "=r"(a) : "l"(p));
    return a;
}

#define MMA16816(d, a0, a1, a2, a3, b0, b1) \
    asm volatile("mma.sync.aligned.m16n8k16.row.col.f32.bf16.bf16.f32 " \
                 "{%0,%1,%2,%3}, {%4,%5,%6,%7}, {%8,%9}, {%0,%1,%2,%3};" \
                 : "+f"((d)[0]), "+f"((d)[1]), "+f"((d)[2]), "+f"((d)[3]) \
                 : "r"(a0), "r"(a1), "r"(a2), "r"(a3), "r"(b0), "r"(b1))

#define LDSM4(r0, r1, r2, r3, addr) \
    asm volatile("ldmatrix.sync.aligned.m8n8.x4.shared.b16 {%0,%1,%2,%3}, [%4];" \
                 : "=r"(r0), "=r"(r1), "=r"(r2), "=r"(r3) : "r"(addr))

#define CP16(dst, src) \
    asm volatile("cp.async.cg.shared.global [%0], [%1], 16;" :: "r"(dst), "l"(src))
#define CPCOMMIT() asm volatile("cp.async.commit_group;")
#define CPWAIT(n)  asm volatile("cp.async.wait_group %0;" :: "n"(n))

// ---------------- HMMA bf16 GEMM: cp.async + ldmatrix pipeline ----------------
// C[m,n] = ep( alpha * sum_k A[m*Arow+k] * B[n*Brow+k] )
// NS=1: Ah*Bh.  NS=2: Ah*Bh + Ah*Bl.  NS=3: + Al*Bh.
// nRemap: B row n += NTOK when >= thresh.  kRemap: B col k += NTOK when k-tile >= thresh.
// ep: 0 none,1 clip±10,2 +bias,3 relu+bias,4 +bias+res,5 C+=clip±1,6 +res,7 clip±1
template<int BN, int NS, int STAGES>
__global__ void __launch_bounds__(256, 2) hgemm(
    const bf16* __restrict__ Ahg, const bf16* __restrict__ Alg,
    const bf16* __restrict__ Bhg, const bf16* __restrict__ Blg,
    float* __restrict__ C, bf16* __restrict__ Ch, bf16* __restrict__ Cl,
    int Kdim, int Arow, int Brow, int ldc,
    float alpha, int ep,
    const float* __restrict__ bias, const float* __restrict__ Rres,
    int nRemap, int kRemap, int thresh,
    long Az, long Bz, long Cz)
{
    constexpr bool AL = (NS == 3);
    constexpr bool BL = (NS >= 2);
    constexpr int AST = 128 * 80;
    constexpr int BST = BN * 80;
    constexpr int NT = BN / 32;
    constexpr int BIT = BN / 64;

    Ahg += (long)blockIdx.z * Az; Bhg += (long)blockIdx.z * Bz;
    if (AL) Alg += (long)blockIdx.z * Az;
    if (BL) Blg += (long)blockIdx.z * Bz;
    if (C)  C  += (long)blockIdx.z * Cz;
    if (Ch) Ch += (long)blockIdx.z * Cz;
    if (Cl) Cl += (long)blockIdx.z * Cz;
    if (Rres) Rres += (long)blockIdx.z * Cz;

    extern __shared__ char sm[];
    const uint32_t smBase = smem_u32(sm);
    const uint32_t offAh = 0;
    const uint32_t offAl = STAGES * AST;                       // valid when AL
    const uint32_t offBh = (AL ? 2u : 1u) * STAGES * AST;
    const uint32_t offBl = offBh + STAGES * BST;               // valid when BL

    const int tid = threadIdx.x;
    const int lane = tid & 31;
    const int wid = tid >> 5;
    const int wm = (wid >> 2) * 64;
    const int wn = (wid & 3) * (BN / 4);
    const int row0 = blockIdx.y * 128;
    const int col0 = blockIdx.x * BN;

    const int g = lane >> 3;
    const uint32_t laneOff = ((g & 1) * 8 + (lane & 7)) * 80 + (g >> 1) * 16;

    float acc[4][NT][4];
    #pragma unroll
    for (int i = 0; i < 4; i++)
        #pragma unroll
        for (int j = 0; j < NT; j++)
            #pragma unroll
            for (int r = 0; r < 4; r++) acc[i][j][r] = 0.f;

    auto fill = [&](int s, int t) {
        int k0 = t * 32;
        long kb = k0 + ((kRemap && k0 >= thresh) ? NTOK : 0);
        #pragma unroll
        for (int r = 0; r < 2; r++) {
            int idx = tid + r * 256;
            int row = idx >> 2, c = idx & 3;
            long go = (long)(row0 + row) * Arow + k0 + c * 8;
            uint32_t dst = smBase + offAh + s * AST + row * 80 + c * 16;
            CP16(dst, Ahg + go);
            if (AL) CP16(dst + (offAl - offAh), Alg + go);
        }
        #pragma unroll
        for (int r = 0; r < BIT; r++) {
            int idx = tid + r * 256;
            int row = idx >> 2, c = idx & 3;
            int ng = col0 + row;
            if (nRemap && ng >= thresh) ng += NTOK;
            long go = (long)ng * Brow + kb + c * 8;
            uint32_t dst = smBase + offBh + s * BST + row * 80 + c * 16;
            CP16(dst, Bhg + go);
            if (BL) CP16(dst + (offBl - offBh), Blg + go);
        }
    };

    auto compute = [&](int buf) {
        const uint32_t aH = smBase + offAh + buf * AST + laneOff;
        const uint32_t aL = smBase + offAl + buf * AST + laneOff;
        const uint32_t bH = smBase + offBh + buf * BST + laneOff;
        const uint32_t bL = smBase + offBl + buf * BST + laneOff;
        #pragma unroll
        for (int s = 0; s < 2; s++) {
            uint32_t bh[NT][2], bl[NT][2];
            #pragma unroll
            for (int p = 0; p < NT / 2; p++) {
                uint32_t addr = bH + (wn + p * 16) * 80 + s * 32;
                LDSM4(bh[2*p][0], bh[2*p+1][0], bh[2*p][1], bh[2*p+1][1], addr);
                if (BL) {
                    uint32_t addr2 = bL + (wn + p * 16) * 80 + s * 32;
                    LDSM4(bl[2*p][0], bl[2*p+1][0], bl[2*p][1], bl[2*p+1][1], addr2);
                }
            }
            #pragma unroll
            for (int mt = 0; mt < 4; mt++) {
                uint32_t a0, a1, a2, a3;
                LDSM4(a0, a1, a2, a3, aH + (wm + mt * 16) * 80 + s * 32);
                #pragma unroll
                for (int nt = 0; nt < NT; nt++)
                    MMA16816(acc[mt][nt], a0, a1, a2, a3, bh[nt][0], bh[nt][1]);
                if (BL) {
                    #pragma unroll
                    for (int nt = 0; nt < NT; nt++)
                        MMA16816(acc[mt][nt], a0, a1, a2, a3, bl[nt][0], bl[nt][1]);
                }
                if (AL) {
                    uint32_t l0, l1, l2, l3;
                    LDSM4(l0, l1, l2, l3, aL + (wm + mt * 16) * 80 + s * 32);
                    #pragma unroll
                    for (int nt = 0; nt < NT; nt++)
                        MMA16816(acc[mt][nt], l0, l1, l2, l3, bh[nt][0], bh[nt][1]);
                }
            }
        }
    };

    const int nk = Kdim / 32;
    #pragma unroll
    for (int s = 0; s < STAGES - 1; s++) {
        if (s < nk) fill(s, s);
        CPCOMMIT();
    }
    for (int t = 0; t < nk; t++) {
        CPWAIT(STAGES - 2);
        __syncthreads();
        int tn = t + STAGES - 1;
        if (tn < nk) fill(tn % STAGES, tn);
        CPCOMMIT();
        compute(t % STAGES);
    }

    // epilogue
    #pragma unroll
    for (int mt = 0; mt < 4; mt++) {
        #pragma unroll
        for (int nt = 0; nt < NT; nt++) {
            #pragma unroll
            for (int rg = 0; rg < 4; rg++) {
                int mg = row0 + wm + mt * 16 + (lane >> 2) + ((rg >= 2) ? 8 : 0);
                int ng = col0 + wn + nt * 8 + (lane & 3) * 2 + (rg & 1);
                long ci = (long)mg * ldc + ng;
                float v = acc[mt][nt][rg] * alpha;
                switch (ep) {
                case 1: v = fminf(fmaxf(v, -10.f), 10.f); break;
                case 2: v += bias[ng]; break;
                case 3: v = fmaxf(v + bias[ng], 0.f); break;
                case 4: v += bias[ng] + Rres[ci]; break;
                case 5: v = C[ci] + fminf(fmaxf(v, -1.f), 1.f); break;
                case 6: v += Rres[ci]; break;
                case 7: v = fminf(fmaxf(v, -1.f), 1.f); break;
                }
                if (C) C[ci] = v;
                if (Ch) {
                    bf16 h, l; split_bf16(v, h, l);
                    Ch[ci] = h;
                    if (Cl) Cl[ci] = l;
                }
            }
        }
    }
}

// ---------------- transpose (bf16) ----------------
__global__ void transpose_bf16(const bf16* __restrict__ in, bf16* __restrict__ out,
                               int ldin, int ldout, long inz, long outz)
{
    __shared__ bf16 t[32][33];
    in += (long)blockIdx.z * inz;
    out += (long)blockIdx.z * outz;
    int r0 = blockIdx.y * 32, c0 = blockIdx.x * 32;
    int tx = threadIdx.x & 31, ty = threadIdx.x >> 5;
    #pragma unroll
    for (int i = 0; i < 32; i += 8)
        t[ty + i][tx] = in[(long)(r0 + ty + i) * ldin + c0 + tx];
    __syncthreads();
    #pragma unroll
    for (int i = 0; i < 32; i += 8)
        out[(long)(c0 + ty + i) * ldout + r0 + tx] = t[tx][ty + i];
}

// ---------------- elementwise kernels ----------------
__global__ void convert_kernel(const float* __restrict__ src, bf16* __restrict__ h,
                               bf16* __restrict__ l, long n4)
{
    long i = (long)blockIdx.x * blockDim.x + threadIdx.x;
    if (i >= n4) return;
    float4 v = ((const float4*)src)[i];
    bf16 hx, lx, hy, ly, hz, lz, hw, lw;
    split_bf16(v.x, hx, lx); split_bf16(v.y, hy, ly);
    split_bf16(v.z, hz, lz); split_bf16(v.w, hw, lw);
    __nv_bfloat162* h2 = (__nv_bfloat162*)h;
    h2[i * 2]     = __nv_bfloat162(hx, hy);
    h2[i * 2 + 1] = __nv_bfloat162(hz, hw);
    if (l) {
        __nv_bfloat162* l2 = (__nv_bfloat162*)l;
        l2[i * 2]     = __nv_bfloat162(lx, ly);
        l2[i * 2 + 1] = __nv_bfloat162(lz, lw);
    }
}

__global__ void ln_kernel(const float* __restrict__ in, float* __restrict__ out,
                          const float* __restrict__ w, const float* __restrict__ b,
                          bf16* __restrict__ oh, bf16* __restrict__ ol)
{
    const long row = blockIdx.x;
    const float* p = in + row * DD;
    const int t = threadIdx.x; // 128
    __shared__ float sh[4];

    float v[4];
    float s = 0.f;
    #pragma unroll
    for (int i = 0; i < 4; i++) { v[i] = p[t + i * 128]; s += v[i]; }
    #pragma unroll
    for (int o = 16; o; o >>= 1) s += __shfl_down_sync(0xffffffffu, s, o);
    if ((t & 31) == 0) sh[t >> 5] = s;
    __syncthreads();
    float mu = (sh[0] + sh[1] + sh[2] + sh[3]) * (1.f / DD);
    __syncthreads();
    float sq = 0.f;
    #pragma unroll
    for (int i = 0; i < 4; i++) { float d = v[i] - mu; sq += d * d; }
    #pragma unroll
    for (int o = 16; o; o >>= 1) sq += __shfl_down_sync(0xffffffffu, sq, o);
    if ((t & 31) == 0) sh[t >> 5] = sq;
    __syncthreads();
    float rstd = rsqrtf((sh[0] + sh[1] + sh[2] + sh[3]) * (1.f / DD) + 1e-5f);

    #pragma unroll
    for (int i = 0; i < 4; i++) {
        int d = t + i * 128;
        float o = (v[i] - mu) * rstd;
        if (w) o = o * w[d] + b[d];
        long gi = row * DD + d;
        if (out) out[gi] = o;
        bf16 hh, ll; split_bf16(o, hh, ll);
        oh[gi] = hh;
        if (ol) ol[gi] = ll;
    }
}

// online softmax: single read pass, single write pass (bf16 hi only unless Ol)
__global__ void softmax_kernel(const float* __restrict__ S, bf16* __restrict__ Oh,
                               bf16* __restrict__ Ol, int cols)
{
    const float4* row = (const float4*)(S + (long)blockIdx.x * cols);
    __nv_bfloat162* oh = (__nv_bfloat162*)(Oh + (long)blockIdx.x * cols);
    __nv_bfloat162* ol = Ol ? (__nv_bfloat162*)(Ol + (long)blockIdx.x * cols) : nullptr;
    const int t = threadIdx.x; // 256
    const int n4 = cols >> 2;
    __shared__ float shm[8], shs[8];

    float m = -1e30f, s = 0.f;
    for (int i = t; i < n4; i += 256) {
        float4 v = row[i];
        float mx = fmaxf(fmaxf(v.x, v.y), fmaxf(v.z, v.w));
        if (mx > m) { s *= expf(m - mx); m = mx; }
        s += expf(v.x - m) + expf(v.y - m) + expf(v.z - m) + expf(v.w - m);
    }
    #pragma unroll
    for (int o = 16; o; o >>= 1) {
        float mo = __shfl_xor_sync(0xffffffffu, m, o);
        float so = __shfl_xor_sync(0xffffffffu, s, o);
        float mn = fmaxf(m, mo);
        s = s * expf(m - mn) + so * expf(mo - mn);
        m = mn;
    }
    if ((t & 31) == 0) { shm[t >> 5] = m; shs[t >> 5] = s; }
    __syncthreads();
    if (t == 0) {
        float M = shm[0], Sm = shs[0];
        #pragma unroll
        for (int w = 1; w < 8; w++) {
            float mn = fmaxf(M, shm[w]);
            Sm = Sm * expf(M - mn) + shs[w] * expf(shm[w] - mn);
            M = mn;
        }
        shm[0] = M; shs[0] = 1.f / Sm;
    }
    __syncthreads();
    const float M = shm[0], inv = shs[0];

    for (int i = t; i < n4; i += 256) {
        float4 v = row[i];
        float p0 = expf(v.x - M) * inv, p1 = expf(v.y - M) * inv;
        float p2 = expf(v.z - M) * inv, p3 = expf(v.w - M) * inv;
        bf16 h0, l0, h1, l1, h2, l2, h3, l3;
        split_bf16(p0, h0, l0); split_bf16(p1, h1, l1);
        split_bf16(p2, h2, l2); split_bf16(p3, h3, l3);
        oh[i * 2]     = __nv_bfloat162(h0, h1);
        oh[i * 2 + 1] = __nv_bfloat162(h2, h3);
        if (ol) {
            ol[i * 2]     = __nv_bfloat162(l0, l1);
            ol[i * 2 + 1] = __nv_bfloat162(l2, l3);
        }
    }
}

__global__ void pool_kernel(const float* __restrict__ x, float* __restrict__ pooled)
{
    int idx = blockIdx.x * blockDim.x + threadIdx.x;
    if (idx >= EE * DD) return;
    int e = idx / DD, d = idx % DD;
    const float* p = x + (long)e * NTOK * DD + d;
    float s = 0.f;
    for (int n = 0; n < NTOK; n++) s += p[(long)n * DD];
    pooled[idx] = s * (1.f / NTOK);
}

__global__ void gate_kernel(const float* __restrict__ pooled, const float* __restrict__ gate,
                            float* __restrict__ out_gw, float* __restrict__ gdev)
{
    const int t = threadIdx.x;
    const int wid = t >> 5, lane = t & 31;
    __shared__ float logits[4];
    float s = 0.f;
    for (int d = lane; d < DD; d += 32) s += pooled[wid * DD + d] * gate[d];
    #pragma unroll
    for (int o = 16; o; o >>= 1) s += __shfl_down_sync(0xffffffffu, s, o);
    if (lane == 0) logits[wid] = fminf(fmaxf(s, -10.f), 10.f);
    __syncthreads();
    if (t == 0) {
        float mx = fmaxf(fmaxf(logits[0], logits[1]), fmaxf(logits[2], logits[3]));
        float e0 = expf(logits[0] - mx), e1 = expf(logits[1] - mx);
        float e2 = expf(logits[2] - mx), e3 = expf(logits[3] - mx);
        float inv = 1.f / (e0 + e1 + e2 + e3);
        out_gw[0] = gdev[0] = e0 * inv;
        out_gw[1] = gdev[1] = e1 * inv;
        out_gw[2] = gdev[2] = e2 * inv;
        out_gw[3] = gdev[3] = e3 * inv;
    }
}

__global__ void fused_kernel(const float* __restrict__ x, const float* __restrict__ gw,
                             float* __restrict__ out)
{
    long i = (long)blockIdx.x * blockDim.x + threadIdx.x;
    if (i >= (long)NTOK * DD) return;
    float s = 0.f;
    #pragma unroll
    for (int e = 0; e < EE; e++) s += gw[e] * x[(long)e * NTOK * DD + i];
    out[i] = s;
}

__global__ void newmem_kernel(const float* __restrict__ mem, const float* __restrict__ upd,
                              float* __restrict__ out)
{
    long i = (long)blockIdx.x * blockDim.x + threadIdx.x;
    if (i >= (long)LL * MMEM * DD) return;
    float u = 0.1f * upd[i];
    u = fminf(fmaxf(u, -0.1f), 0.1f);
    out[i] = 0.9f * mem[i] + u;
}

// ---------------- host-side launcher ----------------
static void hg(const bf16* Ah, const bf16* Bh, const bf16* Bl,
               float* C, bf16* Ch, bf16* Cl,
               int Mdim, int Nc, int Kdim, int Arow, int Brow,
               int ldc, float alpha, int ep, const float* bias, const float* R,
               int nRemap, int kRemap, int thresh, int batch,
               long Az, long Bz, long Cz, int NS)
{
    if (NS == 2) {
        if (Nc % 128 == 0) {
            dim3 g(Nc / 128, Mdim / 128, batch);
            hgemm<128, 2, 3><<<g, 256, 92160>>>(Ah, Ah, Bh, Bl, C, Ch, Cl, Kdim, Arow,
                                                Brow, ldc, alpha, ep, bias, R,
                                                nRemap, kRemap, thresh, Az, Bz, Cz);
        } else {
            dim3 g(Nc / 64, Mdim / 128, batch);
            hgemm<64, 2, 3><<<g, 256, 61440>>>(Ah, Ah, Bh, Bl, C, Ch, Cl, Kdim, Arow,
                                               Brow, ldc, alpha, ep, bias, R,
                                               nRemap, kRemap, thresh, Az, Bz, Cz);
        }
    } else {
        dim3 g(Nc / 128, Mdim / 128, batch);
        hgemm<128, 1, 4><<<g, 256, 81920>>>(Ah, Ah, Bh, Bh, C, Ch, Cl, Kdim, Arow,
                                            Brow, ldc, alpha, ep, bias, R,
                                            nRemap, kRemap, thresh, Az, Bz, Cz);
    }
}

static void tr(const bf16* in, bf16* out, int R, int C, int ldin, int ldout,
               int batch, long inz, long outz)
{
    dim3 g(C / 32, R / 32, batch);
    transpose_bf16<<<g, 256>>>(in, out, ldin, ldout, inz, outz);
}

static void conv(const float* s, bf16* h, bf16* l, long n)
{
    long n4 = n / 4;
    convert_kernel<<<(unsigned)((n4 + 255) / 256), 256>>>(s, h, l, n4);
}

extern "C" void kernel_launch(void* const* d_in, const int* in_sizes, int n_in,
                              void* d_out, int out_size)
{
    const float* tokens   = (const float*)d_in[0];
    const float* memories = (const float*)d_in[1];
    const float* ipw      = (const float*)d_in[2];
    const float* ipb      = (const float*)d_in[3];
    const float* opw      = (const float*)d_in[4];
    const float* opb      = (const float*)d_in[5];
    const float* w1       = (const float*)d_in[6];
    const float* b1       = (const float*)d_in[7];
    const float* w2       = (const float*)d_in[8];
    const float* b2       = (const float*)d_in[9];
    const float* n1w      = (const float*)d_in[10];
    const float* n1b      = (const float*)d_in[11];
    const float* n2w      = (const float*)d_in[12];
    const float* n2b      = (const float*)d_in[13];
    const float* aggw     = (const float*)d_in[14];
    const float* aggb     = (const float*)d_in[15];
    const float* gate     = (const float*)d_in[16];
    float* out = (float*)d_out;

    static bool inited = false;
    if (!inited) {
        cudaFuncSetAttribute((const void*)hgemm<128, 2, 3>, cudaFuncAttributeMaxDynamicSharedMemorySize, 92160);
        cudaFuncSetAttribute((const void*)hgemm<64, 2, 3>,  cudaFuncAttributeMaxDynamicSharedMemorySize, 61440);
        cudaFuncSetAttribute((const void*)hgemm<128, 1, 4>, cudaFuncAttributeMaxDynamicSharedMemorySize, 81920);
        inited = true;
    }

    float *xln, *x, *y, *sc, *upd, *pooled, *gatew;
    cudaGetSymbolAddress((void**)&xln, g_xln);
    cudaGetSymbolAddress((void**)&x, g_x);
    cudaGetSymbolAddress((void**)&y, g_y);
    cudaGetSymbolAddress((void**)&sc, g_scores);
    cudaGetSymbolAddress((void**)&upd, g_upd);
    cudaGetSymbolAddress((void**)&pooled, g_pooled);
    cudaGetSymbolAddress((void**)&gatew, g_gatew);

    bf16 *xlnh, *xlnl, *xlnTh, *xlnTl, *xh, *xTh, *qkvh, *qkvl, *vTh, *vTl;
    bf16 *sah, *ff1h, *sch, *schT, *retrph, *memh, *memTh;
    bf16 *ipwh, *ipwl, *opwh, *opwl, *w1h, *w1l, *w2h, *w2l, *aggwh;
    cudaGetSymbolAddress((void**)&xlnh, g_xlnh);   cudaGetSymbolAddress((void**)&xlnl, g_xlnl);
    cudaGetSymbolAddress((void**)&xlnTh, g_xlnTh); cudaGetSymbolAddress((void**)&xlnTl, g_xlnTl);
    cudaGetSymbolAddress((void**)&xh, g_xh);
    cudaGetSymbolAddress((void**)&xTh, g_xTh);
    cudaGetSymbolAddress((void**)&qkvh, g_qkvh);   cudaGetSymbolAddress((void**)&qkvl, g_qkvl);
    cudaGetSymbolAddress((void**)&vTh, g_vTh);     cudaGetSymbolAddress((void**)&vTl, g_vTl);
    cudaGetSymbolAddress((void**)&sah, g_sah);
    cudaGetSymbolAddress((void**)&ff1h, g_ff1h);
    cudaGetSymbolAddress((void**)&sch, g_sch);
    cudaGetSymbolAddress((void**)&schT, g_schT);
    cudaGetSymbolAddress((void**)&retrph, g_retrph);
    cudaGetSymbolAddress((void**)&memh, g_memh);   cudaGetSymbolAddress((void**)&memTh, g_memTh);
    cudaGetSymbolAddress((void**)&ipwh, g_ipwh);   cudaGetSymbolAddress((void**)&ipwl, g_ipwl);
    cudaGetSymbolAddress((void**)&opwh, g_opwh);   cudaGetSymbolAddress((void**)&opwl, g_opwl);
    cudaGetSymbolAddress((void**)&w1h, g_w1h);     cudaGetSymbolAddress((void**)&w1l, g_w1l);
    cudaGetSymbolAddress((void**)&w2h, g_w2h);     cudaGetSymbolAddress((void**)&w2l, g_w2l);
    cudaGetSymbolAddress((void**)&aggwh, g_aggwh);

    const float isd = 1.0f / sqrtf((float)DD);

    conv(ipw, ipwh, ipwl, (long)EE * 3 * DD * DD);
    conv(opw, opwh, opwl, (long)EE * DD * DD);
    conv(w1, w1h, w1l, (long)EE * FFD * DD);
    conv(w2, w2h, w2l, (long)EE * DD * FFD);
    conv(aggw, aggwh, nullptr, (long)DD * LL * DD);
    conv(memories, memh, nullptr, (long)LL * MMEM * DD);
    tr(memh, memTh, MMEM, DD, DD, MMEM, LL, (long)MMEM * DD, (long)DD * MMEM);

    ln_kernel<<<EE * NTOK, 128>>>(tokens, xln, nullptr, nullptr, xlnh, xlnl);
    tr(xlnh, xlnTh, EE * NTOK, DD, DD, EE * NTOK, 1, 0, 0);
    tr(xlnl, xlnTl, EE * NTOK, DD, DD, EE * NTOK, 1, 0, 0);

    for (int e = 0; e < EE; e++) {
        const long eoff = (long)e * NTOK * DD;
        const int thr = e * NTOK;

        // cross scores: S = clip(xln_e @ ctx^T / sqrt(D))  [N, 3N]  (remap on n)
        hg(xlnh + eoff, xlnh, xlnl, sc, nullptr, nullptr,
           NTOK, 3 * NTOK, DD, DD, DD, 3 * NTOK, isd, 1, nullptr, nullptr,
           1, 0, thr, 1, 0, 0, 0, 2);
        softmax_kernel<<<NTOK, 256>>>(sc, sch, nullptr, 3 * NTOK);
        // x = xln_e + P @ ctx   (B = xlnT h+l, remap on k)
        hg(sch, xlnTh, xlnTl, x + eoff, xh, nullptr,
           NTOK, DD, 3 * NTOK, 3 * NTOK, EE * NTOK, DD, 1.f, 6, nullptr, xln + eoff,
           0, 1, thr, 1, 0, 0, 0, 2);

        // qkv = x @ ipw^T + ipb   (produce h+l: k-side needs lo)
        hg(xh, ipwh + (long)e * 3 * DD * DD, ipwl + (long)e * 3 * DD * DD,
           nullptr, qkvh, qkvl,
           NTOK, 3 * DD, DD, DD, DD, 3 * DD, 1.f, 2, ipb + (long)e * 3 * DD,
           nullptr, 0, 0, 0, 1, 0, 0, 0, 2);
        tr(qkvh + 2 * DD, vTh, NTOK, DD, 3 * DD, NTOK, 1, 0, 0);
        tr(qkvl + 2 * DD, vTl, NTOK, DD, 3 * DD, NTOK, 1, 0, 0);
        // head scores (batch H): A=q hi, B=k h+l
        hg(qkvh, qkvh + DD, qkvl + DD, sc, nullptr, nullptr,
           NTOK, NTOK, DHH, 3 * DD, 3 * DD, NTOK, 0.125f, 0, nullptr, nullptr,
           0, 0, 0, HH, DHH, DHH, (long)NTOK * NTOK, 2);
        softmax_kernel<<<HH * NTOK, 256>>>(sc, sch, nullptr, NTOK);
        // sa = P @ V  (B = vT h+l; batch H)
        hg(sch, vTh, vTl, nullptr, sah, nullptr,
           NTOK, DHH, NTOK, NTOK, NTOK, DD, 1.f, 0, nullptr, nullptr,
           0, 0, 0, HH, (long)NTOK * NTOK, (long)DHH * NTOK, DHH, 2);
        // out_proj + bias + residual
        hg(sah, opwh + (long)e * DD * DD, opwl + (long)e * DD * DD,
           y, nullptr, nullptr,
           NTOK, DD, DD, DD, DD, DD, 1.f, 4, opb + (long)e * DD, x + eoff,
           0, 0, 0, 1, 0, 0, 0, 2);
        ln_kernel<<<NTOK, 128>>>(y, x + eoff, n1w + (long)e * DD, n1b + (long)e * DD,
                                 xh, nullptr);
        // FFN
        hg(xh, w1h + (long)e * FFD * DD, w1l + (long)e * FFD * DD,
           nullptr, ff1h, nullptr,
           NTOK, FFD, DD, DD, DD, FFD, 1.f, 3, b1 + (long)e * FFD, nullptr,
           0, 0, 0, 1, 0, 0, 0, 2);
        hg(ff1h, w2h + (long)e * DD * FFD, w2l + (long)e * DD * FFD,
           y, nullptr, nullptr,
           NTOK, DD, FFD, FFD, FFD, DD, 1.f, 4, b2 + (long)e * DD, x + eoff,
           0, 0, 0, 1, 0, 0, 0, 2);
        ln_kernel<<<NTOK, 128>>>(y, x + eoff, n2w + (long)e * DD, n2b + (long)e * DD,
                                 xh, nullptr);
        tr(xh, xTh, NTOK, DD, DD, NTOK, 1, 0, 0);

        // memory scores (batch L)
        hg(xh, memh, memh, sc, nullptr, nullptr,
           NTOK, MMEM, DD, DD, DD, MMEM, isd, 1, nullptr, nullptr,
           0, 0, 0, LL, 0, (long)MMEM * DD, (long)NTOK * MMEM, 1);
        softmax_kernel<<<LL * NTOK, 256>>>(sc, sch, nullptr, MMEM);
        // schT [L][M][N]
        tr(sch, schT, NTOK, MMEM, MMEM, NTOK, LL, (long)NTOK * MMEM, (long)NTOK * MMEM);
        // retr = A @ mem, written directly as bf16 into retrph [N][L*D]
        hg(sch, memTh, memTh, nullptr, retrph, nullptr,
           NTOK, DD, MMEM, MMEM, MMEM, LL * DD, 1.f, 0, nullptr, nullptr,
           0, 0, 0, LL, (long)NTOK * MMEM, (long)DD * MMEM, DD, 1);
        // upd (+)= clip(A^T @ x)  (A = schT, B = xT; batch L)
        hg(schT, xTh, xTh, upd, nullptr, nullptr,
           MMEM, DD, NTOK, NTOK, NTOK, DD, 1.f, (e == 0) ? 7 : 5, nullptr, nullptr,
           0, 0, 0, LL, (long)MMEM * NTOK, 0, (long)MMEM * DD, 1);
        // x = x + retrp @ agg_w^T + agg_b
        hg(retrph, aggwh, aggwh, x + eoff, nullptr, nullptr,
           NTOK, DD, LL * DD, LL * DD, LL * DD, DD, 1.f, 4, aggb, x + eoff,
           0, 0, 0, 1, 0, 0, 0, 1);
    }

    pool_kernel<<<(EE * DD + 255) / 256, 256>>>(x, pooled);
    gate_kernel<<<1, 128>>>(pooled, gate, out + (long)NTOK * DD, gatew);
    {
        long n = (long)NTOK * DD;
        fused_kernel<<<(unsigned)((n + 255) / 256), 256>>>(x, gatew, out);
    }
    {
        long n = (long)LL * MMEM * DD;
        newmem_kernel<<<(unsigned)((n + 255) / 256), 256>>>(memories, upd,
                                                            out + (long)NTOK * DD + EE);
    }
}

// round 8
// speedup vs baseline: 7.1414x; 1.3539x over previous
#include <cuda_runtime.h>
#include <cuda_bf16.h>
#include <math.h>
#include <stdint.h>

#define EE 4
#define NTOK 2048
#define DD 512
#define HH 8
#define DHH 64
#define FFD 2048
#define LL 4
#define MMEM 4096

typedef __nv_bfloat16 bf16;

// ---------------- static scratch ----------------
__device__ float g_xln[EE * NTOK * DD];
__device__ float g_x[EE * NTOK * DD];
__device__ float g_y[EE * NTOK * DD];
__device__ float g_scores[(size_t)EE * HH * NTOK * NTOK];   // 536MB, reused
__device__ float g_upd4[(size_t)EE * LL * MMEM * DD];       // 268MB
__device__ float g_pooled[EE * DD];
__device__ float g_gatew[EE];

__device__ bf16 g_xlnh[EE * NTOK * DD], g_xlnl[EE * NTOK * DD];
__device__ bf16 g_xlnTh[DD * EE * NTOK], g_xlnTl[DD * EE * NTOK];
__device__ bf16 g_xh[EE * NTOK * DD];
__device__ bf16 g_xTh[EE * DD * NTOK];
__device__ bf16 g_qkvh[EE * NTOK * 3 * DD], g_qkvl[EE * NTOK * 3 * DD];
__device__ bf16 g_vTh[EE * DD * NTOK], g_vTl[EE * DD * NTOK];
__device__ bf16 g_sah[EE * NTOK * DD];
__device__ bf16 g_ff1h[EE * NTOK * FFD];
__device__ bf16 g_sch[(size_t)EE * HH * NTOK * NTOK];       // 268MB
__device__ bf16 g_schT[(size_t)EE * LL * MMEM * NTOK];      // 268MB
__device__ bf16 g_retrph[EE * NTOK * LL * DD];
__device__ bf16 g_memh[LL * MMEM * DD];
__device__ bf16 g_memTh[LL * DD * MMEM];
__device__ bf16 g_ipwh[EE * 3 * DD * DD], g_ipwl[EE * 3 * DD * DD];
__device__ bf16 g_opwh[EE * DD * DD], g_opwl[EE * DD * DD];
__device__ bf16 g_w1h[EE * FFD * DD], g_w1l[EE * FFD * DD];
__device__ bf16 g_w2h[EE * DD * FFD], g_w2l[EE * DD * FFD];
__device__ bf16 g_aggwh[DD * LL * DD];

__device__ __forceinline__ void split_bf16(float v, bf16& h, bf16& l) {
    h = __float2bfloat16(v);
    l = __float2bfloat16(v - __bfloat162float(h));
}
__device__ __forceinline__ uint32_t smem_u32(const void* p) {
    uint32_t a;
    asm("{ .reg .u64 t; cvta.to.shared.u64 t, %1; cvt.u32.u64 %0, t; }" : "=r"(a) : "l"(p));
    return a;
}

#define MMA16816(d, a0, a1, a2, a3, b0, b1) \
    asm volatile("mma.sync.aligned.m16n8k16.row.col.f32.bf16.bf16.f32 " \
                 "{%0,%1,%2,%3}, {%4,%5,%6,%7}, {%8,%9}, {%0,%1,%2,%3};" \
                 : "+f"((d)[0]), "+f"((d)[1]), "+f"((d)[2]), "+f"((d)[3]) \
                 : "r"(a0), "r"(a1), "r"(a2), "r"(a3), "r"(b0), "r"(b1))

#define LDSM4(r0, r1, r2, r3, addr) \
    asm volatile("ldmatrix.sync.aligned.m8n8.x4.shared.b16 {%0,%1,%2,%3}, [%4];" \
                 : "=r"(r0), "=r"(r1), "=r"(r2), "=r"(r3) : "r"(addr))

#define CP16(dst, src) \
    asm volatile("cp.async.cg.shared.global [%0], [%1], 16;" :: "r"(dst), "l"(src))
#define CPCOMMIT() asm volatile("cp.async.commit_group;")
#define CPWAIT(n)  asm volatile("cp.async.wait_group %0;" :: "n"(n))

// ---------------- HMMA bf16 GEMM: cp.async + ldmatrix pipeline, 2-level batch ----
// z1 = z % inner, z2 = z / inner; offsets = z1*Xi + z2*Xo.
// C[m,n] = ep( alpha * sum_k A[m*Arow+k] * B[n*Brow+k] )
// NS=1: Ah*Bh.  NS=2: Ah*Bh + Ah*Bl.  NS=3: + Al*Bh.
// nRemap: B row n += NTOK when >= th.  kRemap: k-tile += NTOK when >= th.
// th = thresh, or z2*NTOK when thresh < 0.
// ep: 0 none,1 clip±10,2 +bias,3 relu+bias,4 +bias+res,6 +res,7 clip±1
template<int BN, int NS, int STAGES>
__global__ void __launch_bounds__(256, 2) hgemm(
    const bf16* __restrict__ Ahg, const bf16* __restrict__ Alg,
    const bf16* __restrict__ Bhg, const bf16* __restrict__ Blg,
    float* __restrict__ C, bf16* __restrict__ Ch, bf16* __restrict__ Cl,
    int Kdim, int Arow, int Brow, int ldc,
    float alpha, int ep,
    const float* __restrict__ bias, long biasZ, const float* __restrict__ Rres,
    int nRemap, int kRemap, int thresh, int inner,
    long Ai, long Ao, long Bi, long Bo, long Ci, long Co)
{
    constexpr bool AL = (NS == 3);
    constexpr bool BL = (NS >= 2);
    constexpr int AST = 128 * 80;
    constexpr int BST = BN * 80;
    constexpr int NT = BN / 32;
    constexpr int BIT = BN / 64;

    const int z1 = blockIdx.z % inner;
    const int z2 = blockIdx.z / inner;
    const long aoff = (long)z1 * Ai + (long)z2 * Ao;
    const long boff = (long)z1 * Bi + (long)z2 * Bo;
    const long coff = (long)z1 * Ci + (long)z2 * Co;
    Ahg += aoff; Bhg += boff;
    if (AL) Alg += aoff;
    if (BL) Blg += boff;
    if (C)  C  += coff;
    if (Ch) Ch += coff;
    if (Cl) Cl += coff;
    if (Rres) Rres += coff;
    if (bias) bias += (long)z2 * biasZ;
    const int th = (thresh < 0) ? z2 * NTOK : thresh;

    extern __shared__ char sm[];
    const uint32_t smBase = smem_u32(sm);
    const uint32_t offAh = 0;
    const uint32_t offAl = STAGES * AST;
    const uint32_t offBh = (AL ? 2u : 1u) * STAGES * AST;
    const uint32_t offBl = offBh + STAGES * BST;

    const int tid = threadIdx.x;
    const int lane = tid & 31;
    const int wid = tid >> 5;
    const int wm = (wid >> 2) * 64;
    const int wn = (wid & 3) * (BN / 4);
    const int row0 = blockIdx.y * 128;
    const int col0 = blockIdx.x * BN;

    const int g = lane >> 3;
    const uint32_t laneOff = ((g & 1) * 8 + (lane & 7)) * 80 + (g >> 1) * 16;

    float acc[4][NT][4];
    #pragma unroll
    for (int i = 0; i < 4; i++)
        #pragma unroll
        for (int j = 0; j < NT; j++)
            #pragma unroll
            for (int r = 0; r < 4; r++) acc[i][j][r] = 0.f;

    auto fill = [&](int s, int t) {
        int k0 = t * 32;
        long kb = k0 + ((kRemap && k0 >= th) ? NTOK : 0);
        #pragma unroll
        for (int r = 0; r < 2; r++) {
            int idx = tid + r * 256;
            int row = idx >> 2, c = idx & 3;
            long go = (long)(row0 + row) * Arow + k0 + c * 8;
            uint32_t dst = smBase + offAh + s * AST + row * 80 + c * 16;
            CP16(dst, Ahg + go);
            if (AL) CP16(dst + (offAl - offAh), Alg + go);
        }
        #pragma unroll
        for (int r = 0; r < BIT; r++) {
            int idx = tid + r * 256;
            int row = idx >> 2, c = idx & 3;
            int ng = col0 + row;
            if (nRemap && ng >= th) ng += NTOK;
            long go = (long)ng * Brow + kb + c * 8;
            uint32_t dst = smBase + offBh + s * BST + row * 80 + c * 16;
            CP16(dst, Bhg + go);
            if (BL) CP16(dst + (offBl - offBh), Blg + go);
        }
    };

    auto compute = [&](int buf) {
        const uint32_t aH = smBase + offAh + buf * AST + laneOff;
        const uint32_t aL = smBase + offAl + buf * AST + laneOff;
        const uint32_t bH = smBase + offBh + buf * BST + laneOff;
        const uint32_t bL = smBase + offBl + buf * BST + laneOff;
        #pragma unroll
        for (int s = 0; s < 2; s++) {
            uint32_t bh[NT][2], bl[NT][2];
            #pragma unroll
            for (int p = 0; p < NT / 2; p++) {
                uint32_t addr = bH + (wn + p * 16) * 80 + s * 32;
                LDSM4(bh[2*p][0], bh[2*p+1][0], bh[2*p][1], bh[2*p+1][1], addr);
                if (BL) {
                    uint32_t addr2 = bL + (wn + p * 16) * 80 + s * 32;
                    LDSM4(bl[2*p][0], bl[2*p+1][0], bl[2*p][1], bl[2*p+1][1], addr2);
                }
            }
            #pragma unroll
            for (int mt = 0; mt < 4; mt++) {
                uint32_t a0, a1, a2, a3;
                LDSM4(a0, a1, a2, a3, aH + (wm + mt * 16) * 80 + s * 32);
                #pragma unroll
                for (int nt = 0; nt < NT; nt++)
                    MMA16816(acc[mt][nt], a0, a1, a2, a3, bh[nt][0], bh[nt][1]);
                if (BL) {
                    #pragma unroll
                    for (int nt = 0; nt < NT; nt++)
                        MMA16816(acc[mt][nt], a0, a1, a2, a3, bl[nt][0], bl[nt][1]);
                }
                if (AL) {
                    uint32_t l0, l1, l2, l3;
                    LDSM4(l0, l1, l2, l3, aL + (wm + mt * 16) * 80 + s * 32);
                    #pragma unroll
                    for (int nt = 0; nt < NT; nt++)
                        MMA16816(acc[mt][nt], l0, l1, l2, l3, bh[nt][0], bh[nt][1]);
                }
            }
        }
    };

    const int nk = Kdim / 32;
    #pragma unroll
    for (int s = 0; s < STAGES - 1; s++) {
        if (s < nk) fill(s, s);
        CPCOMMIT();
    }
    for (int t = 0; t < nk; t++) {
        CPWAIT(STAGES - 2);
        __syncthreads();
        int tn = t + STAGES - 1;
        if (tn < nk) fill(tn % STAGES, tn);
        CPCOMMIT();
        compute(t % STAGES);
    }

    // epilogue
    #pragma unroll
    for (int mt = 0; mt < 4; mt++) {
        #pragma unroll
        for (int nt = 0; nt < NT; nt++) {
            #pragma unroll
            for (int rg = 0; rg < 4; rg++) {
                int mg = row0 + wm + mt * 16 + (lane >> 2) + ((rg >= 2) ? 8 : 0);
                int ng = col0 + wn + nt * 8 + (lane & 3) * 2 + (rg & 1);
                long ci = (long)mg * ldc + ng;
                float v = acc[mt][nt][rg] * alpha;
                switch (ep) {
                case 1: v = fminf(fmaxf(v, -10.f), 10.f); break;
                case 2: v += bias[ng]; break;
                case 3: v = fmaxf(v + bias[ng], 0.f); break;
                case 4: v += bias[ng] + Rres[ci]; break;
                case 6: v += Rres[ci]; break;
                case 7: v = fminf(fmaxf(v, -1.f), 1.f); break;
                }
                if (C) C[ci] = v;
                if (Ch) {
                    bf16 h, l; split_bf16(v, h, l);
                    Ch[ci] = h;
                    if (Cl) Cl[ci] = l;
                }
            }
        }
    }
}

// ---------------- transpose (bf16) ----------------
__global__ void transpose_bf16(const bf16* __restrict__ in, bf16* __restrict__ out,
                               int ldin, int ldout, long inz, long outz)
{
    __shared__ bf16 t[32][33];
    in += (long)blockIdx.z * inz;
    out += (long)blockIdx.z * outz;
    int r0 = blockIdx.y * 32, c0 = blockIdx.x * 32;
    int tx = threadIdx.x & 31, ty = threadIdx.x >> 5;
    #pragma unroll
    for (int i = 0; i < 32; i += 8)
        t[ty + i][tx] = in[(long)(r0 + ty + i) * ldin + c0 + tx];
    __syncthreads();
    #pragma unroll
    for (int i = 0; i < 32; i += 8)
        out[(long)(c0 + ty + i) * ldout + r0 + tx] = t[tx][ty + i];
}

// ---------------- elementwise kernels ----------------
__global__ void convert_kernel(const float* __restrict__ src, bf16* __restrict__ h,
                               bf16* __restrict__ l, long n4)
{
    long i = (long)blockIdx.x * blockDim.x + threadIdx.x;
    if (i >= n4) return;
    float4 v = ((const float4*)src)[i];
    bf16 hx, lx, hy, ly, hz, lz, hw, lw;
    split_bf16(v.x, hx, lx); split_bf16(v.y, hy, ly);
    split_bf16(v.z, hz, lz); split_bf16(v.w, hw, lw);
    __nv_bfloat162* h2 = (__nv_bfloat162*)h;
    h2[i * 2]     = __nv_bfloat162(hx, hy);
    h2[i * 2 + 1] = __nv_bfloat162(hz, hw);
    if (l) {
        __nv_bfloat162* l2 = (__nv_bfloat162*)l;
        l2[i * 2]     = __nv_bfloat162(lx, ly);
        l2[i * 2 + 1] = __nv_bfloat162(lz, lw);
    }
}

// wsel: 0 = shared w/b (or null), 1 = per-expert slice w + (row/NTOK)*DD
__global__ void ln_kernel(const float* __restrict__ in, float* __restrict__ out,
                          const float* __restrict__ w, const float* __restrict__ b,
                          bf16* __restrict__ oh, bf16* __restrict__ ol, int wsel)
{
    const long row = blockIdx.x;
    const float* p = in + row * DD;
    const int t = threadIdx.x; // 128
    __shared__ float sh[4];
    const long wo = wsel ? (row / NTOK) * DD : 0;

    float v[4];
    float s = 0.f;
    #pragma unroll
    for (int i = 0; i < 4; i++) { v[i] = p[t + i * 128]; s += v[i]; }
    #pragma unroll
    for (int o = 16; o; o >>= 1) s += __shfl_down_sync(0xffffffffu, s, o);
    if ((t & 31) == 0) sh[t >> 5] = s;
    __syncthreads();
    float mu = (sh[0] + sh[1] + sh[2] + sh[3]) * (1.f / DD);
    __syncthreads();
    float sq = 0.f;
    #pragma unroll
    for (int i = 0; i < 4; i++) { float d = v[i] - mu; sq += d * d; }
    #pragma unroll
    for (int o = 16; o; o >>= 1) sq += __shfl_down_sync(0xffffffffu, sq, o);
    if ((t & 31) == 0) sh[t >> 5] = sq;
    __syncthreads();
    float rstd = rsqrtf((sh[0] + sh[1] + sh[2] + sh[3]) * (1.f / DD) + 1e-5f);

    #pragma unroll
    for (int i = 0; i < 4; i++) {
        int d = t + i * 128;
        float o = (v[i] - mu) * rstd;
        if (w) o = o * w[wo + d] + b[wo + d];
        long gi = row * DD + d;
        if (out) out[gi] = o;
        bf16 hh, ll; split_bf16(o, hh, ll);
        oh[gi] = hh;
        if (ol) ol[gi] = ll;
    }
}

// online softmax: single read pass, single bf16 write pass
__global__ void softmax_kernel(const float* __restrict__ S, bf16* __restrict__ Oh,
                               int cols)
{
    const float4* row = (const float4*)(S + (long)blockIdx.x * cols);
    __nv_bfloat162* oh = (__nv_bfloat162*)(Oh + (long)blockIdx.x * cols);
    const int t = threadIdx.x; // 256
    const int n4 = cols >> 2;
    __shared__ float shm[8], shs[8];

    float m = -1e30f, s = 0.f;
    for (int i = t; i < n4; i += 256) {
        float4 v = row[i];
        float mx = fmaxf(fmaxf(v.x, v.y), fmaxf(v.z, v.w));
        if (mx > m) { s *= expf(m - mx); m = mx; }
        s += expf(v.x - m) + expf(v.y - m) + expf(v.z - m) + expf(v.w - m);
    }
    #pragma unroll
    for (int o = 16; o; o >>= 1) {
        float mo = __shfl_xor_sync(0xffffffffu, m, o);
        float so = __shfl_xor_sync(0xffffffffu, s, o);
        float mn = fmaxf(m, mo);
        s = s * expf(m - mn) + so * expf(mo - mn);
        m = mn;
    }
    if ((t & 31) == 0) { shm[t >> 5] = m; shs[t >> 5] = s; }
    __syncthreads();
    if (t == 0) {
        float M = shm[0], Sm = shs[0];
        #pragma unroll
        for (int w = 1; w < 8; w++) {
            float mn = fmaxf(M, shm[w]);
            Sm = Sm * expf(M - mn) + shs[w] * expf(shm[w] - mn);
            M = mn;
        }
        shm[0] = M; shs[0] = 1.f / Sm;
    }
    __syncthreads();
    const float M = shm[0], inv = shs[0];

    for (int i = t; i < n4; i += 256) {
        float4 v = row[i];
        float p0 = expf(v.x - M) * inv, p1 = expf(v.y - M) * inv;
        float p2 = expf(v.z - M) * inv, p3 = expf(v.w - M) * inv;
        oh[i * 2]     = __nv_bfloat162(__float2bfloat16(p0), __float2bfloat16(p1));
        oh[i * 2 + 1] = __nv_bfloat162(__float2bfloat16(p2), __float2bfloat16(p3));
    }
}

__global__ void pool_kernel(const float* __restrict__ x, float* __restrict__ pooled)
{
    int idx = blockIdx.x * blockDim.x + threadIdx.x;
    if (idx >= EE * DD) return;
    int e = idx / DD, d = idx % DD;
    const float* p = x + (long)e * NTOK * DD + d;
    float s = 0.f;
    for (int n = 0; n < NTOK; n++) s += p[(long)n * DD];
    pooled[idx] = s * (1.f / NTOK);
}

__global__ void gate_kernel(const float* __restrict__ pooled, const float* __restrict__ gate,
                            float* __restrict__ out_gw, float* __restrict__ gdev)
{
    const int t = threadIdx.x;
    const int wid = t >> 5, lane = t & 31;
    __shared__ float logits[4];
    float s = 0.f;
    for (int d = lane; d < DD; d += 32) s += pooled[wid * DD + d] * gate[d];
    #pragma unroll
    for (int o = 16; o; o >>= 1) s += __shfl_down_sync(0xffffffffu, s, o);
    if (lane == 0) logits[wid] = fminf(fmaxf(s, -10.f), 10.f);
    __syncthreads();
    if (t == 0) {
        float mx = fmaxf(fmaxf(logits[0], logits[1]), fmaxf(logits[2], logits[3]));
        float e0 = expf(logits[0] - mx), e1 = expf(logits[1] - mx);
        float e2 = expf(logits[2] - mx), e3 = expf(logits[3] - mx);
        float inv = 1.f / (e0 + e1 + e2 + e3);
        out_gw[0] = gdev[0] = e0 * inv;
        out_gw[1] = gdev[1] = e1 * inv;
        out_gw[2] = gdev[2] = e2 * inv;
        out_gw[3] = gdev[3] = e3 * inv;
    }
}

__global__ void fused_kernel(const float* __restrict__ x, const float* __restrict__ gw,
                             float* __restrict__ out)
{
    long i = (long)blockIdx.x * blockDim.x + threadIdx.x;
    if (i >= (long)NTOK * DD) return;
    float s = 0.f;
    #pragma unroll
    for (int e = 0; e < EE; e++) s += gw[e] * x[(long)e * NTOK * DD + i];
    out[i] = s;
}

__global__ void newmem_kernel(const float* __restrict__ mem, const float* __restrict__ upd4,
                              float* __restrict__ out)
{
    long i = (long)blockIdx.x * blockDim.x + threadIdx.x;
    const long S = (long)LL * MMEM * DD;
    if (i >= S) return;
    float u = ((upd4[i] + upd4[i + S]) + upd4[i + 2 * S]) + upd4[i + 3 * S];
    u *= 0.1f;
    u = fminf(fmaxf(u, -0.1f), 0.1f);
    out[i] = 0.9f * mem[i] + u;
}

// ---------------- host-side launcher ----------------
struct GArgs {
    const bf16 *Ah, *Bh, *Bl;
    float* C; bf16 *Ch, *Cl;
    int M, N, K, Arow, Brow, ldc;
    float alpha; int ep;
    const float* bias; long biasZ; const float* R;
    int nRemap, kRemap, thresh, inner, batch;
    long Ai, Ao, Bi, Bo, Ci, Co;
    int NS;
};

static void hg(const GArgs& a)
{
    if (a.NS == 2) {
        if (a.N % 128 == 0) {
            dim3 g(a.N / 128, a.M / 128, a.batch);
            hgemm<128, 2, 3><<<g, 256, 92160>>>(a.Ah, a.Ah, a.Bh, a.Bl, a.C, a.Ch, a.Cl,
                a.K, a.Arow, a.Brow, a.ldc, a.alpha, a.ep, a.bias, a.biasZ, a.R,
                a.nRemap, a.kRemap, a.thresh, a.inner, a.Ai, a.Ao, a.Bi, a.Bo, a.Ci, a.Co);
        } else {
            dim3 g(a.N / 64, a.M / 128, a.batch);
            hgemm<64, 2, 3><<<g, 256, 61440>>>(a.Ah, a.Ah, a.Bh, a.Bl, a.C, a.Ch, a.Cl,
                a.K, a.Arow, a.Brow, a.ldc, a.alpha, a.ep, a.bias, a.biasZ, a.R,
                a.nRemap, a.kRemap, a.thresh, a.inner, a.Ai, a.Ao, a.Bi, a.Bo, a.Ci, a.Co);
        }
    } else {
        dim3 g(a.N / 128, a.M / 128, a.batch);
        hgemm<128, 1, 4><<<g, 256, 81920>>>(a.Ah, a.Ah, a.Bh, a.Bh, a.C, a.Ch, a.Cl,
            a.K, a.Arow, a.Brow, a.ldc, a.alpha, a.ep, a.bias, a.biasZ, a.R,
            a.nRemap, a.kRemap, a.thresh, a.inner, a.Ai, a.Ao, a.Bi, a.Bo, a.Ci, a.Co);
    }
}

static void tr(const bf16* in, bf16* out, int R, int C, int ldin, int ldout,
               int batch, long inz, long outz)
{
    dim3 g(C / 32, R / 32, batch);
    transpose_bf16<<<g, 256>>>(in, out, ldin, ldout, inz, outz);
}

static void conv(const float* s, bf16* h, bf16* l, long n)
{
    long n4 = n / 4;
    convert_kernel<<<(unsigned)((n4 + 255) / 256), 256>>>(s, h, l, n4);
}

extern "C" void kernel_launch(void* const* d_in, const int* in_sizes, int n_in,
                              void* d_out, int out_size)
{
    const float* tokens   = (const float*)d_in[0];
    const float* memories = (const float*)d_in[1];
    const float* ipw      = (const float*)d_in[2];
    const float* ipb      = (const float*)d_in[3];
    const float* opw      = (const float*)d_in[4];
    const float* opb      = (const float*)d_in[5];
    const float* w1       = (const float*)d_in[6];
    const float* b1       = (const float*)d_in[7];
    const float* w2       = (const float*)d_in[8];
    const float* b2       = (const float*)d_in[9];
    const float* n1w      = (const float*)d_in[10];
    const float* n1b      = (const float*)d_in[11];
    const float* n2w      = (const float*)d_in[12];
    const float* n2b      = (const float*)d_in[13];
    const float* aggw     = (const float*)d_in[14];
    const float* aggb     = (const float*)d_in[15];
    const float* gate     = (const float*)d_in[16];
    float* out = (float*)d_out;

    static bool inited = false;
    if (!inited) {
        cudaFuncSetAttribute((const void*)hgemm<128, 2, 3>, cudaFuncAttributeMaxDynamicSharedMemorySize, 92160);
        cudaFuncSetAttribute((const void*)hgemm<64, 2, 3>,  cudaFuncAttributeMaxDynamicSharedMemorySize, 61440);
        cudaFuncSetAttribute((const void*)hgemm<128, 1, 4>, cudaFuncAttributeMaxDynamicSharedMemorySize, 81920);
        inited = true;
    }

    float *xln, *x, *y, *sc, *upd4, *pooled, *gatew;
    cudaGetSymbolAddress((void**)&xln, g_xln);
    cudaGetSymbolAddress((void**)&x, g_x);
    cudaGetSymbolAddress((void**)&y, g_y);
    cudaGetSymbolAddress((void**)&sc, g_scores);
    cudaGetSymbolAddress((void**)&upd4, g_upd4);
    cudaGetSymbolAddress((void**)&pooled, g_pooled);
    cudaGetSymbolAddress((void**)&gatew, g_gatew);

    bf16 *xlnh, *xlnl, *xlnTh, *xlnTl, *xh, *xTh, *qkvh, *qkvl, *vTh, *vTl;
    bf16 *sah, *ff1h, *sch, *schT, *retrph, *memh, *memTh;
    bf16 *ipwh, *ipwl, *opwh, *opwl, *w1h, *w1l, *w2h, *w2l, *aggwh;
    cudaGetSymbolAddress((void**)&xlnh, g_xlnh);   cudaGetSymbolAddress((void**)&xlnl, g_xlnl);
    cudaGetSymbolAddress((void**)&xlnTh, g_xlnTh); cudaGetSymbolAddress((void**)&xlnTl, g_xlnTl);
    cudaGetSymbolAddress((void**)&xh, g_xh);
    cudaGetSymbolAddress((void**)&xTh, g_xTh);
    cudaGetSymbolAddress((void**)&qkvh, g_qkvh);   cudaGetSymbolAddress((void**)&qkvl, g_qkvl);
    cudaGetSymbolAddress((void**)&vTh, g_vTh);     cudaGetSymbolAddress((void**)&vTl, g_vTl);
    cudaGetSymbolAddress((void**)&sah, g_sah);
    cudaGetSymbolAddress((void**)&ff1h, g_ff1h);
    cudaGetSymbolAddress((void**)&sch, g_sch);
    cudaGetSymbolAddress((void**)&schT, g_schT);
    cudaGetSymbolAddress((void**)&retrph, g_retrph);
    cudaGetSymbolAddress((void**)&memh, g_memh);   cudaGetSymbolAddress((void**)&memTh, g_memTh);
    cudaGetSymbolAddress((void**)&ipwh, g_ipwh);   cudaGetSymbolAddress((void**)&ipwl, g_ipwl);
    cudaGetSymbolAddress((void**)&opwh, g_opwh);   cudaGetSymbolAddress((void**)&opwl, g_opwl);
    cudaGetSymbolAddress((void**)&w1h, g_w1h);     cudaGetSymbolAddress((void**)&w1l, g_w1l);
    cudaGetSymbolAddress((void**)&w2h, g_w2h);     cudaGetSymbolAddress((void**)&w2l, g_w2l);
    cudaGetSymbolAddress((void**)&aggwh, g_aggwh);

    const float isd = 1.0f / sqrtf((float)DD);
    const long ND = (long)NTOK * DD;
    const long N3N = (long)NTOK * 3 * NTOK;
    const long NN = (long)NTOK * NTOK;
    const long NM = (long)NTOK * MMEM;

    conv(ipw, ipwh, ipwl, (long)EE * 3 * DD * DD);
    conv(opw, opwh, opwl, (long)EE * DD * DD);
    conv(w1, w1h, w1l, (long)EE * FFD * DD);
    conv(w2, w2h, w2l, (long)EE * DD * FFD);
    conv(aggw, aggwh, nullptr, (long)DD * LL * DD);
    conv(memories, memh, nullptr, (long)LL * MMEM * DD);
    tr(memh, memTh, MMEM, DD, DD, MMEM, LL, (long)MMEM * DD, (long)DD * MMEM);

    ln_kernel<<<EE * NTOK, 128>>>(tokens, xln, nullptr, nullptr, xlnh, xlnl, 0);
    tr(xlnh, xlnTh, EE * NTOK, DD, DD, EE * NTOK, 1, 0, 0);
    tr(xlnl, xlnTl, EE * NTOK, DD, DD, EE * NTOK, 1, 0, 0);

    // 1. cross scores: S[e] = clip(xln_e @ ctx^T / sqrt(D))  [N,3N], remap n per z
    { GArgs a{}; a.Ah=xlnh; a.Bh=xlnh; a.Bl=xlnl; a.C=sc;
      a.M=NTOK; a.N=3*NTOK; a.K=DD; a.Arow=DD; a.Brow=DD; a.ldc=3*NTOK;
      a.alpha=isd; a.ep=1; a.nRemap=1; a.thresh=-1; a.inner=1; a.batch=EE;
      a.Ao=ND; a.Co=N3N; a.NS=2; hg(a); }
    softmax_kernel<<<EE * NTOK, 256>>>(sc, sch, 3 * NTOK);
    // 2. x = xln_e + P @ ctx  (B = xlnT h+l, remap k per z)
    { GArgs a{}; a.Ah=sch; a.Bh=xlnTh; a.Bl=xlnTl; a.C=x; a.Ch=xh;
      a.M=NTOK; a.N=DD; a.K=3*NTOK; a.Arow=3*NTOK; a.Brow=EE*NTOK; a.ldc=DD;
      a.alpha=1.f; a.ep=6; a.R=xln; a.kRemap=1; a.thresh=-1; a.inner=1; a.batch=EE;
      a.Ao=N3N; a.Co=ND; a.NS=2; hg(a); }

    // 3. qkv
    { GArgs a{}; a.Ah=xh; a.Bh=ipwh; a.Bl=ipwl; a.Ch=qkvh; a.Cl=qkvl;
      a.M=NTOK; a.N=3*DD; a.K=DD; a.Arow=DD; a.Brow=DD; a.ldc=3*DD;
      a.alpha=1.f; a.ep=2; a.bias=ipb; a.biasZ=3*DD; a.inner=1; a.batch=EE;
      a.Ao=ND; a.Bo=(long)3*DD*DD; a.Co=(long)NTOK*3*DD; a.NS=2; hg(a); }
    tr(qkvh + 2 * DD, vTh, NTOK, DD, 3 * DD, NTOK, EE, (long)NTOK*3*DD, (long)DD*NTOK);
    tr(qkvl + 2 * DD, vTl, NTOK, DD, 3 * DD, NTOK, EE, (long)NTOK*3*DD, (long)DD*NTOK);
    // 4. head scores (z = e*H + h)
    { GArgs a{}; a.Ah=qkvh; a.Bh=qkvh + DD; a.Bl=qkvl + DD; a.C=sc;
      a.M=NTOK; a.N=NTOK; a.K=DHH; a.Arow=3*DD; a.Brow=3*DD; a.ldc=NTOK;
      a.alpha=0.125f; a.ep=0; a.inner=HH; a.batch=EE*HH;
      a.Ai=DHH; a.Ao=(long)NTOK*3*DD; a.Bi=DHH; a.Bo=(long)NTOK*3*DD;
      a.Ci=NN; a.Co=HH*NN; a.NS=2; hg(a); }
    softmax_kernel<<<EE * HH * NTOK, 256>>>(sc, sch, NTOK);
    // 5. sa = P @ V (z = e*H + h)
    { GArgs a{}; a.Ah=sch; a.Bh=vTh; a.Bl=vTl; a.Ch=sah;
      a.M=NTOK; a.N=DHH; a.K=NTOK; a.Arow=NTOK; a.Brow=NTOK; a.ldc=DD;
      a.alpha=1.f; a.ep=0; a.inner=HH; a.batch=EE*HH;
      a.Ai=NN; a.Ao=HH*NN; a.Bi=(long)DHH*NTOK; a.Bo=(long)DD*NTOK;
      a.Ci=DHH; a.Co=ND; a.NS=2; hg(a); }
    // 6. out_proj + bias + residual
    { GArgs a{}; a.Ah=sah; a.Bh=opwh; a.Bl=opwl; a.C=y;
      a.M=NTOK; a.N=DD; a.K=DD; a.Arow=DD; a.Brow=DD; a.ldc=DD;
      a.alpha=1.f; a.ep=4; a.bias=opb; a.biasZ=DD; a.R=x; a.inner=1; a.batch=EE;
      a.Ao=ND; a.Bo=(long)DD*DD; a.Co=ND; a.NS=2; hg(a); }
    ln_kernel<<<EE * NTOK, 128>>>(y, x, n1w, n1b, xh, nullptr, 1);
    // 7. FFN
    { GArgs a{}; a.Ah=xh; a.Bh=w1h; a.Bl=w1l; a.Ch=ff1h;
      a.M=NTOK; a.N=FFD; a.K=DD; a.Arow=DD; a.Brow=DD; a.ldc=FFD;
      a.alpha=1.f; a.ep=3; a.bias=b1; a.biasZ=FFD; a.inner=1; a.batch=EE;
      a.Ao=ND; a.Bo=(long)FFD*DD; a.Co=(long)NTOK*FFD; a.NS=2; hg(a); }
    { GArgs a{}; a.Ah=ff1h; a.Bh=w2h; a.Bl=w2l; a.C=y;
      a.M=NTOK; a.N=DD; a.K=FFD; a.Arow=FFD; a.Brow=FFD; a.ldc=DD;
      a.alpha=1.f; a.ep=4; a.bias=b2; a.biasZ=DD; a.R=x; a.inner=1; a.batch=EE;
      a.Ao=(long)NTOK*FFD; a.Bo=(long)DD*FFD; a.Co=ND; a.NS=2; hg(a); }
    ln_kernel<<<EE * NTOK, 128>>>(y, x, n2w, n2b, xh, nullptr, 1);
    tr(xh, xTh, NTOK, DD, DD, NTOK, EE, ND, ND);

    // 8. memory scores (z = e*L + l)
    { GArgs a{}; a.Ah=xh; a.Bh=memh; a.Bl=memh; a.C=sc;
      a.M=NTOK; a.N=MMEM; a.K=DD; a.Arow=DD; a.Brow=DD; a.ldc=MMEM;
      a.alpha=isd; a.ep=1; a.inner=LL; a.batch=EE*LL;
      a.Ai=0; a.Ao=ND; a.Bi=(long)MMEM*DD; a.Bo=0;
      a.Ci=NM; a.Co=LL*NM; a.NS=1; hg(a); }
    softmax_kernel<<<EE * LL * NTOK, 256>>>(sc, sch, MMEM);
    tr(sch, schT, NTOK, MMEM, MMEM, NTOK, EE * LL, NM, NM);
    // 9. retr -> retrph [e][n][l*D+d] directly (permuted bf16 epilogue)
    { GArgs a{}; a.Ah=sch; a.Bh=memTh; a.Bl=memTh; a.Ch=retrph;
      a.M=NTOK; a.N=DD; a.K=MMEM; a.Arow=MMEM; a.Brow=MMEM; a.ldc=LL*DD;
      a.alpha=1.f; a.ep=0; a.inner=LL; a.batch=EE*LL;
      a.Ai=NM; a.Ao=LL*NM; a.Bi=(long)DD*MMEM; a.Bo=0;
      a.Ci=DD; a.Co=(long)NTOK*LL*DD; a.NS=1; hg(a); }
    // 10. upd4[e][l] = clip(A^T @ x, ±1)
    { GArgs a{}; a.Ah=schT; a.Bh=xTh; a.Bl=xTh; a.C=upd4;
      a.M=MMEM; a.N=DD; a.K=NTOK; a.Arow=NTOK; a.Brow=NTOK; a.ldc=DD;
      a.alpha=1.f; a.ep=7; a.inner=LL; a.batch=EE*LL;
      a.Ai=(long)MMEM*NTOK; a.Ao=(long)LL*MMEM*NTOK; a.Bi=0; a.Bo=(long)DD*NTOK;
      a.Ci=(long)MMEM*DD; a.Co=(long)LL*MMEM*DD; a.NS=1; hg(a); }
    // 11. x = x + retrp @ agg_w^T + agg_b
    { GArgs a{}; a.Ah=retrph; a.Bh=aggwh; a.Bl=aggwh; a.C=x;
      a.M=NTOK; a.N=DD; a.K=LL*DD; a.Arow=LL*DD; a.Brow=LL*DD; a.ldc=DD;
      a.alpha=1.f; a.ep=4; a.bias=aggb; a.biasZ=0; a.R=x; a.inner=1; a.batch=EE;
      a.Ao=(long)NTOK*LL*DD; a.Co=ND; a.NS=1; hg(a); }

    pool_kernel<<<(EE * DD + 255) / 256, 256>>>(x, pooled);
    gate_kernel<<<1, 128>>>(pooled, gate, out + ND, gatew);
    fused_kernel<<<(unsigned)((ND + 255) / 256), 256>>>(x, gatew, out);
    {
        long n = (long)LL * MMEM * DD;
        newmem_kernel<<<(unsigned)((n + 255) / 256), 256>>>(memories, upd4, out + ND + EE);
    }
}

// round 9
// speedup vs baseline: 7.7014x; 1.0784x over previous
#include <cuda_runtime.h>
#include <cuda_bf16.h>
#include <math.h>
#include <stdint.h>

#define EE 4
#define NTOK 2048
#define DD 512
#define HH 8
#define DHH 64
#define FFD 2048
#define LL 4
#define MMEM 4096

typedef __nv_bfloat16 bf16;

// ---------------- static scratch ----------------
__device__ float g_xln[EE * NTOK * DD];
__device__ float g_x[EE * NTOK * DD];
__device__ float g_y[EE * NTOK * DD];
__device__ float g_scores[(size_t)EE * HH * NTOK * NTOK];
__device__ float g_upd4[(size_t)EE * LL * MMEM * DD];
__device__ float g_pooled[EE * DD];
__device__ float g_gatew[EE];

__device__ bf16 g_xlnh[EE * NTOK * DD], g_xlnl[EE * NTOK * DD];
__device__ bf16 g_xlnTh[DD * EE * NTOK], g_xlnTl[DD * EE * NTOK];
__device__ bf16 g_xh[EE * NTOK * DD];
__device__ bf16 g_xTh[EE * DD * NTOK];
__device__ bf16 g_qkvh[EE * NTOK * 3 * DD], g_qkvl[EE * NTOK * 3 * DD];
__device__ bf16 g_vTh[EE * DD * NTOK], g_vTl[EE * DD * NTOK];
__device__ bf16 g_sah[EE * NTOK * DD];
__device__ bf16 g_ff1h[EE * NTOK * FFD];
__device__ bf16 g_sch[(size_t)EE * HH * NTOK * NTOK];
__device__ bf16 g_schT[(size_t)EE * LL * MMEM * NTOK];
__device__ bf16 g_retrph[EE * NTOK * LL * DD];
__device__ bf16 g_memh[LL * MMEM * DD];
__device__ bf16 g_memTh[LL * DD * MMEM];
__device__ bf16 g_ipwh[EE * 3 * DD * DD], g_ipwl[EE * 3 * DD * DD];
__device__ bf16 g_opwh[EE * DD * DD], g_opwl[EE * DD * DD];
__device__ bf16 g_w1h[EE * FFD * DD], g_w1l[EE * FFD * DD];
__device__ bf16 g_w2h[EE * DD * FFD], g_w2l[EE * DD * FFD];
__device__ bf16 g_aggwh[DD * LL * DD];

__device__ __forceinline__ void split_bf16(float v, bf16& h, bf16& l) {
    h = __float2bfloat16(v);
    l = __float2bfloat16(v - __bfloat162float(h));
}
__device__ __forceinline__ uint32_t smem_u32(const void* p) {
    uint32_t a;
    asm("{ .reg .u64 t; cvta.to.shared.u64 t, %1; cvt.u32.u64 %0, t; }" : "=r"(a) : "l"(p));
    return a;
}

#define MMA16816(d, a0, a1, a2, a3, b0, b1) \
    asm volatile("mma.sync.aligned.m16n8k16.row.col.f32.bf16.bf16.f32 " \
                 "{%0,%1,%2,%3}, {%4,%5,%6,%7}, {%8,%9}, {%0,%1,%2,%3};" \
                 : "+f"((d)[0]), "+f"((d)[1]), "+f"((d)[2]), "+f"((d)[3]) \
                 : "r"(a0), "r"(a1), "r"(a2), "r"(a3), "r"(b0), "r"(b1))

#define LDSM4(r0, r1, r2, r3, addr) \
    asm volatile("ldmatrix.sync.aligned.m8n8.x4.shared.b16 {%0,%1,%2,%3}, [%4];" \
                 : "=r"(r0), "=r"(r1), "=r"(r2), "=r"(r3) : "r"(addr))

#define CP16(dst, src) \
    asm volatile("cp.async.cg.shared.global [%0], [%1], 16;" :: "r"(dst), "l"(src))
#define CPCOMMIT() asm volatile("cp.async.commit_group;")
#define CPWAIT(n)  asm volatile("cp.async.wait_group %0;" :: "n"(n))

// ---------------- HMMA bf16 GEMM: cp.async + ldmatrix pipeline, 2-level batch ----
// z1 = z % inner, z2 = z / inner; offsets = z1*Xi + z2*Xo.
// C[m,n] = ep( alpha * sum_k A[m*Arow+k] * B[n*Brow+k] )
// NS=1: Ah*Bh.  NS=2: Ah*Bh + Ah*Bl.  NS=3: + Al*Bh.
// nRemap: B row n += NTOK when >= th.  kRemap: k-tile += NTOK when >= th.
// th = thresh, or z2*NTOK when thresh < 0.
// ep: 0 none,1 clip±10,2 +bias,3 relu+bias,4 +bias+res,6 +res,7 clip±1
template<int BN, int NS, int STAGES>
__global__ void __launch_bounds__(256, 2) hgemm(
    const bf16* __restrict__ Ahg, const bf16* __restrict__ Alg,
    const bf16* __restrict__ Bhg, const bf16* __restrict__ Blg,
    float* __restrict__ C, bf16* __restrict__ Ch, bf16* __restrict__ Cl,
    int Kdim, int Arow, int Brow, int ldc,
    float alpha, int ep,
    const float* __restrict__ bias, long biasZ, const float* __restrict__ Rres,
    int nRemap, int kRemap, int thresh, int inner,
    long Ai, long Ao, long Bi, long Bo, long Ci, long Co)
{
    constexpr bool AL = (NS == 3);
    constexpr bool BL = (NS >= 2);
    constexpr int AST = 128 * 80;
    constexpr int BST = BN * 80;
    constexpr int NT = BN / 32;
    constexpr int BIT = BN / 64;

    const int z1 = blockIdx.z % inner;
    const int z2 = blockIdx.z / inner;
    const long aoff = (long)z1 * Ai + (long)z2 * Ao;
    const long boff = (long)z1 * Bi + (long)z2 * Bo;
    const long coff = (long)z1 * Ci + (long)z2 * Co;
    Ahg += aoff; Bhg += boff;
    if (AL) Alg += aoff;
    if (BL) Blg += boff;
    if (C)  C  += coff;
    if (Ch) Ch += coff;
    if (Cl) Cl += coff;
    if (Rres) Rres += coff;
    if (bias) bias += (long)z2 * biasZ;
    const int th = (thresh < 0) ? z2 * NTOK : thresh;

    extern __shared__ char sm[];
    const uint32_t smBase = smem_u32(sm);
    const uint32_t offAh = 0;
    const uint32_t offAl = STAGES * AST;
    const uint32_t offBh = (AL ? 2u : 1u) * STAGES * AST;
    const uint32_t offBl = offBh + STAGES * BST;

    const int tid = threadIdx.x;
    const int lane = tid & 31;
    const int wid = tid >> 5;
    const int wm = (wid >> 2) * 64;
    const int wn = (wid & 3) * (BN / 4);
    const int row0 = blockIdx.y * 128;
    const int col0 = blockIdx.x * BN;

    const int g = lane >> 3;
    const uint32_t laneOff = ((g & 1) * 8 + (lane & 7)) * 80 + (g >> 1) * 16;

    float acc[4][NT][4];
    #pragma unroll
    for (int i = 0; i < 4; i++)
        #pragma unroll
        for (int j = 0; j < NT; j++)
            #pragma unroll
            for (int r = 0; r < 4; r++) acc[i][j][r] = 0.f;

    auto fill = [&](int s, int t) {
        int k0 = t * 32;
        long kb = k0 + ((kRemap && k0 >= th) ? NTOK : 0);
        #pragma unroll
        for (int r = 0; r < 2; r++) {
            int idx = tid + r * 256;
            int row = idx >> 2, c = idx & 3;
            long go = (long)(row0 + row) * Arow + k0 + c * 8;
            uint32_t dst = smBase + offAh + s * AST + row * 80 + c * 16;
            CP16(dst, Ahg + go);
            if (AL) CP16(dst + (offAl - offAh), Alg + go);
        }
        #pragma unroll
        for (int r = 0; r < BIT; r++) {
            int idx = tid + r * 256;
            int row = idx >> 2, c = idx & 3;
            int ng = col0 + row;
            if (nRemap && ng >= th) ng += NTOK;
            long go = (long)ng * Brow + kb + c * 8;
            uint32_t dst = smBase + offBh + s * BST + row * 80 + c * 16;
            CP16(dst, Bhg + go);
            if (BL) CP16(dst + (offBl - offBh), Blg + go);
        }
    };

    auto compute = [&](int buf) {
        const uint32_t aH = smBase + offAh + buf * AST + laneOff;
        const uint32_t aL = smBase + offAl + buf * AST + laneOff;
        const uint32_t bH = smBase + offBh + buf * BST + laneOff;
        const uint32_t bL = smBase + offBl + buf * BST + laneOff;
        #pragma unroll
        for (int s = 0; s < 2; s++) {
            uint32_t bh[NT][2], bl[NT][2];
            #pragma unroll
            for (int p = 0; p < NT / 2; p++) {
                uint32_t addr = bH + (wn + p * 16) * 80 + s * 32;
                LDSM4(bh[2*p][0], bh[2*p+1][0], bh[2*p][1], bh[2*p+1][1], addr);
                if (BL) {
                    uint32_t addr2 = bL + (wn + p * 16) * 80 + s * 32;
                    LDSM4(bl[2*p][0], bl[2*p+1][0], bl[2*p][1], bl[2*p+1][1], addr2);
                }
            }
            #pragma unroll
            for (int mt = 0; mt < 4; mt++) {
                uint32_t a0, a1, a2, a3;
                LDSM4(a0, a1, a2, a3, aH + (wm + mt * 16) * 80 + s * 32);
                #pragma unroll
                for (int nt = 0; nt < NT; nt++)
                    MMA16816(acc[mt][nt], a0, a1, a2, a3, bh[nt][0], bh[nt][1]);
                if (BL) {
                    #pragma unroll
                    for (int nt = 0; nt < NT; nt++)
                        MMA16816(acc[mt][nt], a0, a1, a2, a3, bl[nt][0], bl[nt][1]);
                }
                if (AL) {
                    uint32_t l0, l1, l2, l3;
                    LDSM4(l0, l1, l2, l3, aL + (wm + mt * 16) * 80 + s * 32);
                    #pragma unroll
                    for (int nt = 0; nt < NT; nt++)
                        MMA16816(acc[mt][nt], l0, l1, l2, l3, bh[nt][0], bh[nt][1]);
                }
            }
        }
    };

    const int nk = Kdim / 32;
    #pragma unroll
    for (int s = 0; s < STAGES - 1; s++) {
        if (s < nk) fill(s, s);
        CPCOMMIT();
    }
    for (int t = 0; t < nk; t++) {
        CPWAIT(STAGES - 2);
        __syncthreads();
        int tn = t + STAGES - 1;
        if (tn < nk) fill(tn % STAGES, tn);
        CPCOMMIT();
        compute(t % STAGES);
    }

    // epilogue (vectorized: column pairs)
    #pragma unroll
    for (int mt = 0; mt < 4; mt++) {
        #pragma unroll
        for (int nt = 0; nt < NT; nt++) {
            int ng = col0 + wn + nt * 8 + (lane & 3) * 2;
            float2 b2 = make_float2(0.f, 0.f);
            if (ep >= 2 && ep <= 4) b2 = *(const float2*)(bias + ng);
            #pragma unroll
            for (int hf = 0; hf < 2; hf++) {
                int mg = row0 + wm + mt * 16 + (lane >> 2) + hf * 8;
                long ci = (long)mg * ldc + ng;
                float v0 = acc[mt][nt][hf * 2 + 0] * alpha;
                float v1 = acc[mt][nt][hf * 2 + 1] * alpha;
                switch (ep) {
                case 1:
                    v0 = fminf(fmaxf(v0, -10.f), 10.f);
                    v1 = fminf(fmaxf(v1, -10.f), 10.f); break;
                case 2: v0 += b2.x; v1 += b2.y; break;
                case 3:
                    v0 = fmaxf(v0 + b2.x, 0.f);
                    v1 = fmaxf(v1 + b2.y, 0.f); break;
                case 4: {
                    float2 r2 = *(const float2*)(Rres + ci);
                    v0 += b2.x + r2.x; v1 += b2.y + r2.y; } break;
                case 6: {
                    float2 r2 = *(const float2*)(Rres + ci);
                    v0 += r2.x; v1 += r2.y; } break;
                case 7:
                    v0 = fminf(fmaxf(v0, -1.f), 1.f);
                    v1 = fminf(fmaxf(v1, -1.f), 1.f); break;
                }
                if (C) *(float2*)(C + ci) = make_float2(v0, v1);
                if (Ch) {
                    bf16 h0, l0, h1, l1;
                    split_bf16(v0, h0, l0); split_bf16(v1, h1, l1);
                    *(__nv_bfloat162*)(Ch + ci) = __nv_bfloat162(h0, h1);
                    if (Cl) *(__nv_bfloat162*)(Cl + ci) = __nv_bfloat162(l0, l1);
                }
            }
        }
    }
}

// ---------------- transpose (bf16, 64x64 tiles, bf162 gmem transactions) --------
__global__ void transpose_bf16(const bf16* __restrict__ in, bf16* __restrict__ out,
                               int ldin, int ldout, long inz, long outz)
{
    __shared__ bf16 t[64][65];
    in += (long)blockIdx.z * inz;
    out += (long)blockIdx.z * outz;
    const int r0 = blockIdx.y * 64, c0 = blockIdx.x * 64;
    const int tx = threadIdx.x & 31;   // column-pair index
    const int ty = threadIdx.x >> 5;   // row base (8 rows)
    #pragma unroll
    for (int i = 0; i < 64; i += 8) {
        __nv_bfloat162 v = *(const __nv_bfloat162*)(in + (long)(r0 + ty + i) * ldin + c0 + tx * 2);
        t[tx * 2][ty + i] = v.x;
        t[tx * 2 + 1][ty + i] = v.y;
    }
    __syncthreads();
    #pragma unroll
    for (int i = 0; i < 64; i += 8) {
        int c = ty + i;
        __nv_bfloat162 v(t[c][tx * 2], t[c][tx * 2 + 1]);
        *(__nv_bfloat162*)(out + (long)(c0 + c) * ldout + r0 + tx * 2) = v;
    }
}

// ---------------- elementwise kernels ----------------
__global__ void convert_kernel(const float* __restrict__ src, bf16* __restrict__ h,
                               bf16* __restrict__ l, long n4h)
{
    long i = (long)blockIdx.x * blockDim.x + threadIdx.x;
    if (i >= n4h) return;
    #pragma unroll
    for (int r = 0; r < 2; r++) {
        long j = i + r * n4h;
        float4 v = ((const float4*)src)[j];
        bf16 hx, lx, hy, ly, hz, lz, hw, lw;
        split_bf16(v.x, hx, lx); split_bf16(v.y, hy, ly);
        split_bf16(v.z, hz, lz); split_bf16(v.w, hw, lw);
        __nv_bfloat162* h2 = (__nv_bfloat162*)h;
        h2[j * 2]     = __nv_bfloat162(hx, hy);
        h2[j * 2 + 1] = __nv_bfloat162(hz, hw);
        if (l) {
            __nv_bfloat162* l2 = (__nv_bfloat162*)l;
            l2[j * 2]     = __nv_bfloat162(lx, ly);
            l2[j * 2 + 1] = __nv_bfloat162(lz, lw);
        }
    }
}

// wsel: 0 = shared w/b (or null), 1 = per-expert slice w + (row/NTOK)*DD
__global__ void ln_kernel(const float* __restrict__ in, float* __restrict__ out,
                          const float* __restrict__ w, const float* __restrict__ b,
                          bf16* __restrict__ oh, bf16* __restrict__ ol, int wsel)
{
    const long row = blockIdx.x;
    const float* p = in + row * DD;
    const int t = threadIdx.x; // 128
    __shared__ float sh[4];
    const long wo = wsel ? (row / NTOK) * DD : 0;

    float v[4];
    float s = 0.f;
    #pragma unroll
    for (int i = 0; i < 4; i++) { v[i] = p[t + i * 128]; s += v[i]; }
    #pragma unroll
    for (int o = 16; o; o >>= 1) s += __shfl_down_sync(0xffffffffu, s, o);
    if ((t & 31) == 0) sh[t >> 5] = s;
    __syncthreads();
    float mu = (sh[0] + sh[1] + sh[2] + sh[3]) * (1.f / DD);
    __syncthreads();
    float sq = 0.f;
    #pragma unroll
    for (int i = 0; i < 4; i++) { float d = v[i] - mu; sq += d * d; }
    #pragma unroll
    for (int o = 16; o; o >>= 1) sq += __shfl_down_sync(0xffffffffu, sq, o);
    if ((t & 31) == 0) sh[t >> 5] = sq;
    __syncthreads();
    float rstd = rsqrtf((sh[0] + sh[1] + sh[2] + sh[3]) * (1.f / DD) + 1e-5f);

    #pragma unroll
    for (int i = 0; i < 4; i++) {
        int d = t + i * 128;
        float o = (v[i] - mu) * rstd;
        if (w) o = o * w[wo + d] + b[wo + d];
        long gi = row * DD + d;
        if (out) out[gi] = o;
        bf16 hh, ll; split_bf16(o, hh, ll);
        oh[gi] = hh;
        if (ol) ol[gi] = ll;
    }
}

// online softmax with smem row cache: ONE gmem read pass + bf16 write pass
__global__ void softmax_kernel(const float* __restrict__ S, bf16* __restrict__ Oh,
                               int cols)
{
    extern __shared__ float srow[];
    const float4* row = (const float4*)(S + (long)blockIdx.x * cols);
    float4* srow4 = (float4*)srow;
    __nv_bfloat162* oh = (__nv_bfloat162*)(Oh + (long)blockIdx.x * cols);
    const int t = threadIdx.x; // 256
    const int n4 = cols >> 2;
    __shared__ float shm[8], shs[8];

    float m = -1e30f, s = 0.f;
    for (int i = t; i < n4; i += 256) {
        float4 v = row[i];
        srow4[i] = v;
        float mx = fmaxf(fmaxf(v.x, v.y), fmaxf(v.z, v.w));
        if (mx > m) { s *= expf(m - mx); m = mx; }
        s += expf(v.x - m) + expf(v.y - m) + expf(v.z - m) + expf(v.w - m);
    }
    #pragma unroll
    for (int o = 16; o; o >>= 1) {
        float mo = __shfl_xor_sync(0xffffffffu, m, o);
        float so = __shfl_xor_sync(0xffffffffu, s, o);
        float mn = fmaxf(m, mo);
        s = s * expf(m - mn) + so * expf(mo - mn);
        m = mn;
    }
    if ((t & 31) == 0) { shm[t >> 5] = m; shs[t >> 5] = s; }
    __syncthreads();
    if (t == 0) {
        float M = shm[0], Sm = shs[0];
        #pragma unroll
        for (int w = 1; w < 8; w++) {
            float mn = fmaxf(M, shm[w]);
            Sm = Sm * expf(M - mn) + shs[w] * expf(shm[w] - mn);
            M = mn;
        }
        shm[0] = M; shs[0] = 1.f / Sm;
    }
    __syncthreads();
    const float M = shm[0], inv = shs[0];

    for (int i = t; i < n4; i += 256) {
        float4 v = srow4[i];
        float p0 = expf(v.x - M) * inv, p1 = expf(v.y - M) * inv;
        float p2 = expf(v.z - M) * inv, p3 = expf(v.w - M) * inv;
        oh[i * 2]     = __nv_bfloat162(__float2bfloat16(p0), __float2bfloat16(p1));
        oh[i * 2 + 1] = __nv_bfloat162(__float2bfloat16(p2), __float2bfloat16(p3));
    }
}

__global__ void pool_kernel(const float* __restrict__ x, float* __restrict__ pooled)
{
    int idx = blockIdx.x * blockDim.x + threadIdx.x;
    if (idx >= EE * DD) return;
    int e = idx / DD, d = idx % DD;
    const float* p = x + (long)e * NTOK * DD + d;
    float s = 0.f;
    #pragma unroll 16
    for (int n = 0; n < NTOK; n++) s += p[(long)n * DD];
    pooled[idx] = s * (1.f / NTOK);
}

__global__ void gate_kernel(const float* __restrict__ pooled, const float* __restrict__ gate,
                            float* __restrict__ out_gw, float* __restrict__ gdev)
{
    const int t = threadIdx.x;
    const int wid = t >> 5, lane = t & 31;
    __shared__ float logits[4];
    float s = 0.f;
    for (int d = lane; d < DD; d += 32) s += pooled[wid * DD + d] * gate[d];
    #pragma unroll
    for (int o = 16; o; o >>= 1) s += __shfl_down_sync(0xffffffffu, s, o);
    if (lane == 0) logits[wid] = fminf(fmaxf(s, -10.f), 10.f);
    __syncthreads();
    if (t == 0) {
        float mx = fmaxf(fmaxf(logits[0], logits[1]), fmaxf(logits[2], logits[3]));
        float e0 = expf(logits[0] - mx), e1 = expf(logits[1] - mx);
        float e2 = expf(logits[2] - mx), e3 = expf(logits[3] - mx);
        float inv = 1.f / (e0 + e1 + e2 + e3);
        out_gw[0] = gdev[0] = e0 * inv;
        out_gw[1] = gdev[1] = e1 * inv;
        out_gw[2] = gdev[2] = e2 * inv;
        out_gw[3] = gdev[3] = e3 * inv;
    }
}

__global__ void fused_kernel(const float* __restrict__ x, const float* __restrict__ gw,
                             float* __restrict__ out)
{
    long i = (long)blockIdx.x * blockDim.x + threadIdx.x;
    if (i >= (long)NTOK * DD) return;
    float s = 0.f;
    #pragma unroll
    for (int e = 0; e < EE; e++) s += gw[e] * x[(long)e * NTOK * DD + i];
    out[i] = s;
}

__global__ void newmem_kernel(const float* __restrict__ mem, const float* __restrict__ upd4,
                              float* __restrict__ out)
{
    long i = (long)blockIdx.x * blockDim.x + threadIdx.x;
    const long S = (long)LL * MMEM * DD;
    if (i >= S) return;
    float u = ((upd4[i] + upd4[i + S]) + upd4[i + 2 * S]) + upd4[i + 3 * S];
    u *= 0.1f;
    u = fminf(fmaxf(u, -0.1f), 0.1f);
    out[i] = 0.9f * mem[i] + u;
}

// ---------------- host-side launcher ----------------
struct GArgs {
    const bf16 *Ah, *Bh, *Bl;
    float* C; bf16 *Ch, *Cl;
    int M, N, K, Arow, Brow, ldc;
    float alpha; int ep;
    const float* bias; long biasZ; const float* R;
    int nRemap, kRemap, thresh, inner, batch;
    long Ai, Ao, Bi, Bo, Ci, Co;
    int NS;
};

static void hg(const GArgs& a)
{
    if (a.NS == 2) {
        if (a.N % 128 == 0) {
            dim3 g(a.N / 128, a.M / 128, a.batch);
            hgemm<128, 2, 3><<<g, 256, 92160>>>(a.Ah, a.Ah, a.Bh, a.Bl, a.C, a.Ch, a.Cl,
                a.K, a.Arow, a.Brow, a.ldc, a.alpha, a.ep, a.bias, a.biasZ, a.R,
                a.nRemap, a.kRemap, a.thresh, a.inner, a.Ai, a.Ao, a.Bi, a.Bo, a.Ci, a.Co);
        } else {
            dim3 g(a.N / 64, a.M / 128, a.batch);
            hgemm<64, 2, 3><<<g, 256, 61440>>>(a.Ah, a.Ah, a.Bh, a.Bl, a.C, a.Ch, a.Cl,
                a.K, a.Arow, a.Brow, a.ldc, a.alpha, a.ep, a.bias, a.biasZ, a.R,
                a.nRemap, a.kRemap, a.thresh, a.inner, a.Ai, a.Ao, a.Bi, a.Bo, a.Ci, a.Co);
        }
    } else {
        dim3 g(a.N / 128, a.M / 128, a.batch);
        hgemm<128, 1, 4><<<g, 256, 81920>>>(a.Ah, a.Ah, a.Bh, a.Bh, a.C, a.Ch, a.Cl,
            a.K, a.Arow, a.Brow, a.ldc, a.alpha, a.ep, a.bias, a.biasZ, a.R,
            a.nRemap, a.kRemap, a.thresh, a.inner, a.Ai, a.Ao, a.Bi, a.Bo, a.Ci, a.Co);
    }
}

static void tr(const bf16* in, bf16* out, int R, int C, int ldin, int ldout,
               int batch, long inz, long outz)
{
    dim3 g(C / 64, R / 64, batch);
    transpose_bf16<<<g, 256>>>(in, out, ldin, ldout, inz, outz);
}

static void conv(const float* s, bf16* h, bf16* l, long n)
{
    long n4h = n / 8;
    convert_kernel<<<(unsigned)((n4h + 255) / 256), 256>>>(s, h, l, n4h);
}

static void smax(float* sc, bf16* oh, int rows, int cols)
{
    softmax_kernel<<<rows, 256, cols * 4>>>(sc, oh, cols);
}

extern "C" void kernel_launch(void* const* d_in, const int* in_sizes, int n_in,
                              void* d_out, int out_size)
{
    const float* tokens   = (const float*)d_in[0];
    const float* memories = (const float*)d_in[1];
    const float* ipw      = (const float*)d_in[2];
    const float* ipb      = (const float*)d_in[3];
    const float* opw      = (const float*)d_in[4];
    const float* opb      = (const float*)d_in[5];
    const float* w1       = (const float*)d_in[6];
    const float* b1       = (const float*)d_in[7];
    const float* w2       = (const float*)d_in[8];
    const float* b2       = (const float*)d_in[9];
    const float* n1w      = (const float*)d_in[10];
    const float* n1b      = (const float*)d_in[11];
    const float* n2w      = (const float*)d_in[12];
    const float* n2b      = (const float*)d_in[13];
    const float* aggw     = (const float*)d_in[14];
    const float* aggb     = (const float*)d_in[15];
    const float* gate     = (const float*)d_in[16];
    float* out = (float*)d_out;

    static bool inited = false;
    if (!inited) {
        cudaFuncSetAttribute((const void*)hgemm<128, 2, 3>, cudaFuncAttributeMaxDynamicSharedMemorySize, 92160);
        cudaFuncSetAttribute((const void*)hgemm<64, 2, 3>,  cudaFuncAttributeMaxDynamicSharedMemorySize, 61440);
        cudaFuncSetAttribute((const void*)hgemm<128, 1, 4>, cudaFuncAttributeMaxDynamicSharedMemorySize, 81920);
        inited = true;
    }

    float *xln, *x, *y, *sc, *upd4, *pooled, *gatew;
    cudaGetSymbolAddress((void**)&xln, g_xln);
    cudaGetSymbolAddress((void**)&x, g_x);
    cudaGetSymbolAddress((void**)&y, g_y);
    cudaGetSymbolAddress((void**)&sc, g_scores);
    cudaGetSymbolAddress((void**)&upd4, g_upd4);
    cudaGetSymbolAddress((void**)&pooled, g_pooled);
    cudaGetSymbolAddress((void**)&gatew, g_gatew);

    bf16 *xlnh, *xlnl, *xlnTh, *xlnTl, *xh, *xTh, *qkvh, *qkvl, *vTh, *vTl;
    bf16 *sah, *ff1h, *sch, *schT, *retrph, *memh, *memTh;
    bf16 *ipwh, *ipwl, *opwh, *opwl, *w1h, *w1l, *w2h, *w2l, *aggwh;
    cudaGetSymbolAddress((void**)&xlnh, g_xlnh);   cudaGetSymbolAddress((void**)&xlnl, g_xlnl);
    cudaGetSymbolAddress((void**)&xlnTh, g_xlnTh); cudaGetSymbolAddress((void**)&xlnTl, g_xlnTl);
    cudaGetSymbolAddress((void**)&xh, g_xh);
    cudaGetSymbolAddress((void**)&xTh, g_xTh);
    cudaGetSymbolAddress((void**)&qkvh, g_qkvh);   cudaGetSymbolAddress((void**)&qkvl, g_qkvl);
    cudaGetSymbolAddress((void**)&vTh, g_vTh);     cudaGetSymbolAddress((void**)&vTl, g_vTl);
    cudaGetSymbolAddress((void**)&sah, g_sah);
    cudaGetSymbolAddress((void**)&ff1h, g_ff1h);
    cudaGetSymbolAddress((void**)&sch, g_sch);
    cudaGetSymbolAddress((void**)&schT, g_schT);
    cudaGetSymbolAddress((void**)&retrph, g_retrph);
    cudaGetSymbolAddress((void**)&memh, g_memh);   cudaGetSymbolAddress((void**)&memTh, g_memTh);
    cudaGetSymbolAddress((void**)&ipwh, g_ipwh);   cudaGetSymbolAddress((void**)&ipwl, g_ipwl);
    cudaGetSymbolAddress((void**)&opwh, g_opwh);   cudaGetSymbolAddress((void**)&opwl, g_opwl);
    cudaGetSymbolAddress((void**)&w1h, g_w1h);     cudaGetSymbolAddress((void**)&w1l, g_w1l);
    cudaGetSymbolAddress((void**)&w2h, g_w2h);     cudaGetSymbolAddress((void**)&w2l, g_w2l);
    cudaGetSymbolAddress((void**)&aggwh, g_aggwh);

    const float isd = 1.0f / sqrtf((float)DD);
    const long ND = (long)NTOK * DD;
    const long N3N = (long)NTOK * 3 * NTOK;
    const long NN = (long)NTOK * NTOK;
    const long NM = (long)NTOK * MMEM;

    conv(ipw, ipwh, ipwl, (long)EE * 3 * DD * DD);
    conv(opw, opwh, opwl, (long)EE * DD * DD);
    conv(w1, w1h, w1l, (long)EE * FFD * DD);
    conv(w2, w2h, w2l, (long)EE * DD * FFD);
    conv(aggw, aggwh, nullptr, (long)DD * LL * DD);
    conv(memories, memh, nullptr, (long)LL * MMEM * DD);
    tr(memh, memTh, MMEM, DD, DD, MMEM, LL, (long)MMEM * DD, (long)DD * MMEM);

    ln_kernel<<<EE * NTOK, 128>>>(tokens, xln, nullptr, nullptr, xlnh, xlnl, 0);
    tr(xlnh, xlnTh, EE * NTOK, DD, DD, EE * NTOK, 1, 0, 0);
    tr(xlnl, xlnTl, EE * NTOK, DD, DD, EE * NTOK, 1, 0, 0);

    // 1. cross scores: S[e] = clip(xln_e @ ctx^T / sqrt(D))  [N,3N], remap n per z
    { GArgs a{}; a.Ah=xlnh; a.Bh=xlnh; a.Bl=xlnl; a.C=sc;
      a.M=NTOK; a.N=3*NTOK; a.K=DD; a.Arow=DD; a.Brow=DD; a.ldc=3*NTOK;
      a.alpha=isd; a.ep=1; a.nRemap=1; a.thresh=-1; a.inner=1; a.batch=EE;
      a.Ao=ND; a.Co=N3N; a.NS=2; hg(a); }
    smax(sc, sch, EE * NTOK, 3 * NTOK);
    // 2. x = xln_e + P @ ctx  (B = xlnT h+l, remap k per z)
    { GArgs a{}; a.Ah=sch; a.Bh=xlnTh; a.Bl=xlnTl; a.C=x; a.Ch=xh;
      a.M=NTOK; a.N=DD; a.K=3*NTOK; a.Arow=3*NTOK; a.Brow=EE*NTOK; a.ldc=DD;
      a.alpha=1.f; a.ep=6; a.R=xln; a.kRemap=1; a.thresh=-1; a.inner=1; a.batch=EE;
      a.Ao=N3N; a.Co=ND; a.NS=2; hg(a); }

    // 3. qkv
    { GArgs a{}; a.Ah=xh; a.Bh=ipwh; a.Bl=ipwl; a.Ch=qkvh; a.Cl=qkvl;
      a.M=NTOK; a.N=3*DD; a.K=DD; a.Arow=DD; a.Brow=DD; a.ldc=3*DD;
      a.alpha=1.f; a.ep=2; a.bias=ipb; a.biasZ=3*DD; a.inner=1; a.batch=EE;
      a.Ao=ND; a.Bo=(long)3*DD*DD; a.Co=(long)NTOK*3*DD; a.NS=2; hg(a); }
    tr(qkvh + 2 * DD, vTh, NTOK, DD, 3 * DD, NTOK, EE, (long)NTOK*3*DD, (long)DD*NTOK);
    tr(qkvl + 2 * DD, vTl, NTOK, DD, 3 * DD, NTOK, EE, (long)NTOK*3*DD, (long)DD*NTOK);
    // 4. head scores (z = e*H + h)
    { GArgs a{}; a.Ah=qkvh; a.Bh=qkvh + DD; a.Bl=qkvl + DD; a.C=sc;
      a.M=NTOK; a.N=NTOK; a.K=DHH; a.Arow=3*DD; a.Brow=3*DD; a.ldc=NTOK;
      a.alpha=0.125f; a.ep=0; a.inner=HH; a.batch=EE*HH;
      a.Ai=DHH; a.Ao=(long)NTOK*3*DD; a.Bi=DHH; a.Bo=(long)NTOK*3*DD;
      a.Ci=NN; a.Co=HH*NN; a.NS=2; hg(a); }
    smax(sc, sch, EE * HH * NTOK, NTOK);
    // 5. sa = P @ V (z = e*H + h)
    { GArgs a{}; a.Ah=sch; a.Bh=vTh; a.Bl=vTl; a.Ch=sah;
      a.M=NTOK; a.N=DHH; a.K=NTOK; a.Arow=NTOK; a.Brow=NTOK; a.ldc=DD;
      a.alpha=1.f; a.ep=0; a.inner=HH; a.batch=EE*HH;
      a.Ai=NN; a.Ao=HH*NN; a.Bi=(long)DHH*NTOK; a.Bo=(long)DD*NTOK;
      a.Ci=DHH; a.Co=ND; a.NS=2; hg(a); }
    // 6. out_proj + bias + residual
    { GArgs a{}; a.Ah=sah; a.Bh=opwh; a.Bl=opwl; a.C=y;
      a.M=NTOK; a.N=DD; a.K=DD; a.Arow=DD; a.Brow=DD; a.ldc=DD;
      a.alpha=1.f; a.ep=4; a.bias=opb; a.biasZ=DD; a.R=x; a.inner=1; a.batch=EE;
      a.Ao=ND; a.Bo=(long)DD*DD; a.Co=ND; a.NS=2; hg(a); }
    ln_kernel<<<EE * NTOK, 128>>>(y, x, n1w, n1b, xh, nullptr, 1);
    // 7. FFN
    { GArgs a{}; a.Ah=xh; a.Bh=w1h; a.Bl=w1l; a.Ch=ff1h;
      a.M=NTOK; a.N=FFD; a.K=DD; a.Arow=DD; a.Brow=DD; a.ldc=FFD;
      a.alpha=1.f; a.ep=3; a.bias=b1; a.biasZ=FFD; a.inner=1; a.batch=EE;
      a.Ao=ND; a.Bo=(long)FFD*DD; a.Co=(long)NTOK*FFD; a.NS=2; hg(a); }
    { GArgs a{}; a.Ah=ff1h; a.Bh=w2h; a.Bl=w2l; a.C=y;
      a.M=NTOK; a.N=DD; a.K=FFD; a.Arow=FFD; a.Brow=FFD; a.ldc=DD;
      a.alpha=1.f; a.ep=4; a.bias=b2; a.biasZ=DD; a.R=x; a.inner=1; a.batch=EE;
      a.Ao=(long)NTOK*FFD; a.Bo=(long)DD*FFD; a.Co=ND; a.NS=2; hg(a); }
    ln_kernel<<<EE * NTOK, 128>>>(y, x, n2w, n2b, xh, nullptr, 1);
    tr(xh, xTh, NTOK, DD, DD, NTOK, EE, ND, ND);

    // 8. memory scores (z = e*L + l)
    { GArgs a{}; a.Ah=xh; a.Bh=memh; a.Bl=memh; a.C=sc;
      a.M=NTOK; a.N=MMEM; a.K=DD; a.Arow=DD; a.Brow=DD; a.ldc=MMEM;
      a.alpha=isd; a.ep=1; a.inner=LL; a.batch=EE*LL;
      a.Ai=0; a.Ao=ND; a.Bi=(long)MMEM*DD; a.Bo=0;
      a.Ci=NM; a.Co=LL*NM; a.NS=1; hg(a); }
    smax(sc, sch, EE * LL * NTOK, MMEM);
    tr(sch, schT, NTOK, MMEM, MMEM, NTOK, EE * LL, NM, NM);
    // 9. retr -> retrph [e][n][l*D+d] directly (permuted bf16 epilogue)
    { GArgs a{}; a.Ah=sch; a.Bh=memTh; a.Bl=memTh; a.Ch=retrph;
      a.M=NTOK; a.N=DD; a.K=MMEM; a.Arow=MMEM; a.Brow=MMEM; a.ldc=LL*DD;
      a.alpha=1.f; a.ep=0; a.inner=LL; a.batch=EE*LL;
      a.Ai=NM; a.Ao=LL*NM; a.Bi=(long)DD*MMEM; a.Bo=0;
      a.Ci=DD; a.Co=(long)NTOK*LL*DD; a.NS=1; hg(a); }
    // 10. upd4[e][l] = clip(A^T @ x, ±1)
    { GArgs a{}; a.Ah=schT; a.Bh=xTh; a.Bl=xTh; a.C=upd4;
      a.M=MMEM; a.N=DD; a.K=NTOK; a.Arow=NTOK; a.Brow=NTOK; a.ldc=DD;
      a.alpha=1.f; a.ep=7; a.inner=LL; a.batch=EE*LL;
      a.Ai=(long)MMEM*NTOK; a.Ao=(long)LL*MMEM*NTOK; a.Bi=0; a.Bo=(long)DD*NTOK;
      a.Ci=(long)MMEM*DD; a.Co=(long)LL*MMEM*DD; a.NS=1; hg(a); }
    // 11. x = x + retrp @ agg_w^T + agg_b
    { GArgs a{}; a.Ah=retrph; a.Bh=aggwh; a.Bl=aggwh; a.C=x;
      a.M=NTOK; a.N=DD; a.K=LL*DD; a.Arow=LL*DD; a.Brow=LL*DD; a.ldc=DD;
      a.alpha=1.f; a.ep=4; a.bias=aggb; a.biasZ=0; a.R=x; a.inner=1; a.batch=EE;
      a.Ao=(long)NTOK*LL*DD; a.Co=ND; a.NS=1; hg(a); }

    pool_kernel<<<(EE * DD + 255) / 256, 256>>>(x, pooled);
    gate_kernel<<<1, 128>>>(pooled, gate, out + ND, gatew);
    fused_kernel<<<(unsigned)((ND + 255) / 256), 256>>>(x, gatew, out);
    {
        long n = (long)LL * MMEM * DD;
        newmem_kernel<<<(unsigned)((n + 255) / 256), 256>>>(memories, upd4, out + ND + EE);
    }
}

// round 10
// speedup vs baseline: 7.8481x; 1.0190x over previous
#include <cuda_runtime.h>
#include <cuda_bf16.h>
#include <math.h>
#include <stdint.h>

#define EE 4
#define NTOK 2048
#define DD 512
#define HH 8
#define DHH 64
#define FFD 2048
#define LL 4
#define MMEM 4096

typedef __nv_bfloat16 bf16;

// ---------------- static scratch ----------------
__device__ float g_xln[EE * NTOK * DD];
__device__ float g_x[EE * NTOK * DD];
__device__ float g_y[EE * NTOK * DD];
__device__ float g_scores[(size_t)EE * HH * NTOK * NTOK];
__device__ float g_upd4[(size_t)EE * LL * MMEM * DD];
__device__ float g_pooled[EE * DD];
__device__ float g_gatew[EE];

__device__ bf16 g_xlnh[EE * NTOK * DD], g_xlnl[EE * NTOK * DD];
__device__ bf16 g_xlnTh[DD * EE * NTOK], g_xlnTl[DD * EE * NTOK];
__device__ bf16 g_xh[EE * NTOK * DD];
__device__ bf16 g_xTh[EE * DD * NTOK];
__device__ bf16 g_qkvh[EE * NTOK * 3 * DD], g_qkvl[EE * NTOK * 3 * DD];
__device__ bf16 g_vTh[EE * DD * NTOK], g_vTl[EE * DD * NTOK];
__device__ bf16 g_sah[EE * NTOK * DD];
__device__ bf16 g_ff1h[EE * NTOK * FFD];
__device__ bf16 g_sch[(size_t)EE * HH * NTOK * NTOK];
__device__ bf16 g_schT[(size_t)EE * LL * MMEM * NTOK];
__device__ bf16 g_retrph[EE * NTOK * LL * DD];
__device__ bf16 g_memh[LL * MMEM * DD];
__device__ bf16 g_memTh[LL * DD * MMEM];
__device__ bf16 g_ipwh[EE * 3 * DD * DD], g_ipwl[EE * 3 * DD * DD];
__device__ bf16 g_opwh[EE * DD * DD], g_opwl[EE * DD * DD];
__device__ bf16 g_w1h[EE * FFD * DD], g_w1l[EE * FFD * DD];
__device__ bf16 g_w2h[EE * DD * FFD], g_w2l[EE * DD * FFD];
__device__ bf16 g_aggwh[DD * LL * DD];

__device__ __forceinline__ void split_bf16(float v, bf16& h, bf16& l) {
    h = __float2bfloat16(v);
    l = __float2bfloat16(v - __bfloat162float(h));
}
__device__ __forceinline__ uint32_t smem_u32(const void* p) {
    uint32_t a;
    asm("{ .reg .u64 t; cvta.to.shared.u64 t, %1; cvt.u32.u64 %0, t; }" : "=r"(a) : "l"(p));
    return a;
}

#define MMA16816(d, a0, a1, a2, a3, b0, b1) \
    asm volatile("mma.sync.aligned.m16n8k16.row.col.f32.bf16.bf16.f32 " \
                 "{%0,%1,%2,%3}, {%4,%5,%6,%7}, {%8,%9}, {%0,%1,%2,%3};" \
                 : "+f"((d)[0]), "+f"((d)[1]), "+f"((d)[2]), "+f"((d)[3]) \
                 : "r"(a0), "r"(a1), "r"(a2), "r"(a3), "r"(b0), "r"(b1))

#define LDSM4(r0, r1, r2, r3, addr) \
    asm volatile("ldmatrix.sync.aligned.m8n8.x4.shared.b16 {%0,%1,%2,%3}, [%4];" \
                 : "=r"(r0), "=r"(r1), "=r"(r2), "=r"(r3) : "r"(addr))

#define CP16(dst, src) \
    asm volatile("cp.async.cg.shared.global [%0], [%1], 16;" :: "r"(dst), "l"(src))
#define CPCOMMIT() asm volatile("cp.async.commit_group;")
#define CPWAIT(n)  asm volatile("cp.async.wait_group %0;" :: "n"(n))

// ---------------- HMMA bf16 GEMM: cp.async + ldmatrix pipeline, 2-level batch ----
template<int BN, int NS, int STAGES>
__global__ void __launch_bounds__(256, 2) hgemm(
    const bf16* __restrict__ Ahg, const bf16* __restrict__ Alg,
    const bf16* __restrict__ Bhg, const bf16* __restrict__ Blg,
    float* __restrict__ C, bf16* __restrict__ Ch, bf16* __restrict__ Cl,
    int Kdim, int Arow, int Brow, int ldc,
    float alpha, int ep,
    const float* __restrict__ bias, long biasZ, const float* __restrict__ Rres,
    int nRemap, int kRemap, int thresh, int inner,
    long Ai, long Ao, long Bi, long Bo, long Ci, long Co)
{
    constexpr bool AL = (NS == 3);
    constexpr bool BL = (NS >= 2);
    constexpr int AST = 128 * 80;
    constexpr int BST = BN * 80;
    constexpr int NT = BN / 32;
    constexpr int BIT = BN / 64;

    const int z1 = blockIdx.z % inner;
    const int z2 = blockIdx.z / inner;
    const long aoff = (long)z1 * Ai + (long)z2 * Ao;
    const long boff = (long)z1 * Bi + (long)z2 * Bo;
    const long coff = (long)z1 * Ci + (long)z2 * Co;
    Ahg += aoff; Bhg += boff;
    if (AL) Alg += aoff;
    if (BL) Blg += boff;
    if (C)  C  += coff;
    if (Ch) Ch += coff;
    if (Cl) Cl += coff;
    if (Rres) Rres += coff;
    if (bias) bias += (long)z2 * biasZ;
    const int th = (thresh < 0) ? z2 * NTOK : thresh;

    extern __shared__ char sm[];
    const uint32_t smBase = smem_u32(sm);
    const uint32_t offAh = 0;
    const uint32_t offAl = STAGES * AST;
    const uint32_t offBh = (AL ? 2u : 1u) * STAGES * AST;
    const uint32_t offBl = offBh + STAGES * BST;

    const int tid = threadIdx.x;
    const int lane = tid & 31;
    const int wid = tid >> 5;
    const int wm = (wid >> 2) * 64;
    const int wn = (wid & 3) * (BN / 4);
    const int row0 = blockIdx.y * 128;
    const int col0 = blockIdx.x * BN;

    const int g = lane >> 3;
    const uint32_t laneOff = ((g & 1) * 8 + (lane & 7)) * 80 + (g >> 1) * 16;

    float acc[4][NT][4];
    #pragma unroll
    for (int i = 0; i < 4; i++)
        #pragma unroll
        for (int j = 0; j < NT; j++)
            #pragma unroll
            for (int r = 0; r < 4; r++) acc[i][j][r] = 0.f;

    auto fill = [&](int s, int t) {
        int k0 = t * 32;
        long kb = k0 + ((kRemap && k0 >= th) ? NTOK : 0);
        #pragma unroll
        for (int r = 0; r < 2; r++) {
            int idx = tid + r * 256;
            int row = idx >> 2, c = idx & 3;
            long go = (long)(row0 + row) * Arow + k0 + c * 8;
            uint32_t dst = smBase + offAh + s * AST + row * 80 + c * 16;
            CP16(dst, Ahg + go);
            if (AL) CP16(dst + (offAl - offAh), Alg + go);
        }
        #pragma unroll
        for (int r = 0; r < BIT; r++) {
            int idx = tid + r * 256;
            int row = idx >> 2, c = idx & 3;
            int ng = col0 + row;
            if (nRemap && ng >= th) ng += NTOK;
            long go = (long)ng * Brow + kb + c * 8;
            uint32_t dst = smBase + offBh + s * BST + row * 80 + c * 16;
            CP16(dst, Bhg + go);
            if (BL) CP16(dst + (offBl - offBh), Blg + go);
        }
    };

    auto compute = [&](int buf) {
        const uint32_t aH = smBase + offAh + buf * AST + laneOff;
        const uint32_t aL = smBase + offAl + buf * AST + laneOff;
        const uint32_t bH = smBase + offBh + buf * BST + laneOff;
        const uint32_t bL = smBase + offBl + buf * BST + laneOff;
        #pragma unroll
        for (int s = 0; s < 2; s++) {
            uint32_t bh[NT][2], bl[NT][2];
            #pragma unroll
            for (int p = 0; p < NT / 2; p++) {
                uint32_t addr = bH + (wn + p * 16) * 80 + s * 32;
                LDSM4(bh[2*p][0], bh[2*p+1][0], bh[2*p][1], bh[2*p+1][1], addr);
                if (BL) {
                    uint32_t addr2 = bL + (wn + p * 16) * 80 + s * 32;
                    LDSM4(bl[2*p][0], bl[2*p+1][0], bl[2*p][1], bl[2*p+1][1], addr2);
                }
            }
            #pragma unroll
            for (int mt = 0; mt < 4; mt++) {
                uint32_t a0, a1, a2, a3;
                LDSM4(a0, a1, a2, a3, aH + (wm + mt * 16) * 80 + s * 32);
                #pragma unroll
                for (int nt = 0; nt < NT; nt++)
                    MMA16816(acc[mt][nt], a0, a1, a2, a3, bh[nt][0], bh[nt][1]);
                if (BL) {
                    #pragma unroll
                    for (int nt = 0; nt < NT; nt++)
                        MMA16816(acc[mt][nt], a0, a1, a2, a3, bl[nt][0], bl[nt][1]);
                }
                if (AL) {
                    uint32_t l0, l1, l2, l3;
                    LDSM4(l0, l1, l2, l3, aL + (wm + mt * 16) * 80 + s * 32);
                    #pragma unroll
                    for (int nt = 0; nt < NT; nt++)
                        MMA16816(acc[mt][nt], l0, l1, l2, l3, bh[nt][0], bh[nt][1]);
                }
            }
        }
    };

    const int nk = Kdim / 32;
    #pragma unroll
    for (int s = 0; s < STAGES - 1; s++) {
        if (s < nk) fill(s, s);
        CPCOMMIT();
    }
    for (int t = 0; t < nk; t++) {
        CPWAIT(STAGES - 2);
        __syncthreads();
        int tn = t + STAGES - 1;
        if (tn < nk) fill(tn % STAGES, tn);
        CPCOMMIT();
        compute(t % STAGES);
    }

    // epilogue (vectorized: column pairs)
    #pragma unroll
    for (int mt = 0; mt < 4; mt++) {
        #pragma unroll
        for (int nt = 0; nt < NT; nt++) {
            int ng = col0 + wn + nt * 8 + (lane & 3) * 2;
            float2 b2 = make_float2(0.f, 0.f);
            if (ep >= 2 && ep <= 4) b2 = *(const float2*)(bias + ng);
            #pragma unroll
            for (int hf = 0; hf < 2; hf++) {
                int mg = row0 + wm + mt * 16 + (lane >> 2) + hf * 8;
                long ci = (long)mg * ldc + ng;
                float v0 = acc[mt][nt][hf * 2 + 0] * alpha;
                float v1 = acc[mt][nt][hf * 2 + 1] * alpha;
                switch (ep) {
                case 1:
                    v0 = fminf(fmaxf(v0, -10.f), 10.f);
                    v1 = fminf(fmaxf(v1, -10.f), 10.f); break;
                case 2: v0 += b2.x; v1 += b2.y; break;
                case 3:
                    v0 = fmaxf(v0 + b2.x, 0.f);
                    v1 = fmaxf(v1 + b2.y, 0.f); break;
                case 4: {
                    float2 r2 = *(const float2*)(Rres + ci);
                    v0 += b2.x + r2.x; v1 += b2.y + r2.y; } break;
                case 6: {
                    float2 r2 = *(const float2*)(Rres + ci);
                    v0 += r2.x; v1 += r2.y; } break;
                case 7:
                    v0 = fminf(fmaxf(v0, -1.f), 1.f);
                    v1 = fminf(fmaxf(v1, -1.f), 1.f); break;
                }
                if (C) *(float2*)(C + ci) = make_float2(v0, v1);
                if (Ch) {
                    bf16 h0, l0, h1, l1;
                    split_bf16(v0, h0, l0); split_bf16(v1, h1, l1);
                    *(__nv_bfloat162*)(Ch + ci) = __nv_bfloat162(h0, h1);
                    if (Cl) *(__nv_bfloat162*)(Cl + ci) = __nv_bfloat162(l0, l1);
                }
            }
        }
    }
}

// ---------------- transpose (bf16, 64x64 tiles, bf162 gmem transactions) --------
__global__ void transpose_bf16(const bf16* __restrict__ in, bf16* __restrict__ out,
                               int ldin, int ldout, long inz, long outz)
{
    __shared__ bf16 t[64][65];
    in += (long)blockIdx.z * inz;
    out += (long)blockIdx.z * outz;
    const int r0 = blockIdx.y * 64, c0 = blockIdx.x * 64;
    const int tx = threadIdx.x & 31;
    const int ty = threadIdx.x >> 5;
    #pragma unroll
    for (int i = 0; i < 64; i += 8) {
        __nv_bfloat162 v = *(const __nv_bfloat162*)(in + (long)(r0 + ty + i) * ldin + c0 + tx * 2);
        t[tx * 2][ty + i] = v.x;
        t[tx * 2 + 1][ty + i] = v.y;
    }
    __syncthreads();
    #pragma unroll
    for (int i = 0; i < 64; i += 8) {
        int c = ty + i;
        __nv_bfloat162 v(t[c][tx * 2], t[c][tx * 2 + 1]);
        *(__nv_bfloat162*)(out + (long)(c0 + c) * ldout + r0 + tx * 2) = v;
    }
}

// ---------------- elementwise kernels ----------------
__global__ void convert_kernel(const float* __restrict__ src, bf16* __restrict__ h,
                               bf16* __restrict__ l, long n4h)
{
    long i = (long)blockIdx.x * blockDim.x + threadIdx.x;
    if (i >= n4h) return;
    #pragma unroll
    for (int r = 0; r < 2; r++) {
        long j = i + r * n4h;
        float4 v = ((const float4*)src)[j];
        bf16 hx, lx, hy, ly, hz, lz, hw, lw;
        split_bf16(v.x, hx, lx); split_bf16(v.y, hy, ly);
        split_bf16(v.z, hz, lz); split_bf16(v.w, hw, lw);
        __nv_bfloat162* h2 = (__nv_bfloat162*)h;
        h2[j * 2]     = __nv_bfloat162(hx, hy);
        h2[j * 2 + 1] = __nv_bfloat162(hz, hw);
        if (l) {
            __nv_bfloat162* l2 = (__nv_bfloat162*)l;
            l2[j * 2]     = __nv_bfloat162(lx, ly);
            l2[j * 2 + 1] = __nv_bfloat162(lz, lw);
        }
    }
}

__global__ void ln_kernel(const float* __restrict__ in, float* __restrict__ out,
                          const float* __restrict__ w, const float* __restrict__ b,
                          bf16* __restrict__ oh, bf16* __restrict__ ol, int wsel)
{
    const long row = blockIdx.x;
    const float* p = in + row * DD;
    const int t = threadIdx.x; // 128
    __shared__ float sh[4];
    const long wo = wsel ? (row / NTOK) * DD : 0;

    float v[4];
    float s = 0.f;
    #pragma unroll
    for (int i = 0; i < 4; i++) { v[i] = p[t + i * 128]; s += v[i]; }
    #pragma unroll
    for (int o = 16; o; o >>= 1) s += __shfl_down_sync(0xffffffffu, s, o);
    if ((t & 31) == 0) sh[t >> 5] = s;
    __syncthreads();
    float mu = (sh[0] + sh[1] + sh[2] + sh[3]) * (1.f / DD);
    __syncthreads();
    float sq = 0.f;
    #pragma unroll
    for (int i = 0; i < 4; i++) { float d = v[i] - mu; sq += d * d; }
    #pragma unroll
    for (int o = 16; o; o >>= 1) sq += __shfl_down_sync(0xffffffffu, sq, o);
    if ((t & 31) == 0) sh[t >> 5] = sq;
    __syncthreads();
    float rstd = rsqrtf((sh[0] + sh[1] + sh[2] + sh[3]) * (1.f / DD) + 1e-5f);

    #pragma unroll
    for (int i = 0; i < 4; i++) {
        int d = t + i * 128;
        float o = (v[i] - mu) * rstd;
        if (w) o = o * w[wo + d] + b[wo + d];
        long gi = row * DD + d;
        if (out) out[gi] = o;
        bf16 hh, ll; split_bf16(o, hh, ll);
        oh[gi] = hh;
        if (ol) ol[gi] = ll;
    }
}

// online softmax with smem row cache
__global__ void softmax_kernel(const float* __restrict__ S, bf16* __restrict__ Oh,
                               int cols)
{
    extern __shared__ float srow[];
    const float4* row = (const float4*)(S + (long)blockIdx.x * cols);
    float4* srow4 = (float4*)srow;
    __nv_bfloat162* oh = (__nv_bfloat162*)(Oh + (long)blockIdx.x * cols);
    const int t = threadIdx.x; // 256
    const int n4 = cols >> 2;
    __shared__ float shm[8], shs[8];

    float m = -1e30f, s = 0.f;
    for (int i = t; i < n4; i += 256) {
        float4 v = row[i];
        srow4[i] = v;
        float mx = fmaxf(fmaxf(v.x, v.y), fmaxf(v.z, v.w));
        if (mx > m) { s *= expf(m - mx); m = mx; }
        s += expf(v.x - m) + expf(v.y - m) + expf(v.z - m) + expf(v.w - m);
    }
    #pragma unroll
    for (int o = 16; o; o >>= 1) {
        float mo = __shfl_xor_sync(0xffffffffu, m, o);
        float so = __shfl_xor_sync(0xffffffffu, s, o);
        float mn = fmaxf(m, mo);
        s = s * expf(m - mn) + so * expf(mo - mn);
        m = mn;
    }
    if ((t & 31) == 0) { shm[t >> 5] = m; shs[t >> 5] = s; }
    __syncthreads();
    if (t == 0) {
        float M = shm[0], Sm = shs[0];
        #pragma unroll
        for (int w = 1; w < 8; w++) {
            float mn = fmaxf(M, shm[w]);
            Sm = Sm * expf(M - mn) + shs[w] * expf(shm[w] - mn);
            M = mn;
        }
        shm[0] = M; shs[0] = 1.f / Sm;
    }
    __syncthreads();
    const float M = shm[0], inv = shs[0];

    for (int i = t; i < n4; i += 256) {
        float4 v = srow4[i];
        float p0 = expf(v.x - M) * inv, p1 = expf(v.y - M) * inv;
        float p2 = expf(v.z - M) * inv, p3 = expf(v.w - M) * inv;
        oh[i * 2]     = __nv_bfloat162(__float2bfloat16(p0), __float2bfloat16(p1));
        oh[i * 2 + 1] = __nv_bfloat162(__float2bfloat16(p2), __float2bfloat16(p3));
    }
}

__global__ void pool_kernel(const float* __restrict__ x, float* __restrict__ pooled)
{
    int idx = blockIdx.x * blockDim.x + threadIdx.x;
    if (idx >= EE * DD) return;
    int e = idx / DD, d = idx % DD;
    const float* p = x + (long)e * NTOK * DD + d;
    float s = 0.f;
    #pragma unroll 16
    for (int n = 0; n < NTOK; n++) s += p[(long)n * DD];
    pooled[idx] = s * (1.f / NTOK);
}

__global__ void gate_kernel(const float* __restrict__ pooled, const float* __restrict__ gate,
                            float* __restrict__ out_gw, float* __restrict__ gdev)
{
    const int t = threadIdx.x;
    const int wid = t >> 5, lane = t & 31;
    __shared__ float logits[4];
    float s = 0.f;
    for (int d = lane; d < DD; d += 32) s += pooled[wid * DD + d] * gate[d];
    #pragma unroll
    for (int o = 16; o; o >>= 1) s += __shfl_down_sync(0xffffffffu, s, o);
    if (lane == 0) logits[wid] = fminf(fmaxf(s, -10.f), 10.f);
    __syncthreads();
    if (t == 0) {
        float mx = fmaxf(fmaxf(logits[0], logits[1]), fmaxf(logits[2], logits[3]));
        float e0 = expf(logits[0] - mx), e1 = expf(logits[1] - mx);
        float e2 = expf(logits[2] - mx), e3 = expf(logits[3] - mx);
        float inv = 1.f / (e0 + e1 + e2 + e3);
        out_gw[0] = gdev[0] = e0 * inv;
        out_gw[1] = gdev[1] = e1 * inv;
        out_gw[2] = gdev[2] = e2 * inv;
        out_gw[3] = gdev[3] = e3 * inv;
    }
}

__global__ void fused_kernel(const float* __restrict__ x, const float* __restrict__ gw,
                             float* __restrict__ out)
{
    long i = (long)blockIdx.x * blockDim.x + threadIdx.x;
    if (i >= (long)NTOK * DD) return;
    float s = 0.f;
    #pragma unroll
    for (int e = 0; e < EE; e++) s += gw[e] * x[(long)e * NTOK * DD + i];
    out[i] = s;
}

__global__ void newmem_kernel(const float* __restrict__ mem, const float* __restrict__ upd4,
                              float* __restrict__ out)
{
    long i = (long)blockIdx.x * blockDim.x + threadIdx.x;
    const long S = (long)LL * MMEM * DD;
    if (i >= S) return;
    float u = ((upd4[i] + upd4[i + S]) + upd4[i + 2 * S]) + upd4[i + 3 * S];
    u *= 0.1f;
    u = fminf(fmaxf(u, -0.1f), 0.1f);
    out[i] = 0.9f * mem[i] + u;
}

// ---------------- host-side launcher ----------------
struct GArgs {
    const bf16 *Ah, *Bh, *Bl;
    float* C; bf16 *Ch, *Cl;
    int M, N, K, Arow, Brow, ldc;
    float alpha; int ep;
    const float* bias; long biasZ; const float* R;
    int nRemap, kRemap, thresh, inner, batch;
    long Ai, Ao, Bi, Bo, Ci, Co;
    int NS;
    cudaStream_t st;
};

static void hg(const GArgs& a)
{
    if (a.NS == 2) {
        if (a.N % 128 == 0) {
            dim3 g(a.N / 128, a.M / 128, a.batch);
            hgemm<128, 2, 3><<<g, 256, 92160, a.st>>>(a.Ah, a.Ah, a.Bh, a.Bl, a.C, a.Ch, a.Cl,
                a.K, a.Arow, a.Brow, a.ldc, a.alpha, a.ep, a.bias, a.biasZ, a.R,
                a.nRemap, a.kRemap, a.thresh, a.inner, a.Ai, a.Ao, a.Bi, a.Bo, a.Ci, a.Co);
        } else {
            dim3 g(a.N / 64, a.M / 128, a.batch);
            hgemm<64, 2, 3><<<g, 256, 61440, a.st>>>(a.Ah, a.Ah, a.Bh, a.Bl, a.C, a.Ch, a.Cl,
                a.K, a.Arow, a.Brow, a.ldc, a.alpha, a.ep, a.bias, a.biasZ, a.R,
                a.nRemap, a.kRemap, a.thresh, a.inner, a.Ai, a.Ao, a.Bi, a.Bo, a.Ci, a.Co);
        }
    } else {
        dim3 g(a.N / 128, a.M / 128, a.batch);
        hgemm<128, 1, 4><<<g, 256, 81920, a.st>>>(a.Ah, a.Ah, a.Bh, a.Bh, a.C, a.Ch, a.Cl,
            a.K, a.Arow, a.Brow, a.ldc, a.alpha, a.ep, a.bias, a.biasZ, a.R,
            a.nRemap, a.kRemap, a.thresh, a.inner, a.Ai, a.Ao, a.Bi, a.Bo, a.Ci, a.Co);
    }
}

static void tr(const bf16* in, bf16* out, int R, int C, int ldin, int ldout,
               int batch, long inz, long outz, cudaStream_t st = 0)
{
    dim3 g(C / 64, R / 64, batch);
    transpose_bf16<<<g, 256, 0, st>>>(in, out, ldin, ldout, inz, outz);
}

static void conv(const float* s, bf16* h, bf16* l, long n, cudaStream_t st = 0)
{
    long n4h = n / 8;
    convert_kernel<<<(unsigned)((n4h + 255) / 256), 256, 0, st>>>(s, h, l, n4h);
}

static void smax(float* sc, bf16* oh, int rows, int cols)
{
    softmax_kernel<<<rows, 256, cols * 4>>>(sc, oh, cols);
}

extern "C" void kernel_launch(void* const* d_in, const int* in_sizes, int n_in,
                              void* d_out, int out_size)
{
    const float* tokens   = (const float*)d_in[0];
    const float* memories = (const float*)d_in[1];
    const float* ipw      = (const float*)d_in[2];
    const float* ipb      = (const float*)d_in[3];
    const float* opw      = (const float*)d_in[4];
    const float* opb      = (const float*)d_in[5];
    const float* w1       = (const float*)d_in[6];
    const float* b1       = (const float*)d_in[7];
    const float* w2       = (const float*)d_in[8];
    const float* b2       = (const float*)d_in[9];
    const float* n1w      = (const float*)d_in[10];
    const float* n1b      = (const float*)d_in[11];
    const float* n2w      = (const float*)d_in[12];
    const float* n2b      = (const float*)d_in[13];
    const float* aggw     = (const float*)d_in[14];
    const float* aggb     = (const float*)d_in[15];
    const float* gate     = (const float*)d_in[16];
    float* out = (float*)d_out;

    static bool inited = false;
    static cudaStream_t s2;
    static cudaEvent_t ev[8];
    if (!inited) {
        cudaFuncSetAttribute((const void*)hgemm<128, 2, 3>, cudaFuncAttributeMaxDynamicSharedMemorySize, 92160);
        cudaFuncSetAttribute((const void*)hgemm<64, 2, 3>,  cudaFuncAttributeMaxDynamicSharedMemorySize, 61440);
        cudaFuncSetAttribute((const void*)hgemm<128, 1, 4>, cudaFuncAttributeMaxDynamicSharedMemorySize, 81920);
        cudaStreamCreateWithFlags(&s2, cudaStreamNonBlocking);
        for (int i = 0; i < 8; i++) cudaEventCreateWithFlags(&ev[i], cudaEventDisableTiming);
        inited = true;
    }

    float *xln, *x, *y, *sc, *upd4, *pooled, *gatew;
    cudaGetSymbolAddress((void**)&xln, g_xln);
    cudaGetSymbolAddress((void**)&x, g_x);
    cudaGetSymbolAddress((void**)&y, g_y);
    cudaGetSymbolAddress((void**)&sc, g_scores);
    cudaGetSymbolAddress((void**)&upd4, g_upd4);
    cudaGetSymbolAddress((void**)&pooled, g_pooled);
    cudaGetSymbolAddress((void**)&gatew, g_gatew);

    bf16 *xlnh, *xlnl, *xlnTh, *xlnTl, *xh, *xTh, *qkvh, *qkvl, *vTh, *vTl;
    bf16 *sah, *ff1h, *sch, *schT, *retrph, *memh, *memTh;
    bf16 *ipwh, *ipwl, *opwh, *opwl, *w1h, *w1l, *w2h, *w2l, *aggwh;
    cudaGetSymbolAddress((void**)&xlnh, g_xlnh);   cudaGetSymbolAddress((void**)&xlnl, g_xlnl);
    cudaGetSymbolAddress((void**)&xlnTh, g_xlnTh); cudaGetSymbolAddress((void**)&xlnTl, g_xlnTl);
    cudaGetSymbolAddress((void**)&xh, g_xh);
    cudaGetSymbolAddress((void**)&xTh, g_xTh);
    cudaGetSymbolAddress((void**)&qkvh, g_qkvh);   cudaGetSymbolAddress((void**)&qkvl, g_qkvl);
    cudaGetSymbolAddress((void**)&vTh, g_vTh);     cudaGetSymbolAddress((void**)&vTl, g_vTl);
    cudaGetSymbolAddress((void**)&sah, g_sah);
    cudaGetSymbolAddress((void**)&ff1h, g_ff1h);
    cudaGetSymbolAddress((void**)&sch, g_sch);
    cudaGetSymbolAddress((void**)&schT, g_schT);
    cudaGetSymbolAddress((void**)&retrph, g_retrph);
    cudaGetSymbolAddress((void**)&memh, g_memh);   cudaGetSymbolAddress((void**)&memTh, g_memTh);
    cudaGetSymbolAddress((void**)&ipwh, g_ipwh);   cudaGetSymbolAddress((void**)&ipwl, g_ipwl);
    cudaGetSymbolAddress((void**)&opwh, g_opwh);   cudaGetSymbolAddress((void**)&opwl, g_opwl);
    cudaGetSymbolAddress((void**)&w1h, g_w1h);     cudaGetSymbolAddress((void**)&w1l, g_w1l);
    cudaGetSymbolAddress((void**)&w2h, g_w2h);     cudaGetSymbolAddress((void**)&w2l, g_w2l);
    cudaGetSymbolAddress((void**)&aggwh, g_aggwh);

    const float isd = 1.0f / sqrtf((float)DD);
    const long ND = (long)NTOK * DD;
    const long N3N = (long)NTOK * 3 * NTOK;
    const long NN = (long)NTOK * NTOK;
    const long NM = (long)NTOK * MMEM;

    // ---- fork side stream: weight/memory conversions + memT ----
    cudaEventRecord(ev[0], 0);
    cudaStreamWaitEvent(s2, ev[0], 0);
    conv(ipw, ipwh, ipwl, (long)EE * 3 * DD * DD, s2);
    conv(opw, opwh, opwl, (long)EE * DD * DD, s2);
    conv(w1, w1h, w1l, (long)EE * FFD * DD, s2);
    conv(w2, w2h, w2l, (long)EE * DD * FFD, s2);
    conv(aggw, aggwh, nullptr, (long)DD * LL * DD, s2);
    conv(memories, memh, nullptr, (long)LL * MMEM * DD, s2);
    tr(memh, memTh, MMEM, DD, DD, MMEM, LL, (long)MMEM * DD, (long)DD * MMEM, s2);
    cudaEventRecord(ev[1], s2);

    // ---- main: LN / cross attention (doesn't need converted weights) ----
    ln_kernel<<<EE * NTOK, 128>>>(tokens, xln, nullptr, nullptr, xlnh, xlnl, 0);
    tr(xlnh, xlnTh, EE * NTOK, DD, DD, EE * NTOK, 1, 0, 0);
    tr(xlnl, xlnTl, EE * NTOK, DD, DD, EE * NTOK, 1, 0, 0);

    { GArgs a{}; a.Ah=xlnh; a.Bh=xlnh; a.Bl=xlnl; a.C=sc;
      a.M=NTOK; a.N=3*NTOK; a.K=DD; a.Arow=DD; a.Brow=DD; a.ldc=3*NTOK;
      a.alpha=isd; a.ep=1; a.nRemap=1; a.thresh=-1; a.inner=1; a.batch=EE;
      a.Ao=ND; a.Co=N3N; a.NS=2; hg(a); }
    smax(sc, sch, EE * NTOK, 3 * NTOK);
    { GArgs a{}; a.Ah=sch; a.Bh=xlnTh; a.Bl=xlnTl; a.C=x; a.Ch=xh;
      a.M=NTOK; a.N=DD; a.K=3*NTOK; a.Arow=3*NTOK; a.Brow=EE*NTOK; a.ldc=DD;
      a.alpha=1.f; a.ep=6; a.R=xln; a.kRemap=1; a.thresh=-1; a.inner=1; a.batch=EE;
      a.Ao=N3N; a.Co=ND; a.NS=2; hg(a); }

    // join: qkv needs converted ipw
    cudaStreamWaitEvent(0, ev[1], 0);
    { GArgs a{}; a.Ah=xh; a.Bh=ipwh; a.Bl=ipwl; a.Ch=qkvh; a.Cl=qkvl;
      a.M=NTOK; a.N=3*DD; a.K=DD; a.Arow=DD; a.Brow=DD; a.ldc=3*DD;
      a.alpha=1.f; a.ep=2; a.bias=ipb; a.biasZ=3*DD; a.inner=1; a.batch=EE;
      a.Ao=ND; a.Bo=(long)3*DD*DD; a.Co=(long)NTOK*3*DD; a.NS=2; hg(a); }
    // fork: vT transposes overlap head-score GEMM + softmax
    cudaEventRecord(ev[2], 0);
    cudaStreamWaitEvent(s2, ev[2], 0);
    tr(qkvh + 2 * DD, vTh, NTOK, DD, 3 * DD, NTOK, EE, (long)NTOK*3*DD, (long)DD*NTOK, s2);
    tr(qkvl + 2 * DD, vTl, NTOK, DD, 3 * DD, NTOK, EE, (long)NTOK*3*DD, (long)DD*NTOK, s2);
    cudaEventRecord(ev[3], s2);
    { GArgs a{}; a.Ah=qkvh; a.Bh=qkvh + DD; a.Bl=qkvl + DD; a.C=sc;
      a.M=NTOK; a.N=NTOK; a.K=DHH; a.Arow=3*DD; a.Brow=3*DD; a.ldc=NTOK;
      a.alpha=0.125f; a.ep=0; a.inner=HH; a.batch=EE*HH;
      a.Ai=DHH; a.Ao=(long)NTOK*3*DD; a.Bi=DHH; a.Bo=(long)NTOK*3*DD;
      a.Ci=NN; a.Co=HH*NN; a.NS=2; hg(a); }
    smax(sc, sch, EE * HH * NTOK, NTOK);
    cudaStreamWaitEvent(0, ev[3], 0);
    { GArgs a{}; a.Ah=sch; a.Bh=vTh; a.Bl=vTl; a.Ch=sah;
      a.M=NTOK; a.N=DHH; a.K=NTOK; a.Arow=NTOK; a.Brow=NTOK; a.ldc=DD;
      a.alpha=1.f; a.ep=0; a.inner=HH; a.batch=EE*HH;
      a.Ai=NN; a.Ao=HH*NN; a.Bi=(long)DHH*NTOK; a.Bo=(long)DD*NTOK;
      a.Ci=DHH; a.Co=ND; a.NS=2; hg(a); }
    { GArgs a{}; a.Ah=sah; a.Bh=opwh; a.Bl=opwl; a.C=y;
      a.M=NTOK; a.N=DD; a.K=DD; a.Arow=DD; a.Brow=DD; a.ldc=DD;
      a.alpha=1.f; a.ep=4; a.bias=opb; a.biasZ=DD; a.R=x; a.inner=1; a.batch=EE;
      a.Ao=ND; a.Bo=(long)DD*DD; a.Co=ND; a.NS=2; hg(a); }
    ln_kernel<<<EE * NTOK, 128>>>(y, x, n1w, n1b, xh, nullptr, 1);
    { GArgs a{}; a.Ah=xh; a.Bh=w1h; a.Bl=w1l; a.Ch=ff1h;
      a.M=NTOK; a.N=FFD; a.K=DD; a.Arow=DD; a.Brow=DD; a.ldc=FFD;
      a.alpha=1.f; a.ep=3; a.bias=b1; a.biasZ=FFD; a.inner=1; a.batch=EE;
      a.Ao=ND; a.Bo=(long)FFD*DD; a.Co=(long)NTOK*FFD; a.NS=2; hg(a); }
    { GArgs a{}; a.Ah=ff1h; a.Bh=w2h; a.Bl=w2l; a.C=y;
      a.M=NTOK; a.N=DD; a.K=FFD; a.Arow=FFD; a.Brow=FFD; a.ldc=DD;
      a.alpha=1.f; a.ep=4; a.bias=b2; a.biasZ=DD; a.R=x; a.inner=1; a.batch=EE;
      a.Ao=(long)NTOK*FFD; a.Bo=(long)DD*FFD; a.Co=ND; a.NS=2; hg(a); }
    ln_kernel<<<EE * NTOK, 128>>>(y, x, n2w, n2b, xh, nullptr, 1);

    // fork: xT overlaps memory-score GEMM
    cudaEventRecord(ev[4], 0);
    cudaStreamWaitEvent(s2, ev[4], 0);
    tr(xh, xTh, NTOK, DD, DD, NTOK, EE, ND, ND, s2);

    { GArgs a{}; a.Ah=xh; a.Bh=memh; a.Bl=memh; a.C=sc;
      a.M=NTOK; a.N=MMEM; a.K=DD; a.Arow=DD; a.Brow=DD; a.ldc=MMEM;
      a.alpha=isd; a.ep=1; a.inner=LL; a.batch=EE*LL;
      a.Ai=0; a.Ao=ND; a.Bi=(long)MMEM*DD; a.Bo=0;
      a.Ci=NM; a.Co=LL*NM; a.NS=1; hg(a); }
    smax(sc, sch, EE * LL * NTOK, MMEM);

    // fork: schT + upd GEMM + newmem on side stream, ∥ retr/agg/pool/gate/fused
    cudaEventRecord(ev[5], 0);
    cudaStreamWaitEvent(s2, ev[5], 0);
    tr(sch, schT, NTOK, MMEM, MMEM, NTOK, EE * LL, NM, NM, s2);
    { GArgs a{}; a.Ah=schT; a.Bh=xTh; a.Bl=xTh; a.C=upd4;
      a.M=MMEM; a.N=DD; a.K=NTOK; a.Arow=NTOK; a.Brow=NTOK; a.ldc=DD;
      a.alpha=1.f; a.ep=7; a.inner=LL; a.batch=EE*LL;
      a.Ai=(long)MMEM*NTOK; a.Ao=(long)LL*MMEM*NTOK; a.Bi=0; a.Bo=(long)DD*NTOK;
      a.Ci=(long)MMEM*DD; a.Co=(long)LL*MMEM*DD; a.NS=1; a.st=s2; hg(a); }
    {
        long n = (long)LL * MMEM * DD;
        newmem_kernel<<<(unsigned)((n + 255) / 256), 256, 0, s2>>>(memories, upd4, out + ND + EE);
    }
    cudaEventRecord(ev[6], s2);

    // main: retr -> retrph, agg, pool/gate/fused
    { GArgs a{}; a.Ah=sch; a.Bh=memTh; a.Bl=memTh; a.Ch=retrph;
      a.M=NTOK; a.N=DD; a.K=MMEM; a.Arow=MMEM; a.Brow=MMEM; a.ldc=LL*DD;
      a.alpha=1.f; a.ep=0; a.inner=LL; a.batch=EE*LL;
      a.Ai=NM; a.Ao=LL*NM; a.Bi=(long)DD*MMEM; a.Bo=0;
      a.Ci=DD; a.Co=(long)NTOK*LL*DD; a.NS=1; hg(a); }
    { GArgs a{}; a.Ah=retrph; a.Bh=aggwh; a.Bl=aggwh; a.C=x;
      a.M=NTOK; a.N=DD; a.K=LL*DD; a.Arow=LL*DD; a.Brow=LL*DD; a.ldc=DD;
      a.alpha=1.f; a.ep=4; a.bias=aggb; a.biasZ=0; a.R=x; a.inner=1; a.batch=EE;
      a.Ao=(long)NTOK*LL*DD; a.Co=ND; a.NS=1; hg(a); }

    pool_kernel<<<(EE * DD + 255) / 256, 256>>>(x, pooled);
    gate_kernel<<<1, 128>>>(pooled, gate, out + ND, gatew);
    fused_kernel<<<(unsigned)((ND + 255) / 256), 256>>>(x, gatew, out);

    // join side stream before returning
    cudaStreamWaitEvent(0, ev[6], 0);
}

// round 11
// speedup vs baseline: 8.2560x; 1.0520x over previous
#include <cuda_runtime.h>
#include <cuda_bf16.h>
#include <math.h>
#include <stdint.h>

#define EE 4
#define NTOK 2048
#define DD 512
#define HH 8
#define DHH 64
#define FFD 2048
#define LL 4
#define MMEM 4096

typedef __nv_bfloat16 bf16;

// ---------------- static scratch ----------------
__device__ float g_xln[EE * NTOK * DD];
__device__ float g_x[EE * NTOK * DD];
__device__ float g_y[EE * NTOK * DD];
__device__ float g_scores[(size_t)EE * HH * NTOK * NTOK];
__device__ float g_upd4[(size_t)EE * LL * MMEM * DD];
__device__ float g_pooled[EE * DD];
__device__ float g_gatew[EE];

__device__ bf16 g_xlnh[EE * NTOK * DD], g_xlnl[EE * NTOK * DD];
__device__ bf16 g_xh[EE * NTOK * DD];
__device__ bf16 g_qkvh[EE * NTOK * 3 * DD], g_qkvl[EE * NTOK * 3 * DD];
__device__ bf16 g_sah[EE * NTOK * DD];
__device__ bf16 g_ff1h[EE * NTOK * FFD];
__device__ bf16 g_sch[(size_t)EE * HH * NTOK * NTOK];
__device__ bf16 g_retrph[EE * NTOK * LL * DD];
__device__ bf16 g_memh[LL * MMEM * DD];
__device__ bf16 g_ipwh[EE * 3 * DD * DD], g_ipwl[EE * 3 * DD * DD];
__device__ bf16 g_opwh[EE * DD * DD], g_opwl[EE * DD * DD];
__device__ bf16 g_w1h[EE * FFD * DD], g_w1l[EE * FFD * DD];
__device__ bf16 g_w2h[EE * DD * FFD], g_w2l[EE * DD * FFD];
__device__ bf16 g_aggwh[DD * LL * DD];

__device__ __forceinline__ void split_bf16(float v, bf16& h, bf16& l) {
    h = __float2bfloat16(v);
    l = __float2bfloat16(v - __bfloat162float(h));
}
__device__ __forceinline__ uint32_t smem_u32(const void* p) {
    uint32_t a;
    asm("{ .reg .u64 t; cvta.to.shared.u64 t, %1; cvt.u32.u64 %0, t; }" : "=r"(a) : "l"(p));
    return a;
}

#define MMA16816(d, a0, a1, a2, a3, b0, b1) \
    asm volatile("mma.sync.aligned.m16n8k16.row.col.f32.bf16.bf16.f32 " \
                 "{%0,%1,%2,%3}, {%4,%5,%6,%7}, {%8,%9}, {%0,%1,%2,%3};" \
                 : "+f"((d)[0]), "+f"((d)[1]), "+f"((d)[2]), "+f"((d)[3]) \
                 : "r"(a0), "r"(a1), "r"(a2), "r"(a3), "r"(b0), "r"(b1))

#define LDSM4(r0, r1, r2, r3, addr) \
    asm volatile("ldmatrix.sync.aligned.m8n8.x4.shared.b16 {%0,%1,%2,%3}, [%4];" \
                 : "=r"(r0), "=r"(r1), "=r"(r2), "=r"(r3) : "r"(addr))

#define LDSM4T(r0, r1, r2, r3, addr) \
    asm volatile("ldmatrix.sync.aligned.m8n8.x4.trans.shared.b16 {%0,%1,%2,%3}, [%4];" \
                 : "=r"(r0), "=r"(r1), "=r"(r2), "=r"(r3) : "r"(addr))

#define CP16(dst, src) \
    asm volatile("cp.async.cg.shared.global [%0], [%1], 16;" :: "r"(dst), "l"(src))
#define CPCOMMIT() asm volatile("cp.async.commit_group;")
#define CPWAIT(n)  asm volatile("cp.async.wait_group %0;" :: "n"(n))

// ---------------- HMMA bf16 GEMM: cp.async + ldmatrix(+trans) pipeline ----------
// z1 = z % inner, z2 = z / inner; offsets = z1*Xi + z2*Xo.
// C[m,n] = ep( alpha * sum_k a(m,k) * b(n,k) )
// TA=0: A gmem [m][k] (k-contig, row stride Arow).  TA=1: A gmem [k][m] (m-contig,
//   k-row stride Arow) loaded via ldmatrix.trans.  Same for TB with n.
// NS=1: Ah*Bh.  NS=2: Ah*Bh + Ah*Bl.
// nRemap (TB=0 only): B row n += NTOK when >= th. kRemap: B k index += NTOK when >= th.
// th = thresh, or z2*NTOK when thresh < 0.
// ep: 0 none,1 clip±10,2 +bias,3 relu+bias,4 +bias+res,6 +res,7 clip±1
template<int BN, int NS, int STAGES, int TA, int TB>
__global__ void __launch_bounds__(256, 2) hgemm(
    const bf16* __restrict__ Ahg, const bf16* __restrict__ Alg,
    const bf16* __restrict__ Bhg, const bf16* __restrict__ Blg,
    float* __restrict__ C, bf16* __restrict__ Ch, bf16* __restrict__ Cl,
    int Kdim, int Arow, int Brow, int ldc,
    float alpha, int ep,
    const float* __restrict__ bias, long biasZ, const float* __restrict__ Rres,
    int nRemap, int kRemap, int thresh, int inner,
    long Ai, long Ao, long Bi, long Bo, long Ci, long Co)
{
    constexpr bool BL = (NS >= 2);
    constexpr int AST = 128 * 80;          // stage stride (bytes); TA uses 32x272<=AST
    constexpr int BST = BN * 80;           // TB uses 32x(2BN+16)<=BST
    constexpr int NT = BN / 32;
    constexpr int BIT = BN / 64;
    constexpr int ASTR = 272;              // TA k-row stride
    constexpr int BSTR = BN * 2 + 16;      // TB k-row stride
    constexpr int BCH = BN / 8;            // TB 16B chunks per k-row

    const int z1 = blockIdx.z % inner;
    const int z2 = blockIdx.z / inner;
    Ahg += (long)z1 * Ai + (long)z2 * Ao;
    Bhg += (long)z1 * Bi + (long)z2 * Bo;
    if (BL) Blg += (long)z1 * Bi + (long)z2 * Bo;
    const long coff = (long)z1 * Ci + (long)z2 * Co;
    if (C)  C  += coff;
    if (Ch) Ch += coff;
    if (Cl) Cl += coff;
    if (Rres) Rres += coff;
    if (bias) bias += (long)z2 * biasZ;
    const int th = (thresh < 0) ? z2 * NTOK : thresh;

    extern __shared__ char sm[];
    const uint32_t smBase = smem_u32(sm);
    const uint32_t offAh = 0;
    const uint32_t offBh = STAGES * AST;
    const uint32_t offBl = offBh + STAGES * BST;

    const int tid = threadIdx.x;
    const int lane = tid & 31;
    const int wid = tid >> 5;
    const int wm = (wid >> 2) * 64;
    const int wn = (wid & 3) * (BN / 4);
    const int row0 = blockIdx.y * 128;
    const int col0 = blockIdx.x * BN;

    const int g = lane >> 3;
    const uint32_t laneOffA = TA
        ? ((lane & 7) + (g >> 1) * 8) * ASTR + (g & 1) * 16
        : ((g & 1) * 8 + (lane & 7)) * 80 + (g >> 1) * 16;
    const uint32_t laneOffB = TB
        ? ((lane & 7) + (g >> 1) * 8) * BSTR + (g & 1) * 16
        : ((g & 1) * 8 + (lane & 7)) * 80 + (g >> 1) * 16;

    float acc[4][NT][4];
    #pragma unroll
    for (int i = 0; i < 4; i++)
        #pragma unroll
        for (int j = 0; j < NT; j++)
            #pragma unroll
            for (int r = 0; r < 4; r++) acc[i][j][r] = 0.f;

    auto fill = [&](int s, int t) {
        int k0 = t * 32;
        if (!TA) {
            #pragma unroll
            for (int r = 0; r < 2; r++) {
                int idx = tid + r * 256;
                int row = idx >> 2, c = idx & 3;
                long go = (long)(row0 + row) * Arow + k0 + c * 8;
                CP16(smBase + offAh + s * AST + row * 80 + c * 16, Ahg + go);
            }
        } else {
            #pragma unroll
            for (int r = 0; r < 2; r++) {
                int idx = tid + r * 256;
                int row = idx >> 4, c = idx & 15;           // 32 k-rows x 16 chunks
                long go = (long)(k0 + row) * Arow + row0 + c * 8;
                CP16(smBase + offAh + s * AST + row * ASTR + c * 16, Ahg + go);
            }
        }
        if (!TB) {
            long kb = k0 + ((kRemap && k0 >= th) ? NTOK : 0);
            #pragma unroll
            for (int r = 0; r < BIT; r++) {
                int idx = tid + r * 256;
                int row = idx >> 2, c = idx & 3;
                int ng = col0 + row;
                if (nRemap && ng >= th) ng += NTOK;
                long go = (long)ng * Brow + kb + c * 8;
                uint32_t dst = smBase + offBh + s * BST + row * 80 + c * 16;
                CP16(dst, Bhg + go);
                if (BL) CP16(dst + (offBl - offBh), Blg + go);
            }
        } else {
            #pragma unroll
            for (int r = 0; r < BIT; r++) {
                int idx = tid + r * 256;
                int row = idx / BCH, c = idx % BCH;         // 32 k-rows x BCH chunks
                int kg = k0 + row;
                if (kRemap && kg >= th) kg += NTOK;
                long go = (long)kg * Brow + col0 + c * 8;
                uint32_t dst = smBase + offBh + s * BST + row * BSTR + c * 16;
                CP16(dst, Bhg + go);
                if (BL) CP16(dst + (offBl - offBh), Blg + go);
            }
        }
    };

    auto compute = [&](int buf) {
        const uint32_t aH = smBase + offAh + buf * AST + laneOffA;
        const uint32_t bH = smBase + offBh + buf * BST + laneOffB;
        const uint32_t bLb = smBase + offBl + buf * BST + laneOffB;
        #pragma unroll
        for (int s = 0; s < 2; s++) {
            uint32_t bh[NT][2], bl[NT][2];
            #pragma unroll
            for (int p = 0; p < NT / 2; p++) {
                uint32_t addr = TB ? bH + s * (16 * BSTR) + (wn + p * 16) * 2
                                   : bH + (wn + p * 16) * 80 + s * 32;
                if (TB) { LDSM4T(bh[2*p][0], bh[2*p+1][0], bh[2*p][1], bh[2*p+1][1], addr); }
                else    { LDSM4 (bh[2*p][0], bh[2*p+1][0], bh[2*p][1], bh[2*p+1][1], addr); }
                if (BL) {
                    uint32_t addr2 = TB ? bLb + s * (16 * BSTR) + (wn + p * 16) * 2
                                        : bLb + (wn + p * 16) * 80 + s * 32;
                    if (TB) { LDSM4T(bl[2*p][0], bl[2*p+1][0], bl[2*p][1], bl[2*p+1][1], addr2); }
                    else    { LDSM4 (bl[2*p][0], bl[2*p+1][0], bl[2*p][1], bl[2*p+1][1], addr2); }
                }
            }
            #pragma unroll
            for (int mt = 0; mt < 4; mt++) {
                uint32_t a0, a1, a2, a3;
                uint32_t addr = TA ? aH + s * (16 * ASTR) + (wm + mt * 16) * 2
                                   : aH + (wm + mt * 16) * 80 + s * 32;
                if (TA) { LDSM4T(a0, a1, a2, a3, addr); }
                else    { LDSM4 (a0, a1, a2, a3, addr); }
                #pragma unroll
                for (int nt = 0; nt < NT; nt++)
                    MMA16816(acc[mt][nt], a0, a1, a2, a3, bh[nt][0], bh[nt][1]);
                if (BL) {
                    #pragma unroll
                    for (int nt = 0; nt < NT; nt++)
                        MMA16816(acc[mt][nt], a0, a1, a2, a3, bl[nt][0], bl[nt][1]);
                }
            }
        }
    };

    const int nk = Kdim / 32;
    #pragma unroll
    for (int s = 0; s < STAGES - 1; s++) {
        if (s < nk) fill(s, s);
        CPCOMMIT();
    }
    for (int t = 0; t < nk; t++) {
        CPWAIT(STAGES - 2);
        __syncthreads();
        int tn = t + STAGES - 1;
        if (tn < nk) fill(tn % STAGES, tn);
        CPCOMMIT();
        compute(t % STAGES);
    }

    // epilogue (vectorized: column pairs)
    #pragma unroll
    for (int mt = 0; mt < 4; mt++) {
        #pragma unroll
        for (int nt = 0; nt < NT; nt++) {
            int ng = col0 + wn + nt * 8 + (lane & 3) * 2;
            float2 b2 = make_float2(0.f, 0.f);
            if (ep >= 2 && ep <= 4) b2 = *(const float2*)(bias + ng);
            #pragma unroll
            for (int hf = 0; hf < 2; hf++) {
                int mg = row0 + wm + mt * 16 + (lane >> 2) + hf * 8;
                long ci = (long)mg * ldc + ng;
                float v0 = acc[mt][nt][hf * 2 + 0] * alpha;
                float v1 = acc[mt][nt][hf * 2 + 1] * alpha;
                switch (ep) {
                case 1:
                    v0 = fminf(fmaxf(v0, -10.f), 10.f);
                    v1 = fminf(fmaxf(v1, -10.f), 10.f); break;
                case 2: v0 += b2.x; v1 += b2.y; break;
                case 3:
                    v0 = fmaxf(v0 + b2.x, 0.f);
                    v1 = fmaxf(v1 + b2.y, 0.f); break;
                case 4: {
                    float2 r2 = *(const float2*)(Rres + ci);
                    v0 += b2.x + r2.x; v1 += b2.y + r2.y; } break;
                case 6: {
                    float2 r2 = *(const float2*)(Rres + ci);
                    v0 += r2.x; v1 += r2.y; } break;
                case 7:
                    v0 = fminf(fmaxf(v0, -1.f), 1.f);
                    v1 = fminf(fmaxf(v1, -1.f), 1.f); break;
                }
                if (C) *(float2*)(C + ci) = make_float2(v0, v1);
                if (Ch) {
                    bf16 h0, l0, h1, l1;
                    split_bf16(v0, h0, l0); split_bf16(v1, h1, l1);
                    *(__nv_bfloat162*)(Ch + ci) = __nv_bfloat162(h0, h1);
                    if (Cl) *(__nv_bfloat162*)(Cl + ci) = __nv_bfloat162(l0, l1);
                }
            }
        }
    }
}

// ---------------- elementwise kernels ----------------
__global__ void convert_kernel(const float* __restrict__ src, bf16* __restrict__ h,
                               bf16* __restrict__ l, long n4h)
{
    long i = (long)blockIdx.x * blockDim.x + threadIdx.x;
    if (i >= n4h) return;
    #pragma unroll
    for (int r = 0; r < 2; r++) {
        long j = i + r * n4h;
        float4 v = ((const float4*)src)[j];
        bf16 hx, lx, hy, ly, hz, lz, hw, lw;
        split_bf16(v.x, hx, lx); split_bf16(v.y, hy, ly);
        split_bf16(v.z, hz, lz); split_bf16(v.w, hw, lw);
        __nv_bfloat162* h2 = (__nv_bfloat162*)h;
        h2[j * 2]     = __nv_bfloat162(hx, hy);
        h2[j * 2 + 1] = __nv_bfloat162(hz, hw);
        if (l) {
            __nv_bfloat162* l2 = (__nv_bfloat162*)l;
            l2[j * 2]     = __nv_bfloat162(lx, ly);
            l2[j * 2 + 1] = __nv_bfloat162(lz, lw);
        }
    }
}

__global__ void ln_kernel(const float* __restrict__ in, float* __restrict__ out,
                          const float* __restrict__ w, const float* __restrict__ b,
                          bf16* __restrict__ oh, bf16* __restrict__ ol, int wsel)
{
    const long row = blockIdx.x;
    const float* p = in + row * DD;
    const int t = threadIdx.x; // 128
    __shared__ float sh[4];
    const long wo = wsel ? (row / NTOK) * DD : 0;

    float v[4];
    float s = 0.f;
    #pragma unroll
    for (int i = 0; i < 4; i++) { v[i] = p[t + i * 128]; s += v[i]; }
    #pragma unroll
    for (int o = 16; o; o >>= 1) s += __shfl_down_sync(0xffffffffu, s, o);
    if ((t & 31) == 0) sh[t >> 5] = s;
    __syncthreads();
    float mu = (sh[0] + sh[1] + sh[2] + sh[3]) * (1.f / DD);
    __syncthreads();
    float sq = 0.f;
    #pragma unroll
    for (int i = 0; i < 4; i++) { float d = v[i] - mu; sq += d * d; }
    #pragma unroll
    for (int o = 16; o; o >>= 1) sq += __shfl_down_sync(0xffffffffu, sq, o);
    if ((t & 31) == 0) sh[t >> 5] = sq;
    __syncthreads();
    float rstd = rsqrtf((sh[0] + sh[1] + sh[2] + sh[3]) * (1.f / DD) + 1e-5f);

    #pragma unroll
    for (int i = 0; i < 4; i++) {
        int d = t + i * 128;
        float o = (v[i] - mu) * rstd;
        if (w) o = o * w[wo + d] + b[wo + d];
        long gi = row * DD + d;
        if (out) out[gi] = o;
        bf16 hh, ll; split_bf16(o, hh, ll);
        oh[gi] = hh;
        if (ol) ol[gi] = ll;
    }
}

// online softmax with smem row cache
__global__ void softmax_kernel(const float* __restrict__ S, bf16* __restrict__ Oh,
                               int cols)
{
    extern __shared__ float srow[];
    const float4* row = (const float4*)(S + (long)blockIdx.x * cols);
    float4* srow4 = (float4*)srow;
    __nv_bfloat162* oh = (__nv_bfloat162*)(Oh + (long)blockIdx.x * cols);
    const int t = threadIdx.x; // 256
    const int n4 = cols >> 2;
    __shared__ float shm[8], shs[8];

    float m = -1e30f, s = 0.f;
    for (int i = t; i < n4; i += 256) {
        float4 v = row[i];
        srow4[i] = v;
        float mx = fmaxf(fmaxf(v.x, v.y), fmaxf(v.z, v.w));
        if (mx > m) { s *= expf(m - mx); m = mx; }
        s += expf(v.x - m) + expf(v.y - m) + expf(v.z - m) + expf(v.w - m);
    }
    #pragma unroll
    for (int o = 16; o; o >>= 1) {
        float mo = __shfl_xor_sync(0xffffffffu, m, o);
        float so = __shfl_xor_sync(0xffffffffu, s, o);
        float mn = fmaxf(m, mo);
        s = s * expf(m - mn) + so * expf(mo - mn);
        m = mn;
    }
    if ((t & 31) == 0) { shm[t >> 5] = m; shs[t >> 5] = s; }
    __syncthreads();
    if (t == 0) {
        float M = shm[0], Sm = shs[0];
        #pragma unroll
        for (int w = 1; w < 8; w++) {
            float mn = fmaxf(M, shm[w]);
            Sm = Sm * expf(M - mn) + shs[w] * expf(shm[w] - mn);
            M = mn;
        }
        shm[0] = M; shs[0] = 1.f / Sm;
    }
    __syncthreads();
    const float M = shm[0], inv = shs[0];

    for (int i = t; i < n4; i += 256) {
        float4 v = srow4[i];
        float p0 = expf(v.x - M) * inv, p1 = expf(v.y - M) * inv;
        float p2 = expf(v.z - M) * inv, p3 = expf(v.w - M) * inv;
        oh[i * 2]     = __nv_bfloat162(__float2bfloat16(p0), __float2bfloat16(p1));
        oh[i * 2 + 1] = __nv_bfloat162(__float2bfloat16(p2), __float2bfloat16(p3));
    }
}

__global__ void pool_kernel(const float* __restrict__ x, float* __restrict__ pooled)
{
    int idx = blockIdx.x * blockDim.x + threadIdx.x;
    if (idx >= EE * DD) return;
    int e = idx / DD, d = idx % DD;
    const float* p = x + (long)e * NTOK * DD + d;
    float s = 0.f;
    #pragma unroll 16
    for (int n = 0; n < NTOK; n++) s += p[(long)n * DD];
    pooled[idx] = s * (1.f / NTOK);
}

__global__ void gate_kernel(const float* __restrict__ pooled, const float* __restrict__ gate,
                            float* __restrict__ out_gw, float* __restrict__ gdev)
{
    const int t = threadIdx.x;
    const int wid = t >> 5, lane = t & 31;
    __shared__ float logits[4];
    float s = 0.f;
    for (int d = lane; d < DD; d += 32) s += pooled[wid * DD + d] * gate[d];
    #pragma unroll
    for (int o = 16; o; o >>= 1) s += __shfl_down_sync(0xffffffffu, s, o);
    if (lane == 0) logits[wid] = fminf(fmaxf(s, -10.f), 10.f);
    __syncthreads();
    if (t == 0) {
        float mx = fmaxf(fmaxf(logits[0], logits[1]), fmaxf(logits[2], logits[3]));
        float e0 = expf(logits[0] - mx), e1 = expf(logits[1] - mx);
        float e2 = expf(logits[2] - mx), e3 = expf(logits[3] - mx);
        float inv = 1.f / (e0 + e1 + e2 + e3);
        out_gw[0] = gdev[0] = e0 * inv;
        out_gw[1] = gdev[1] = e1 * inv;
        out_gw[2] = gdev[2] = e2 * inv;
        out_gw[3] = gdev[3] = e3 * inv;
    }
}

__global__ void fused_kernel(const float* __restrict__ x, const float* __restrict__ gw,
                             float* __restrict__ out)
{
    long i = (long)blockIdx.x * blockDim.x + threadIdx.x;
    if (i >= (long)NTOK * DD) return;
    float s = 0.f;
    #pragma unroll
    for (int e = 0; e < EE; e++) s += gw[e] * x[(long)e * NTOK * DD + i];
    out[i] = s;
}

__global__ void newmem_kernel(const float* __restrict__ mem, const float* __restrict__ upd4,
                              float* __restrict__ out)
{
    long i = (long)blockIdx.x * blockDim.x + threadIdx.x;
    const long S = (long)LL * MMEM * DD;
    if (i >= S) return;
    float u = ((upd4[i] + upd4[i + S]) + upd4[i + 2 * S]) + upd4[i + 3 * S];
    u *= 0.1f;
    u = fminf(fmaxf(u, -0.1f), 0.1f);
    out[i] = 0.9f * mem[i] + u;
}

// ---------------- host-side launcher ----------------
struct GArgs {
    const bf16 *Ah, *Bh, *Bl;
    float* C; bf16 *Ch, *Cl;
    int M, N, K, Arow, Brow, ldc;
    float alpha; int ep;
    const float* bias; long biasZ; const float* R;
    int nRemap, kRemap, thresh, inner, batch;
    long Ai, Ao, Bi, Bo, Ci, Co;
    int NS, TA, TB;
    cudaStream_t st;
};

static void hg(const GArgs& a)
{
    #define HGCALL(BN, NS_, ST, TA_, TB_, SMEM) \
        hgemm<BN, NS_, ST, TA_, TB_><<<grid, 256, SMEM, a.st>>>( \
            a.Ah, a.Ah, a.Bh, a.Bl, a.C, a.Ch, a.Cl, a.K, a.Arow, a.Brow, a.ldc, \
            a.alpha, a.ep, a.bias, a.biasZ, a.R, a.nRemap, a.kRemap, a.thresh, \
            a.inner, a.Ai, a.Ao, a.Bi, a.Bo, a.Ci, a.Co)
    if (a.NS == 2) {
        if (a.N % 128 == 0) {
            dim3 grid(a.N / 128, a.M / 128, a.batch);
            if (a.TB) HGCALL(128, 2, 3, 0, 1, 92160);
            else      HGCALL(128, 2, 3, 0, 0, 92160);
        } else {
            dim3 grid(a.N / 64, a.M / 128, a.batch);
            HGCALL(64, 2, 3, 0, 1, 61440);
        }
    } else {
        dim3 grid(a.N / 128, a.M / 128, a.batch);
        if (a.TA)      HGCALL(128, 1, 4, 1, 1, 81920);
        else if (a.TB) HGCALL(128, 1, 4, 0, 1, 81920);
        else           HGCALL(128, 1, 4, 0, 0, 81920);
    }
    #undef HGCALL
}

static void conv(const float* s, bf16* h, bf16* l, long n, cudaStream_t st = 0)
{
    long n4h = n / 8;
    convert_kernel<<<(unsigned)((n4h + 255) / 256), 256, 0, st>>>(s, h, l, n4h);
}

static void smax(float* sc, bf16* oh, int rows, int cols)
{
    softmax_kernel<<<rows, 256, cols * 4>>>(sc, oh, cols);
}

extern "C" void kernel_launch(void* const* d_in, const int* in_sizes, int n_in,
                              void* d_out, int out_size)
{
    const float* tokens   = (const float*)d_in[0];
    const float* memories = (const float*)d_in[1];
    const float* ipw      = (const float*)d_in[2];
    const float* ipb      = (const float*)d_in[3];
    const float* opw      = (const float*)d_in[4];
    const float* opb      = (const float*)d_in[5];
    const float* w1       = (const float*)d_in[6];
    const float* b1       = (const float*)d_in[7];
    const float* w2       = (const float*)d_in[8];
    const float* b2       = (const float*)d_in[9];
    const float* n1w      = (const float*)d_in[10];
    const float* n1b      = (const float*)d_in[11];
    const float* n2w      = (const float*)d_in[12];
    const float* n2b      = (const float*)d_in[13];
    const float* aggw     = (const float*)d_in[14];
    const float* aggb     = (const float*)d_in[15];
    const float* gate     = (const float*)d_in[16];
    float* out = (float*)d_out;

    static bool inited = false;
    static cudaStream_t s2;
    static cudaEvent_t ev[4];
    if (!inited) {
        cudaFuncSetAttribute((const void*)hgemm<128, 2, 3, 0, 0>, cudaFuncAttributeMaxDynamicSharedMemorySize, 92160);
        cudaFuncSetAttribute((const void*)hgemm<128, 2, 3, 0, 1>, cudaFuncAttributeMaxDynamicSharedMemorySize, 92160);
        cudaFuncSetAttribute((const void*)hgemm<64, 2, 3, 0, 1>,  cudaFuncAttributeMaxDynamicSharedMemorySize, 61440);
        cudaFuncSetAttribute((const void*)hgemm<128, 1, 4, 0, 0>, cudaFuncAttributeMaxDynamicSharedMemorySize, 81920);
        cudaFuncSetAttribute((const void*)hgemm<128, 1, 4, 0, 1>, cudaFuncAttributeMaxDynamicSharedMemorySize, 81920);
        cudaFuncSetAttribute((const void*)hgemm<128, 1, 4, 1, 1>, cudaFuncAttributeMaxDynamicSharedMemorySize, 81920);
        cudaStreamCreateWithFlags(&s2, cudaStreamNonBlocking);
        for (int i = 0; i < 4; i++) cudaEventCreateWithFlags(&ev[i], cudaEventDisableTiming);
        inited = true;
    }

    float *xln, *x, *y, *sc, *upd4, *pooled, *gatew;
    cudaGetSymbolAddress((void**)&xln, g_xln);
    cudaGetSymbolAddress((void**)&x, g_x);
    cudaGetSymbolAddress((void**)&y, g_y);
    cudaGetSymbolAddress((void**)&sc, g_scores);
    cudaGetSymbolAddress((void**)&upd4, g_upd4);
    cudaGetSymbolAddress((void**)&pooled, g_pooled);
    cudaGetSymbolAddress((void**)&gatew, g_gatew);

    bf16 *xlnh, *xlnl, *xh, *qkvh, *qkvl, *sah, *ff1h, *sch, *retrph, *memh;
    bf16 *ipwh, *ipwl, *opwh, *opwl, *w1h, *w1l, *w2h, *w2l, *aggwh;
    cudaGetSymbolAddress((void**)&xlnh, g_xlnh);   cudaGetSymbolAddress((void**)&xlnl, g_xlnl);
    cudaGetSymbolAddress((void**)&xh, g_xh);
    cudaGetSymbolAddress((void**)&qkvh, g_qkvh);   cudaGetSymbolAddress((void**)&qkvl, g_qkvl);
    cudaGetSymbolAddress((void**)&sah, g_sah);
    cudaGetSymbolAddress((void**)&ff1h, g_ff1h);
    cudaGetSymbolAddress((void**)&sch, g_sch);
    cudaGetSymbolAddress((void**)&retrph, g_retrph);
    cudaGetSymbolAddress((void**)&memh, g_memh);
    cudaGetSymbolAddress((void**)&ipwh, g_ipwh);   cudaGetSymbolAddress((void**)&ipwl, g_ipwl);
    cudaGetSymbolAddress((void**)&opwh, g_opwh);   cudaGetSymbolAddress((void**)&opwl, g_opwl);
    cudaGetSymbolAddress((void**)&w1h, g_w1h);     cudaGetSymbolAddress((void**)&w1l, g_w1l);
    cudaGetSymbolAddress((void**)&w2h, g_w2h);     cudaGetSymbolAddress((void**)&w2l, g_w2l);
    cudaGetSymbolAddress((void**)&aggwh, g_aggwh);

    const float isd = 1.0f / sqrtf((float)DD);
    const long ND = (long)NTOK * DD;
    const long N3N = (long)NTOK * 3 * NTOK;
    const long NN = (long)NTOK * NTOK;
    const long NM = (long)NTOK * MMEM;

    // ---- fork side stream: weight/memory conversions ----
    cudaEventRecord(ev[0], 0);
    cudaStreamWaitEvent(s2, ev[0], 0);
    conv(ipw, ipwh, ipwl, (long)EE * 3 * DD * DD, s2);
    conv(opw, opwh, opwl, (long)EE * DD * DD, s2);
    conv(w1, w1h, w1l, (long)EE * FFD * DD, s2);
    conv(w2, w2h, w2l, (long)EE * DD * FFD, s2);
    conv(aggw, aggwh, nullptr, (long)DD * LL * DD, s2);
    conv(memories, memh, nullptr, (long)LL * MMEM * DD, s2);
    cudaEventRecord(ev[1], s2);

    // ---- main: LN + cross attention ----
    ln_kernel<<<EE * NTOK, 128>>>(tokens, xln, nullptr, nullptr, xlnh, xlnl, 0);

    // 1. cross scores: S[e] = clip(xln_e @ ctx^T / sqrt(D)), remap n per z
    { GArgs a{}; a.Ah=xlnh; a.Bh=xlnh; a.Bl=xlnl; a.C=sc;
      a.M=NTOK; a.N=3*NTOK; a.K=DD; a.Arow=DD; a.Brow=DD; a.ldc=3*NTOK;
      a.alpha=isd; a.ep=1; a.nRemap=1; a.thresh=-1; a.inner=1; a.batch=EE;
      a.Ao=ND; a.Co=N3N; a.NS=2; hg(a); }
    smax(sc, sch, EE * NTOK, 3 * NTOK);
    // 2. x = xln_e + P @ ctx  (B = xln native via TB, remap k per z)
    { GArgs a{}; a.Ah=sch; a.Bh=xlnh; a.Bl=xlnl; a.C=x; a.Ch=xh;
      a.M=NTOK; a.N=DD; a.K=3*NTOK; a.Arow=3*NTOK; a.Brow=DD; a.ldc=DD;
      a.alpha=1.f; a.ep=6; a.R=xln; a.kRemap=1; a.thresh=-1; a.inner=1; a.batch=EE;
      a.Ao=N3N; a.Co=ND; a.NS=2; a.TB=1; hg(a); }

    // join: qkv needs converted ipw
    cudaStreamWaitEvent(0, ev[1], 0);
    // 3. qkv
    { GArgs a{}; a.Ah=xh; a.Bh=ipwh; a.Bl=ipwl; a.Ch=qkvh; a.Cl=qkvl;
      a.M=NTOK; a.N=3*DD; a.K=DD; a.Arow=DD; a.Brow=DD; a.ldc=3*DD;
      a.alpha=1.f; a.ep=2; a.bias=ipb; a.biasZ=3*DD; a.inner=1; a.batch=EE;
      a.Ao=ND; a.Bo=(long)3*DD*DD; a.Co=(long)NTOK*3*DD; a.NS=2; hg(a); }
    // 4. head scores (z = e*H + h)
    { GArgs a{}; a.Ah=qkvh; a.Bh=qkvh + DD; a.Bl=qkvl + DD; a.C=sc;
      a.M=NTOK; a.N=NTOK; a.K=DHH; a.Arow=3*DD; a.Brow=3*DD; a.ldc=NTOK;
      a.alpha=0.125f; a.ep=0; a.inner=HH; a.batch=EE*HH;
      a.Ai=DHH; a.Ao=(long)NTOK*3*DD; a.Bi=DHH; a.Bo=(long)NTOK*3*DD;
      a.Ci=NN; a.Co=HH*NN; a.NS=2; hg(a); }
    smax(sc, sch, EE * HH * NTOK, NTOK);
    // 5. sa = P @ V  (B = V native [seq][dh] via TB; batch e*H+h)
    { GArgs a{}; a.Ah=sch; a.Bh=qkvh + 2*DD; a.Bl=qkvl + 2*DD; a.Ch=sah;
      a.M=NTOK; a.N=DHH; a.K=NTOK; a.Arow=NTOK; a.Brow=3*DD; a.ldc=DD;
      a.alpha=1.f; a.ep=0; a.inner=HH; a.batch=EE*HH;
      a.Ai=NN; a.Ao=HH*NN; a.Bi=DHH; a.Bo=(long)NTOK*3*DD;
      a.Ci=DHH; a.Co=ND; a.NS=2; a.TB=1; hg(a); }
    // 6. out_proj + bias + residual
    { GArgs a{}; a.Ah=sah; a.Bh=opwh; a.Bl=opwl; a.C=y;
      a.M=NTOK; a.N=DD; a.K=DD; a.Arow=DD; a.Brow=DD; a.ldc=DD;
      a.alpha=1.f; a.ep=4; a.bias=opb; a.biasZ=DD; a.R=x; a.inner=1; a.batch=EE;
      a.Ao=ND; a.Bo=(long)DD*DD; a.Co=ND; a.NS=2; hg(a); }
    ln_kernel<<<EE * NTOK, 128>>>(y, x, n1w, n1b, xh, nullptr, 1);
    // 7. FFN
    { GArgs a{}; a.Ah=xh; a.Bh=w1h; a.Bl=w1l; a.Ch=ff1h;
      a.M=NTOK; a.N=FFD; a.K=DD; a.Arow=DD; a.Brow=DD; a.ldc=FFD;
      a.alpha=1.f; a.ep=3; a.bias=b1; a.biasZ=FFD; a.inner=1; a.batch=EE;
      a.Ao=ND; a.Bo=(long)FFD*DD; a.Co=(long)NTOK*FFD; a.NS=2; hg(a); }
    { GArgs a{}; a.Ah=ff1h; a.Bh=w2h; a.Bl=w2l; a.C=y;
      a.M=NTOK; a.N=DD; a.K=FFD; a.Arow=FFD; a.Brow=FFD; a.ldc=DD;
      a.alpha=1.f; a.ep=4; a.bias=b2; a.biasZ=DD; a.R=x; a.inner=1; a.batch=EE;
      a.Ao=(long)NTOK*FFD; a.Bo=(long)DD*FFD; a.Co=ND; a.NS=2; hg(a); }
    ln_kernel<<<EE * NTOK, 128>>>(y, x, n2w, n2b, xh, nullptr, 1);

    // 8. memory scores (z = e*L + l)
    { GArgs a{}; a.Ah=xh; a.Bh=memh; a.Bl=memh; a.C=sc;
      a.M=NTOK; a.N=MMEM; a.K=DD; a.Arow=DD; a.Brow=DD; a.ldc=MMEM;
      a.alpha=isd; a.ep=1; a.inner=LL; a.batch=EE*LL;
      a.Ai=0; a.Ao=ND; a.Bi=(long)MMEM*DD; a.Bo=0;
      a.Ci=NM; a.Co=LL*NM; a.NS=1; hg(a); }
    smax(sc, sch, EE * LL * NTOK, MMEM);

    // fork: upd GEMM (A = sch via TA, B = xh via TB) + newmem on side stream
    cudaEventRecord(ev[2], 0);
    cudaStreamWaitEvent(s2, ev[2], 0);
    { GArgs a{}; a.Ah=sch; a.Bh=xh; a.Bl=xh; a.C=upd4;
      a.M=MMEM; a.N=DD; a.K=NTOK; a.Arow=MMEM; a.Brow=DD; a.ldc=DD;
      a.alpha=1.f; a.ep=7; a.inner=LL; a.batch=EE*LL;
      a.Ai=NM; a.Ao=LL*NM; a.Bi=0; a.Bo=ND;
      a.Ci=(long)MMEM*DD; a.Co=(long)LL*MMEM*DD; a.NS=1; a.TA=1; a.TB=1; a.st=s2; hg(a); }
    {
        long n = (long)LL * MMEM * DD;
        newmem_kernel<<<(unsigned)((n + 255) / 256), 256, 0, s2>>>(memories, upd4, out + ND + EE);
    }
    cudaEventRecord(ev[3], s2);

    // main: retr (B = mem native via TB) -> retrph permuted, agg, pool/gate/fused
    { GArgs a{}; a.Ah=sch; a.Bh=memh; a.Bl=memh; a.Ch=retrph;
      a.M=NTOK; a.N=DD; a.K=MMEM; a.Arow=MMEM; a.Brow=DD; a.ldc=LL*DD;
      a.alpha=1.f; a.ep=0; a.inner=LL; a.batch=EE*LL;
      a.Ai=NM; a.Ao=LL*NM; a.Bi=(long)MMEM*DD; a.Bo=0;
      a.Ci=DD; a.Co=(long)NTOK*LL*DD; a.NS=1; a.TB=1; hg(a); }
    { GArgs a{}; a.Ah=retrph; a.Bh=aggwh; a.Bl=aggwh; a.C=x;
      a.M=NTOK; a.N=DD; a.K=LL*DD; a.Arow=LL*DD; a.Brow=LL*DD; a.ldc=DD;
      a.alpha=1.f; a.ep=4; a.bias=aggb; a.biasZ=0; a.R=x; a.inner=1; a.batch=EE;
      a.Ao=(long)NTOK*LL*DD; a.Co=ND; a.NS=1; hg(a); }

    pool_kernel<<<(EE * DD + 255) / 256, 256>>>(x, pooled);
    gate_kernel<<<1, 128>>>(pooled, gate, out + ND, gatew);
    fused_kernel<<<(unsigned)((ND + 255) / 256), 256>>>(x, gatew, out);

    // join side stream
    cudaStreamWaitEvent(0, ev[3], 0);
}

// round 12
// speedup vs baseline: 9.7667x; 1.1830x over previous
#include <cuda_runtime.h>
#include <cuda_fp16.h>
#include <math.h>
#include <stdint.h>

#define EE 4
#define NTOK 2048
#define DD 512
#define HH 8
#define DHH 64
#define FFD 2048
#define LL 4
#define MMEM 4096

typedef __half f16;

// ---------------- static scratch ----------------
__device__ float g_xln[EE * NTOK * DD];
__device__ float g_x[EE * NTOK * DD];
__device__ float g_y[EE * NTOK * DD];
__device__ float g_scores[(size_t)EE * HH * NTOK * NTOK];
__device__ float g_upd4[(size_t)EE * LL * MMEM * DD];
__device__ float g_pooled[EE * DD];
__device__ float g_gatew[EE];

__device__ f16 g_xlnh[EE * NTOK * DD];
__device__ f16 g_xh[EE * NTOK * DD];
__device__ f16 g_qkvh[EE * NTOK * 3 * DD];
__device__ f16 g_sah[EE * NTOK * DD];
__device__ f16 g_ff1h[EE * NTOK * FFD];
__device__ f16 g_sch[(size_t)EE * HH * NTOK * NTOK];
__device__ f16 g_retrph[EE * NTOK * LL * DD];
__device__ f16 g_memh[LL * MMEM * DD];
__device__ f16 g_ipwh[EE * 3 * DD * DD];
__device__ f16 g_opwh[EE * DD * DD];
__device__ f16 g_w1h[EE * FFD * DD];
__device__ f16 g_w2h[EE * DD * FFD];
__device__ f16 g_aggwh[DD * LL * DD];

__device__ __forceinline__ uint32_t smem_u32(const void* p) {
    uint32_t a;
    asm("{ .reg .u64 t; cvta.to.shared.u64 t, %1; cvt.u32.u64 %0, t; }" : "=r"(a) : "l"(p));
    return a;
}

#define MMA16816(d, a0, a1, a2, a3, b0, b1) \
    asm volatile("mma.sync.aligned.m16n8k16.row.col.f32.f16.f16.f32 " \
                 "{%0,%1,%2,%3}, {%4,%5,%6,%7}, {%8,%9}, {%0,%1,%2,%3};" \
                 : "+f"((d)[0]), "+f"((d)[1]), "+f"((d)[2]), "+f"((d)[3]) \
                 : "r"(a0), "r"(a1), "r"(a2), "r"(a3), "r"(b0), "r"(b1))

#define LDSM4(r0, r1, r2, r3, addr) \
    asm volatile("ldmatrix.sync.aligned.m8n8.x4.shared.b16 {%0,%1,%2,%3}, [%4];" \
                 : "=r"(r0), "=r"(r1), "=r"(r2), "=r"(r3) : "r"(addr))

#define LDSM4T(r0, r1, r2, r3, addr) \
    asm volatile("ldmatrix.sync.aligned.m8n8.x4.trans.shared.b16 {%0,%1,%2,%3}, [%4];" \
                 : "=r"(r0), "=r"(r1), "=r"(r2), "=r"(r3) : "r"(addr))

#define CP16(dst, src) \
    asm volatile("cp.async.cg.shared.global [%0], [%1], 16;" :: "r"(dst), "l"(src))
#define CPCOMMIT() asm volatile("cp.async.commit_group;")
#define CPWAIT(n)  asm volatile("cp.async.wait_group %0;" :: "n"(n))

// ---------------- HMMA fp16 GEMM: cp.async + ldmatrix(+trans), 2-level batch -----
// z1 = z % inner, z2 = z / inner; offsets = z1*Xi + z2*Xo.
// C[m,n] = ep( alpha * sum_k a(m,k) * b(n,k) )   fp32 accumulate, fp16 operands.
// TA=0: A gmem [m][k] (k-contig, row stride Arow). TA=1: A gmem [k][m] via ldsm.trans.
// Same for TB with n.  nRemap (TB=0): B row n += NTOK when >= th.
// kRemap: B k index += NTOK when >= th.  th = thresh, or z2*NTOK when thresh < 0.
// ep: 0 none,1 clip±10,2 +bias,3 relu+bias,4 +bias+res,6 +res,7 clip±1
template<int BN, int STAGES, int TA, int TB>
__global__ void __launch_bounds__(256, 2) hgemm(
    const f16* __restrict__ Ahg, const f16* __restrict__ Bhg,
    float* __restrict__ C, f16* __restrict__ Ch,
    int Kdim, int Arow, int Brow, int ldc,
    float alpha, int ep,
    const float* __restrict__ bias, long biasZ, const float* __restrict__ Rres,
    int nRemap, int kRemap, int thresh, int inner,
    long Ai, long Ao, long Bi, long Bo, long Ci, long Co)
{
    constexpr int AST = 128 * 80;
    constexpr int BST = BN * 80;
    constexpr int NT = BN / 32;
    constexpr int BIT = BN / 64;
    constexpr int ASTR = 272;
    constexpr int BSTR = BN * 2 + 16;
    constexpr int BCH = BN / 8;

    const int z1 = blockIdx.z % inner;
    const int z2 = blockIdx.z / inner;
    Ahg += (long)z1 * Ai + (long)z2 * Ao;
    Bhg += (long)z1 * Bi + (long)z2 * Bo;
    const long coff = (long)z1 * Ci + (long)z2 * Co;
    if (C)  C  += coff;
    if (Ch) Ch += coff;
    if (Rres) Rres += coff;
    if (bias) bias += (long)z2 * biasZ;
    const int th = (thresh < 0) ? z2 * NTOK : thresh;

    extern __shared__ char sm[];
    const uint32_t smBase = smem_u32(sm);
    const uint32_t offAh = 0;
    const uint32_t offBh = STAGES * AST;

    const int tid = threadIdx.x;
    const int lane = tid & 31;
    const int wid = tid >> 5;
    const int wm = (wid >> 2) * 64;
    const int wn = (wid & 3) * (BN / 4);
    const int row0 = blockIdx.y * 128;
    const int col0 = blockIdx.x * BN;

    const int g = lane >> 3;
    const uint32_t laneOffA = TA
        ? ((lane & 7) + (g >> 1) * 8) * ASTR + (g & 1) * 16
        : ((g & 1) * 8 + (lane & 7)) * 80 + (g >> 1) * 16;
    const uint32_t laneOffB = TB
        ? ((lane & 7) + (g >> 1) * 8) * BSTR + (g & 1) * 16
        : ((g & 1) * 8 + (lane & 7)) * 80 + (g >> 1) * 16;

    float acc[4][NT][4];
    #pragma unroll
    for (int i = 0; i < 4; i++)
        #pragma unroll
        for (int j = 0; j < NT; j++)
            #pragma unroll
            for (int r = 0; r < 4; r++) acc[i][j][r] = 0.f;

    auto fill = [&](int s, int t) {
        int k0 = t * 32;
        if (!TA) {
            #pragma unroll
            for (int r = 0; r < 2; r++) {
                int idx = tid + r * 256;
                int row = idx >> 2, c = idx & 3;
                long go = (long)(row0 + row) * Arow + k0 + c * 8;
                CP16(smBase + offAh + s * AST + row * 80 + c * 16, Ahg + go);
            }
        } else {
            #pragma unroll
            for (int r = 0; r < 2; r++) {
                int idx = tid + r * 256;
                int row = idx >> 4, c = idx & 15;
                long go = (long)(k0 + row) * Arow + row0 + c * 8;
                CP16(smBase + offAh + s * AST + row * ASTR + c * 16, Ahg + go);
            }
        }
        if (!TB) {
            long kb = k0 + ((kRemap && k0 >= th) ? NTOK : 0);
            #pragma unroll
            for (int r = 0; r < BIT; r++) {
                int idx = tid + r * 256;
                int row = idx >> 2, c = idx & 3;
                int ng = col0 + row;
                if (nRemap && ng >= th) ng += NTOK;
                long go = (long)ng * Brow + kb + c * 8;
                CP16(smBase + offBh + s * BST + row * 80 + c * 16, Bhg + go);
            }
        } else {
            #pragma unroll
            for (int r = 0; r < BIT; r++) {
                int idx = tid + r * 256;
                int row = idx / BCH, c = idx % BCH;
                int kg = k0 + row;
                if (kRemap && kg >= th) kg += NTOK;
                long go = (long)kg * Brow + col0 + c * 8;
                CP16(smBase + offBh + s * BST + row * BSTR + c * 16, Bhg + go);
            }
        }
    };

    auto compute = [&](int buf) {
        const uint32_t aH = smBase + offAh + buf * AST + laneOffA;
        const uint32_t bH = smBase + offBh + buf * BST + laneOffB;
        #pragma unroll
        for (int s = 0; s < 2; s++) {
            uint32_t bh[NT][2];
            #pragma unroll
            for (int p = 0; p < NT / 2; p++) {
                uint32_t addr = TB ? bH + s * (16 * BSTR) + (wn + p * 16) * 2
                                   : bH + (wn + p * 16) * 80 + s * 32;
                if (TB) { LDSM4T(bh[2*p][0], bh[2*p+1][0], bh[2*p][1], bh[2*p+1][1], addr); }
                else    { LDSM4 (bh[2*p][0], bh[2*p+1][0], bh[2*p][1], bh[2*p+1][1], addr); }
            }
            #pragma unroll
            for (int mt = 0; mt < 4; mt++) {
                uint32_t a0, a1, a2, a3;
                uint32_t addr = TA ? aH + s * (16 * ASTR) + (wm + mt * 16) * 2
                                   : aH + (wm + mt * 16) * 80 + s * 32;
                if (TA) { LDSM4T(a0, a1, a2, a3, addr); }
                else    { LDSM4 (a0, a1, a2, a3, addr); }
                #pragma unroll
                for (int nt = 0; nt < NT; nt++)
                    MMA16816(acc[mt][nt], a0, a1, a2, a3, bh[nt][0], bh[nt][1]);
            }
        }
    };

    const int nk = Kdim / 32;
    #pragma unroll
    for (int s = 0; s < STAGES - 1; s++) {
        if (s < nk) fill(s, s);
        CPCOMMIT();
    }
    for (int t = 0; t < nk; t++) {
        CPWAIT(STAGES - 2);
        __syncthreads();
        int tn = t + STAGES - 1;
        if (tn < nk) fill(tn % STAGES, tn);
        CPCOMMIT();
        compute(t % STAGES);
    }

    // epilogue (vectorized: column pairs)
    #pragma unroll
    for (int mt = 0; mt < 4; mt++) {
        #pragma unroll
        for (int nt = 0; nt < NT; nt++) {
            int ng = col0 + wn + nt * 8 + (lane & 3) * 2;
            float2 b2 = make_float2(0.f, 0.f);
            if (ep >= 2 && ep <= 4) b2 = *(const float2*)(bias + ng);
            #pragma unroll
            for (int hf = 0; hf < 2; hf++) {
                int mg = row0 + wm + mt * 16 + (lane >> 2) + hf * 8;
                long ci = (long)mg * ldc + ng;
                float v0 = acc[mt][nt][hf * 2 + 0] * alpha;
                float v1 = acc[mt][nt][hf * 2 + 1] * alpha;
                switch (ep) {
                case 1:
                    v0 = fminf(fmaxf(v0, -10.f), 10.f);
                    v1 = fminf(fmaxf(v1, -10.f), 10.f); break;
                case 2: v0 += b2.x; v1 += b2.y; break;
                case 3:
                    v0 = fmaxf(v0 + b2.x, 0.f);
                    v1 = fmaxf(v1 + b2.y, 0.f); break;
                case 4: {
                    float2 r2 = *(const float2*)(Rres + ci);
                    v0 += b2.x + r2.x; v1 += b2.y + r2.y; } break;
                case 6: {
                    float2 r2 = *(const float2*)(Rres + ci);
                    v0 += r2.x; v1 += r2.y; } break;
                case 7:
                    v0 = fminf(fmaxf(v0, -1.f), 1.f);
                    v1 = fminf(fmaxf(v1, -1.f), 1.f); break;
                }
                if (C) *(float2*)(C + ci) = make_float2(v0, v1);
                if (Ch) *(__half2*)(Ch + ci) =
                    __halves2half2(__float2half_rn(v0), __float2half_rn(v1));
            }
        }
    }
}

// ---------------- elementwise kernels ----------------
__global__ void convert_kernel(const float* __restrict__ src, f16* __restrict__ h,
                               long n4h)
{
    long i = (long)blockIdx.x * blockDim.x + threadIdx.x;
    if (i >= n4h) return;
    #pragma unroll
    for (int r = 0; r < 2; r++) {
        long j = i + r * n4h;
        float4 v = ((const float4*)src)[j];
        __half2* h2 = (__half2*)h;
        h2[j * 2]     = __halves2half2(__float2half_rn(v.x), __float2half_rn(v.y));
        h2[j * 2 + 1] = __halves2half2(__float2half_rn(v.z), __float2half_rn(v.w));
    }
}

__global__ void ln_kernel(const float* __restrict__ in, float* __restrict__ out,
                          const float* __restrict__ w, const float* __restrict__ b,
                          f16* __restrict__ oh, int wsel)
{
    const long row = blockIdx.x;
    const float* p = in + row * DD;
    const int t = threadIdx.x; // 128
    __shared__ float sh[4];
    const long wo = wsel ? (row / NTOK) * DD : 0;

    float v[4];
    float s = 0.f;
    #pragma unroll
    for (int i = 0; i < 4; i++) { v[i] = p[t + i * 128]; s += v[i]; }
    #pragma unroll
    for (int o = 16; o; o >>= 1) s += __shfl_down_sync(0xffffffffu, s, o);
    if ((t & 31) == 0) sh[t >> 5] = s;
    __syncthreads();
    float mu = (sh[0] + sh[1] + sh[2] + sh[3]) * (1.f / DD);
    __syncthreads();
    float sq = 0.f;
    #pragma unroll
    for (int i = 0; i < 4; i++) { float d = v[i] - mu; sq += d * d; }
    #pragma unroll
    for (int o = 16; o; o >>= 1) sq += __shfl_down_sync(0xffffffffu, sq, o);
    if ((t & 31) == 0) sh[t >> 5] = sq;
    __syncthreads();
    float rstd = rsqrtf((sh[0] + sh[1] + sh[2] + sh[3]) * (1.f / DD) + 1e-5f);

    #pragma unroll
    for (int i = 0; i < 4; i++) {
        int d = t + i * 128;
        float o = (v[i] - mu) * rstd;
        if (w) o = o * w[wo + d] + b[wo + d];
        long gi = row * DD + d;
        if (out) out[gi] = o;
        oh[gi] = __float2half_rn(o);
    }
}

// online softmax with smem row cache
__global__ void softmax_kernel(const float* __restrict__ S, f16* __restrict__ Oh,
                               int cols)
{
    extern __shared__ float srow[];
    const float4* row = (const float4*)(S + (long)blockIdx.x * cols);
    float4* srow4 = (float4*)srow;
    __half2* oh = (__half2*)(Oh + (long)blockIdx.x * cols);
    const int t = threadIdx.x; // 256
    const int n4 = cols >> 2;
    __shared__ float shm[8], shs[8];

    float m = -1e30f, s = 0.f;
    for (int i = t; i < n4; i += 256) {
        float4 v = row[i];
        srow4[i] = v;
        float mx = fmaxf(fmaxf(v.x, v.y), fmaxf(v.z, v.w));
        if (mx > m) { s *= expf(m - mx); m = mx; }
        s += expf(v.x - m) + expf(v.y - m) + expf(v.z - m) + expf(v.w - m);
    }
    #pragma unroll
    for (int o = 16; o; o >>= 1) {
        float mo = __shfl_xor_sync(0xffffffffu, m, o);
        float so = __shfl_xor_sync(0xffffffffu, s, o);
        float mn = fmaxf(m, mo);
        s = s * expf(m - mn) + so * expf(mo - mn);
        m = mn;
    }
    if ((t & 31) == 0) { shm[t >> 5] = m; shs[t >> 5] = s; }
    __syncthreads();
    if (t == 0) {
        float M = shm[0], Sm = shs[0];
        #pragma unroll
        for (int w = 1; w < 8; w++) {
            float mn = fmaxf(M, shm[w]);
            Sm = Sm * expf(M - mn) + shs[w] * expf(shm[w] - mn);
            M = mn;
        }
        shm[0] = M; shs[0] = 1.f / Sm;
    }
    __syncthreads();
    const float M = shm[0], inv = shs[0];

    for (int i = t; i < n4; i += 256) {
        float4 v = srow4[i];
        float p0 = expf(v.x - M) * inv, p1 = expf(v.y - M) * inv;
        float p2 = expf(v.z - M) * inv, p3 = expf(v.w - M) * inv;
        oh[i * 2]     = __halves2half2(__float2half_rn(p0), __float2half_rn(p1));
        oh[i * 2 + 1] = __halves2half2(__float2half_rn(p2), __float2half_rn(p3));
    }
}

__global__ void pool_kernel(const float* __restrict__ x, float* __restrict__ pooled)
{
    int idx = blockIdx.x * blockDim.x + threadIdx.x;
    if (idx >= EE * DD) return;
    int e = idx / DD, d = idx % DD;
    const float* p = x + (long)e * NTOK * DD + d;
    float s = 0.f;
    #pragma unroll 16
    for (int n = 0; n < NTOK; n++) s += p[(long)n * DD];
    pooled[idx] = s * (1.f / NTOK);
}

__global__ void gate_kernel(const float* __restrict__ pooled, const float* __restrict__ gate,
                            float* __restrict__ out_gw, float* __restrict__ gdev)
{
    const int t = threadIdx.x;
    const int wid = t >> 5, lane = t & 31;
    __shared__ float logits[4];
    float s = 0.f;
    for (int d = lane; d < DD; d += 32) s += pooled[wid * DD + d] * gate[d];
    #pragma unroll
    for (int o = 16; o; o >>= 1) s += __shfl_down_sync(0xffffffffu, s, o);
    if (lane == 0) logits[wid] = fminf(fmaxf(s, -10.f), 10.f);
    __syncthreads();
    if (t == 0) {
        float mx = fmaxf(fmaxf(logits[0], logits[1]), fmaxf(logits[2], logits[3]));
        float e0 = expf(logits[0] - mx), e1 = expf(logits[1] - mx);
        float e2 = expf(logits[2] - mx), e3 = expf(logits[3] - mx);
        float inv = 1.f / (e0 + e1 + e2 + e3);
        out_gw[0] = gdev[0] = e0 * inv;
        out_gw[1] = gdev[1] = e1 * inv;
        out_gw[2] = gdev[2] = e2 * inv;
        out_gw[3] = gdev[3] = e3 * inv;
    }
}

__global__ void fused_kernel(const float* __restrict__ x, const float* __restrict__ gw,
                             float* __restrict__ out)
{
    long i = (long)blockIdx.x * blockDim.x + threadIdx.x;
    if (i >= (long)NTOK * DD) return;
    float s = 0.f;
    #pragma unroll
    for (int e = 0; e < EE; e++) s += gw[e] * x[(long)e * NTOK * DD + i];
    out[i] = s;
}

__global__ void newmem_kernel(const float* __restrict__ mem, const float* __restrict__ upd4,
                              float* __restrict__ out)
{
    long i = (long)blockIdx.x * blockDim.x + threadIdx.x;
    const long S = (long)LL * MMEM * DD;
    if (i >= S) return;
    float u = ((upd4[i] + upd4[i + S]) + upd4[i + 2 * S]) + upd4[i + 3 * S];
    u *= 0.1f;
    u = fminf(fmaxf(u, -0.1f), 0.1f);
    out[i] = 0.9f * mem[i] + u;
}

// ---------------- host-side launcher ----------------
struct GArgs {
    const f16 *Ah, *Bh;
    float* C; f16* Ch;
    int M, N, K, Arow, Brow, ldc;
    float alpha; int ep;
    const float* bias; long biasZ; const float* R;
    int nRemap, kRemap, thresh, inner, batch;
    long Ai, Ao, Bi, Bo, Ci, Co;
    int TA, TB;
    cudaStream_t st;
};

static void hg(const GArgs& a)
{
    #define HGCALL(BN, TA_, TB_, SMEM) \
        hgemm<BN, 4, TA_, TB_><<<grid, 256, SMEM, a.st>>>( \
            a.Ah, a.Bh, a.C, a.Ch, a.K, a.Arow, a.Brow, a.ldc, \
            a.alpha, a.ep, a.bias, a.biasZ, a.R, a.nRemap, a.kRemap, a.thresh, \
            a.inner, a.Ai, a.Ao, a.Bi, a.Bo, a.Ci, a.Co)
    if (a.N % 128 == 0) {
        dim3 grid(a.N / 128, a.M / 128, a.batch);
        if (a.TA)      HGCALL(128, 1, 1, 81920);
        else if (a.TB) HGCALL(128, 0, 1, 81920);
        else           HGCALL(128, 0, 0, 81920);
    } else {
        dim3 grid(a.N / 64, a.M / 128, a.batch);
        HGCALL(64, 0, 1, 61440);
    }
    #undef HGCALL
}

static void conv(const float* s, f16* h, long n, cudaStream_t st = 0)
{
    long n4h = n / 8;
    convert_kernel<<<(unsigned)((n4h + 255) / 256), 256, 0, st>>>(s, h, n4h);
}

static void smax(float* sc, f16* oh, int rows, int cols)
{
    softmax_kernel<<<rows, 256, cols * 4>>>(sc, oh, cols);
}

extern "C" void kernel_launch(void* const* d_in, const int* in_sizes, int n_in,
                              void* d_out, int out_size)
{
    const float* tokens   = (const float*)d_in[0];
    const float* memories = (const float*)d_in[1];
    const float* ipw      = (const float*)d_in[2];
    const float* ipb      = (const float*)d_in[3];
    const float* opw      = (const float*)d_in[4];
    const float* opb      = (const float*)d_in[5];
    const float* w1       = (const float*)d_in[6];
    const float* b1       = (const float*)d_in[7];
    const float* w2       = (const float*)d_in[8];
    const float* b2       = (const float*)d_in[9];
    const float* n1w      = (const float*)d_in[10];
    const float* n1b      = (const float*)d_in[11];
    const float* n2w      = (const float*)d_in[12];
    const float* n2b      = (const float*)d_in[13];
    const float* aggw     = (const float*)d_in[14];
    const float* aggb     = (const float*)d_in[15];
    const float* gate     = (const float*)d_in[16];
    float* out = (float*)d_out;

    static bool inited = false;
    static cudaStream_t s2;
    static cudaEvent_t ev[4];
    if (!inited) {
        cudaFuncSetAttribute((const void*)hgemm<128, 4, 0, 0>, cudaFuncAttributeMaxDynamicSharedMemorySize, 81920);
        cudaFuncSetAttribute((const void*)hgemm<128, 4, 0, 1>, cudaFuncAttributeMaxDynamicSharedMemorySize, 81920);
        cudaFuncSetAttribute((const void*)hgemm<128, 4, 1, 1>, cudaFuncAttributeMaxDynamicSharedMemorySize, 81920);
        cudaFuncSetAttribute((const void*)hgemm<64, 4, 0, 1>,  cudaFuncAttributeMaxDynamicSharedMemorySize, 61440);
        cudaStreamCreateWithFlags(&s2, cudaStreamNonBlocking);
        for (int i = 0; i < 4; i++) cudaEventCreateWithFlags(&ev[i], cudaEventDisableTiming);
        inited = true;
    }

    float *xln, *x, *y, *sc, *upd4, *pooled, *gatew;
    cudaGetSymbolAddress((void**)&xln, g_xln);
    cudaGetSymbolAddress((void**)&x, g_x);
    cudaGetSymbolAddress((void**)&y, g_y);
    cudaGetSymbolAddress((void**)&sc, g_scores);
    cudaGetSymbolAddress((void**)&upd4, g_upd4);
    cudaGetSymbolAddress((void**)&pooled, g_pooled);
    cudaGetSymbolAddress((void**)&gatew, g_gatew);

    f16 *xlnh, *xh, *qkvh, *sah, *ff1h, *sch, *retrph, *memh;
    f16 *ipwh, *opwh, *w1h, *w2h, *aggwh;
    cudaGetSymbolAddress((void**)&xlnh, g_xlnh);
    cudaGetSymbolAddress((void**)&xh, g_xh);
    cudaGetSymbolAddress((void**)&qkvh, g_qkvh);
    cudaGetSymbolAddress((void**)&sah, g_sah);
    cudaGetSymbolAddress((void**)&ff1h, g_ff1h);
    cudaGetSymbolAddress((void**)&sch, g_sch);
    cudaGetSymbolAddress((void**)&retrph, g_retrph);
    cudaGetSymbolAddress((void**)&memh, g_memh);
    cudaGetSymbolAddress((void**)&ipwh, g_ipwh);
    cudaGetSymbolAddress((void**)&opwh, g_opwh);
    cudaGetSymbolAddress((void**)&w1h, g_w1h);
    cudaGetSymbolAddress((void**)&w2h, g_w2h);
    cudaGetSymbolAddress((void**)&aggwh, g_aggwh);

    const float isd = 1.0f / sqrtf((float)DD);
    const long ND = (long)NTOK * DD;
    const long N3N = (long)NTOK * 3 * NTOK;
    const long NN = (long)NTOK * NTOK;
    const long NM = (long)NTOK * MMEM;

    // ---- fork side stream: weight/memory conversions ----
    cudaEventRecord(ev[0], 0);
    cudaStreamWaitEvent(s2, ev[0], 0);
    conv(ipw, ipwh, (long)EE * 3 * DD * DD, s2);
    conv(opw, opwh, (long)EE * DD * DD, s2);
    conv(w1, w1h, (long)EE * FFD * DD, s2);
    conv(w2, w2h, (long)EE * DD * FFD, s2);
    conv(aggw, aggwh, (long)DD * LL * DD, s2);
    conv(memories, memh, (long)LL * MMEM * DD, s2);
    cudaEventRecord(ev[1], s2);

    // ---- main: LN + cross attention ----
    ln_kernel<<<EE * NTOK, 128>>>(tokens, xln, nullptr, nullptr, xlnh, 0);

    // 1. cross scores: S[e] = clip(xln_e @ ctx^T / sqrt(D)), remap n per z
    { GArgs a{}; a.Ah=xlnh; a.Bh=xlnh; a.C=sc;
      a.M=NTOK; a.N=3*NTOK; a.K=DD; a.Arow=DD; a.Brow=DD; a.ldc=3*NTOK;
      a.alpha=isd; a.ep=1; a.nRemap=1; a.thresh=-1; a.inner=1; a.batch=EE;
      a.Ao=ND; a.Co=N3N; hg(a); }
    smax(sc, sch, EE * NTOK, 3 * NTOK);
    // 2. x = xln_e + P @ ctx  (B = xln native via TB, remap k per z)
    { GArgs a{}; a.Ah=sch; a.Bh=xlnh; a.C=x; a.Ch=xh;
      a.M=NTOK; a.N=DD; a.K=3*NTOK; a.Arow=3*NTOK; a.Brow=DD; a.ldc=DD;
      a.alpha=1.f; a.ep=6; a.R=xln; a.kRemap=1; a.thresh=-1; a.inner=1; a.batch=EE;
      a.Ao=N3N; a.Co=ND; a.TB=1; hg(a); }

    // join: qkv needs converted ipw
    cudaStreamWaitEvent(0, ev[1], 0);
    // 3. qkv
    { GArgs a{}; a.Ah=xh; a.Bh=ipwh; a.Ch=qkvh;
      a.M=NTOK; a.N=3*DD; a.K=DD; a.Arow=DD; a.Brow=DD; a.ldc=3*DD;
      a.alpha=1.f; a.ep=2; a.bias=ipb; a.biasZ=3*DD; a.inner=1; a.batch=EE;
      a.Ao=ND; a.Bo=(long)3*DD*DD; a.Co=(long)NTOK*3*DD; hg(a); }
    // 4. head scores (z = e*H + h)
    { GArgs a{}; a.Ah=qkvh; a.Bh=qkvh + DD; a.C=sc;
      a.M=NTOK; a.N=NTOK; a.K=DHH; a.Arow=3*DD; a.Brow=3*DD; a.ldc=NTOK;
      a.alpha=0.125f; a.ep=0; a.inner=HH; a.batch=EE*HH;
      a.Ai=DHH; a.Ao=(long)NTOK*3*DD; a.Bi=DHH; a.Bo=(long)NTOK*3*DD;
      a.Ci=NN; a.Co=HH*NN; hg(a); }
    smax(sc, sch, EE * HH * NTOK, NTOK);
    // 5. sa = P @ V  (B = V native [seq][dh] via TB; batch e*H+h)
    { GArgs a{}; a.Ah=sch; a.Bh=qkvh + 2*DD; a.Ch=sah;
      a.M=NTOK; a.N=DHH; a.K=NTOK; a.Arow=NTOK; a.Brow=3*DD; a.ldc=DD;
      a.alpha=1.f; a.ep=0; a.inner=HH; a.batch=EE*HH;
      a.Ai=NN; a.Ao=HH*NN; a.Bi=DHH; a.Bo=(long)NTOK*3*DD;
      a.Ci=DHH; a.Co=ND; a.TB=1; hg(a); }
    // 6. out_proj + bias + residual
    { GArgs a{}; a.Ah=sah; a.Bh=opwh; a.C=y;
      a.M=NTOK; a.N=DD; a.K=DD; a.Arow=DD; a.Brow=DD; a.ldc=DD;
      a.alpha=1.f; a.ep=4; a.bias=opb; a.biasZ=DD; a.R=x; a.inner=1; a.batch=EE;
      a.Ao=ND; a.Bo=(long)DD*DD; a.Co=ND; hg(a); }
    ln_kernel<<<EE * NTOK, 128>>>(y, x, n1w, n1b, xh, 1);
    // 7. FFN
    { GArgs a{}; a.Ah=xh; a.Bh=w1h; a.Ch=ff1h;
      a.M=NTOK; a.N=FFD; a.K=DD; a.Arow=DD; a.Brow=DD; a.ldc=FFD;
      a.alpha=1.f; a.ep=3; a.bias=b1; a.biasZ=FFD; a.inner=1; a.batch=EE;
      a.Ao=ND; a.Bo=(long)FFD*DD; a.Co=(long)NTOK*FFD; hg(a); }
    { GArgs a{}; a.Ah=ff1h; a.Bh=w2h; a.C=y;
      a.M=NTOK; a.N=DD; a.K=FFD; a.Arow=FFD; a.Brow=FFD; a.ldc=DD;
      a.alpha=1.f; a.ep=4; a.bias=b2; a.biasZ=DD; a.R=x; a.inner=1; a.batch=EE;
      a.Ao=(long)NTOK*FFD; a.Bo=(long)DD*FFD; a.Co=ND; hg(a); }
    ln_kernel<<<EE * NTOK, 128>>>(y, x, n2w, n2b, xh, 1);

    // 8. memory scores (z = e*L + l)
    { GArgs a{}; a.Ah=xh; a.Bh=memh; a.C=sc;
      a.M=NTOK; a.N=MMEM; a.K=DD; a.Arow=DD; a.Brow=DD; a.ldc=MMEM;
      a.alpha=isd; a.ep=1; a.inner=LL; a.batch=EE*LL;
      a.Ai=0; a.Ao=ND; a.Bi=(long)MMEM*DD; a.Bo=0;
      a.Ci=NM; a.Co=LL*NM; hg(a); }
    smax(sc, sch, EE * LL * NTOK, MMEM);

    // fork: upd GEMM (A = sch via TA, B = xh via TB) + newmem on side stream
    cudaEventRecord(ev[2], 0);
    cudaStreamWaitEvent(s2, ev[2], 0);
    { GArgs a{}; a.Ah=sch; a.Bh=xh; a.C=upd4;
      a.M=MMEM; a.N=DD; a.K=NTOK; a.Arow=MMEM; a.Brow=DD; a.ldc=DD;
      a.alpha=1.f; a.ep=7; a.inner=LL; a.batch=EE*LL;
      a.Ai=NM; a.Ao=LL*NM; a.Bi=0; a.Bo=ND;
      a.Ci=(long)MMEM*DD; a.Co=(long)LL*MMEM*DD; a.TA=1; a.TB=1; a.st=s2; hg(a); }
    {
        long n = (long)LL * MMEM * DD;
        newmem_kernel<<<(unsigned)((n + 255) / 256), 256, 0, s2>>>(memories, upd4, out + ND + EE);
    }
    cudaEventRecord(ev[3], s2);

    // main: retr (B = mem native via TB) -> retrph permuted, agg, pool/gate/fused
    { GArgs a{}; a.Ah=sch; a.Bh=memh; a.Ch=retrph;
      a.M=NTOK; a.N=DD; a.K=MMEM; a.Arow=MMEM; a.Brow=DD; a.ldc=LL*DD;
      a.alpha=1.f; a.ep=0; a.inner=LL; a.batch=EE*LL;
      a.Ai=NM; a.Ao=LL*NM; a.Bi=(long)MMEM*DD; a.Bo=0;
      a.Ci=DD; a.Co=(long)NTOK*LL*DD; a.TB=1; hg(a); }
    { GArgs a{}; a.Ah=retrph; a.Bh=aggwh; a.C=x;
      a.M=NTOK; a.N=DD; a.K=LL*DD; a.Arow=LL*DD; a.Brow=LL*DD; a.ldc=DD;
      a.alpha=1.f; a.ep=4; a.bias=aggb; a.biasZ=0; a.R=x; a.inner=1; a.batch=EE;
      a.Ao=(long)NTOK*LL*DD; a.Co=ND; hg(a); }

    pool_kernel<<<(EE * DD + 255) / 256, 256>>>(x, pooled);
    gate_kernel<<<1, 128>>>(pooled, gate, out + ND, gatew);
    fused_kernel<<<(unsigned)((ND + 255) / 256), 256>>>(x, gatew, out);

    // join side stream
    cudaStreamWaitEvent(0, ev[3], 0);
}

// round 13
// speedup vs baseline: 9.9631x; 1.0201x over previous
#include <cuda_runtime.h>
#include <cuda_fp16.h>
#include <math.h>
#include <stdint.h>

#define EE 4
#define NTOK 2048
#define DD 512
#define HH 8
#define DHH 64
#define FFD 2048
#define LL 4
#define MMEM 4096

typedef __half f16;

// ---------------- static scratch ----------------
__device__ float g_xln[EE * NTOK * DD];
__device__ float g_x[EE * NTOK * DD];
__device__ float g_y[EE * NTOK * DD];
__device__ float g_upd4[(size_t)EE * LL * MMEM * DD];
__device__ float g_pooled[EE * DD];
__device__ float g_gatew[EE];

__device__ f16 g_xlnh[EE * NTOK * DD];
__device__ f16 g_xh[EE * NTOK * DD];
__device__ f16 g_qkvh[EE * NTOK * 3 * DD];
__device__ f16 g_sah[EE * NTOK * DD];
__device__ f16 g_ff1h[EE * NTOK * FFD];
__device__ f16 g_sch[(size_t)EE * HH * NTOK * NTOK];   // scores in-place -> probs
__device__ f16 g_retrph[EE * NTOK * LL * DD];
__device__ f16 g_memh[LL * MMEM * DD];
__device__ f16 g_ipwh[EE * 3 * DD * DD];
__device__ f16 g_opwh[EE * DD * DD];
__device__ f16 g_w1h[EE * FFD * DD];
__device__ f16 g_w2h[EE * DD * FFD];
__device__ f16 g_aggwh[DD * LL * DD];

__device__ __forceinline__ uint32_t smem_u32(const void* p) {
    uint32_t a;
    asm("{ .reg .u64 t; cvta.to.shared.u64 t, %1; cvt.u32.u64 %0, t; }" : "=r"(a) : "l"(p));
    return a;
}

#define MMA16816(d, a0, a1, a2, a3, b0, b1) \
    asm volatile("mma.sync.aligned.m16n8k16.row.col.f32.f16.f16.f32 " \
                 "{%0,%1,%2,%3}, {%4,%5,%6,%7}, {%8,%9}, {%0,%1,%2,%3};" \
                 : "+f"((d)[0]), "+f"((d)[1]), "+f"((d)[2]), "+f"((d)[3]) \
                 : "r"(a0), "r"(a1), "r"(a2), "r"(a3), "r"(b0), "r"(b1))

#define LDSM4(r0, r1, r2, r3, addr) \
    asm volatile("ldmatrix.sync.aligned.m8n8.x4.shared.b16 {%0,%1,%2,%3}, [%4];" \
                 : "=r"(r0), "=r"(r1), "=r"(r2), "=r"(r3) : "r"(addr))

#define LDSM4T(r0, r1, r2, r3, addr) \
    asm volatile("ldmatrix.sync.aligned.m8n8.x4.trans.shared.b16 {%0,%1,%2,%3}, [%4];" \
                 : "=r"(r0), "=r"(r1), "=r"(r2), "=r"(r3) : "r"(addr))

#define CP16(dst, src) \
    asm volatile("cp.async.cg.shared.global [%0], [%1], 16;" :: "r"(dst), "l"(src))
#define CPCOMMIT() asm volatile("cp.async.commit_group;")
#define CPWAIT(n)  asm volatile("cp.async.wait_group %0;" :: "n"(n))

// ---------------- HMMA fp16 GEMM: cp.async + ldmatrix(+trans), 2-level batch -----
// z1 = z % inner, z2 = z / inner; offsets = z1*Xi + z2*Xo.
// C[m,n] = ep( alpha * sum_k a(m,k) * b(n,k) )   fp32 accumulate, fp16 operands.
// TA=0: A gmem [m][k] (k-contig). TA=1: A gmem [k][m] via ldsm.trans. Same for TB.
// nRemap (TB=0): B row n += NTOK when >= th.  kRemap: B k index += NTOK when >= th.
// th = thresh, or z2*NTOK when thresh < 0.
// ep: 0 none,1 clip±10,2 +bias,3 relu+bias,4 +bias+res,6 +res,7 clip±1
template<int BN, int STAGES, int TA, int TB>
__global__ void __launch_bounds__(256, 2) hgemm(
    const f16* __restrict__ Ahg, const f16* __restrict__ Bhg,
    float* __restrict__ C, f16* __restrict__ Ch,
    int Kdim, int Arow, int Brow, int ldc,
    float alpha, int ep,
    const float* __restrict__ bias, long biasZ, const float* __restrict__ Rres,
    int nRemap, int kRemap, int thresh, int inner,
    long Ai, long Ao, long Bi, long Bo, long Ci, long Co)
{
    constexpr int AST = 128 * 80;
    constexpr int BST = BN * 80;
    constexpr int NT = BN / 32;
    constexpr int BIT = BN / 64;
    constexpr int ASTR = 272;
    constexpr int BSTR = BN * 2 + 16;
    constexpr int BCH = BN / 8;

    const int z1 = blockIdx.z % inner;
    const int z2 = blockIdx.z / inner;
    Ahg += (long)z1 * Ai + (long)z2 * Ao;
    Bhg += (long)z1 * Bi + (long)z2 * Bo;
    const long coff = (long)z1 * Ci + (long)z2 * Co;
    if (C)  C  += coff;
    if (Ch) Ch += coff;
    if (Rres) Rres += coff;
    if (bias) bias += (long)z2 * biasZ;
    const int th = (thresh < 0) ? z2 * NTOK : thresh;

    extern __shared__ char sm[];
    const uint32_t smBase = smem_u32(sm);
    const uint32_t offAh = 0;
    const uint32_t offBh = STAGES * AST;

    const int tid = threadIdx.x;
    const int lane = tid & 31;
    const int wid = tid >> 5;
    const int wm = (wid >> 2) * 64;
    const int wn = (wid & 3) * (BN / 4);
    const int row0 = blockIdx.y * 128;
    const int col0 = blockIdx.x * BN;

    const int g = lane >> 3;
    const uint32_t laneOffA = TA
        ? ((lane & 7) + (g >> 1) * 8) * ASTR + (g & 1) * 16
        : ((g & 1) * 8 + (lane & 7)) * 80 + (g >> 1) * 16;
    const uint32_t laneOffB = TB
        ? ((lane & 7) + (g >> 1) * 8) * BSTR + (g & 1) * 16
        : ((g & 1) * 8 + (lane & 7)) * 80 + (g >> 1) * 16;

    float acc[4][NT][4];
    #pragma unroll
    for (int i = 0; i < 4; i++)
        #pragma unroll
        for (int j = 0; j < NT; j++)
            #pragma unroll
            for (int r = 0; r < 4; r++) acc[i][j][r] = 0.f;

    auto fill = [&](int s, int t) {
        int k0 = t * 32;
        if (!TA) {
            #pragma unroll
            for (int r = 0; r < 2; r++) {
                int idx = tid + r * 256;
                int row = idx >> 2, c = idx & 3;
                long go = (long)(row0 + row) * Arow + k0 + c * 8;
                CP16(smBase + offAh + s * AST + row * 80 + c * 16, Ahg + go);
            }
        } else {
            #pragma unroll
            for (int r = 0; r < 2; r++) {
                int idx = tid + r * 256;
                int row = idx >> 4, c = idx & 15;
                long go = (long)(k0 + row) * Arow + row0 + c * 8;
                CP16(smBase + offAh + s * AST + row * ASTR + c * 16, Ahg + go);
            }
        }
        if (!TB) {
            long kb = k0 + ((kRemap && k0 >= th) ? NTOK : 0);
            #pragma unroll
            for (int r = 0; r < BIT; r++) {
                int idx = tid + r * 256;
                int row = idx >> 2, c = idx & 3;
                int ng = col0 + row;
                if (nRemap && ng >= th) ng += NTOK;
                long go = (long)ng * Brow + kb + c * 8;
                CP16(smBase + offBh + s * BST + row * 80 + c * 16, Bhg + go);
            }
        } else {
            #pragma unroll
            for (int r = 0; r < BIT; r++) {
                int idx = tid + r * 256;
                int row = idx / BCH, c = idx % BCH;
                int kg = k0 + row;
                if (kRemap && kg >= th) kg += NTOK;
                long go = (long)kg * Brow + col0 + c * 8;
                CP16(smBase + offBh + s * BST + row * BSTR + c * 16, Bhg + go);
            }
        }
    };

    auto compute = [&](int buf) {
        const uint32_t aH = smBase + offAh + buf * AST + laneOffA;
        const uint32_t bH = smBase + offBh + buf * BST + laneOffB;
        #pragma unroll
        for (int s = 0; s < 2; s++) {
            uint32_t bh[NT][2];
            #pragma unroll
            for (int p = 0; p < NT / 2; p++) {
                uint32_t addr = TB ? bH + s * (16 * BSTR) + (wn + p * 16) * 2
                                   : bH + (wn + p * 16) * 80 + s * 32;
                if (TB) { LDSM4T(bh[2*p][0], bh[2*p+1][0], bh[2*p][1], bh[2*p+1][1], addr); }
                else    { LDSM4 (bh[2*p][0], bh[2*p+1][0], bh[2*p][1], bh[2*p+1][1], addr); }
            }
            #pragma unroll
            for (int mt = 0; mt < 4; mt++) {
                uint32_t a0, a1, a2, a3;
                uint32_t addr = TA ? aH + s * (16 * ASTR) + (wm + mt * 16) * 2
                                   : aH + (wm + mt * 16) * 80 + s * 32;
                if (TA) { LDSM4T(a0, a1, a2, a3, addr); }
                else    { LDSM4 (a0, a1, a2, a3, addr); }
                #pragma unroll
                for (int nt = 0; nt < NT; nt++)
                    MMA16816(acc[mt][nt], a0, a1, a2, a3, bh[nt][0], bh[nt][1]);
            }
        }
    };

    const int nk = Kdim / 32;
    #pragma unroll
    for (int s = 0; s < STAGES - 1; s++) {
        if (s < nk) fill(s, s);
        CPCOMMIT();
    }
    for (int t = 0; t < nk; t++) {
        CPWAIT(STAGES - 2);
        __syncthreads();
        int tn = t + STAGES - 1;
        if (tn < nk) fill(tn % STAGES, tn);
        CPCOMMIT();
        compute(t % STAGES);
    }

    // epilogue (vectorized: column pairs)
    #pragma unroll
    for (int mt = 0; mt < 4; mt++) {
        #pragma unroll
        for (int nt = 0; nt < NT; nt++) {
            int ng = col0 + wn + nt * 8 + (lane & 3) * 2;
            float2 b2 = make_float2(0.f, 0.f);
            if (ep >= 2 && ep <= 4) b2 = *(const float2*)(bias + ng);
            #pragma unroll
            for (int hf = 0; hf < 2; hf++) {
                int mg = row0 + wm + mt * 16 + (lane >> 2) + hf * 8;
                long ci = (long)mg * ldc + ng;
                float v0 = acc[mt][nt][hf * 2 + 0] * alpha;
                float v1 = acc[mt][nt][hf * 2 + 1] * alpha;
                switch (ep) {
                case 1:
                    v0 = fminf(fmaxf(v0, -10.f), 10.f);
                    v1 = fminf(fmaxf(v1, -10.f), 10.f); break;
                case 2: v0 += b2.x; v1 += b2.y; break;
                case 3:
                    v0 = fmaxf(v0 + b2.x, 0.f);
                    v1 = fmaxf(v1 + b2.y, 0.f); break;
                case 4: {
                    float2 r2 = *(const float2*)(Rres + ci);
                    v0 += b2.x + r2.x; v1 += b2.y + r2.y; } break;
                case 6: {
                    float2 r2 = *(const float2*)(Rres + ci);
                    v0 += r2.x; v1 += r2.y; } break;
                case 7:
                    v0 = fminf(fmaxf(v0, -1.f), 1.f);
                    v1 = fminf(fmaxf(v1, -1.f), 1.f); break;
                }
                if (C) *(float2*)(C + ci) = make_float2(v0, v1);
                if (Ch) *(__half2*)(Ch + ci) =
                    __halves2half2(__float2half_rn(v0), __float2half_rn(v1));
            }
        }
    }
}

// ---------------- elementwise kernels ----------------
__global__ void convert_kernel(const float* __restrict__ src, f16* __restrict__ h,
                               long n4h)
{
    long i = (long)blockIdx.x * blockDim.x + threadIdx.x;
    if (i >= n4h) return;
    #pragma unroll
    for (int r = 0; r < 2; r++) {
        long j = i + r * n4h;
        float4 v = ((const float4*)src)[j];
        __half2* h2 = (__half2*)h;
        h2[j * 2]     = __halves2half2(__float2half_rn(v.x), __float2half_rn(v.y));
        h2[j * 2 + 1] = __halves2half2(__float2half_rn(v.z), __float2half_rn(v.w));
    }
}

__global__ void ln_kernel(const float* __restrict__ in, float* __restrict__ out,
                          const float* __restrict__ w, const float* __restrict__ b,
                          f16* __restrict__ oh, int wsel)
{
    const long row = blockIdx.x;
    const float* p = in + row * DD;
    const int t = threadIdx.x; // 128
    __shared__ float sh[4];
    const long wo = wsel ? (row / NTOK) * DD : 0;

    float v[4];
    float s = 0.f;
    #pragma unroll
    for (int i = 0; i < 4; i++) { v[i] = p[t + i * 128]; s += v[i]; }
    #pragma unroll
    for (int o = 16; o; o >>= 1) s += __shfl_down_sync(0xffffffffu, s, o);
    if ((t & 31) == 0) sh[t >> 5] = s;
    __syncthreads();
    float mu = (sh[0] + sh[1] + sh[2] + sh[3]) * (1.f / DD);
    __syncthreads();
    float sq = 0.f;
    #pragma unroll
    for (int i = 0; i < 4; i++) { float d = v[i] - mu; sq += d * d; }
    #pragma unroll
    for (int o = 16; o; o >>= 1) sq += __shfl_down_sync(0xffffffffu, sq, o);
    if ((t & 31) == 0) sh[t >> 5] = sq;
    __syncthreads();
    float rstd = rsqrtf((sh[0] + sh[1] + sh[2] + sh[3]) * (1.f / DD) + 1e-5f);

    #pragma unroll
    for (int i = 0; i < 4; i++) {
        int d = t + i * 128;
        float o = (v[i] - mu) * rstd;
        if (w) o = o * w[wo + d] + b[wo + d];
        long gi = row * DD + d;
        if (out) out[gi] = o;
        oh[gi] = __float2half_rn(o);
    }
}

// online softmax, fully in-place on an f16 score row (fp32 math via smem cache)
__global__ void softmax_kernel(f16* __restrict__ S, int cols)
{
    extern __shared__ float srow[];
    f16* rowp = S + (long)blockIdx.x * cols;
    const uint4* row8 = (const uint4*)rowp;
    __half2* oh = (__half2*)rowp;
    const int t = threadIdx.x; // 256
    const int n8 = cols >> 3;
    __shared__ float shm[8], shs[8];

    float m = -1e30f, s = 0.f;
    for (int i = t; i < n8; i += 256) {
        uint4 u = row8[i];
        const __half2* hp = (const __half2*)&u;
        float vv[8];
        #pragma unroll
        for (int q = 0; q < 4; q++) {
            float2 f2 = __half22float2(hp[q]);
            vv[q * 2] = f2.x; vv[q * 2 + 1] = f2.y;
        }
        float mx = vv[0];
        #pragma unroll
        for (int q = 1; q < 8; q++) mx = fmaxf(mx, vv[q]);
        if (mx > m) { s *= expf(m - mx); m = mx; }
        #pragma unroll
        for (int q = 0; q < 8; q++) {
            srow[i * 8 + q] = vv[q];
            s += expf(vv[q] - m);
        }
    }
    #pragma unroll
    for (int o = 16; o; o >>= 1) {
        float mo = __shfl_xor_sync(0xffffffffu, m, o);
        float so = __shfl_xor_sync(0xffffffffu, s, o);
        float mn = fmaxf(m, mo);
        s = s * expf(m - mn) + so * expf(mo - mn);
        m = mn;
    }
    if ((t & 31) == 0) { shm[t >> 5] = m; shs[t >> 5] = s; }
    __syncthreads();
    if (t == 0) {
        float M = shm[0], Sm = shs[0];
        #pragma unroll
        for (int w = 1; w < 8; w++) {
            float mn = fmaxf(M, shm[w]);
            Sm = Sm * expf(M - mn) + shs[w] * expf(shm[w] - mn);
            M = mn;
        }
        shm[0] = M; shs[0] = 1.f / Sm;
    }
    __syncthreads();
    const float M = shm[0], inv = shs[0];

    for (int i = t; i < (cols >> 2); i += 256) {
        float p0 = expf(srow[i * 4 + 0] - M) * inv;
        float p1 = expf(srow[i * 4 + 1] - M) * inv;
        float p2 = expf(srow[i * 4 + 2] - M) * inv;
        float p3 = expf(srow[i * 4 + 3] - M) * inv;
        oh[i * 2]     = __halves2half2(__float2half_rn(p0), __float2half_rn(p1));
        oh[i * 2 + 1] = __halves2half2(__float2half_rn(p2), __float2half_rn(p3));
    }
}

__global__ void pool_kernel(const float* __restrict__ x, float* __restrict__ pooled)
{
    int idx = blockIdx.x * blockDim.x + threadIdx.x;
    if (idx >= EE * DD) return;
    int e = idx / DD, d = idx % DD;
    const float* p = x + (long)e * NTOK * DD + d;
    float s = 0.f;
    #pragma unroll 16
    for (int n = 0; n < NTOK; n++) s += p[(long)n * DD];
    pooled[idx] = s * (1.f / NTOK);
}

__global__ void gate_kernel(const float* __restrict__ pooled, const float* __restrict__ gate,
                            float* __restrict__ out_gw, float* __restrict__ gdev)
{
    const int t = threadIdx.x;
    const int wid = t >> 5, lane = t & 31;
    __shared__ float logits[4];
    float s = 0.f;
    for (int d = lane; d < DD; d += 32) s += pooled[wid * DD + d] * gate[d];
    #pragma unroll
    for (int o = 16; o; o >>= 1) s += __shfl_down_sync(0xffffffffu, s, o);
    if (lane == 0) logits[wid] = fminf(fmaxf(s, -10.f), 10.f);
    __syncthreads();
    if (t == 0) {
        float mx = fmaxf(fmaxf(logits[0], logits[1]), fmaxf(logits[2], logits[3]));
        float e0 = expf(logits[0] - mx), e1 = expf(logits[1] - mx);
        float e2 = expf(logits[2] - mx), e3 = expf(logits[3] - mx);
        float inv = 1.f / (e0 + e1 + e2 + e3);
        out_gw[0] = gdev[0] = e0 * inv;
        out_gw[1] = gdev[1] = e1 * inv;
        out_gw[2] = gdev[2] = e2 * inv;
        out_gw[3] = gdev[3] = e3 * inv;
    }
}

__global__ void fused_kernel(const float* __restrict__ x, const float* __restrict__ gw,
                             float* __restrict__ out)
{
    long i = (long)blockIdx.x * blockDim.x + threadIdx.x;
    if (i >= (long)NTOK * DD) return;
    float s = 0.f;
    #pragma unroll
    for (int e = 0; e < EE; e++) s += gw[e] * x[(long)e * NTOK * DD + i];
    out[i] = s;
}

__global__ void newmem_kernel(const float* __restrict__ mem, const float* __restrict__ upd4,
                              float* __restrict__ out)
{
    long i = (long)blockIdx.x * blockDim.x + threadIdx.x;
    const long S = (long)LL * MMEM * DD;
    if (i >= S) return;
    float u = ((upd4[i] + upd4[i + S]) + upd4[i + 2 * S]) + upd4[i + 3 * S];
    u *= 0.1f;
    u = fminf(fmaxf(u, -0.1f), 0.1f);
    out[i] = 0.9f * mem[i] + u;
}

// ---------------- host-side launcher ----------------
struct GArgs {
    const f16 *Ah, *Bh;
    float* C; f16* Ch;
    int M, N, K, Arow, Brow, ldc;
    float alpha; int ep;
    const float* bias; long biasZ; const float* R;
    int nRemap, kRemap, thresh, inner, batch;
    long Ai, Ao, Bi, Bo, Ci, Co;
    int TA, TB;
    cudaStream_t st;
};

static void hg(const GArgs& a)
{
    #define HGCALL(BN, TA_, TB_, SMEM) \
        hgemm<BN, 4, TA_, TB_><<<grid, 256, SMEM, a.st>>>( \
            a.Ah, a.Bh, a.C, a.Ch, a.K, a.Arow, a.Brow, a.ldc, \
            a.alpha, a.ep, a.bias, a.biasZ, a.R, a.nRemap, a.kRemap, a.thresh, \
            a.inner, a.Ai, a.Ao, a.Bi, a.Bo, a.Ci, a.Co)
    if (a.N % 128 == 0) {
        dim3 grid(a.N / 128, a.M / 128, a.batch);
        if (a.TA)      HGCALL(128, 1, 1, 81920);
        else if (a.TB) HGCALL(128, 0, 1, 81920);
        else           HGCALL(128, 0, 0, 81920);
    } else {
        dim3 grid(a.N / 64, a.M / 128, a.batch);
        HGCALL(64, 0, 1, 61440);
    }
    #undef HGCALL
}

static void conv(const float* s, f16* h, long n, cudaStream_t st = 0)
{
    long n4h = n / 8;
    convert_kernel<<<(unsigned)((n4h + 255) / 256), 256, 0, st>>>(s, h, n4h);
}

static void smax(f16* s, int rows, int cols)
{
    softmax_kernel<<<rows, 256, cols * 4>>>(s, cols);
}

extern "C" void kernel_launch(void* const* d_in, const int* in_sizes, int n_in,
                              void* d_out, int out_size)
{
    const float* tokens   = (const float*)d_in[0];
    const float* memories = (const float*)d_in[1];
    const float* ipw      = (const float*)d_in[2];
    const float* ipb      = (const float*)d_in[3];
    const float* opw      = (const float*)d_in[4];
    const float* opb      = (const float*)d_in[5];
    const float* w1       = (const float*)d_in[6];
    const float* b1       = (const float*)d_in[7];
    const float* w2       = (const float*)d_in[8];
    const float* b2       = (const float*)d_in[9];
    const float* n1w      = (const float*)d_in[10];
    const float* n1b      = (const float*)d_in[11];
    const float* n2w      = (const float*)d_in[12];
    const float* n2b      = (const float*)d_in[13];
    const float* aggw     = (const float*)d_in[14];
    const float* aggb     = (const float*)d_in[15];
    const float* gate     = (const float*)d_in[16];
    float* out = (float*)d_out;

    static bool inited = false;
    static cudaStream_t s2;
    static cudaEvent_t ev[4];
    if (!inited) {
        cudaFuncSetAttribute((const void*)hgemm<128, 4, 0, 0>, cudaFuncAttributeMaxDynamicSharedMemorySize, 81920);
        cudaFuncSetAttribute((const void*)hgemm<128, 4, 0, 1>, cudaFuncAttributeMaxDynamicSharedMemorySize, 81920);
        cudaFuncSetAttribute((const void*)hgemm<128, 4, 1, 1>, cudaFuncAttributeMaxDynamicSharedMemorySize, 81920);
        cudaFuncSetAttribute((const void*)hgemm<64, 4, 0, 1>,  cudaFuncAttributeMaxDynamicSharedMemorySize, 61440);
        cudaStreamCreateWithFlags(&s2, cudaStreamNonBlocking);
        for (int i = 0; i < 4; i++) cudaEventCreateWithFlags(&ev[i], cudaEventDisableTiming);
        inited = true;
    }

    float *xln, *x, *y, *upd4, *pooled, *gatew;
    cudaGetSymbolAddress((void**)&xln, g_xln);
    cudaGetSymbolAddress((void**)&x, g_x);
    cudaGetSymbolAddress((void**)&y, g_y);
    cudaGetSymbolAddress((void**)&upd4, g_upd4);
    cudaGetSymbolAddress((void**)&pooled, g_pooled);
    cudaGetSymbolAddress((void**)&gatew, g_gatew);

    f16 *xlnh, *xh, *qkvh, *sah, *ff1h, *sch, *retrph, *memh;
    f16 *ipwh, *opwh, *w1h, *w2h, *aggwh;
    cudaGetSymbolAddress((void**)&xlnh, g_xlnh);
    cudaGetSymbolAddress((void**)&xh, g_xh);
    cudaGetSymbolAddress((void**)&qkvh, g_qkvh);
    cudaGetSymbolAddress((void**)&sah, g_sah);
    cudaGetSymbolAddress((void**)&ff1h, g_ff1h);
    cudaGetSymbolAddress((void**)&sch, g_sch);
    cudaGetSymbolAddress((void**)&retrph, g_retrph);
    cudaGetSymbolAddress((void**)&memh, g_memh);
    cudaGetSymbolAddress((void**)&ipwh, g_ipwh);
    cudaGetSymbolAddress((void**)&opwh, g_opwh);
    cudaGetSymbolAddress((void**)&w1h, g_w1h);
    cudaGetSymbolAddress((void**)&w2h, g_w2h);
    cudaGetSymbolAddress((void**)&aggwh, g_aggwh);

    const float isd = 1.0f / sqrtf((float)DD);
    const long ND = (long)NTOK * DD;
    const long N3N = (long)NTOK * 3 * NTOK;
    const long NN = (long)NTOK * NTOK;
    const long NM = (long)NTOK * MMEM;

    // ---- fork side stream: weight/memory conversions ----
    cudaEventRecord(ev[0], 0);
    cudaStreamWaitEvent(s2, ev[0], 0);
    conv(ipw, ipwh, (long)EE * 3 * DD * DD, s2);
    conv(opw, opwh, (long)EE * DD * DD, s2);
    conv(w1, w1h, (long)EE * FFD * DD, s2);
    conv(w2, w2h, (long)EE * DD * FFD, s2);
    conv(aggw, aggwh, (long)DD * LL * DD, s2);
    conv(memories, memh, (long)LL * MMEM * DD, s2);
    cudaEventRecord(ev[1], s2);

    // ---- main: LN + cross attention ----
    ln_kernel<<<EE * NTOK, 128>>>(tokens, xln, nullptr, nullptr, xlnh, 0);

    // 1. cross scores -> f16 clipped, in-place softmax
    { GArgs a{}; a.Ah=xlnh; a.Bh=xlnh; a.Ch=sch;
      a.M=NTOK; a.N=3*NTOK; a.K=DD; a.Arow=DD; a.Brow=DD; a.ldc=3*NTOK;
      a.alpha=isd; a.ep=1; a.nRemap=1; a.thresh=-1; a.inner=1; a.batch=EE;
      a.Ao=ND; a.Co=N3N; hg(a); }
    smax(sch, EE * NTOK, 3 * NTOK);
    // 2. x = xln_e + P @ ctx  (B = xln native via TB, remap k per z)
    { GArgs a{}; a.Ah=sch; a.Bh=xlnh; a.C=x; a.Ch=xh;
      a.M=NTOK; a.N=DD; a.K=3*NTOK; a.Arow=3*NTOK; a.Brow=DD; a.ldc=DD;
      a.alpha=1.f; a.ep=6; a.R=xln; a.kRemap=1; a.thresh=-1; a.inner=1; a.batch=EE;
      a.Ao=N3N; a.Co=ND; a.TB=1; hg(a); }

    // join: qkv needs converted ipw
    cudaStreamWaitEvent(0, ev[1], 0);
    // 3. qkv
    { GArgs a{}; a.Ah=xh; a.Bh=ipwh; a.Ch=qkvh;
      a.M=NTOK; a.N=3*DD; a.K=DD; a.Arow=DD; a.Brow=DD; a.ldc=3*DD;
      a.alpha=1.f; a.ep=2; a.bias=ipb; a.biasZ=3*DD; a.inner=1; a.batch=EE;
      a.Ao=ND; a.Bo=(long)3*DD*DD; a.Co=(long)NTOK*3*DD; hg(a); }
    // 4. head scores -> f16, in-place softmax (z = e*H + h)
    { GArgs a{}; a.Ah=qkvh; a.Bh=qkvh + DD; a.Ch=sch;
      a.M=NTOK; a.N=NTOK; a.K=DHH; a.Arow=3*DD; a.Brow=3*DD; a.ldc=NTOK;
      a.alpha=0.125f; a.ep=0; a.inner=HH; a.batch=EE*HH;
      a.Ai=DHH; a.Ao=(long)NTOK*3*DD; a.Bi=DHH; a.Bo=(long)NTOK*3*DD;
      a.Ci=NN; a.Co=HH*NN; hg(a); }
    smax(sch, EE * HH * NTOK, NTOK);
    // 5. sa = P @ V  (B = V native [seq][dh] via TB; batch e*H+h)
    { GArgs a{}; a.Ah=sch; a.Bh=qkvh + 2*DD; a.Ch=sah;
      a.M=NTOK; a.N=DHH; a.K=NTOK; a.Arow=NTOK; a.Brow=3*DD; a.ldc=DD;
      a.alpha=1.f; a.ep=0; a.inner=HH; a.batch=EE*HH;
      a.Ai=NN; a.Ao=HH*NN; a.Bi=DHH; a.Bo=(long)NTOK*3*DD;
      a.Ci=DHH; a.Co=ND; a.TB=1; hg(a); }
    // 6. out_proj + bias + residual
    { GArgs a{}; a.Ah=sah; a.Bh=opwh; a.C=y;
      a.M=NTOK; a.N=DD; a.K=DD; a.Arow=DD; a.Brow=DD; a.ldc=DD;
      a.alpha=1.f; a.ep=4; a.bias=opb; a.biasZ=DD; a.R=x; a.inner=1; a.batch=EE;
      a.Ao=ND; a.Bo=(long)DD*DD; a.Co=ND; hg(a); }
    ln_kernel<<<EE * NTOK, 128>>>(y, x, n1w, n1b, xh, 1);
    // 7. FFN
    { GArgs a{}; a.Ah=xh; a.Bh=w1h; a.Ch=ff1h;
      a.M=NTOK; a.N=FFD; a.K=DD; a.Arow=DD; a.Brow=DD; a.ldc=FFD;
      a.alpha=1.f; a.ep=3; a.bias=b1; a.biasZ=FFD; a.inner=1; a.batch=EE;
      a.Ao=ND; a.Bo=(long)FFD*DD; a.Co=(long)NTOK*FFD; hg(a); }
    { GArgs a{}; a.Ah=ff1h; a.Bh=w2h; a.C=y;
      a.M=NTOK; a.N=DD; a.K=FFD; a.Arow=FFD; a.Brow=FFD; a.ldc=DD;
      a.alpha=1.f; a.ep=4; a.bias=b2; a.biasZ=DD; a.R=x; a.inner=1; a.batch=EE;
      a.Ao=(long)NTOK*FFD; a.Bo=(long)DD*FFD; a.Co=ND; hg(a); }
    ln_kernel<<<EE * NTOK, 128>>>(y, x, n2w, n2b, xh, 1);

    // 8. memory scores -> f16, in-place softmax (z = e*L + l)
    { GArgs a{}; a.Ah=xh; a.Bh=memh; a.Ch=sch;
      a.M=NTOK; a.N=MMEM; a.K=DD; a.Arow=DD; a.Brow=DD; a.ldc=MMEM;
      a.alpha=isd; a.ep=1; a.inner=LL; a.batch=EE*LL;
      a.Ai=0; a.Ao=ND; a.Bi=(long)MMEM*DD; a.Bo=0;
      a.Ci=NM; a.Co=LL*NM; hg(a); }
    smax(sch, EE * LL * NTOK, MMEM);

    // fork: upd GEMM (A = sch via TA, B = xh via TB) + newmem on side stream
    cudaEventRecord(ev[2], 0);
    cudaStreamWaitEvent(s2, ev[2], 0);
    { GArgs a{}; a.Ah=sch; a.Bh=xh; a.C=upd4;
      a.M=MMEM; a.N=DD; a.K=NTOK; a.Arow=MMEM; a.Brow=DD; a.ldc=DD;
      a.alpha=1.f; a.ep=7; a.inner=LL; a.batch=EE*LL;
      a.Ai=NM; a.Ao=LL*NM; a.Bi=0; a.Bo=ND;
      a.Ci=(long)MMEM*DD; a.Co=(long)LL*MMEM*DD; a.TA=1; a.TB=1; a.st=s2; hg(a); }
    {
        long n = (long)LL * MMEM * DD;
        newmem_kernel<<<(unsigned)((n + 255) / 256), 256, 0, s2>>>(memories, upd4, out + ND + EE);
    }
    cudaEventRecord(ev[3], s2);

    // main: retr (B = mem native via TB) -> retrph permuted, agg, pool/gate/fused
    { GArgs a{}; a.Ah=sch; a.Bh=memh; a.Ch=retrph;
      a.M=NTOK; a.N=DD; a.K=MMEM; a.Arow=MMEM; a.Brow=DD; a.ldc=LL*DD;
      a.alpha=1.f; a.ep=0; a.inner=LL; a.batch=EE*LL;
      a.Ai=NM; a.Ao=LL*NM; a.Bi=(long)MMEM*DD; a.Bo=0;
      a.Ci=DD; a.Co=(long)NTOK*LL*DD; a.TB=1; hg(a); }
    { GArgs a{}; a.Ah=retrph; a.Bh=aggwh; a.C=x;
      a.M=NTOK; a.N=DD; a.K=LL*DD; a.Arow=LL*DD; a.Brow=LL*DD; a.ldc=DD;
      a.alpha=1.f; a.ep=4; a.bias=aggb; a.biasZ=0; a.R=x; a.inner=1; a.batch=EE;
      a.Ao=(long)NTOK*LL*DD; a.Co=ND; hg(a); }

    pool_kernel<<<(EE * DD + 255) / 256, 256>>>(x, pooled);
    gate_kernel<<<1, 128>>>(pooled, gate, out + ND, gatew);
    fused_kernel<<<(unsigned)((ND + 255) / 256), 256>>>(x, gatew, out);

    // join side stream
    cudaStreamWaitEvent(0, ev[3], 0);
}

// round 14
// speedup vs baseline: 10.2678x; 1.0306x over previous
#include <cuda_runtime.h>
#include <cuda_fp16.h>
#include <math.h>
#include <stdint.h>

#define EE 4
#define NTOK 2048
#define DD 512
#define HH 8
#define DHH 64
#define FFD 2048
#define LL 4
#define MMEM 4096

typedef __half f16;

// ---------------- static scratch ----------------
__device__ float g_xln[EE * NTOK * DD];
__device__ float g_x[EE * NTOK * DD];
__device__ float g_y[EE * NTOK * DD];
__device__ float g_upd4[(size_t)EE * LL * MMEM * DD];
__device__ float g_pooled[EE * DD];
__device__ float g_gatew[EE];

__device__ f16 g_xlnh[EE * NTOK * DD];
__device__ f16 g_xh[EE * NTOK * DD];
__device__ f16 g_qkvh[EE * NTOK * 3 * DD];
__device__ f16 g_sah[EE * NTOK * DD];
__device__ f16 g_ff1h[EE * NTOK * FFD];
__device__ f16 g_sch[(size_t)EE * HH * NTOK * NTOK];   // scores in-place -> probs
__device__ f16 g_retrph[EE * NTOK * LL * DD];
__device__ f16 g_memh[LL * MMEM * DD];
__device__ f16 g_ipwh[EE * 3 * DD * DD];
__device__ f16 g_opwh[EE * DD * DD];
__device__ f16 g_w1h[EE * FFD * DD];
__device__ f16 g_w2h[EE * DD * FFD];
__device__ f16 g_aggwh[DD * LL * DD];

__device__ __forceinline__ uint32_t smem_u32(const void* p) {
    uint32_t a;
    asm("{ .reg .u64 t; cvta.to.shared.u64 t, %1; cvt.u32.u64 %0, t; }" : "=r"(a) : "l"(p));
    return a;
}

#define MMA16816(d, a0, a1, a2, a3, b0, b1) \
    asm volatile("mma.sync.aligned.m16n8k16.row.col.f32.f16.f16.f32 " \
                 "{%0,%1,%2,%3}, {%4,%5,%6,%7}, {%8,%9}, {%0,%1,%2,%3};" \
                 : "+f"((d)[0]), "+f"((d)[1]), "+f"((d)[2]), "+f"((d)[3]) \
                 : "r"(a0), "r"(a1), "r"(a2), "r"(a3), "r"(b0), "r"(b1))

#define LDSM4(r0, r1, r2, r3, addr) \
    asm volatile("ldmatrix.sync.aligned.m8n8.x4.shared.b16 {%0,%1,%2,%3}, [%4];" \
                 : "=r"(r0), "=r"(r1), "=r"(r2), "=r"(r3) : "r"(addr))

#define LDSM4T(r0, r1, r2, r3, addr) \
    asm volatile("ldmatrix.sync.aligned.m8n8.x4.trans.shared.b16 {%0,%1,%2,%3}, [%4];" \
                 : "=r"(r0), "=r"(r1), "=r"(r2), "=r"(r3) : "r"(addr))

#define CP16(dst, src) \
    asm volatile("cp.async.cg.shared.global [%0], [%1], 16;" :: "r"(dst), "l"(src))
#define CPCOMMIT() asm volatile("cp.async.commit_group;")
#define CPWAIT(n)  asm volatile("cp.async.wait_group %0;" :: "n"(n))

// ---------------- HMMA fp16 GEMM: cp.async + ldmatrix(+trans), 2-level batch -----
// z1 = z % inner, z2 = z / inner; offsets = z1*Xi + z2*Xo.
// C[m,n] = ep( alpha * sum_k a(m,k) * b(n,k) )   fp32 accumulate, fp16 operands.
// TA=0: A gmem [m][k] (k-contig). TA=1: A gmem [k][m] via ldsm.trans. Same for TB.
// nRemap (TB=0): B row n += NTOK when >= th.  kRemap: B k index += NTOK when >= th.
// th = thresh, or z2*NTOK when thresh < 0.
// ep: 0 none,1 clip±10,2 +bias,3 relu+bias,4 +bias+res,6 +res,7 clip±1
template<int BN, int STAGES, int TA, int TB>
__global__ void __launch_bounds__(256, 2) hgemm(
    const f16* __restrict__ Ahg, const f16* __restrict__ Bhg,
    float* __restrict__ C, f16* __restrict__ Ch,
    int Kdim, int Arow, int Brow, int ldc,
    float alpha, int ep,
    const float* __restrict__ bias, long biasZ, const float* __restrict__ Rres,
    int nRemap, int kRemap, int thresh, int inner,
    long Ai, long Ao, long Bi, long Bo, long Ci, long Co)
{
    constexpr int AST = 128 * 80;
    constexpr int BST = BN * 80;
    constexpr int NT = BN / 32;
    constexpr int BIT = BN / 64;
    constexpr int ASTR = 272;
    constexpr int BSTR = BN * 2 + 16;
    constexpr int BCH = BN / 8;

    const int z1 = blockIdx.z % inner;
    const int z2 = blockIdx.z / inner;
    Ahg += (long)z1 * Ai + (long)z2 * Ao;
    Bhg += (long)z1 * Bi + (long)z2 * Bo;
    const long coff = (long)z1 * Ci + (long)z2 * Co;
    if (C)  C  += coff;
    if (Ch) Ch += coff;
    if (Rres) Rres += coff;
    if (bias) bias += (long)z2 * biasZ;
    const int th = (thresh < 0) ? z2 * NTOK : thresh;

    extern __shared__ char sm[];
    const uint32_t smBase = smem_u32(sm);
    const uint32_t offAh = 0;
    const uint32_t offBh = STAGES * AST;

    const int tid = threadIdx.x;
    const int lane = tid & 31;
    const int wid = tid >> 5;
    const int wm = (wid >> 2) * 64;
    const int wn = (wid & 3) * (BN / 4);
    const int row0 = blockIdx.y * 128;
    const int col0 = blockIdx.x * BN;

    const int g = lane >> 3;
    const uint32_t laneOffA = TA
        ? ((lane & 7) + (g >> 1) * 8) * ASTR + (g & 1) * 16
        : ((g & 1) * 8 + (lane & 7)) * 80 + (g >> 1) * 16;
    const uint32_t laneOffB = TB
        ? ((lane & 7) + (g >> 1) * 8) * BSTR + (g & 1) * 16
        : ((g & 1) * 8 + (lane & 7)) * 80 + (g >> 1) * 16;

    float acc[4][NT][4];
    #pragma unroll
    for (int i = 0; i < 4; i++)
        #pragma unroll
        for (int j = 0; j < NT; j++)
            #pragma unroll
            for (int r = 0; r < 4; r++) acc[i][j][r] = 0.f;

    auto fill = [&](int s, int t) {
        int k0 = t * 32;
        if (!TA) {
            #pragma unroll
            for (int r = 0; r < 2; r++) {
                int idx = tid + r * 256;
                int row = idx >> 2, c = idx & 3;
                long go = (long)(row0 + row) * Arow + k0 + c * 8;
                CP16(smBase + offAh + s * AST + row * 80 + c * 16, Ahg + go);
            }
        } else {
            #pragma unroll
            for (int r = 0; r < 2; r++) {
                int idx = tid + r * 256;
                int row = idx >> 4, c = idx & 15;
                long go = (long)(k0 + row) * Arow + row0 + c * 8;
                CP16(smBase + offAh + s * AST + row * ASTR + c * 16, Ahg + go);
            }
        }
        if (!TB) {
            long kb = k0 + ((kRemap && k0 >= th) ? NTOK : 0);
            #pragma unroll
            for (int r = 0; r < BIT; r++) {
                int idx = tid + r * 256;
                int row = idx >> 2, c = idx & 3;
                int ng = col0 + row;
                if (nRemap && ng >= th) ng += NTOK;
                long go = (long)ng * Brow + kb + c * 8;
                CP16(smBase + offBh + s * BST + row * 80 + c * 16, Bhg + go);
            }
        } else {
            #pragma unroll
            for (int r = 0; r < BIT; r++) {
                int idx = tid + r * 256;
                int row = idx / BCH, c = idx % BCH;
                int kg = k0 + row;
                if (kRemap && kg >= th) kg += NTOK;
                long go = (long)kg * Brow + col0 + c * 8;
                CP16(smBase + offBh + s * BST + row * BSTR + c * 16, Bhg + go);
            }
        }
    };

    auto compute = [&](int buf) {
        const uint32_t aH = smBase + offAh + buf * AST + laneOffA;
        const uint32_t bH = smBase + offBh + buf * BST + laneOffB;
        #pragma unroll
        for (int s = 0; s < 2; s++) {
            uint32_t bh[NT][2];
            #pragma unroll
            for (int p = 0; p < NT / 2; p++) {
                uint32_t addr = TB ? bH + s * (16 * BSTR) + (wn + p * 16) * 2
                                   : bH + (wn + p * 16) * 80 + s * 32;
                if (TB) { LDSM4T(bh[2*p][0], bh[2*p+1][0], bh[2*p][1], bh[2*p+1][1], addr); }
                else    { LDSM4 (bh[2*p][0], bh[2*p+1][0], bh[2*p][1], bh[2*p+1][1], addr); }
            }
            #pragma unroll
            for (int mt = 0; mt < 4; mt++) {
                uint32_t a0, a1, a2, a3;
                uint32_t addr = TA ? aH + s * (16 * ASTR) + (wm + mt * 16) * 2
                                   : aH + (wm + mt * 16) * 80 + s * 32;
                if (TA) { LDSM4T(a0, a1, a2, a3, addr); }
                else    { LDSM4 (a0, a1, a2, a3, addr); }
                #pragma unroll
                for (int nt = 0; nt < NT; nt++)
                    MMA16816(acc[mt][nt], a0, a1, a2, a3, bh[nt][0], bh[nt][1]);
            }
        }
    };

    const int nk = Kdim / 32;
    #pragma unroll
    for (int s = 0; s < STAGES - 1; s++) {
        if (s < nk) fill(s, s);
        CPCOMMIT();
    }
    for (int t = 0; t < nk; t++) {
        CPWAIT(STAGES - 2);
        __syncthreads();
        int tn = t + STAGES - 1;
        if (tn < nk) fill(tn % STAGES, tn);
        CPCOMMIT();
        compute(t % STAGES);
    }

    // epilogue (vectorized: column pairs)
    #pragma unroll
    for (int mt = 0; mt < 4; mt++) {
        #pragma unroll
        for (int nt = 0; nt < NT; nt++) {
            int ng = col0 + wn + nt * 8 + (lane & 3) * 2;
            float2 b2 = make_float2(0.f, 0.f);
            if (ep >= 2 && ep <= 4) b2 = *(const float2*)(bias + ng);
            #pragma unroll
            for (int hf = 0; hf < 2; hf++) {
                int mg = row0 + wm + mt * 16 + (lane >> 2) + hf * 8;
                long ci = (long)mg * ldc + ng;
                float v0 = acc[mt][nt][hf * 2 + 0] * alpha;
                float v1 = acc[mt][nt][hf * 2 + 1] * alpha;
                switch (ep) {
                case 1:
                    v0 = fminf(fmaxf(v0, -10.f), 10.f);
                    v1 = fminf(fmaxf(v1, -10.f), 10.f); break;
                case 2: v0 += b2.x; v1 += b2.y; break;
                case 3:
                    v0 = fmaxf(v0 + b2.x, 0.f);
                    v1 = fmaxf(v1 + b2.y, 0.f); break;
                case 4: {
                    float2 r2 = *(const float2*)(Rres + ci);
                    v0 += b2.x + r2.x; v1 += b2.y + r2.y; } break;
                case 6: {
                    float2 r2 = *(const float2*)(Rres + ci);
                    v0 += r2.x; v1 += r2.y; } break;
                case 7:
                    v0 = fminf(fmaxf(v0, -1.f), 1.f);
                    v1 = fminf(fmaxf(v1, -1.f), 1.f); break;
                }
                if (C) *(float2*)(C + ci) = make_float2(v0, v1);
                if (Ch) *(__half2*)(Ch + ci) =
                    __halves2half2(__float2half_rn(v0), __float2half_rn(v1));
            }
        }
    }
}

// ---------------- elementwise kernels ----------------
__global__ void convert_kernel(const float* __restrict__ src, f16* __restrict__ h,
                               long n4h)
{
    long i = (long)blockIdx.x * blockDim.x + threadIdx.x;
    if (i >= n4h) return;
    #pragma unroll
    for (int r = 0; r < 2; r++) {
        long j = i + r * n4h;
        float4 v = ((const float4*)src)[j];
        __half2* h2 = (__half2*)h;
        h2[j * 2]     = __halves2half2(__float2half_rn(v.x), __float2half_rn(v.y));
        h2[j * 2 + 1] = __halves2half2(__float2half_rn(v.z), __float2half_rn(v.w));
    }
}

__global__ void ln_kernel(const float* __restrict__ in, float* __restrict__ out,
                          const float* __restrict__ w, const float* __restrict__ b,
                          f16* __restrict__ oh, int wsel)
{
    const long row = blockIdx.x;
    const float* p = in + row * DD;
    const int t = threadIdx.x; // 128
    __shared__ float sh[4];
    const long wo = wsel ? (row / NTOK) * DD : 0;

    float v[4];
    float s = 0.f;
    #pragma unroll
    for (int i = 0; i < 4; i++) { v[i] = p[t + i * 128]; s += v[i]; }
    #pragma unroll
    for (int o = 16; o; o >>= 1) s += __shfl_down_sync(0xffffffffu, s, o);
    if ((t & 31) == 0) sh[t >> 5] = s;
    __syncthreads();
    float mu = (sh[0] + sh[1] + sh[2] + sh[3]) * (1.f / DD);
    __syncthreads();
    float sq = 0.f;
    #pragma unroll
    for (int i = 0; i < 4; i++) { float d = v[i] - mu; sq += d * d; }
    #pragma unroll
    for (int o = 16; o; o >>= 1) sq += __shfl_down_sync(0xffffffffu, sq, o);
    if ((t & 31) == 0) sh[t >> 5] = sq;
    __syncthreads();
    float rstd = rsqrtf((sh[0] + sh[1] + sh[2] + sh[3]) * (1.f / DD) + 1e-5f);

    #pragma unroll
    for (int i = 0; i < 4; i++) {
        int d = t + i * 128;
        float o = (v[i] - mu) * rstd;
        if (w) o = o * w[wo + d] + b[wo + d];
        long gi = row * DD + d;
        if (out) out[gi] = o;
        oh[gi] = __float2half_rn(o);
    }
}

// 3-phase softmax, in-place on f16 row, single __expf per element.
// phase 1: f16 row -> fp32 smem, max reduce (no exp)
// phase 2: e = __expf(v - M) -> smem, sum reduce
// phase 3: write f16 probs = e * inv
__global__ void softmax_kernel(f16* __restrict__ S, int cols)
{
    extern __shared__ float srow[];
    f16* rowp = S + (long)blockIdx.x * cols;
    const uint4* row8 = (const uint4*)rowp;
    __half2* oh = (__half2*)rowp;
    const int t = threadIdx.x; // 256
    const int n8 = cols >> 3;
    const int n4 = cols >> 2;
    __shared__ float shr[8];

    // phase 1: load + max
    float m = -1e30f;
    for (int i = t; i < n8; i += 256) {
        uint4 u = row8[i];
        const __half2* hp = (const __half2*)&u;
        #pragma unroll
        for (int q = 0; q < 4; q++) {
            float2 f2 = __half22float2(hp[q]);
            srow[i * 8 + q * 2] = f2.x;
            srow[i * 8 + q * 2 + 1] = f2.y;
            m = fmaxf(m, fmaxf(f2.x, f2.y));
        }
    }
    #pragma unroll
    for (int o = 16; o; o >>= 1) m = fmaxf(m, __shfl_xor_sync(0xffffffffu, m, o));
    if ((t & 31) == 0) shr[t >> 5] = m;
    __syncthreads();
    if (t == 0) {
        float M = shr[0];
        #pragma unroll
        for (int w = 1; w < 8; w++) M = fmaxf(M, shr[w]);
        shr[0] = M;
    }
    __syncthreads();
    const float M = shr[0];
    __syncthreads();

    // phase 2: exp once + sum
    float s = 0.f;
    for (int i = t; i < n4; i += 256) {
        float e0 = __expf(srow[i * 4 + 0] - M);
        float e1 = __expf(srow[i * 4 + 1] - M);
        float e2 = __expf(srow[i * 4 + 2] - M);
        float e3 = __expf(srow[i * 4 + 3] - M);
        srow[i * 4 + 0] = e0; srow[i * 4 + 1] = e1;
        srow[i * 4 + 2] = e2; srow[i * 4 + 3] = e3;
        s += (e0 + e1) + (e2 + e3);
    }
    #pragma unroll
    for (int o = 16; o; o >>= 1) s += __shfl_xor_sync(0xffffffffu, s, o);
    if ((t & 31) == 0) shr[t >> 5] = s;
    __syncthreads();
    if (t == 0) {
        float Sm = 0.f;
        #pragma unroll
        for (int w = 0; w < 8; w++) Sm += shr[w];
        shr[0] = 1.f / Sm;
    }
    __syncthreads();
    const float inv = shr[0];

    // phase 3: scale + write f16
    for (int i = t; i < n4; i += 256) {
        float p0 = srow[i * 4 + 0] * inv, p1 = srow[i * 4 + 1] * inv;
        float p2 = srow[i * 4 + 2] * inv, p3 = srow[i * 4 + 3] * inv;
        oh[i * 2]     = __halves2half2(__float2half_rn(p0), __float2half_rn(p1));
        oh[i * 2 + 1] = __halves2half2(__float2half_rn(p2), __float2half_rn(p3));
    }
}

__global__ void pool_kernel(const float* __restrict__ x, float* __restrict__ pooled)
{
    int idx = blockIdx.x * blockDim.x + threadIdx.x;
    if (idx >= EE * DD) return;
    int e = idx / DD, d = idx % DD;
    const float* p = x + (long)e * NTOK * DD + d;
    float s = 0.f;
    #pragma unroll 16
    for (int n = 0; n < NTOK; n++) s += p[(long)n * DD];
    pooled[idx] = s * (1.f / NTOK);
}

__global__ void gate_kernel(const float* __restrict__ pooled, const float* __restrict__ gate,
                            float* __restrict__ out_gw, float* __restrict__ gdev)
{
    const int t = threadIdx.x;
    const int wid = t >> 5, lane = t & 31;
    __shared__ float logits[4];
    float s = 0.f;
    for (int d = lane; d < DD; d += 32) s += pooled[wid * DD + d] * gate[d];
    #pragma unroll
    for (int o = 16; o; o >>= 1) s += __shfl_down_sync(0xffffffffu, s, o);
    if (lane == 0) logits[wid] = fminf(fmaxf(s, -10.f), 10.f);
    __syncthreads();
    if (t == 0) {
        float mx = fmaxf(fmaxf(logits[0], logits[1]), fmaxf(logits[2], logits[3]));
        float e0 = expf(logits[0] - mx), e1 = expf(logits[1] - mx);
        float e2 = expf(logits[2] - mx), e3 = expf(logits[3] - mx);
        float inv = 1.f / (e0 + e1 + e2 + e3);
        out_gw[0] = gdev[0] = e0 * inv;
        out_gw[1] = gdev[1] = e1 * inv;
        out_gw[2] = gdev[2] = e2 * inv;
        out_gw[3] = gdev[3] = e3 * inv;
    }
}

__global__ void fused_kernel(const float* __restrict__ x, const float* __restrict__ gw,
                             float* __restrict__ out)
{
    long i = (long)blockIdx.x * blockDim.x + threadIdx.x;
    if (i >= (long)NTOK * DD) return;
    float s = 0.f;
    #pragma unroll
    for (int e = 0; e < EE; e++) s += gw[e] * x[(long)e * NTOK * DD + i];
    out[i] = s;
}

__global__ void newmem_kernel(const float* __restrict__ mem, const float* __restrict__ upd4,
                              float* __restrict__ out)
{
    long i = (long)blockIdx.x * blockDim.x + threadIdx.x;
    const long S = (long)LL * MMEM * DD;
    if (i >= S) return;
    float u = ((upd4[i] + upd4[i + S]) + upd4[i + 2 * S]) + upd4[i + 3 * S];
    u *= 0.1f;
    u = fminf(fmaxf(u, -0.1f), 0.1f);
    out[i] = 0.9f * mem[i] + u;
}

// ---------------- host-side launcher ----------------
struct GArgs {
    const f16 *Ah, *Bh;
    float* C; f16* Ch;
    int M, N, K, Arow, Brow, ldc;
    float alpha; int ep;
    const float* bias; long biasZ; const float* R;
    int nRemap, kRemap, thresh, inner, batch;
    long Ai, Ao, Bi, Bo, Ci, Co;
    int TA, TB;
    cudaStream_t st;
};

static void hg(const GArgs& a)
{
    #define HGCALL(BN, TA_, TB_, SMEM) \
        hgemm<BN, 4, TA_, TB_><<<grid, 256, SMEM, a.st>>>( \
            a.Ah, a.Bh, a.C, a.Ch, a.K, a.Arow, a.Brow, a.ldc, \
            a.alpha, a.ep, a.bias, a.biasZ, a.R, a.nRemap, a.kRemap, a.thresh, \
            a.inner, a.Ai, a.Ao, a.Bi, a.Bo, a.Ci, a.Co)
    if (a.N % 128 == 0) {
        dim3 grid(a.N / 128, a.M / 128, a.batch);
        if (a.TA)      HGCALL(128, 1, 1, 81920);
        else if (a.TB) HGCALL(128, 0, 1, 81920);
        else           HGCALL(128, 0, 0, 81920);
    } else {
        dim3 grid(a.N / 64, a.M / 128, a.batch);
        HGCALL(64, 0, 1, 61440);
    }
    #undef HGCALL
}

static void conv(const float* s, f16* h, long n, cudaStream_t st = 0)
{
    long n4h = n / 8;
    convert_kernel<<<(unsigned)((n4h + 255) / 256), 256, 0, st>>>(s, h, n4h);
}

static void smax(f16* s, int rows, int cols)
{
    softmax_kernel<<<rows, 256, cols * 4>>>(s, cols);
}

extern "C" void kernel_launch(void* const* d_in, const int* in_sizes, int n_in,
                              void* d_out, int out_size)
{
    const float* tokens   = (const float*)d_in[0];
    const float* memories = (const float*)d_in[1];
    const float* ipw      = (const float*)d_in[2];
    const float* ipb      = (const float*)d_in[3];
    const float* opw      = (const float*)d_in[4];
    const float* opb      = (const float*)d_in[5];
    const float* w1       = (const float*)d_in[6];
    const float* b1       = (const float*)d_in[7];
    const float* w2       = (const float*)d_in[8];
    const float* b2       = (const float*)d_in[9];
    const float* n1w      = (const float*)d_in[10];
    const float* n1b      = (const float*)d_in[11];
    const float* n2w      = (const float*)d_in[12];
    const float* n2b      = (const float*)d_in[13];
    const float* aggw     = (const float*)d_in[14];
    const float* aggb     = (const float*)d_in[15];
    const float* gate     = (const float*)d_in[16];
    float* out = (float*)d_out;

    static bool inited = false;
    static cudaStream_t s2;
    static cudaEvent_t ev[4];
    if (!inited) {
        cudaFuncSetAttribute((const void*)hgemm<128, 4, 0, 0>, cudaFuncAttributeMaxDynamicSharedMemorySize, 81920);
        cudaFuncSetAttribute((const void*)hgemm<128, 4, 0, 1>, cudaFuncAttributeMaxDynamicSharedMemorySize, 81920);
        cudaFuncSetAttribute((const void*)hgemm<128, 4, 1, 1>, cudaFuncAttributeMaxDynamicSharedMemorySize, 81920);
        cudaFuncSetAttribute((const void*)hgemm<64, 4, 0, 1>,  cudaFuncAttributeMaxDynamicSharedMemorySize, 61440);
        cudaStreamCreateWithFlags(&s2, cudaStreamNonBlocking);
        for (int i = 0; i < 4; i++) cudaEventCreateWithFlags(&ev[i], cudaEventDisableTiming);
        inited = true;
    }

    float *xln, *x, *y, *upd4, *pooled, *gatew;
    cudaGetSymbolAddress((void**)&xln, g_xln);
    cudaGetSymbolAddress((void**)&x, g_x);
    cudaGetSymbolAddress((void**)&y, g_y);
    cudaGetSymbolAddress((void**)&upd4, g_upd4);
    cudaGetSymbolAddress((void**)&pooled, g_pooled);
    cudaGetSymbolAddress((void**)&gatew, g_gatew);

    f16 *xlnh, *xh, *qkvh, *sah, *ff1h, *sch, *retrph, *memh;
    f16 *ipwh, *opwh, *w1h, *w2h, *aggwh;
    cudaGetSymbolAddress((void**)&xlnh, g_xlnh);
    cudaGetSymbolAddress((void**)&xh, g_xh);
    cudaGetSymbolAddress((void**)&qkvh, g_qkvh);
    cudaGetSymbolAddress((void**)&sah, g_sah);
    cudaGetSymbolAddress((void**)&ff1h, g_ff1h);
    cudaGetSymbolAddress((void**)&sch, g_sch);
    cudaGetSymbolAddress((void**)&retrph, g_retrph);
    cudaGetSymbolAddress((void**)&memh, g_memh);
    cudaGetSymbolAddress((void**)&ipwh, g_ipwh);
    cudaGetSymbolAddress((void**)&opwh, g_opwh);
    cudaGetSymbolAddress((void**)&w1h, g_w1h);
    cudaGetSymbolAddress((void**)&w2h, g_w2h);
    cudaGetSymbolAddress((void**)&aggwh, g_aggwh);

    const float isd = 1.0f / sqrtf((float)DD);
    const long ND = (long)NTOK * DD;
    const long N3N = (long)NTOK * 3 * NTOK;
    const long NN = (long)NTOK * NTOK;
    const long NM = (long)NTOK * MMEM;

    // ---- fork side stream: weight/memory conversions ----
    cudaEventRecord(ev[0], 0);
    cudaStreamWaitEvent(s2, ev[0], 0);
    conv(ipw, ipwh, (long)EE * 3 * DD * DD, s2);
    conv(opw, opwh, (long)EE * DD * DD, s2);
    conv(w1, w1h, (long)EE * FFD * DD, s2);
    conv(w2, w2h, (long)EE * DD * FFD, s2);
    conv(aggw, aggwh, (long)DD * LL * DD, s2);
    conv(memories, memh, (long)LL * MMEM * DD, s2);
    cudaEventRecord(ev[1], s2);

    // ---- main: LN + cross attention ----
    ln_kernel<<<EE * NTOK, 128>>>(tokens, xln, nullptr, nullptr, xlnh, 0);

    // 1. cross scores -> f16 clipped, in-place softmax
    { GArgs a{}; a.Ah=xlnh; a.Bh=xlnh; a.Ch=sch;
      a.M=NTOK; a.N=3*NTOK; a.K=DD; a.Arow=DD; a.Brow=DD; a.ldc=3*NTOK;
      a.alpha=isd; a.ep=1; a.nRemap=1; a.thresh=-1; a.inner=1; a.batch=EE;
      a.Ao=ND; a.Co=N3N; hg(a); }
    smax(sch, EE * NTOK, 3 * NTOK);
    // 2. x = xln_e + P @ ctx  (B = xln native via TB, remap k per z)
    { GArgs a{}; a.Ah=sch; a.Bh=xlnh; a.C=x; a.Ch=xh;
      a.M=NTOK; a.N=DD; a.K=3*NTOK; a.Arow=3*NTOK; a.Brow=DD; a.ldc=DD;
      a.alpha=1.f; a.ep=6; a.R=xln; a.kRemap=1; a.thresh=-1; a.inner=1; a.batch=EE;
      a.Ao=N3N; a.Co=ND; a.TB=1; hg(a); }

    // join: qkv needs converted ipw
    cudaStreamWaitEvent(0, ev[1], 0);
    // 3. qkv
    { GArgs a{}; a.Ah=xh; a.Bh=ipwh; a.Ch=qkvh;
      a.M=NTOK; a.N=3*DD; a.K=DD; a.Arow=DD; a.Brow=DD; a.ldc=3*DD;
      a.alpha=1.f; a.ep=2; a.bias=ipb; a.biasZ=3*DD; a.inner=1; a.batch=EE;
      a.Ao=ND; a.Bo=(long)3*DD*DD; a.Co=(long)NTOK*3*DD; hg(a); }
    // 4. head scores -> f16, in-place softmax (z = e*H + h)
    { GArgs a{}; a.Ah=qkvh; a.Bh=qkvh + DD; a.Ch=sch;
      a.M=NTOK; a.N=NTOK; a.K=DHH; a.Arow=3*DD; a.Brow=3*DD; a.ldc=NTOK;
      a.alpha=0.125f; a.ep=0; a.inner=HH; a.batch=EE*HH;
      a.Ai=DHH; a.Ao=(long)NTOK*3*DD; a.Bi=DHH; a.Bo=(long)NTOK*3*DD;
      a.Ci=NN; a.Co=HH*NN; hg(a); }
    smax(sch, EE * HH * NTOK, NTOK);
    // 5. sa = P @ V  (B = V native [seq][dh] via TB; batch e*H+h)
    { GArgs a{}; a.Ah=sch; a.Bh=qkvh + 2*DD; a.Ch=sah;
      a.M=NTOK; a.N=DHH; a.K=NTOK; a.Arow=NTOK; a.Brow=3*DD; a.ldc=DD;
      a.alpha=1.f; a.ep=0; a.inner=HH; a.batch=EE*HH;
      a.Ai=NN; a.Ao=HH*NN; a.Bi=DHH; a.Bo=(long)NTOK*3*DD;
      a.Ci=DHH; a.Co=ND; a.TB=1; hg(a); }
    // 6. out_proj + bias + residual
    { GArgs a{}; a.Ah=sah; a.Bh=opwh; a.C=y;
      a.M=NTOK; a.N=DD; a.K=DD; a.Arow=DD; a.Brow=DD; a.ldc=DD;
      a.alpha=1.f; a.ep=4; a.bias=opb; a.biasZ=DD; a.R=x; a.inner=1; a.batch=EE;
      a.Ao=ND; a.Bo=(long)DD*DD; a.Co=ND; hg(a); }
    ln_kernel<<<EE * NTOK, 128>>>(y, x, n1w, n1b, xh, 1);
    // 7. FFN
    { GArgs a{}; a.Ah=xh; a.Bh=w1h; a.Ch=ff1h;
      a.M=NTOK; a.N=FFD; a.K=DD; a.Arow=DD; a.Brow=DD; a.ldc=FFD;
      a.alpha=1.f; a.ep=3; a.bias=b1; a.biasZ=FFD; a.inner=1; a.batch=EE;
      a.Ao=ND; a.Bo=(long)FFD*DD; a.Co=(long)NTOK*FFD; hg(a); }
    { GArgs a{}; a.Ah=ff1h; a.Bh=w2h; a.C=y;
      a.M=NTOK; a.N=DD; a.K=FFD; a.Arow=FFD; a.Brow=FFD; a.ldc=DD;
      a.alpha=1.f; a.ep=4; a.bias=b2; a.biasZ=DD; a.R=x; a.inner=1; a.batch=EE;
      a.Ao=(long)NTOK*FFD; a.Bo=(long)DD*FFD; a.Co=ND; hg(a); }
    ln_kernel<<<EE * NTOK, 128>>>(y, x, n2w, n2b, xh, 1);

    // 8. memory scores -> f16, in-place softmax (z = e*L + l)
    { GArgs a{}; a.Ah=xh; a.Bh=memh; a.Ch=sch;
      a.M=NTOK; a.N=MMEM; a.K=DD; a.Arow=DD; a.Brow=DD; a.ldc=MMEM;
      a.alpha=isd; a.ep=1; a.inner=LL; a.batch=EE*LL;
      a.Ai=0; a.Ao=ND; a.Bi=(long)MMEM*DD; a.Bo=0;
      a.Ci=NM; a.Co=LL*NM; hg(a); }
    smax(sch, EE * LL * NTOK, MMEM);

    // fork: upd GEMM (A = sch via TA, B = xh via TB) + newmem on side stream
    cudaEventRecord(ev[2], 0);
    cudaStreamWaitEvent(s2, ev[2], 0);
    { GArgs a{}; a.Ah=sch; a.Bh=xh; a.C=upd4;
      a.M=MMEM; a.N=DD; a.K=NTOK; a.Arow=MMEM; a.Brow=DD; a.ldc=DD;
      a.alpha=1.f; a.ep=7; a.inner=LL; a.batch=EE*LL;
      a.Ai=NM; a.Ao=LL*NM; a.Bi=0; a.Bo=ND;
      a.Ci=(long)MMEM*DD; a.Co=(long)LL*MMEM*DD; a.TA=1; a.TB=1; a.st=s2; hg(a); }
    {
        long n = (long)LL * MMEM * DD;
        newmem_kernel<<<(unsigned)((n + 255) / 256), 256, 0, s2>>>(memories, upd4, out + ND + EE);
    }
    cudaEventRecord(ev[3], s2);

    // main: retr (B = mem native via TB) -> retrph permuted, agg, pool/gate/fused
    { GArgs a{}; a.Ah=sch; a.Bh=memh; a.Ch=retrph;
      a.M=NTOK; a.N=DD; a.K=MMEM; a.Arow=MMEM; a.Brow=DD; a.ldc=LL*DD;
      a.alpha=1.f; a.ep=0; a.inner=LL; a.batch=EE*LL;
      a.Ai=NM; a.Ao=LL*NM; a.Bi=(long)MMEM*DD; a.Bo=0;
      a.Ci=DD; a.Co=(long)NTOK*LL*DD; a.TB=1; hg(a); }
    { GArgs a{}; a.Ah=retrph; a.Bh=aggwh; a.C=x;
      a.M=NTOK; a.N=DD; a.K=LL*DD; a.Arow=LL*DD; a.Brow=LL*DD; a.ldc=DD;
      a.alpha=1.f; a.ep=4; a.bias=aggb; a.biasZ=0; a.R=x; a.inner=1; a.batch=EE;
      a.Ao=(long)NTOK*LL*DD; a.Co=ND; hg(a); }

    pool_kernel<<<(EE * DD + 255) / 256, 256>>>(x, pooled);
    gate_kernel<<<1, 128>>>(pooled, gate, out + ND, gatew);
    fused_kernel<<<(unsigned)((ND + 255) / 256), 256>>>(x, gatew, out);

    // join side stream
    cudaStreamWaitEvent(0, ev[3], 0);
}